// round 3
// baseline (speedup 1.0000x reference)
#include <cuda_runtime.h>
#include <cuda_bf16.h>

// ---------------------------------------------------------------------------
// LLaDAModel fused forward, fp32 SIMT baseline.
// B=8,S=2048,D=1024,H=2048,A=128,E=8.  N=B*S=16384 tokens.
//
// Pipeline (all launches on default stream, graph-capturable, no allocs):
//   0. M = w_out @ w_eproj                      [D,A]   (expert projection fused)
//   1. U    = x @ w_up^T                        [N,H]
//   2. Hid  = silu(x @ w_gate^T) * U            [N,H]
//   3. pre  = x @ w_pre^T                       [N,A]
//   4. ain  = LN(pre)                           [N,A]
//   5. pt   = Hid @ w_post^T                    [N,A]
//   6. aout = LN(pt)                            [N,A]
//   7. scr  = silu(clip(ain @ aout^T))  per b   [S,S]x8
//   8. adp  = scr @ ain                 per b   [N,A]
//   9. Hid += 0.1 * adp @ w_aproj^T             [N,H]
//  10. out  = Hid @ w_down^T                    [N,D]
//  11. out += 0.1 * expert(pre, last-positive-expert) @ M^T   (per token)
// ---------------------------------------------------------------------------

constexpr int B_ = 8, S_ = 2048, D_ = 1024, H_ = 2048, A_ = 128, E_ = 8;
constexpr int NTOK = B_ * S_;   // 16384

// Scratch (device globals: allocation-free rule)
__device__ float g_U  [(size_t)NTOK * H_];
__device__ float g_Hd [(size_t)NTOK * H_];
__device__ float g_pre[(size_t)NTOK * A_];
__device__ float g_ain[(size_t)NTOK * A_];
__device__ float g_pt [(size_t)NTOK * A_];
__device__ float g_aout[(size_t)NTOK * A_];
__device__ float g_adp[(size_t)NTOK * A_];
__device__ float g_scr[(size_t)B_ * S_ * S_];
__device__ float g_M  [(size_t)D_ * A_];

__device__ __forceinline__ float siluf(float x) {
    return x * (1.0f / (1.0f + __expf(-x)));
}

// ---------------------------------------------------------------------------
// Tiled SGEMM: C[M,N] = A[M,K] * op(B)^T
//   NN=false: B is [N,K] row-major (K-contiguous both sides)
//   NN=true : B is [K,N] row-major
// BN=128, BK=8, TN=8 fixed; BM/TM templated (128/8 or 64/4); 256 threads.
// Epilogues:
//   0: C = acc
//   1: C = silu(acc) * aux[idx]
//   2: C = aux[idx] + 0.1*acc     (in-place accumulate when aux==C)
//   3: C = silu(clip(acc,-5,5))
// Batched via blockIdx.z with strides sA/sB/sC.
// ---------------------------------------------------------------------------
template<int BM, int TM, int EPI, bool NN>
__global__ void __launch_bounds__(256) gemm_k(
    const float* __restrict__ A, const float* __restrict__ Bm,
    float* __restrict__ C, const float* __restrict__ aux,
    int M, int N, int K, long sA, long sB, long sC)
{
    constexpr int BN = 128, BK = 8, TN = 8;
    __shared__ float As[BK][BM];
    __shared__ float Bs[BK][BN];

    const long zb = blockIdx.z;
    A  += zb * sA;
    Bm += zb * sB;
    C  += zb * sC;
    const float* auxp = aux ? aux + zb * sC : nullptr;

    const int m0 = blockIdx.y * BM;
    const int n0 = blockIdx.x * BN;
    const int tid = threadIdx.x;
    const int tx = tid & 15;          // 16 col groups
    const int ty = tid >> 4;          // BM/TM row groups
    const int cA = tx * 4;            // first 4 columns
    const int cB = 64 + tx * 4;       // second 4 columns (bank-conflict-free split)

    float acc[TM][TN];
#pragma unroll
    for (int i = 0; i < TM; i++)
#pragma unroll
        for (int j = 0; j < TN; j++) acc[i][j] = 0.f;

    for (int k0 = 0; k0 < K; k0 += BK) {
        // A tile: BM x 8, float4 along K, transposed into As
        for (int i = tid; i < BM * 2; i += 256) {
            int r = i >> 1, c4 = (i & 1) << 2;
            float4 v = *(const float4*)(A + (long)(m0 + r) * K + k0 + c4);
            As[c4 + 0][r] = v.x; As[c4 + 1][r] = v.y;
            As[c4 + 2][r] = v.z; As[c4 + 3][r] = v.w;
        }
        if (!NN) {
            // B tile: 128 x 8 from [N,K], transposed
            for (int i = tid; i < 256; i += 256) {
                int r = i >> 1, c4 = (i & 1) << 2;
                float4 v = *(const float4*)(Bm + (long)(n0 + r) * K + k0 + c4);
                Bs[c4 + 0][r] = v.x; Bs[c4 + 1][r] = v.y;
                Bs[c4 + 2][r] = v.z; Bs[c4 + 3][r] = v.w;
            }
        } else {
            // B tile: 8 x 128 from [K,N], direct
            for (int i = tid; i < 256; i += 256) {
                int kk = i >> 5, c = (i & 31) << 2;
                *(float4*)&Bs[kk][c] =
                    *(const float4*)(Bm + (long)(k0 + kk) * N + n0 + c);
            }
        }
        __syncthreads();

#pragma unroll
        for (int kk = 0; kk < BK; kk++) {
            float ra[TM], rb[TN];
#pragma unroll
            for (int i = 0; i < TM; i++) ra[i] = As[kk][ty * TM + i];
#pragma unroll
            for (int j = 0; j < 4; j++) { rb[j] = Bs[kk][cA + j]; rb[j + 4] = Bs[kk][cB + j]; }
#pragma unroll
            for (int i = 0; i < TM; i++)
#pragma unroll
                for (int j = 0; j < TN; j++)
                    acc[i][j] = fmaf(ra[i], rb[j], acc[i][j]);
        }
        __syncthreads();
    }

    // Epilogue
#pragma unroll
    for (int i = 0; i < TM; i++) {
        const long rowb = (long)(m0 + ty * TM + i) * N;
#pragma unroll
        for (int half = 0; half < 2; half++) {
            const long base = rowb + n0 + (half ? cB : cA);
            const int j0 = half * 4;
            float4 ax;
            if (EPI == 1 || EPI == 2) ax = *(const float4*)(auxp + base);
            float o[4];
            const float axa[4] = {ax.x, ax.y, ax.z, ax.w};
#pragma unroll
            for (int e = 0; e < 4; e++) {
                float t = acc[i][j0 + e];
                if (EPI == 0)      o[e] = t;
                else if (EPI == 1) o[e] = siluf(t) * axa[e];
                else if (EPI == 2) o[e] = fmaf(0.1f, t, axa[e]);
                else { t = fminf(fmaxf(t, -5.f), 5.f); o[e] = siluf(t); }
            }
            *(float4*)(C + base) = make_float4(o[0], o[1], o[2], o[3]);
        }
    }
}

// ---------------------------------------------------------------------------
// LayerNorm over rows of length 128 (one warp per row), y = (x-m)*rsqrt(v+eps)*g+b
// ---------------------------------------------------------------------------
__global__ void ln_k(const float* __restrict__ X, float* __restrict__ Y,
                     const float* __restrict__ g, const float* __restrict__ b,
                     int rows)
{
    int row  = (blockIdx.x * blockDim.x + threadIdx.x) >> 5;
    int lane = threadIdx.x & 31;
    if (row >= rows) return;
    float4 x = *(const float4*)(X + (long)row * 128 + lane * 4);
    float s  = x.x + x.y + x.z + x.w;
    float ss = fmaf(x.x, x.x, fmaf(x.y, x.y, fmaf(x.z, x.z, x.w * x.w)));
#pragma unroll
    for (int o = 16; o > 0; o >>= 1) {
        s  += __shfl_xor_sync(0xffffffffu, s,  o);
        ss += __shfl_xor_sync(0xffffffffu, ss, o);
    }
    float m   = s * (1.f / 128.f);
    float inv = rsqrtf(ss * (1.f / 128.f) - m * m + 1e-5f);
    float4 gg = *(const float4*)(g + lane * 4);
    float4 bb = *(const float4*)(b + lane * 4);
    float4 y;
    y.x = fmaf((x.x - m) * inv, gg.x, bb.x);
    y.y = fmaf((x.y - m) * inv, gg.y, bb.y);
    y.z = fmaf((x.z - m) * inv, gg.z, bb.z);
    y.w = fmaf((x.w - m) * inv, gg.w, bb.w);
    *(float4*)(Y + (long)row * 128 + lane * 4) = y;
}

// ---------------------------------------------------------------------------
// M[d,a] = sum_h w_out[d,h] * w_eproj[h,a].  Block = 8 d-rows, 256 threads.
// ---------------------------------------------------------------------------
__global__ void __launch_bounds__(256) mmat_k(
    const float* __restrict__ w_out, const float* __restrict__ w_eproj,
    float* __restrict__ Mo)
{
    __shared__ float ws[8][64];
    const int d0 = blockIdx.x * 8;
    const int a  = threadIdx.x & 127;
    const int ds = threadIdx.x >> 7;   // 0..1
    float acc[4] = {0.f, 0.f, 0.f, 0.f};
    for (int h0 = 0; h0 < H_; h0 += 64) {
        for (int i = threadIdx.x; i < 512; i += 256) {
            int r = i >> 6, c = i & 63;
            ws[r][c] = w_out[(long)(d0 + r) * H_ + h0 + c];
        }
        __syncthreads();
        for (int hh = 0; hh < 64; hh++) {
            float e = w_eproj[(long)(h0 + hh) * A_ + a];
#pragma unroll
            for (int j = 0; j < 4; j++)
                acc[j] = fmaf(ws[ds * 4 + j][hh], e, acc[j]);
        }
        __syncthreads();
    }
#pragma unroll
    for (int j = 0; j < 4; j++)
        Mo[(long)(d0 + ds * 4 + j) * A_ + a] = acc[j];
}

// ---------------------------------------------------------------------------
// Expert kernel: per token n, idx = LAST expert with ew>0 (masked-overwrite
// semantics → later experts win).  c = LN(pre @ w_exp[idx]^T, eln[idx]);
// out[n,:] += 0.1 * c @ M^T.   16 tokens/block, 128 threads.
// ---------------------------------------------------------------------------
__global__ void __launch_bounds__(128) expert_k(
    const float* __restrict__ pre, const float* __restrict__ ew,
    const float* __restrict__ w_exp, const float* __restrict__ eg,
    const float* __restrict__ eb, const float* __restrict__ Mm,
    float* __restrict__ out)
{
    __shared__ float cs[16][132];                       // normalized c, padded
    __shared__ union { float pre_s[16][128]; float Ms[64][132]; } u;
    __shared__ int sidx[16];

    const int tid = threadIdx.x;
    const int n0  = blockIdx.x * 16;

    if (tid < 16) {
        const float* e = ew + (long)(n0 + tid) * E_;
        int best = -1;
#pragma unroll
        for (int i = 0; i < E_; i++) if (e[i] > 0.f) best = i;
        sidx[tid] = best;
    }
    for (int i = tid; i < 16 * 32; i += 128) {
        int r = i >> 5, a4 = (i & 31) << 2;
        *(float4*)&u.pre_s[r][a4] = *(const float4*)(pre + (long)(n0 + r) * A_ + a4);
    }
    __syncthreads();

    {   // c = pre @ w_exp[idx]^T  +  LN(eln[idx])
        const int tt = tid >> 3, g = tid & 7;   // token, 16-col group
        const int idx = sidx[tt];
        float cr[16];
        if (idx >= 0) {
            const float*  wb = w_exp + ((long)idx * A_ + g * 16) * A_;
            const float4* pr = (const float4*)&u.pre_s[tt][0];
#pragma unroll 2
            for (int q = 0; q < 16; q++) {
                const float4* wr = (const float4*)(wb + q * A_);
                float aq = 0.f;
#pragma unroll 8
                for (int a4 = 0; a4 < 32; a4++) {
                    float4 w = wr[a4], p = pr[a4];
                    aq = fmaf(w.x, p.x, aq); aq = fmaf(w.y, p.y, aq);
                    aq = fmaf(w.z, p.z, aq); aq = fmaf(w.w, p.w, aq);
                }
                cr[q] = aq;
            }
        } else {
#pragma unroll
            for (int q = 0; q < 16; q++) cr[q] = 0.f;
        }
        float s = 0.f, ss = 0.f;
#pragma unroll
        for (int q = 0; q < 16; q++) { s += cr[q]; ss = fmaf(cr[q], cr[q], ss); }
#pragma unroll
        for (int o = 4; o > 0; o >>= 1) {
            s  += __shfl_xor_sync(0xffffffffu, s,  o, 8);
            ss += __shfl_xor_sync(0xffffffffu, ss, o, 8);
        }
        float mean = s * (1.f / 128.f);
        float inv  = rsqrtf(ss * (1.f / 128.f) - mean * mean + 1e-5f);
        if (idx >= 0) {
            const float* gg = eg + (long)idx * A_ + g * 16;
            const float* bb = eb + (long)idx * A_ + g * 16;
#pragma unroll
            for (int q = 0; q < 16; q++)
                cs[tt][g * 16 + q] = fmaf((cr[q] - mean) * inv, gg[q], bb[q]);
        } else {
#pragma unroll
            for (int q = 0; q < 16; q++) cs[tt][g * 16 + q] = 0.f;
        }
    }

    // out += 0.1 * cs @ M^T, M staged in smem 64 d-rows at a time
    const int drel = tid & 63, th = tid >> 6;
    for (int T = 0; T < 16; T++) {
        __syncthreads();   // also guards the pre_s -> Ms union switch at T=0
        for (int i = tid; i < 64 * 32; i += 128) {
            int r = i >> 5, a4 = (i & 31) << 2;
            *(float4*)&u.Ms[r][a4] =
                *(const float4*)(Mm + (long)(T * 64 + r) * A_ + a4);
        }
        __syncthreads();
        float acc[8] = {0.f,0.f,0.f,0.f,0.f,0.f,0.f,0.f};
#pragma unroll 4
        for (int a4 = 0; a4 < 32; a4++) {
            float4 m = *(const float4*)&u.Ms[drel][a4 << 2];
#pragma unroll
            for (int j = 0; j < 8; j++) {
                float4 c = *(const float4*)&cs[th * 8 + j][a4 << 2];
                acc[j] = fmaf(m.x, c.x, acc[j]); acc[j] = fmaf(m.y, c.y, acc[j]);
                acc[j] = fmaf(m.z, c.z, acc[j]); acc[j] = fmaf(m.w, c.w, acc[j]);
            }
        }
#pragma unroll
        for (int j = 0; j < 8; j++) {
            long n = n0 + th * 8 + j;
            long oidx = n * (long)D_ + T * 64 + drel;
            out[oidx] += 0.1f * acc[j];
        }
    }
}

// ---------------------------------------------------------------------------
extern "C" void kernel_launch(void* const* d_in, const int* in_sizes, int n_in,
                              void* d_out, int out_size)
{
    const float* x       = (const float*)d_in[0];
    const float* ew      = (const float*)d_in[1];
    const float* w_up    = (const float*)d_in[2];
    const float* w_gate  = (const float*)d_in[3];
    const float* w_down  = (const float*)d_in[4];
    const float* w_pre   = (const float*)d_in[5];
    const float* w_post  = (const float*)d_in[6];
    const float* an_g    = (const float*)d_in[7];
    const float* an_b    = (const float*)d_in[8];
    const float* w_aproj = (const float*)d_in[9];
    const float* w_exp   = (const float*)d_in[10];
    const float* eln_g   = (const float*)d_in[11];
    const float* eln_b   = (const float*)d_in[12];
    const float* w_eproj = (const float*)d_in[13];
    const float* w_out   = (const float*)d_in[14];
    float* out = (float*)d_out;

    float *U, *Hd, *pre, *ain, *pt, *aout, *adp, *scr, *Mm;
    cudaGetSymbolAddress((void**)&U,    g_U);
    cudaGetSymbolAddress((void**)&Hd,   g_Hd);
    cudaGetSymbolAddress((void**)&pre,  g_pre);
    cudaGetSymbolAddress((void**)&ain,  g_ain);
    cudaGetSymbolAddress((void**)&pt,   g_pt);
    cudaGetSymbolAddress((void**)&aout, g_aout);
    cudaGetSymbolAddress((void**)&adp,  g_adp);
    cudaGetSymbolAddress((void**)&scr,  g_scr);
    cudaGetSymbolAddress((void**)&Mm,   g_M);

    // 0. Fused expert projection M = w_out @ w_eproj  [D,A]
    mmat_k<<<D_ / 8, 256>>>(w_out, w_eproj, Mm);

    // 1. U = x @ w_up^T
    gemm_k<128,8,0,false><<<dim3(H_/128, NTOK/128, 1), 256>>>(
        x, w_up, U, nullptr, NTOK, H_, D_, 0, 0, 0);

    // 2. Hid = silu(x @ w_gate^T) * U
    gemm_k<128,8,1,false><<<dim3(H_/128, NTOK/128, 1), 256>>>(
        x, w_gate, Hd, U, NTOK, H_, D_, 0, 0, 0);

    // 3. pre = x @ w_pre^T
    gemm_k<64,4,0,false><<<dim3(1, NTOK/64, 1), 256>>>(
        x, w_pre, pre, nullptr, NTOK, A_, D_, 0, 0, 0);

    // 4. ain = LN(pre)
    ln_k<<<NTOK/8, 256>>>(pre, ain, an_g, an_b, NTOK);

    // 5. pt = Hid @ w_post^T
    gemm_k<64,4,0,false><<<dim3(1, NTOK/64, 1), 256>>>(
        Hd, w_post, pt, nullptr, NTOK, A_, H_, 0, 0, 0);

    // 6. aout = LN(pt)
    ln_k<<<NTOK/8, 256>>>(pt, aout, an_g, an_b, NTOK);

    // 7. scr[b] = silu(clip(ain[b] @ aout[b]^T))    (batched, z = batch)
    gemm_k<128,8,3,false><<<dim3(S_/128, S_/128, B_), 256>>>(
        ain, aout, scr, nullptr, S_, S_, A_,
        (long)S_ * A_, (long)S_ * A_, (long)S_ * S_);

    // 8. adp[b] = scr[b] @ ain[b]                   (NN form, batched)
    gemm_k<64,4,0,true><<<dim3(1, S_/64, B_), 256>>>(
        scr, ain, adp, nullptr, S_, A_, S_,
        (long)S_ * S_, (long)S_ * A_, (long)S_ * A_);

    // 9. Hid += 0.1 * adp @ w_aproj^T
    gemm_k<128,8,2,false><<<dim3(H_/128, NTOK/128, 1), 256>>>(
        adp, w_aproj, Hd, Hd, NTOK, H_, A_, 0, 0, 0);

    // 10. out = Hid @ w_down^T
    gemm_k<128,8,0,false><<<dim3(D_/128, NTOK/128, 1), 256>>>(
        Hd, w_down, out, nullptr, NTOK, D_, H_, 0, 0, 0);

    // 11. out += 0.1 * expert path
    expert_k<<<NTOK/16, 128>>>(pre, ew, w_exp, eln_g, eln_b, Mm, out);
}

// round 4
// speedup vs baseline: 1.8735x; 1.8735x over previous
#include <cuda_runtime.h>
#include <cuda_bf16.h>

// ---------------------------------------------------------------------------
// LLaDAModel fused forward.  Tensor-core (mma.sync bf16x2-split) GEMMs.
// B=8,S=2048,D=1024,H=2048,A=128,E=8.  N=16384 tokens.
//
//   0.  M = w_out @ w_eproj                       [D,A]
//   s.  split x / weights into bf16 (hi,lo) pairs
//   1.  U    = x @ w_up^T                         [N,H]   (tensor)
//   2.  Hid  = silu(x @ w_gate^T) * U  (+split)   [N,H]   (tensor)
//   3.  pre  = x @ w_pre^T                        [N,A]   (tensor)
//   4.  ain  = LN(pre)              (+split)      [N,A]
//   5.  pt   = Hid @ w_post^T                     [N,A]   (tensor)
//   6.  aout = LN(pt)               (+split)      [N,A]
//   7.  scr  = silu(clip(ain @ aout^T))  per b    [S,S]x8 (tensor)
//   8.  adp  = scr @ ain                 per b    [N,A]   (SIMT, NN layout)
//   8b. split adp
//   9.  Hid += 0.1 * adp @ w_aproj^T (+split)     [N,H]   (tensor)
//  10.  out  = Hid @ w_down^T                     [N,D]   (tensor)
//  11.  out += 0.1 * expert(pre, last-positive) @ M^T
// ---------------------------------------------------------------------------

constexpr int B_ = 8, S_ = 2048, D_ = 1024, H_ = 2048, A_ = 128, E_ = 8;
constexpr int NTOK = B_ * S_;   // 16384

// fp32 scratch
__device__ float g_U   [(size_t)NTOK * H_];
__device__ float g_Hd  [(size_t)NTOK * H_];
__device__ float g_pre [(size_t)NTOK * A_];
__device__ float g_ain [(size_t)NTOK * A_];
__device__ float g_pt  [(size_t)NTOK * A_];
__device__ float g_aout[(size_t)NTOK * A_];
__device__ float g_adp [(size_t)NTOK * A_];
__device__ float g_scr [(size_t)B_ * S_ * S_];
__device__ float g_M   [(size_t)D_ * A_];

// bf16 split scratch (hi/lo)
__device__ __nv_bfloat16 g_xh[(size_t)NTOK * D_],  g_xl[(size_t)NTOK * D_];
__device__ __nv_bfloat16 g_Hdh[(size_t)NTOK * H_], g_Hdl[(size_t)NTOK * H_];
__device__ __nv_bfloat16 g_ainh[(size_t)NTOK * A_], g_ainl[(size_t)NTOK * A_];
__device__ __nv_bfloat16 g_aouth[(size_t)NTOK * A_], g_aoutl[(size_t)NTOK * A_];
__device__ __nv_bfloat16 g_adph[(size_t)NTOK * A_], g_adpl[(size_t)NTOK * A_];
__device__ __nv_bfloat16 g_wuph[(size_t)H_ * D_],  g_wupl[(size_t)H_ * D_];
__device__ __nv_bfloat16 g_wgh [(size_t)H_ * D_],  g_wgl [(size_t)H_ * D_];
__device__ __nv_bfloat16 g_wdh [(size_t)D_ * H_],  g_wdl [(size_t)D_ * H_];
__device__ __nv_bfloat16 g_wpreh[(size_t)A_ * D_], g_wprel[(size_t)A_ * D_];
__device__ __nv_bfloat16 g_wpoh[(size_t)A_ * H_],  g_wpol[(size_t)A_ * H_];
__device__ __nv_bfloat16 g_waph[(size_t)H_ * A_],  g_wapl[(size_t)H_ * A_];

__device__ __forceinline__ float siluf(float x) {
    return x * (1.0f / (1.0f + __expf(-x)));
}

// ---------------------------------------------------------------------------
// Elementwise fp32 -> (bf16 hi, bf16 lo) split, float4 vectorized
// ---------------------------------------------------------------------------
__global__ void split_k(const float* __restrict__ X,
                        __nv_bfloat16* __restrict__ Hh,
                        __nv_bfloat16* __restrict__ Hl, long n4)
{
    long i = blockIdx.x * (long)blockDim.x + threadIdx.x;
    if (i >= n4) return;
    float4 v = ((const float4*)X)[i];
    __nv_bfloat162 h0, h1, l0, l1;
    h0.x = __float2bfloat16(v.x); l0.x = __float2bfloat16(v.x - __bfloat162float(h0.x));
    h0.y = __float2bfloat16(v.y); l0.y = __float2bfloat16(v.y - __bfloat162float(h0.y));
    h1.x = __float2bfloat16(v.z); l1.x = __float2bfloat16(v.z - __bfloat162float(h1.x));
    h1.y = __float2bfloat16(v.w); l1.y = __float2bfloat16(v.w - __bfloat162float(h1.y));
    ((__nv_bfloat162*)Hh)[2*i]   = h0; ((__nv_bfloat162*)Hh)[2*i+1] = h1;
    ((__nv_bfloat162*)Hl)[2*i]   = l0; ((__nv_bfloat162*)Hl)[2*i+1] = l1;
}

// ---------------------------------------------------------------------------
// Tensor-core GEMM: C[M,N](fp32) = split(A)[M,K] @ split(B)[N,K]^T
// A,B given as bf16 hi/lo pairs; acc = Ah*Bh + Ah*Bl + Al*Bh in fp32.
// CTA tile 128x128x32, 8 warps (4x2), warp tile 32x64, m16n8k16 mma.
// Double-buffered cp.async; smem rows padded to 80B (conflict-free ldmatrix).
// EPI: 0: C=acc   1: C=silu(acc)*aux   2: C=aux+0.1*acc   3: C=silu(clip(acc))
// WSPLIT: additionally write bf16 hi/lo of C.
// Batched via blockIdx.z (element strides sA,sB,sC).
// ---------------------------------------------------------------------------
#define LDSM4(r0,r1,r2,r3,addr) \
    asm volatile("ldmatrix.sync.aligned.m8n8.x4.shared.b16 {%0,%1,%2,%3},[%4];\n" \
        : "=r"(r0),"=r"(r1),"=r"(r2),"=r"(r3) : "r"(addr))

#define MMA16816(c,a,b) \
    asm volatile("mma.sync.aligned.m16n8k16.row.col.f32.bf16.bf16.f32 " \
        "{%0,%1,%2,%3},{%4,%5,%6,%7},{%8,%9},{%0,%1,%2,%3};\n" \
        : "+f"((c)[0]),"+f"((c)[1]),"+f"((c)[2]),"+f"((c)[3]) \
        : "r"((a)[0]),"r"((a)[1]),"r"((a)[2]),"r"((a)[3]),"r"((b)[0]),"r"((b)[1]))

#define CPA16(dst,src) \
    asm volatile("cp.async.cg.shared.global [%0],[%1],16;\n" :: "r"(dst),"l"(src))

constexpr int TG_STAGE = 40960;          // bytes per pipeline stage
constexpr int TG_SMEM  = 2 * TG_STAGE;   // 80 KB dynamic smem

template<int EPI, bool WSPLIT>
__global__ void __launch_bounds__(256, 1) tgemm_k(
    const __nv_bfloat16* __restrict__ Ah, const __nv_bfloat16* __restrict__ Al,
    const __nv_bfloat16* __restrict__ Bh, const __nv_bfloat16* __restrict__ Bl,
    float* __restrict__ C, const float* __restrict__ aux,
    __nv_bfloat16* __restrict__ Ch, __nv_bfloat16* __restrict__ Cl,
    int M, int N, int K, long sA, long sB, long sC)
{
    extern __shared__ char smem[];
    const unsigned sbase = (unsigned)__cvta_generic_to_shared(smem);
    const int tid = threadIdx.x, lane = tid & 31, warp = tid >> 5;
    const int wm = warp >> 1, wn = warp & 1;

    const long z = blockIdx.z;
    Ah += z * sA; Al += z * sA; Bh += z * sB; Bl += z * sB; C += z * sC;
    const float* auxp = (EPI == 1 || EPI == 2) ? aux + z * sC : nullptr;

    const int m0 = blockIdx.y * 128, n0 = blockIdx.x * 128;
    const int KT = K / 32;

    float acc[2][8][4];
#pragma unroll
    for (int i = 0; i < 2; i++)
#pragma unroll
        for (int j = 0; j < 8; j++)
#pragma unroll
            for (int e = 0; e < 4; e++) acc[i][j][e] = 0.f;

    // per-thread ldmatrix base byte offsets within a stage
    const unsigned aAddr = (unsigned)((wm * 32 + (lane & 15)) * 80 + (lane >> 4) * 16);
    const unsigned bAddr = (unsigned)(20480 +
        (wn * 64 + ((lane >> 4) << 3) + (lane & 7)) * 80 + ((lane >> 3) & 1) * 16);

    auto issue = [&](int kt, int s) {
        const long k0 = (long)kt * 32;
        const unsigned st = sbase + s * TG_STAGE;
#pragma unroll
        for (int i = tid; i < 512; i += 256) {
            const int r = i >> 2, c = i & 3;
            const unsigned da = st + r * 80 + c * 16;
            const long  ga = (long)(m0 + r) * K + k0 + c * 8;
            CPA16(da,          Ah + ga);
            CPA16(da + 10240,  Al + ga);
            const unsigned db = st + 20480 + r * 80 + c * 16;
            const long  gb = (long)(n0 + r) * K + k0 + c * 8;
            CPA16(db,          Bh + gb);
            CPA16(db + 10240,  Bl + gb);
        }
        asm volatile("cp.async.commit_group;\n");
    };

    issue(0, 0);
    for (int kt = 0; kt < KT; ++kt) {
        asm volatile("cp.async.wait_group 0;\n");
        __syncthreads();
        if (kt + 1 < KT) issue(kt + 1, (kt + 1) & 1);

        const unsigned st = sbase + (kt & 1) * TG_STAGE;
#pragma unroll
        for (int kk = 0; kk < 2; kk++) {
            const unsigned ko = kk * 32;
            unsigned ah[2][4], al[2][4], bh[8][2], bl[8][2];
#pragma unroll
            for (int im = 0; im < 2; im++) {
                LDSM4(ah[im][0], ah[im][1], ah[im][2], ah[im][3],
                      st + aAddr + im * 1280 + ko);
                LDSM4(al[im][0], al[im][1], al[im][2], al[im][3],
                      st + 10240 + aAddr + im * 1280 + ko);
            }
#pragma unroll
            for (int jp = 0; jp < 4; jp++) {
                LDSM4(bh[2*jp][0], bh[2*jp][1], bh[2*jp+1][0], bh[2*jp+1][1],
                      st + bAddr + jp * 1280 + ko);
                LDSM4(bl[2*jp][0], bl[2*jp][1], bl[2*jp+1][0], bl[2*jp+1][1],
                      st + 10240 + bAddr + jp * 1280 + ko);
            }
            // 3 passes: hi*hi, hi*lo, lo*hi (fp32 accumulate)
#pragma unroll
            for (int im = 0; im < 2; im++)
#pragma unroll
                for (int jn = 0; jn < 8; jn++) MMA16816(acc[im][jn], ah[im], bh[jn]);
#pragma unroll
            for (int im = 0; im < 2; im++)
#pragma unroll
                for (int jn = 0; jn < 8; jn++) MMA16816(acc[im][jn], ah[im], bl[jn]);
#pragma unroll
            for (int im = 0; im < 2; im++)
#pragma unroll
                for (int jn = 0; jn < 8; jn++) MMA16816(acc[im][jn], al[im], bh[jn]);
        }
        __syncthreads();
    }

    // epilogue
    const int gr = lane >> 2, q = lane & 3;
#pragma unroll
    for (int im = 0; im < 2; im++) {
#pragma unroll
        for (int jn = 0; jn < 8; jn++) {
            const long r0  = m0 + wm * 32 + im * 16 + gr;
            const long col = n0 + wn * 64 + jn * 8 + q * 2;
            const long i0 = r0 * N + col, i1 = i0 + 8L * N;
            float v0 = acc[im][jn][0], v1 = acc[im][jn][1];
            float v2 = acc[im][jn][2], v3 = acc[im][jn][3];
            if (EPI == 1) {
                float2 a0 = *(const float2*)(auxp + i0);
                float2 a1 = *(const float2*)(auxp + i1);
                v0 = siluf(v0) * a0.x; v1 = siluf(v1) * a0.y;
                v2 = siluf(v2) * a1.x; v3 = siluf(v3) * a1.y;
            } else if (EPI == 2) {
                float2 a0 = *(const float2*)(auxp + i0);
                float2 a1 = *(const float2*)(auxp + i1);
                v0 = fmaf(0.1f, v0, a0.x); v1 = fmaf(0.1f, v1, a0.y);
                v2 = fmaf(0.1f, v2, a1.x); v3 = fmaf(0.1f, v3, a1.y);
            } else if (EPI == 3) {
                v0 = siluf(fminf(fmaxf(v0, -5.f), 5.f));
                v1 = siluf(fminf(fmaxf(v1, -5.f), 5.f));
                v2 = siluf(fminf(fmaxf(v2, -5.f), 5.f));
                v3 = siluf(fminf(fmaxf(v3, -5.f), 5.f));
            }
            *(float2*)(C + i0) = make_float2(v0, v1);
            *(float2*)(C + i1) = make_float2(v2, v3);
            if (WSPLIT) {
                __nv_bfloat162 h, l;
                h.x = __float2bfloat16(v0); l.x = __float2bfloat16(v0 - __bfloat162float(h.x));
                h.y = __float2bfloat16(v1); l.y = __float2bfloat16(v1 - __bfloat162float(h.y));
                *(__nv_bfloat162*)(Ch + i0) = h; *(__nv_bfloat162*)(Cl + i0) = l;
                h.x = __float2bfloat16(v2); l.x = __float2bfloat16(v2 - __bfloat162float(h.x));
                h.y = __float2bfloat16(v3); l.y = __float2bfloat16(v3 - __bfloat162float(h.y));
                *(__nv_bfloat162*)(Ch + i1) = h; *(__nv_bfloat162*)(Cl + i1) = l;
            }
        }
    }
}

// ---------------------------------------------------------------------------
// SIMT SGEMM (kept only for step 8: NN layout).  See round-0 comments.
// ---------------------------------------------------------------------------
template<int BM, int TM, int EPI, bool NN>
__global__ void __launch_bounds__(256) gemm_k(
    const float* __restrict__ A, const float* __restrict__ Bm,
    float* __restrict__ C, const float* __restrict__ aux,
    int M, int N, int K, long sA, long sB, long sC)
{
    constexpr int BN = 128, BK = 8, TN = 8;
    __shared__ float As[BK][BM];
    __shared__ float Bs[BK][BN];

    const long zb = blockIdx.z;
    A  += zb * sA; Bm += zb * sB; C  += zb * sC;
    const float* auxp = aux ? aux + zb * sC : nullptr;

    const int m0 = blockIdx.y * BM, n0 = blockIdx.x * BN;
    const int tid = threadIdx.x;
    const int tx = tid & 15, ty = tid >> 4;
    const int cA = tx * 4, cB = 64 + tx * 4;

    float acc[TM][TN];
#pragma unroll
    for (int i = 0; i < TM; i++)
#pragma unroll
        for (int j = 0; j < TN; j++) acc[i][j] = 0.f;

    for (int k0 = 0; k0 < K; k0 += BK) {
        for (int i = tid; i < BM * 2; i += 256) {
            int r = i >> 1, c4 = (i & 1) << 2;
            float4 v = *(const float4*)(A + (long)(m0 + r) * K + k0 + c4);
            As[c4 + 0][r] = v.x; As[c4 + 1][r] = v.y;
            As[c4 + 2][r] = v.z; As[c4 + 3][r] = v.w;
        }
        if (!NN) {
            for (int i = tid; i < 256; i += 256) {
                int r = i >> 1, c4 = (i & 1) << 2;
                float4 v = *(const float4*)(Bm + (long)(n0 + r) * K + k0 + c4);
                Bs[c4 + 0][r] = v.x; Bs[c4 + 1][r] = v.y;
                Bs[c4 + 2][r] = v.z; Bs[c4 + 3][r] = v.w;
            }
        } else {
            for (int i = tid; i < 256; i += 256) {
                int kk = i >> 5, c = (i & 31) << 2;
                *(float4*)&Bs[kk][c] =
                    *(const float4*)(Bm + (long)(k0 + kk) * N + n0 + c);
            }
        }
        __syncthreads();
#pragma unroll
        for (int kk = 0; kk < BK; kk++) {
            float ra[TM], rb[TN];
#pragma unroll
            for (int i = 0; i < TM; i++) ra[i] = As[kk][ty * TM + i];
#pragma unroll
            for (int j = 0; j < 4; j++) { rb[j] = Bs[kk][cA + j]; rb[j + 4] = Bs[kk][cB + j]; }
#pragma unroll
            for (int i = 0; i < TM; i++)
#pragma unroll
                for (int j = 0; j < TN; j++)
                    acc[i][j] = fmaf(ra[i], rb[j], acc[i][j]);
        }
        __syncthreads();
    }
#pragma unroll
    for (int i = 0; i < TM; i++) {
        const long rowb = (long)(m0 + ty * TM + i) * N;
#pragma unroll
        for (int half = 0; half < 2; half++) {
            const long base = rowb + n0 + (half ? cB : cA);
            const int j0 = half * 4;
            float4 ax;
            if (EPI == 1 || EPI == 2) ax = *(const float4*)(auxp + base);
            float o[4];
            const float axa[4] = {ax.x, ax.y, ax.z, ax.w};
#pragma unroll
            for (int e = 0; e < 4; e++) {
                float t = acc[i][j0 + e];
                if (EPI == 0)      o[e] = t;
                else if (EPI == 1) o[e] = siluf(t) * axa[e];
                else if (EPI == 2) o[e] = fmaf(0.1f, t, axa[e]);
                else { t = fminf(fmaxf(t, -5.f), 5.f); o[e] = siluf(t); }
            }
            *(float4*)(C + base) = make_float4(o[0], o[1], o[2], o[3]);
        }
    }
}

// ---------------------------------------------------------------------------
// LayerNorm over rows of 128 (one warp/row); writes fp32 + bf16 hi/lo splits
// ---------------------------------------------------------------------------
__global__ void ln_k(const float* __restrict__ X, float* __restrict__ Y,
                     __nv_bfloat16* __restrict__ Yh, __nv_bfloat16* __restrict__ Yl,
                     const float* __restrict__ g, const float* __restrict__ b,
                     int rows)
{
    int row  = (blockIdx.x * blockDim.x + threadIdx.x) >> 5;
    int lane = threadIdx.x & 31;
    if (row >= rows) return;
    float4 x = *(const float4*)(X + (long)row * 128 + lane * 4);
    float s  = x.x + x.y + x.z + x.w;
    float ss = fmaf(x.x, x.x, fmaf(x.y, x.y, fmaf(x.z, x.z, x.w * x.w)));
#pragma unroll
    for (int o = 16; o > 0; o >>= 1) {
        s  += __shfl_xor_sync(0xffffffffu, s,  o);
        ss += __shfl_xor_sync(0xffffffffu, ss, o);
    }
    float m   = s * (1.f / 128.f);
    float inv = rsqrtf(ss * (1.f / 128.f) - m * m + 1e-5f);
    float4 gg = *(const float4*)(g + lane * 4);
    float4 bb = *(const float4*)(b + lane * 4);
    float4 y;
    y.x = fmaf((x.x - m) * inv, gg.x, bb.x);
    y.y = fmaf((x.y - m) * inv, gg.y, bb.y);
    y.z = fmaf((x.z - m) * inv, gg.z, bb.z);
    y.w = fmaf((x.w - m) * inv, gg.w, bb.w);
    const long base = (long)row * 128 + lane * 4;
    *(float4*)(Y + base) = y;
    __nv_bfloat162 h0, h1, l0, l1;
    h0.x = __float2bfloat16(y.x); l0.x = __float2bfloat16(y.x - __bfloat162float(h0.x));
    h0.y = __float2bfloat16(y.y); l0.y = __float2bfloat16(y.y - __bfloat162float(h0.y));
    h1.x = __float2bfloat16(y.z); l1.x = __float2bfloat16(y.z - __bfloat162float(h1.x));
    h1.y = __float2bfloat16(y.w); l1.y = __float2bfloat16(y.w - __bfloat162float(h1.y));
    *(__nv_bfloat162*)(Yh + base)     = h0;  *(__nv_bfloat162*)(Yh + base + 2) = h1;
    *(__nv_bfloat162*)(Yl + base)     = l0;  *(__nv_bfloat162*)(Yl + base + 2) = l1;
}

// ---------------------------------------------------------------------------
// M[d,a] = sum_h w_out[d,h] * w_eproj[h,a]
// ---------------------------------------------------------------------------
__global__ void __launch_bounds__(256) mmat_k(
    const float* __restrict__ w_out, const float* __restrict__ w_eproj,
    float* __restrict__ Mo)
{
    __shared__ float ws[8][64];
    const int d0 = blockIdx.x * 8;
    const int a  = threadIdx.x & 127;
    const int ds = threadIdx.x >> 7;
    float acc[4] = {0.f, 0.f, 0.f, 0.f};
    for (int h0 = 0; h0 < H_; h0 += 64) {
        for (int i = threadIdx.x; i < 512; i += 256) {
            int r = i >> 6, c = i & 63;
            ws[r][c] = w_out[(long)(d0 + r) * H_ + h0 + c];
        }
        __syncthreads();
        for (int hh = 0; hh < 64; hh++) {
            float e = w_eproj[(long)(h0 + hh) * A_ + a];
#pragma unroll
            for (int j = 0; j < 4; j++)
                acc[j] = fmaf(ws[ds * 4 + j][hh], e, acc[j]);
        }
        __syncthreads();
    }
#pragma unroll
    for (int j = 0; j < 4; j++)
        Mo[(long)(d0 + ds * 4 + j) * A_ + a] = acc[j];
}

// ---------------------------------------------------------------------------
// Expert kernel (last positive expert wins) — unchanged from baseline
// ---------------------------------------------------------------------------
__global__ void __launch_bounds__(128) expert_k(
    const float* __restrict__ pre, const float* __restrict__ ew,
    const float* __restrict__ w_exp, const float* __restrict__ eg,
    const float* __restrict__ eb, const float* __restrict__ Mm,
    float* __restrict__ out)
{
    __shared__ float cs[16][132];
    __shared__ union { float pre_s[16][128]; float Ms[64][132]; } u;
    __shared__ int sidx[16];

    const int tid = threadIdx.x;
    const int n0  = blockIdx.x * 16;

    if (tid < 16) {
        const float* e = ew + (long)(n0 + tid) * E_;
        int best = -1;
#pragma unroll
        for (int i = 0; i < E_; i++) if (e[i] > 0.f) best = i;
        sidx[tid] = best;
    }
    for (int i = tid; i < 16 * 32; i += 128) {
        int r = i >> 5, a4 = (i & 31) << 2;
        *(float4*)&u.pre_s[r][a4] = *(const float4*)(pre + (long)(n0 + r) * A_ + a4);
    }
    __syncthreads();

    {
        const int tt = tid >> 3, g = tid & 7;
        const int idx = sidx[tt];
        float cr[16];
        if (idx >= 0) {
            const float*  wb = w_exp + ((long)idx * A_ + g * 16) * A_;
            const float4* pr = (const float4*)&u.pre_s[tt][0];
#pragma unroll 2
            for (int q = 0; q < 16; q++) {
                const float4* wr = (const float4*)(wb + q * A_);
                float aq = 0.f;
#pragma unroll 8
                for (int a4 = 0; a4 < 32; a4++) {
                    float4 w = wr[a4], p = pr[a4];
                    aq = fmaf(w.x, p.x, aq); aq = fmaf(w.y, p.y, aq);
                    aq = fmaf(w.z, p.z, aq); aq = fmaf(w.w, p.w, aq);
                }
                cr[q] = aq;
            }
        } else {
#pragma unroll
            for (int q = 0; q < 16; q++) cr[q] = 0.f;
        }
        float s = 0.f, ss = 0.f;
#pragma unroll
        for (int q = 0; q < 16; q++) { s += cr[q]; ss = fmaf(cr[q], cr[q], ss); }
#pragma unroll
        for (int o = 4; o > 0; o >>= 1) {
            s  += __shfl_xor_sync(0xffffffffu, s,  o, 8);
            ss += __shfl_xor_sync(0xffffffffu, ss, o, 8);
        }
        float mean = s * (1.f / 128.f);
        float inv  = rsqrtf(ss * (1.f / 128.f) - mean * mean + 1e-5f);
        if (idx >= 0) {
            const float* gg = eg + (long)idx * A_ + g * 16;
            const float* bb = eb + (long)idx * A_ + g * 16;
#pragma unroll
            for (int q = 0; q < 16; q++)
                cs[tt][g * 16 + q] = fmaf((cr[q] - mean) * inv, gg[q], bb[q]);
        } else {
#pragma unroll
            for (int q = 0; q < 16; q++) cs[tt][g * 16 + q] = 0.f;
        }
    }

    const int drel = tid & 63, th = tid >> 6;
    for (int T = 0; T < 16; T++) {
        __syncthreads();
        for (int i = tid; i < 64 * 32; i += 128) {
            int r = i >> 5, a4 = (i & 31) << 2;
            *(float4*)&u.Ms[r][a4] =
                *(const float4*)(Mm + (long)(T * 64 + r) * A_ + a4);
        }
        __syncthreads();
        float acc[8] = {0.f,0.f,0.f,0.f,0.f,0.f,0.f,0.f};
#pragma unroll 4
        for (int a4 = 0; a4 < 32; a4++) {
            float4 m = *(const float4*)&u.Ms[drel][a4 << 2];
#pragma unroll
            for (int j = 0; j < 8; j++) {
                float4 c = *(const float4*)&cs[th * 8 + j][a4 << 2];
                acc[j] = fmaf(m.x, c.x, acc[j]); acc[j] = fmaf(m.y, c.y, acc[j]);
                acc[j] = fmaf(m.z, c.z, acc[j]); acc[j] = fmaf(m.w, c.w, acc[j]);
            }
        }
#pragma unroll
        for (int j = 0; j < 8; j++) {
            long n = n0 + th * 8 + j;
            long oidx = n * (long)D_ + T * 64 + drel;
            out[oidx] += 0.1f * acc[j];
        }
    }
}

// ---------------------------------------------------------------------------
static void do_split(const float* X, __nv_bfloat16* Hh, __nv_bfloat16* Hl, long n)
{
    long n4 = n / 4;
    split_k<<<(unsigned)((n4 + 255) / 256), 256>>>(X, Hh, Hl, n4);
}

extern "C" void kernel_launch(void* const* d_in, const int* in_sizes, int n_in,
                              void* d_out, int out_size)
{
    const float* x       = (const float*)d_in[0];
    const float* ew      = (const float*)d_in[1];
    const float* w_up    = (const float*)d_in[2];
    const float* w_gate  = (const float*)d_in[3];
    const float* w_down  = (const float*)d_in[4];
    const float* w_pre   = (const float*)d_in[5];
    const float* w_post  = (const float*)d_in[6];
    const float* an_g    = (const float*)d_in[7];
    const float* an_b    = (const float*)d_in[8];
    const float* w_aproj = (const float*)d_in[9];
    const float* w_exp   = (const float*)d_in[10];
    const float* eln_g   = (const float*)d_in[11];
    const float* eln_b   = (const float*)d_in[12];
    const float* w_eproj = (const float*)d_in[13];
    const float* w_out   = (const float*)d_in[14];
    float* out = (float*)d_out;

    float *U, *Hd, *pre, *ain, *pt, *aout, *adp, *scr, *Mm;
    cudaGetSymbolAddress((void**)&U,    g_U);
    cudaGetSymbolAddress((void**)&Hd,   g_Hd);
    cudaGetSymbolAddress((void**)&pre,  g_pre);
    cudaGetSymbolAddress((void**)&ain,  g_ain);
    cudaGetSymbolAddress((void**)&pt,   g_pt);
    cudaGetSymbolAddress((void**)&aout, g_aout);
    cudaGetSymbolAddress((void**)&adp,  g_adp);
    cudaGetSymbolAddress((void**)&scr,  g_scr);
    cudaGetSymbolAddress((void**)&Mm,   g_M);

    __nv_bfloat16 *xh,*xl,*Hdh,*Hdl,*ainh,*ainl,*aouth,*aoutl,*adph,*adpl;
    __nv_bfloat16 *wuph,*wupl,*wgh,*wgl,*wdh,*wdl,*wpreh,*wprel,*wpoh,*wpol,*waph,*wapl;
    cudaGetSymbolAddress((void**)&xh,    g_xh);   cudaGetSymbolAddress((void**)&xl,    g_xl);
    cudaGetSymbolAddress((void**)&Hdh,   g_Hdh);  cudaGetSymbolAddress((void**)&Hdl,   g_Hdl);
    cudaGetSymbolAddress((void**)&ainh,  g_ainh); cudaGetSymbolAddress((void**)&ainl,  g_ainl);
    cudaGetSymbolAddress((void**)&aouth, g_aouth);cudaGetSymbolAddress((void**)&aoutl, g_aoutl);
    cudaGetSymbolAddress((void**)&adph,  g_adph); cudaGetSymbolAddress((void**)&adpl,  g_adpl);
    cudaGetSymbolAddress((void**)&wuph,  g_wuph); cudaGetSymbolAddress((void**)&wupl,  g_wupl);
    cudaGetSymbolAddress((void**)&wgh,   g_wgh);  cudaGetSymbolAddress((void**)&wgl,   g_wgl);
    cudaGetSymbolAddress((void**)&wdh,   g_wdh);  cudaGetSymbolAddress((void**)&wdl,   g_wdl);
    cudaGetSymbolAddress((void**)&wpreh, g_wpreh);cudaGetSymbolAddress((void**)&wprel, g_wprel);
    cudaGetSymbolAddress((void**)&wpoh,  g_wpoh); cudaGetSymbolAddress((void**)&wpol,  g_wpol);
    cudaGetSymbolAddress((void**)&waph,  g_waph); cudaGetSymbolAddress((void**)&wapl,  g_wapl);

    cudaFuncSetAttribute(tgemm_k<0,false>, cudaFuncAttributeMaxDynamicSharedMemorySize, TG_SMEM);
    cudaFuncSetAttribute(tgemm_k<1,true >, cudaFuncAttributeMaxDynamicSharedMemorySize, TG_SMEM);
    cudaFuncSetAttribute(tgemm_k<2,true >, cudaFuncAttributeMaxDynamicSharedMemorySize, TG_SMEM);
    cudaFuncSetAttribute(tgemm_k<3,false>, cudaFuncAttributeMaxDynamicSharedMemorySize, TG_SMEM);

    // 0. fused expert projection
    mmat_k<<<D_ / 8, 256>>>(w_out, w_eproj, Mm);

    // s. splits of inputs/weights
    do_split(x,      xh,    xl,    (long)NTOK * D_);
    do_split(w_up,   wuph,  wupl,  (long)H_ * D_);
    do_split(w_gate, wgh,   wgl,   (long)H_ * D_);
    do_split(w_down, wdh,   wdl,   (long)D_ * H_);
    do_split(w_pre,  wpreh, wprel, (long)A_ * D_);
    do_split(w_post, wpoh,  wpol,  (long)A_ * H_);
    do_split(w_aproj,waph,  wapl,  (long)H_ * A_);

    // 1. U = x @ w_up^T
    tgemm_k<0,false><<<dim3(H_/128, NTOK/128, 1), 256, TG_SMEM>>>(
        xh, xl, wuph, wupl, U, nullptr, nullptr, nullptr, NTOK, H_, D_, 0, 0, 0);

    // 2. Hid = silu(x @ w_gate^T) * U   (+ split Hid)
    tgemm_k<1,true><<<dim3(H_/128, NTOK/128, 1), 256, TG_SMEM>>>(
        xh, xl, wgh, wgl, Hd, U, Hdh, Hdl, NTOK, H_, D_, 0, 0, 0);

    // 3. pre = x @ w_pre^T
    tgemm_k<0,false><<<dim3(1, NTOK/128, 1), 256, TG_SMEM>>>(
        xh, xl, wpreh, wprel, pre, nullptr, nullptr, nullptr, NTOK, A_, D_, 0, 0, 0);

    // 4. ain = LN(pre)  (+ split)
    ln_k<<<NTOK/8, 256>>>(pre, ain, ainh, ainl, an_g, an_b, NTOK);

    // 5. pt = Hid @ w_post^T
    tgemm_k<0,false><<<dim3(1, NTOK/128, 1), 256, TG_SMEM>>>(
        Hdh, Hdl, wpoh, wpol, pt, nullptr, nullptr, nullptr, NTOK, A_, H_, 0, 0, 0);

    // 6. aout = LN(pt)  (+ split)
    ln_k<<<NTOK/8, 256>>>(pt, aout, aouth, aoutl, an_g, an_b, NTOK);

    // 7. scr[b] = silu(clip(ain[b] @ aout[b]^T))
    tgemm_k<3,false><<<dim3(S_/128, S_/128, B_), 256, TG_SMEM>>>(
        ainh, ainl, aouth, aoutl, scr, nullptr, nullptr, nullptr,
        S_, S_, A_, (long)S_ * A_, (long)S_ * A_, (long)S_ * S_);

    // 8. adp[b] = scr[b] @ ain[b]   (NN, SIMT)
    gemm_k<64,4,0,true><<<dim3(1, S_/64, B_), 256>>>(
        scr, ain, adp, nullptr, S_, A_, S_,
        (long)S_ * S_, (long)S_ * A_, (long)S_ * A_);

    // 8b. split adp
    do_split(adp, adph, adpl, (long)NTOK * A_);

    // 9. Hid += 0.1 * adp @ w_aproj^T  (+ re-split Hid)
    tgemm_k<2,true><<<dim3(H_/128, NTOK/128, 1), 256, TG_SMEM>>>(
        adph, adpl, waph, wapl, Hd, Hd, Hdh, Hdl, NTOK, H_, A_, 0, 0, 0);

    // 10. out = Hid @ w_down^T
    tgemm_k<0,false><<<dim3(D_/128, NTOK/128, 1), 256, TG_SMEM>>>(
        Hdh, Hdl, wdh, wdl, out, nullptr, nullptr, nullptr, NTOK, D_, H_, 0, 0, 0);

    // 11. out += 0.1 * expert path
    expert_k<<<NTOK/16, 128>>>(pre, ew, w_exp, eln_g, eln_b, Mm, out);
}

// round 6
// speedup vs baseline: 2.4973x; 1.3329x over previous
#include <cuda_runtime.h>
#include <cuda_fp16.h>
#include <cuda_bf16.h>
#include <cstdint>

// ---------------------------------------------------------------------------
// LLaDAModel fused forward — mma.sync fp16x2-split GEMMs (2-pass on big GEMMs).
// B=8,S=2048,D=1024,H=2048,A=128,E=8.  N=16384 tokens.
//
//   0.  M = w_out @ w_eproj                        [D,A]
//   s.  split x / weights into fp16 (hi,lo); astd weights pre-scaled by 512
//   1.  U    = x @ w_up^T                          [N,H]  tc 2-pass
//   2.  Hid  = silu(x @ w_gate^T)*U  (+Hdh)        [N,H]  tc 2-pass
//   3.  pre  = x @ w_pre^T                         [N,A]  tc 3-pass (ds=1/512)
//   4.  ain  = LN(pre)              (+h/l)         [N,A]
//   5.  pt   = Hid @ w_post^T                      [N,A]  tc 2-pass (ds=1/512)
//   6.  aout = LN(pt)               (+h/l)         [N,A]
//   7.  scrh = silu(clip(ain @ aout^T))  per b     [S,S]  tc 3-pass (fp16 hi)
//   7b. aT h/l = transpose(ain)          per b     [A,S]
//   8.  adph = scr @ aT^T                per b     [N,A]  tc 2-pass
//   9.  Hdh  = Hid + 0.1*adp @ w_aproj^T           [N,H]  tc 2-pass (ds=1/512)
//  10.  out  = Hid @ w_down^T                      [N,D]  tc 2-pass
//  11.  out += 0.1 * expert(pre, last-positive) @ M^T
// ---------------------------------------------------------------------------

constexpr int B_ = 8, S_ = 2048, D_ = 1024, H_ = 2048, A_ = 128, E_ = 8;
constexpr int NTOK = B_ * S_;   // 16384

// fp32 scratch
__device__ float g_U   [(size_t)NTOK * H_];
__device__ float g_Hd  [(size_t)NTOK * H_];
__device__ float g_pre [(size_t)NTOK * A_];
__device__ float g_ain [(size_t)NTOK * A_];
__device__ float g_pt  [(size_t)NTOK * A_];
__device__ float g_aout[(size_t)NTOK * A_];
__device__ float g_M   [(size_t)D_ * A_];

// fp16 scratch
__device__ __half g_xh [(size_t)NTOK * D_], g_xl [(size_t)NTOK * D_];
__device__ __half g_Hdh[(size_t)NTOK * H_];
__device__ __half g_ainh[(size_t)NTOK * A_], g_ainl[(size_t)NTOK * A_];
__device__ __half g_aouth[(size_t)NTOK * A_], g_aoutl[(size_t)NTOK * A_];
__device__ __half g_adph[(size_t)NTOK * A_];
__device__ __half g_scrh[(size_t)B_ * S_ * S_];
__device__ __half g_aTh[(size_t)B_ * A_ * S_], g_aTl[(size_t)B_ * A_ * S_];
__device__ __half g_wuph[(size_t)H_ * D_],  g_wupl[(size_t)H_ * D_];
__device__ __half g_wgh [(size_t)H_ * D_],  g_wgl [(size_t)H_ * D_];
__device__ __half g_wdh [(size_t)D_ * H_],  g_wdl [(size_t)D_ * H_];
__device__ __half g_wpreh[(size_t)A_ * D_], g_wprel[(size_t)A_ * D_];
__device__ __half g_wpoh[(size_t)A_ * H_],  g_wpol[(size_t)A_ * H_];
__device__ __half g_waph[(size_t)H_ * A_],  g_wapl[(size_t)H_ * A_];

__device__ __forceinline__ float siluf(float x) {
    return x * (1.0f / (1.0f + __expf(-x)));
}

#define LDSM4(r0,r1,r2,r3,addr) \
    asm volatile("ldmatrix.sync.aligned.m8n8.x4.shared.b16 {%0,%1,%2,%3},[%4];\n" \
        : "=r"(r0),"=r"(r1),"=r"(r2),"=r"(r3) : "r"(addr))

#define MMA16816(c,a,b) \
    asm volatile("mma.sync.aligned.m16n8k16.row.col.f32.f16.f16.f32 " \
        "{%0,%1,%2,%3},{%4,%5,%6,%7},{%8,%9},{%0,%1,%2,%3};\n" \
        : "+f"((c)[0]),"+f"((c)[1]),"+f"((c)[2]),"+f"((c)[3]) \
        : "r"((a)[0]),"r"((a)[1]),"r"((a)[2]),"r"((a)[3]),"r"((b)[0]),"r"((b)[1]))

#define CPA16(dst,src) \
    asm volatile("cp.async.cg.shared.global [%0],[%1],16;\n" :: "r"(dst),"l"(src))

constexpr int TG_STAGE = 40960;          // bytes per pipeline stage
constexpr int TG_SMEM  = 2 * TG_STAGE;   // 80 KB dynamic smem

// ---------------------------------------------------------------------------
// Tensor GEMM: C[M,N](f32) = split(A)[M,K] @ split(B)[N,K]^T
// PASSES=2: acc = Ah*Bh + Ah*Bl   (A-lo never loaded)
// PASSES=3: acc = Ah*Bh + Ah*Bl + Al*Bh
// CTA tile 128x128x32, 8 warps (4x2), warp tile 32x64, m16n8k16 fp16 mma.
// Double-buffered cp.async; smem rows padded to 80B.
// ds multiplies acc before the epilogue transform (weight descale).
// EPI: 0 C=acc  1 C=silu(acc)*aux  2 C=aux+0.1*acc  3 C=silu(clip(acc,±5))
// WFP32: write fp32 C.  WH: write fp16 hi of C to Ch.  Batched via z.
// ---------------------------------------------------------------------------
template<int EPI, int PASSES, bool WFP32, bool WH>
__global__ void __launch_bounds__(256, 1) tgemm_k(
    const __half* __restrict__ Ah, const __half* __restrict__ Al,
    const __half* __restrict__ Bh, const __half* __restrict__ Bl,
    float* __restrict__ C, const float* __restrict__ aux,
    __half* __restrict__ Ch,
    int M, int N, int K, long sA, long sB, long sC, float ds)
{
    extern __shared__ char smem[];
    const unsigned sbase = (unsigned)__cvta_generic_to_shared(smem);
    const int tid = threadIdx.x, lane = tid & 31, warp = tid >> 5;
    const int wm = warp >> 1, wn = warp & 1;

    const long z = blockIdx.z;
    Ah += z * sA; Bh += z * sB; Bl += z * sB;
    if (PASSES == 3) Al += z * sA;
    const float* auxp = (EPI == 1 || EPI == 2) ? aux + z * sC : nullptr;
    float* Cp = WFP32 ? C + z * sC : nullptr;
    __half* Chp = WH ? Ch + z * sC : nullptr;

    const int m0 = blockIdx.y * 128, n0 = blockIdx.x * 128;
    const int KT = K / 32;

    float acc[2][8][4];
#pragma unroll
    for (int i = 0; i < 2; i++)
#pragma unroll
        for (int j = 0; j < 8; j++)
#pragma unroll
            for (int e = 0; e < 4; e++) acc[i][j][e] = 0.f;

    const unsigned aAddr = (unsigned)((wm * 32 + (lane & 15)) * 80 + (lane >> 4) * 16);
    const unsigned bAddr = (unsigned)(20480 +
        (wn * 64 + ((lane >> 4) << 3) + (lane & 7)) * 80 + ((lane >> 3) & 1) * 16);

    auto issue = [&](int kt, int s) {
        const long k0 = (long)kt * 32;
        const unsigned st = sbase + s * TG_STAGE;
#pragma unroll
        for (int i = tid; i < 512; i += 256) {
            const int r = i >> 2, c = i & 3;
            const unsigned da = st + r * 80 + c * 16;
            const long  ga = (long)(m0 + r) * K + k0 + c * 8;
            CPA16(da, Ah + ga);
            if (PASSES == 3) CPA16(da + 10240, Al + ga);
            const unsigned db = st + 20480 + r * 80 + c * 16;
            const long  gb = (long)(n0 + r) * K + k0 + c * 8;
            CPA16(db,          Bh + gb);
            CPA16(db + 10240,  Bl + gb);
        }
        asm volatile("cp.async.commit_group;\n");
    };

    issue(0, 0);
    for (int kt = 0; kt < KT; ++kt) {
        asm volatile("cp.async.wait_group 0;\n");
        __syncthreads();
        if (kt + 1 < KT) issue(kt + 1, (kt + 1) & 1);

        const unsigned st = sbase + (kt & 1) * TG_STAGE;
#pragma unroll
        for (int kk = 0; kk < 2; kk++) {
            const unsigned ko = kk * 32;
            unsigned ah[2][4], al[2][4], bh[8][2], bl[8][2];
#pragma unroll
            for (int im = 0; im < 2; im++) {
                LDSM4(ah[im][0], ah[im][1], ah[im][2], ah[im][3],
                      st + aAddr + im * 1280 + ko);
                if (PASSES == 3)
                    LDSM4(al[im][0], al[im][1], al[im][2], al[im][3],
                          st + 10240 + aAddr + im * 1280 + ko);
            }
#pragma unroll
            for (int jp = 0; jp < 4; jp++) {
                LDSM4(bh[2*jp][0], bh[2*jp][1], bh[2*jp+1][0], bh[2*jp+1][1],
                      st + bAddr + jp * 1280 + ko);
                LDSM4(bl[2*jp][0], bl[2*jp][1], bl[2*jp+1][0], bl[2*jp+1][1],
                      st + 10240 + bAddr + jp * 1280 + ko);
            }
#pragma unroll
            for (int im = 0; im < 2; im++)
#pragma unroll
                for (int jn = 0; jn < 8; jn++) MMA16816(acc[im][jn], ah[im], bh[jn]);
#pragma unroll
            for (int im = 0; im < 2; im++)
#pragma unroll
                for (int jn = 0; jn < 8; jn++) MMA16816(acc[im][jn], ah[im], bl[jn]);
            if (PASSES == 3) {
#pragma unroll
                for (int im = 0; im < 2; im++)
#pragma unroll
                    for (int jn = 0; jn < 8; jn++) MMA16816(acc[im][jn], al[im], bh[jn]);
            }
        }
        __syncthreads();
    }

    // epilogue
    const int gr = lane >> 2, q = lane & 3;
#pragma unroll
    for (int im = 0; im < 2; im++) {
#pragma unroll
        for (int jn = 0; jn < 8; jn++) {
            const long r0  = m0 + wm * 32 + im * 16 + gr;
            const long col = n0 + wn * 64 + jn * 8 + q * 2;
            const long i0 = r0 * N + col, i1 = i0 + 8L * N;
            float v0 = acc[im][jn][0] * ds, v1 = acc[im][jn][1] * ds;
            float v2 = acc[im][jn][2] * ds, v3 = acc[im][jn][3] * ds;
            if (EPI == 1) {
                float2 a0 = *(const float2*)(auxp + i0);
                float2 a1 = *(const float2*)(auxp + i1);
                v0 = siluf(v0) * a0.x; v1 = siluf(v1) * a0.y;
                v2 = siluf(v2) * a1.x; v3 = siluf(v3) * a1.y;
            } else if (EPI == 2) {
                float2 a0 = *(const float2*)(auxp + i0);
                float2 a1 = *(const float2*)(auxp + i1);
                v0 = fmaf(0.1f, v0, a0.x); v1 = fmaf(0.1f, v1, a0.y);
                v2 = fmaf(0.1f, v2, a1.x); v3 = fmaf(0.1f, v3, a1.y);
            } else if (EPI == 3) {
                v0 = siluf(fminf(fmaxf(v0, -5.f), 5.f));
                v1 = siluf(fminf(fmaxf(v1, -5.f), 5.f));
                v2 = siluf(fminf(fmaxf(v2, -5.f), 5.f));
                v3 = siluf(fminf(fmaxf(v3, -5.f), 5.f));
            }
            if (WFP32) {
                *(float2*)(Cp + i0) = make_float2(v0, v1);
                *(float2*)(Cp + i1) = make_float2(v2, v3);
            }
            if (WH) {
                __half2 hh;
                hh.x = __float2half(v0); hh.y = __float2half(v1);
                *(__half2*)(Chp + i0) = hh;
                hh.x = __float2half(v2); hh.y = __float2half(v3);
                *(__half2*)(Chp + i1) = hh;
            }
        }
    }
}

// ---------------------------------------------------------------------------
// fp32 -> fp16 hi/lo split with pre-scale (for subnormal-safe tiny weights)
// ---------------------------------------------------------------------------
__global__ void split_k(const float* __restrict__ X,
                        __half* __restrict__ Hh, __half* __restrict__ Hl,
                        long n4, float scale)
{
    long i = blockIdx.x * (long)blockDim.x + threadIdx.x;
    if (i >= n4) return;
    float4 v = ((const float4*)X)[i];
    v.x *= scale; v.y *= scale; v.z *= scale; v.w *= scale;
    __half2 h0, h1, l0, l1;
    h0.x = __float2half(v.x); l0.x = __float2half(v.x - __half2float(h0.x));
    h0.y = __float2half(v.y); l0.y = __float2half(v.y - __half2float(h0.y));
    h1.x = __float2half(v.z); l1.x = __float2half(v.z - __half2float(h1.x));
    h1.y = __float2half(v.w); l1.y = __float2half(v.w - __half2float(h1.y));
    ((__half2*)Hh)[2*i]   = h0; ((__half2*)Hh)[2*i+1] = h1;
    ((__half2*)Hl)[2*i]   = l0; ((__half2*)Hl)[2*i+1] = l1;
}

// ---------------------------------------------------------------------------
// Per-batch transpose [S,A]->[A,S], fp16 hi/lo output.  grid(S/32,A/32,B)
// ---------------------------------------------------------------------------
__global__ void tsplit_k(const float* __restrict__ X,
                         __half* __restrict__ Th, __half* __restrict__ Tl)
{
    __shared__ float t[32][33];
    const int b = blockIdx.z;
    const int t0 = blockIdx.x * 32, a0 = blockIdx.y * 32;
    const int tx = threadIdx.x, ty = threadIdx.y;
#pragma unroll
    for (int i = 0; i < 4; i++) {
        int tt = ty * 4 + i;
        t[tt][tx] = X[((long)b * S_ + t0 + tt) * A_ + a0 + tx];
    }
    __syncthreads();
#pragma unroll
    for (int i = 0; i < 4; i++) {
        int aa = ty * 4 + i;
        float v = t[tx][aa];
        __half h = __float2half(v);
        __half l = __float2half(v - __half2float(h));
        long o = ((long)b * A_ + a0 + aa) * S_ + t0 + tx;
        Th[o] = h; Tl[o] = l;
    }
}

// ---------------------------------------------------------------------------
// LayerNorm rows of 128 (one warp/row); writes fp32 + fp16 hi/lo
// ---------------------------------------------------------------------------
__global__ void ln_k(const float* __restrict__ X, float* __restrict__ Y,
                     __half* __restrict__ Yh, __half* __restrict__ Yl,
                     const float* __restrict__ g, const float* __restrict__ b,
                     int rows)
{
    int row  = (blockIdx.x * blockDim.x + threadIdx.x) >> 5;
    int lane = threadIdx.x & 31;
    if (row >= rows) return;
    float4 x = *(const float4*)(X + (long)row * 128 + lane * 4);
    float s  = x.x + x.y + x.z + x.w;
    float ss = fmaf(x.x, x.x, fmaf(x.y, x.y, fmaf(x.z, x.z, x.w * x.w)));
#pragma unroll
    for (int o = 16; o > 0; o >>= 1) {
        s  += __shfl_xor_sync(0xffffffffu, s,  o);
        ss += __shfl_xor_sync(0xffffffffu, ss, o);
    }
    float m   = s * (1.f / 128.f);
    float inv = rsqrtf(ss * (1.f / 128.f) - m * m + 1e-5f);
    float4 gg = *(const float4*)(g + lane * 4);
    float4 bb = *(const float4*)(b + lane * 4);
    float4 y;
    y.x = fmaf((x.x - m) * inv, gg.x, bb.x);
    y.y = fmaf((x.y - m) * inv, gg.y, bb.y);
    y.z = fmaf((x.z - m) * inv, gg.z, bb.z);
    y.w = fmaf((x.w - m) * inv, gg.w, bb.w);
    const long base = (long)row * 128 + lane * 4;
    *(float4*)(Y + base) = y;
    __half2 h0, h1, l0, l1;
    h0.x = __float2half(y.x); l0.x = __float2half(y.x - __half2float(h0.x));
    h0.y = __float2half(y.y); l0.y = __float2half(y.y - __half2float(h0.y));
    h1.x = __float2half(y.z); l1.x = __float2half(y.z - __half2float(h1.x));
    h1.y = __float2half(y.w); l1.y = __float2half(y.w - __half2float(h1.y));
    *(__half2*)(Yh + base)     = h0;  *(__half2*)(Yh + base + 2) = h1;
    *(__half2*)(Yl + base)     = l0;  *(__half2*)(Yl + base + 2) = l1;
}

// ---------------------------------------------------------------------------
// M[d,a] = sum_h w_out[d,h] * w_eproj[h,a]
// ---------------------------------------------------------------------------
__global__ void __launch_bounds__(256) mmat_k(
    const float* __restrict__ w_out, const float* __restrict__ w_eproj,
    float* __restrict__ Mo)
{
    __shared__ float ws[8][64];
    const int d0 = blockIdx.x * 8;
    const int a  = threadIdx.x & 127;
    const int ds = threadIdx.x >> 7;
    float acc[4] = {0.f, 0.f, 0.f, 0.f};
    for (int h0 = 0; h0 < H_; h0 += 64) {
        for (int i = threadIdx.x; i < 512; i += 256) {
            int r = i >> 6, c = i & 63;
            ws[r][c] = w_out[(long)(d0 + r) * H_ + h0 + c];
        }
        __syncthreads();
        for (int hh = 0; hh < 64; hh++) {
            float e = w_eproj[(long)(h0 + hh) * A_ + a];
#pragma unroll
            for (int j = 0; j < 4; j++)
                acc[j] = fmaf(ws[ds * 4 + j][hh], e, acc[j]);
        }
        __syncthreads();
    }
#pragma unroll
    for (int j = 0; j < 4; j++)
        Mo[(long)(d0 + ds * 4 + j) * A_ + a] = acc[j];
}

// ---------------------------------------------------------------------------
// Expert kernel (last positive expert wins)
// ---------------------------------------------------------------------------
__global__ void __launch_bounds__(128) expert_k(
    const float* __restrict__ pre, const float* __restrict__ ew,
    const float* __restrict__ w_exp, const float* __restrict__ eg,
    const float* __restrict__ eb, const float* __restrict__ Mm,
    float* __restrict__ out)
{
    __shared__ float cs[16][132];
    __shared__ union { float pre_s[16][128]; float Ms[64][132]; } u;
    __shared__ int sidx[16];

    const int tid = threadIdx.x;
    const int n0  = blockIdx.x * 16;

    if (tid < 16) {
        const float* e = ew + (long)(n0 + tid) * E_;
        int best = -1;
#pragma unroll
        for (int i = 0; i < E_; i++) if (e[i] > 0.f) best = i;
        sidx[tid] = best;
    }
    for (int i = tid; i < 16 * 32; i += 128) {
        int r = i >> 5, a4 = (i & 31) << 2;
        *(float4*)&u.pre_s[r][a4] = *(const float4*)(pre + (long)(n0 + r) * A_ + a4);
    }
    __syncthreads();

    {
        const int tt = tid >> 3, g = tid & 7;
        const int idx = sidx[tt];
        float cr[16];
        if (idx >= 0) {
            const float*  wb = w_exp + ((long)idx * A_ + g * 16) * A_;
            const float4* pr = (const float4*)&u.pre_s[tt][0];
#pragma unroll 2
            for (int q = 0; q < 16; q++) {
                const float4* wr = (const float4*)(wb + q * A_);
                float aq = 0.f;
#pragma unroll 8
                for (int a4 = 0; a4 < 32; a4++) {
                    float4 w = wr[a4], p = pr[a4];
                    aq = fmaf(w.x, p.x, aq); aq = fmaf(w.y, p.y, aq);
                    aq = fmaf(w.z, p.z, aq); aq = fmaf(w.w, p.w, aq);
                }
                cr[q] = aq;
            }
        } else {
#pragma unroll
            for (int q = 0; q < 16; q++) cr[q] = 0.f;
        }
        float s = 0.f, ss = 0.f;
#pragma unroll
        for (int q = 0; q < 16; q++) { s += cr[q]; ss = fmaf(cr[q], cr[q], ss); }
#pragma unroll
        for (int o = 4; o > 0; o >>= 1) {
            s  += __shfl_xor_sync(0xffffffffu, s,  o, 8);
            ss += __shfl_xor_sync(0xffffffffu, ss, o, 8);
        }
        float mean = s * (1.f / 128.f);
        float inv  = rsqrtf(ss * (1.f / 128.f) - mean * mean + 1e-5f);
        if (idx >= 0) {
            const float* gg = eg + (long)idx * A_ + g * 16;
            const float* bb = eb + (long)idx * A_ + g * 16;
#pragma unroll
            for (int q = 0; q < 16; q++)
                cs[tt][g * 16 + q] = fmaf((cr[q] - mean) * inv, gg[q], bb[q]);
        } else {
#pragma unroll
            for (int q = 0; q < 16; q++) cs[tt][g * 16 + q] = 0.f;
        }
    }

    const int drel = tid & 63, th = tid >> 6;
    for (int T = 0; T < 16; T++) {
        __syncthreads();
        for (int i = tid; i < 64 * 32; i += 128) {
            int r = i >> 5, a4 = (i & 31) << 2;
            *(float4*)&u.Ms[r][a4] =
                *(const float4*)(Mm + (long)(T * 64 + r) * A_ + a4);
        }
        __syncthreads();
        float acc[8] = {0.f,0.f,0.f,0.f,0.f,0.f,0.f,0.f};
#pragma unroll 4
        for (int a4 = 0; a4 < 32; a4++) {
            float4 m = *(const float4*)&u.Ms[drel][a4 << 2];
#pragma unroll
            for (int j = 0; j < 8; j++) {
                float4 c = *(const float4*)&cs[th * 8 + j][a4 << 2];
                acc[j] = fmaf(m.x, c.x, acc[j]); acc[j] = fmaf(m.y, c.y, acc[j]);
                acc[j] = fmaf(m.z, c.z, acc[j]); acc[j] = fmaf(m.w, c.w, acc[j]);
            }
        }
#pragma unroll
        for (int j = 0; j < 8; j++) {
            long n = n0 + th * 8 + j;
            long oidx = n * (long)D_ + T * 64 + drel;
            out[oidx] += 0.1f * acc[j];
        }
    }
}

// ---------------------------------------------------------------------------
static void do_split(const float* X, __half* Hh, __half* Hl, long n, float sc)
{
    long n4 = n / 4;
    split_k<<<(unsigned)((n4 + 255) / 256), 256>>>(X, Hh, Hl, n4, sc);
}

extern "C" void kernel_launch(void* const* d_in, const int* in_sizes, int n_in,
                              void* d_out, int out_size)
{
    const float* x       = (const float*)d_in[0];
    const float* ew      = (const float*)d_in[1];
    const float* w_up    = (const float*)d_in[2];
    const float* w_gate  = (const float*)d_in[3];
    const float* w_down  = (const float*)d_in[4];
    const float* w_pre   = (const float*)d_in[5];
    const float* w_post  = (const float*)d_in[6];
    const float* an_g    = (const float*)d_in[7];
    const float* an_b    = (const float*)d_in[8];
    const float* w_aproj = (const float*)d_in[9];
    const float* w_exp   = (const float*)d_in[10];
    const float* eln_g   = (const float*)d_in[11];
    const float* eln_b   = (const float*)d_in[12];
    const float* w_eproj = (const float*)d_in[13];
    const float* w_out   = (const float*)d_in[14];
    float* out = (float*)d_out;

    float *U, *Hd, *pre, *ain, *pt, *aout, *Mm;
    cudaGetSymbolAddress((void**)&U,    g_U);
    cudaGetSymbolAddress((void**)&Hd,   g_Hd);
    cudaGetSymbolAddress((void**)&pre,  g_pre);
    cudaGetSymbolAddress((void**)&ain,  g_ain);
    cudaGetSymbolAddress((void**)&pt,   g_pt);
    cudaGetSymbolAddress((void**)&aout, g_aout);
    cudaGetSymbolAddress((void**)&Mm,   g_M);

    __half *xh,*xl,*Hdh,*ainh,*ainl,*aouth,*aoutl,*adph,*scrh,*aTh,*aTl;
    __half *wuph,*wupl,*wgh,*wgl,*wdh,*wdl,*wpreh,*wprel,*wpoh,*wpol,*waph,*wapl;
    cudaGetSymbolAddress((void**)&xh,    g_xh);   cudaGetSymbolAddress((void**)&xl,    g_xl);
    cudaGetSymbolAddress((void**)&Hdh,   g_Hdh);
    cudaGetSymbolAddress((void**)&ainh,  g_ainh); cudaGetSymbolAddress((void**)&ainl,  g_ainl);
    cudaGetSymbolAddress((void**)&aouth, g_aouth);cudaGetSymbolAddress((void**)&aoutl, g_aoutl);
    cudaGetSymbolAddress((void**)&adph,  g_adph);
    cudaGetSymbolAddress((void**)&scrh,  g_scrh);
    cudaGetSymbolAddress((void**)&aTh,   g_aTh);  cudaGetSymbolAddress((void**)&aTl,   g_aTl);
    cudaGetSymbolAddress((void**)&wuph,  g_wuph); cudaGetSymbolAddress((void**)&wupl,  g_wupl);
    cudaGetSymbolAddress((void**)&wgh,   g_wgh);  cudaGetSymbolAddress((void**)&wgl,   g_wgl);
    cudaGetSymbolAddress((void**)&wdh,   g_wdh);  cudaGetSymbolAddress((void**)&wdl,   g_wdl);
    cudaGetSymbolAddress((void**)&wpreh, g_wpreh);cudaGetSymbolAddress((void**)&wprel, g_wprel);
    cudaGetSymbolAddress((void**)&wpoh,  g_wpoh); cudaGetSymbolAddress((void**)&wpol,  g_wpol);
    cudaGetSymbolAddress((void**)&waph,  g_waph); cudaGetSymbolAddress((void**)&wapl,  g_wapl);

    cudaFuncSetAttribute(tgemm_k<0,2,true ,false>, cudaFuncAttributeMaxDynamicSharedMemorySize, TG_SMEM);
    cudaFuncSetAttribute(tgemm_k<1,2,true ,true >, cudaFuncAttributeMaxDynamicSharedMemorySize, TG_SMEM);
    cudaFuncSetAttribute(tgemm_k<0,3,true ,false>, cudaFuncAttributeMaxDynamicSharedMemorySize, TG_SMEM);
    cudaFuncSetAttribute(tgemm_k<3,3,false,true >, cudaFuncAttributeMaxDynamicSharedMemorySize, TG_SMEM);
    cudaFuncSetAttribute(tgemm_k<0,2,false,true >, cudaFuncAttributeMaxDynamicSharedMemorySize, TG_SMEM);
    cudaFuncSetAttribute(tgemm_k<2,2,false,true >, cudaFuncAttributeMaxDynamicSharedMemorySize, TG_SMEM);

    const float DS = 1.0f / 512.0f;   // descale for astd-weight GEMMs

    // 0. fused expert projection
    mmat_k<<<D_ / 8, 256>>>(w_out, w_eproj, Mm);

    // s. splits (astd weights pre-scaled by 512 to dodge fp16 subnormals)
    do_split(x,       xh,    xl,    (long)NTOK * D_, 1.f);
    do_split(w_up,    wuph,  wupl,  (long)H_ * D_,   1.f);
    do_split(w_gate,  wgh,   wgl,   (long)H_ * D_,   1.f);
    do_split(w_down,  wdh,   wdl,   (long)D_ * H_,   1.f);
    do_split(w_pre,   wpreh, wprel, (long)A_ * D_,   512.f);
    do_split(w_post,  wpoh,  wpol,  (long)A_ * H_,   512.f);
    do_split(w_aproj, waph,  wapl,  (long)H_ * A_,   512.f);

    // 1. U = x @ w_up^T                         (2-pass)
    tgemm_k<0,2,true,false><<<dim3(H_/128, NTOK/128, 1), 256, TG_SMEM>>>(
        xh, nullptr, wuph, wupl, U, nullptr, nullptr, NTOK, H_, D_, 0, 0, 0, 1.f);

    // 2. Hid = silu(x @ w_gate^T) * U  (+Hdh)   (2-pass)
    tgemm_k<1,2,true,true><<<dim3(H_/128, NTOK/128, 1), 256, TG_SMEM>>>(
        xh, nullptr, wgh, wgl, Hd, U, Hdh, NTOK, H_, D_, 0, 0, 0, 1.f);

    // 3. pre = x @ w_pre^T                      (3-pass, descale 1/512)
    tgemm_k<0,3,true,false><<<dim3(1, NTOK/128, 1), 256, TG_SMEM>>>(
        xh, xl, wpreh, wprel, pre, nullptr, nullptr, NTOK, A_, D_, 0, 0, 0, DS);

    // 4. ain = LN(pre)  (+h/l)
    ln_k<<<NTOK/8, 256>>>(pre, ain, ainh, ainl, an_g, an_b, NTOK);

    // 5. pt = Hid @ w_post^T                    (2-pass, descale 1/512)
    tgemm_k<0,2,true,false><<<dim3(1, NTOK/128, 1), 256, TG_SMEM>>>(
        Hdh, nullptr, wpoh, wpol, pt, nullptr, nullptr, NTOK, A_, H_, 0, 0, 0, DS);

    // 6. aout = LN(pt)  (+h/l)
    ln_k<<<NTOK/8, 256>>>(pt, aout, aouth, aoutl, an_g, an_b, NTOK);

    // 7. scrh[b] = silu(clip(ain[b] @ aout[b]^T))   (3-pass, fp16 hi only)
    tgemm_k<3,3,false,true><<<dim3(S_/128, S_/128, B_), 256, TG_SMEM>>>(
        ainh, ainl, aouth, aoutl, nullptr, nullptr, scrh,
        S_, S_, A_, (long)S_ * A_, (long)S_ * A_, (long)S_ * S_, 1.f);

    // 7b. aT h/l = transpose(ain)
    tsplit_k<<<dim3(S_/32, A_/32, B_), dim3(32, 8)>>>(ain, aTh, aTl);

    // 8. adph[b] = scr[b] @ aT[b]^T             (2-pass)
    tgemm_k<0,2,false,true><<<dim3(1, S_/128, B_), 256, TG_SMEM>>>(
        scrh, nullptr, aTh, aTl, nullptr, nullptr, adph,
        S_, A_, S_, (long)S_ * S_, (long)A_ * S_, (long)S_ * A_, 1.f);

    // 9. Hdh = Hid + 0.1 * adp @ w_aproj^T      (2-pass, descale 1/512)
    tgemm_k<2,2,false,true><<<dim3(H_/128, NTOK/128, 1), 256, TG_SMEM>>>(
        adph, nullptr, waph, wapl, nullptr, Hd, Hdh, NTOK, H_, A_, 0, 0, 0, DS);

    // 10. out = Hid @ w_down^T                  (2-pass)
    tgemm_k<0,2,true,false><<<dim3(D_/128, NTOK/128, 1), 256, TG_SMEM>>>(
        Hdh, nullptr, wdh, wdl, out, nullptr, nullptr, NTOK, D_, H_, 0, 0, 0, 1.f);

    // 11. out += 0.1 * expert path
    expert_k<<<NTOK/16, 128>>>(pre, ew, w_exp, eln_g, eln_b, Mm, out);
}

// round 7
// speedup vs baseline: 3.0066x; 1.2040x over previous
#include <cuda_runtime.h>
#include <cuda_fp16.h>
#include <cstdint>

// ---------------------------------------------------------------------------
// LLaDAModel fused forward — mma.sync fp16-split GEMMs, pass counts tuned to
// each branch's error budget.  B=8,S=2048,D=1024,H=2048,A=128,E=8. N=16384.
//
//   0.  M = w_out @ w_eproj (fp32) ; Mh = fp16(16384*M)
//   s.  fp16 splits (astd weights prescaled 512)
//   1.  U    = x @ w_up^T                          [N,H]  2-pass
//   2.  Hid  = silu(x @ w_gate^T)*U  (+Hdh)        [N,H]  2-pass
//   3.  pre  = x @ w_pre^T  (+preh*512)            [N,A]  3-pass
//   4.  ain  = LN(pre)  (+h/l)                     [N,A]
//   5.  pt   = Hid @ w_post^T                      [N,A]  1-pass
//   6.  aout = LN(pt)   (+h/l)                     [N,A]
//   7.  scrh = silu(clip(ain @ aout^T)) per b      [S,S]  2-pass
//   7b. aTh  = transpose(ain) hi          per b    [A,S]
//   8.  adph = scr @ aT^T                 per b    [N,A]  1-pass
//   9.  Hdh  = Hid + 0.1*adp @ w_aproj^T           [N,H]  1-pass
//  10.  out  = Hid @ w_down^T                      [N,D]  2-pass
//  e1.  ec_i = pre @ w_exp[i]^T  (all 8, batched)  [N,A]  1-pass
//  e2.  ch   = LN(ec[last-positive], eln)  per tok [N,A]
//  e3.  out += 0.1 * ch @ Mh^T                     [N,D]  1-pass
// ---------------------------------------------------------------------------

constexpr int B_ = 8, S_ = 2048, D_ = 1024, H_ = 2048, A_ = 128, E_ = 8;
constexpr int NTOK = B_ * S_;   // 16384

// fp32 scratch
__device__ float g_U   [(size_t)NTOK * H_];
__device__ float g_Hd  [(size_t)NTOK * H_];
__device__ float g_pre [(size_t)NTOK * A_];
__device__ float g_ain [(size_t)NTOK * A_];
__device__ float g_pt  [(size_t)NTOK * A_];
__device__ float g_aout[(size_t)NTOK * A_];
__device__ float g_M   [(size_t)D_ * A_];
__device__ float g_ec  [(size_t)E_ * NTOK * A_];

// fp16 scratch
__device__ __half g_xh [(size_t)NTOK * D_], g_xl [(size_t)NTOK * D_];
__device__ __half g_Hdh[(size_t)NTOK * H_];
__device__ __half g_preh[(size_t)NTOK * A_];
__device__ __half g_ainh[(size_t)NTOK * A_], g_ainl[(size_t)NTOK * A_];
__device__ __half g_aouth[(size_t)NTOK * A_], g_aoutl[(size_t)NTOK * A_];
__device__ __half g_adph[(size_t)NTOK * A_];
__device__ __half g_ch  [(size_t)NTOK * A_];
__device__ __half g_scrh[(size_t)B_ * S_ * S_];
__device__ __half g_aTh[(size_t)B_ * A_ * S_];
__device__ __half g_Mh [(size_t)D_ * A_];
__device__ __half g_wexph[(size_t)E_ * A_ * A_];
__device__ __half g_wuph[(size_t)H_ * D_],  g_wupl[(size_t)H_ * D_];
__device__ __half g_wgh [(size_t)H_ * D_],  g_wgl [(size_t)H_ * D_];
__device__ __half g_wdh [(size_t)D_ * H_],  g_wdl [(size_t)D_ * H_];
__device__ __half g_wpreh[(size_t)A_ * D_], g_wprel[(size_t)A_ * D_];
__device__ __half g_wpoh[(size_t)A_ * H_];
__device__ __half g_waph[(size_t)H_ * A_];

__device__ __forceinline__ float siluf(float x) {
    return x * (1.0f / (1.0f + __expf(-x)));
}

#define LDSM4(r0,r1,r2,r3,addr) \
    asm volatile("ldmatrix.sync.aligned.m8n8.x4.shared.b16 {%0,%1,%2,%3},[%4];\n" \
        : "=r"(r0),"=r"(r1),"=r"(r2),"=r"(r3) : "r"(addr))

#define MMA16816(c,a,b) \
    asm volatile("mma.sync.aligned.m16n8k16.row.col.f32.f16.f16.f32 " \
        "{%0,%1,%2,%3},{%4,%5,%6,%7},{%8,%9},{%0,%1,%2,%3};\n" \
        : "+f"((c)[0]),"+f"((c)[1]),"+f"((c)[2]),"+f"((c)[3]) \
        : "r"((a)[0]),"r"((a)[1]),"r"((a)[2]),"r"((a)[3]),"r"((b)[0]),"r"((b)[1]))

#define CPA16(dst,src) \
    asm volatile("cp.async.cg.shared.global [%0],[%1],16;\n" :: "r"(dst),"l"(src))

constexpr int TG_STAGE = 40960;          // bytes per pipeline stage
constexpr int TG_SMEM  = 2 * TG_STAGE;   // 80 KB dynamic smem

// ---------------------------------------------------------------------------
// Tensor GEMM: C[M,N](f32) = split(A)[M,K] @ split(B)[N,K]^T
// PASSES=1: acc = Ah*Bh           PASSES=2: + Ah*Bl      PASSES=3: + Al*Bh
// CTA tile 128x128x32, 8 warps (4x2), warp tile 32x64, m16n8k16 fp16 mma.
// ds scales acc before epilogue transform; hs scales the fp16 write.
// EPI: 0 C=acc  1 C=silu(acc)*aux  2 C=aux+0.1*acc  3 C=silu(clip(acc,±5))
// WFP32 -> write fp32 C;  WH -> write fp16(hs*value) to Ch.  Batched via z.
// ---------------------------------------------------------------------------
template<int EPI, int PASSES, bool WFP32, bool WH>
__global__ void __launch_bounds__(256, 1) tgemm_k(
    const __half* __restrict__ Ah, const __half* __restrict__ Al,
    const __half* __restrict__ Bh, const __half* __restrict__ Bl,
    float* __restrict__ C, const float* __restrict__ aux,
    __half* __restrict__ Ch,
    int M, int N, int K, long sA, long sB, long sC, float ds, float hs)
{
    extern __shared__ char smem[];
    const unsigned sbase = (unsigned)__cvta_generic_to_shared(smem);
    const int tid = threadIdx.x, lane = tid & 31, warp = tid >> 5;
    const int wm = warp >> 1, wn = warp & 1;

    const long z = blockIdx.z;
    Ah += z * sA; Bh += z * sB;
    if (PASSES >= 2) Bl += z * sB;
    if (PASSES == 3) Al += z * sA;
    const float* auxp = (EPI == 1 || EPI == 2) ? aux + z * sC : nullptr;
    float* Cp = WFP32 ? C + z * sC : nullptr;
    __half* Chp = WH ? Ch + z * sC : nullptr;

    const int m0 = blockIdx.y * 128, n0 = blockIdx.x * 128;
    const int KT = K / 32;

    float acc[2][8][4];
#pragma unroll
    for (int i = 0; i < 2; i++)
#pragma unroll
        for (int j = 0; j < 8; j++)
#pragma unroll
            for (int e = 0; e < 4; e++) acc[i][j][e] = 0.f;

    const unsigned aAddr = (unsigned)((wm * 32 + (lane & 15)) * 80 + (lane >> 4) * 16);
    const unsigned bAddr = (unsigned)(20480 +
        (wn * 64 + ((lane >> 4) << 3) + (lane & 7)) * 80 + ((lane >> 3) & 1) * 16);

    auto issue = [&](int kt, int s) {
        const long k0 = (long)kt * 32;
        const unsigned st = sbase + s * TG_STAGE;
#pragma unroll
        for (int i = tid; i < 512; i += 256) {
            const int r = i >> 2, c = i & 3;
            const unsigned da = st + r * 80 + c * 16;
            const long  ga = (long)(m0 + r) * K + k0 + c * 8;
            CPA16(da, Ah + ga);
            if (PASSES == 3) CPA16(da + 10240, Al + ga);
            const unsigned db = st + 20480 + r * 80 + c * 16;
            const long  gb = (long)(n0 + r) * K + k0 + c * 8;
            CPA16(db, Bh + gb);
            if (PASSES >= 2) CPA16(db + 10240, Bl + gb);
        }
        asm volatile("cp.async.commit_group;\n");
    };

    issue(0, 0);
    for (int kt = 0; kt < KT; ++kt) {
        asm volatile("cp.async.wait_group 0;\n");
        __syncthreads();
        if (kt + 1 < KT) issue(kt + 1, (kt + 1) & 1);

        const unsigned st = sbase + (kt & 1) * TG_STAGE;
#pragma unroll
        for (int kk = 0; kk < 2; kk++) {
            const unsigned ko = kk * 32;
            unsigned ah[2][4], al[2][4], bh[8][2], bl[8][2];
#pragma unroll
            for (int im = 0; im < 2; im++) {
                LDSM4(ah[im][0], ah[im][1], ah[im][2], ah[im][3],
                      st + aAddr + im * 1280 + ko);
                if (PASSES == 3)
                    LDSM4(al[im][0], al[im][1], al[im][2], al[im][3],
                          st + 10240 + aAddr + im * 1280 + ko);
            }
#pragma unroll
            for (int jp = 0; jp < 4; jp++) {
                LDSM4(bh[2*jp][0], bh[2*jp][1], bh[2*jp+1][0], bh[2*jp+1][1],
                      st + bAddr + jp * 1280 + ko);
                if (PASSES >= 2)
                    LDSM4(bl[2*jp][0], bl[2*jp][1], bl[2*jp+1][0], bl[2*jp+1][1],
                          st + 10240 + bAddr + jp * 1280 + ko);
            }
#pragma unroll
            for (int im = 0; im < 2; im++)
#pragma unroll
                for (int jn = 0; jn < 8; jn++) MMA16816(acc[im][jn], ah[im], bh[jn]);
            if (PASSES >= 2) {
#pragma unroll
                for (int im = 0; im < 2; im++)
#pragma unroll
                    for (int jn = 0; jn < 8; jn++) MMA16816(acc[im][jn], ah[im], bl[jn]);
            }
            if (PASSES == 3) {
#pragma unroll
                for (int im = 0; im < 2; im++)
#pragma unroll
                    for (int jn = 0; jn < 8; jn++) MMA16816(acc[im][jn], al[im], bh[jn]);
            }
        }
        __syncthreads();
    }

    // epilogue
    const int gr = lane >> 2, q = lane & 3;
#pragma unroll
    for (int im = 0; im < 2; im++) {
#pragma unroll
        for (int jn = 0; jn < 8; jn++) {
            const long r0  = m0 + wm * 32 + im * 16 + gr;
            const long col = n0 + wn * 64 + jn * 8 + q * 2;
            const long i0 = r0 * N + col, i1 = i0 + 8L * N;
            float v0 = acc[im][jn][0] * ds, v1 = acc[im][jn][1] * ds;
            float v2 = acc[im][jn][2] * ds, v3 = acc[im][jn][3] * ds;
            if (EPI == 1) {
                float2 a0 = *(const float2*)(auxp + i0);
                float2 a1 = *(const float2*)(auxp + i1);
                v0 = siluf(v0) * a0.x; v1 = siluf(v1) * a0.y;
                v2 = siluf(v2) * a1.x; v3 = siluf(v3) * a1.y;
            } else if (EPI == 2) {
                float2 a0 = *(const float2*)(auxp + i0);
                float2 a1 = *(const float2*)(auxp + i1);
                v0 = fmaf(0.1f, v0, a0.x); v1 = fmaf(0.1f, v1, a0.y);
                v2 = fmaf(0.1f, v2, a1.x); v3 = fmaf(0.1f, v3, a1.y);
            } else if (EPI == 3) {
                v0 = siluf(fminf(fmaxf(v0, -5.f), 5.f));
                v1 = siluf(fminf(fmaxf(v1, -5.f), 5.f));
                v2 = siluf(fminf(fmaxf(v2, -5.f), 5.f));
                v3 = siluf(fminf(fmaxf(v3, -5.f), 5.f));
            }
            if (WFP32) {
                *(float2*)(Cp + i0) = make_float2(v0, v1);
                *(float2*)(Cp + i1) = make_float2(v2, v3);
            }
            if (WH) {
                __half2 hh;
                hh.x = __float2half(v0 * hs); hh.y = __float2half(v1 * hs);
                *(__half2*)(Chp + i0) = hh;
                hh.x = __float2half(v2 * hs); hh.y = __float2half(v3 * hs);
                *(__half2*)(Chp + i1) = hh;
            }
        }
    }
}

// ---------------------------------------------------------------------------
// fp32 -> fp16 hi/lo split with pre-scale
// ---------------------------------------------------------------------------
__global__ void split_k(const float* __restrict__ X,
                        __half* __restrict__ Hh, __half* __restrict__ Hl,
                        long n4, float scale)
{
    long i = blockIdx.x * (long)blockDim.x + threadIdx.x;
    if (i >= n4) return;
    float4 v = ((const float4*)X)[i];
    v.x *= scale; v.y *= scale; v.z *= scale; v.w *= scale;
    __half2 h0, h1, l0, l1;
    h0.x = __float2half(v.x); l0.x = __float2half(v.x - __half2float(h0.x));
    h0.y = __float2half(v.y); l0.y = __float2half(v.y - __half2float(h0.y));
    h1.x = __float2half(v.z); l1.x = __float2half(v.z - __half2float(h1.x));
    h1.y = __float2half(v.w); l1.y = __float2half(v.w - __half2float(h1.y));
    ((__half2*)Hh)[2*i]   = h0; ((__half2*)Hh)[2*i+1] = h1;
    ((__half2*)Hl)[2*i]   = l0; ((__half2*)Hl)[2*i+1] = l1;
}

// fp32 -> fp16 hi only, pre-scaled
__global__ void splith_k(const float* __restrict__ X,
                         __half* __restrict__ Hh, long n4, float scale)
{
    long i = blockIdx.x * (long)blockDim.x + threadIdx.x;
    if (i >= n4) return;
    float4 v = ((const float4*)X)[i];
    __half2 h0, h1;
    h0.x = __float2half(v.x * scale); h0.y = __float2half(v.y * scale);
    h1.x = __float2half(v.z * scale); h1.y = __float2half(v.w * scale);
    ((__half2*)Hh)[2*i] = h0; ((__half2*)Hh)[2*i+1] = h1;
}

// ---------------------------------------------------------------------------
// Per-batch transpose [S,A]->[A,S], fp16 hi output.  grid(S/32,A/32,B)
// ---------------------------------------------------------------------------
__global__ void tsplit_k(const float* __restrict__ X, __half* __restrict__ Th)
{
    __shared__ float t[32][33];
    const int b = blockIdx.z;
    const int t0 = blockIdx.x * 32, a0 = blockIdx.y * 32;
    const int tx = threadIdx.x, ty = threadIdx.y;
#pragma unroll
    for (int i = 0; i < 4; i++) {
        int tt = ty * 4 + i;
        t[tt][tx] = X[((long)b * S_ + t0 + tt) * A_ + a0 + tx];
    }
    __syncthreads();
#pragma unroll
    for (int i = 0; i < 4; i++) {
        int aa = ty * 4 + i;
        long o = ((long)b * A_ + a0 + aa) * S_ + t0 + tx;
        Th[o] = __float2half(t[tx][aa]);
    }
}

// ---------------------------------------------------------------------------
// LayerNorm rows of 128 (one warp/row); writes fp32 + fp16 hi/lo
// ---------------------------------------------------------------------------
__global__ void ln_k(const float* __restrict__ X, float* __restrict__ Y,
                     __half* __restrict__ Yh, __half* __restrict__ Yl,
                     const float* __restrict__ g, const float* __restrict__ b,
                     int rows)
{
    int row  = (blockIdx.x * blockDim.x + threadIdx.x) >> 5;
    int lane = threadIdx.x & 31;
    if (row >= rows) return;
    float4 x = *(const float4*)(X + (long)row * 128 + lane * 4);
    float s  = x.x + x.y + x.z + x.w;
    float ss = fmaf(x.x, x.x, fmaf(x.y, x.y, fmaf(x.z, x.z, x.w * x.w)));
#pragma unroll
    for (int o = 16; o > 0; o >>= 1) {
        s  += __shfl_xor_sync(0xffffffffu, s,  o);
        ss += __shfl_xor_sync(0xffffffffu, ss, o);
    }
    float m   = s * (1.f / 128.f);
    float inv = rsqrtf(ss * (1.f / 128.f) - m * m + 1e-5f);
    float4 gg = *(const float4*)(g + lane * 4);
    float4 bb = *(const float4*)(b + lane * 4);
    float4 y;
    y.x = fmaf((x.x - m) * inv, gg.x, bb.x);
    y.y = fmaf((x.y - m) * inv, gg.y, bb.y);
    y.z = fmaf((x.z - m) * inv, gg.z, bb.z);
    y.w = fmaf((x.w - m) * inv, gg.w, bb.w);
    const long base = (long)row * 128 + lane * 4;
    *(float4*)(Y + base) = y;
    __half2 h0, h1, l0, l1;
    h0.x = __float2half(y.x); l0.x = __float2half(y.x - __half2float(h0.x));
    h0.y = __float2half(y.y); l0.y = __float2half(y.y - __half2float(h0.y));
    h1.x = __float2half(y.z); l1.x = __float2half(y.z - __half2float(h1.x));
    h1.y = __float2half(y.w); l1.y = __float2half(y.w - __half2float(h1.y));
    *(__half2*)(Yh + base)     = h0;  *(__half2*)(Yh + base + 2) = h1;
    *(__half2*)(Yl + base)     = l0;  *(__half2*)(Yl + base + 2) = l1;
}

// ---------------------------------------------------------------------------
// Expert select + LN: per token (one warp), idx = LAST expert with ew>0;
// ch = fp16(LN(ec[idx], eln[idx])) or 0 if none.
// ---------------------------------------------------------------------------
__global__ void lnsel_k(const float* __restrict__ ec, const float* __restrict__ ew,
                        const float* __restrict__ eg, const float* __restrict__ eb,
                        __half* __restrict__ ch, int rows)
{
    int row  = (blockIdx.x * blockDim.x + threadIdx.x) >> 5;
    int lane = threadIdx.x & 31;
    if (row >= rows) return;
    float w = (lane < E_) ? ew[(long)row * E_ + lane] : 0.f;
    unsigned m = __ballot_sync(0xffffffffu, w > 0.f) & 0xFFu;
    const long base = (long)row * 128 + lane * 4;
    if (m == 0) {
        __half2 zz; zz.x = __float2half(0.f); zz.y = zz.x;
        *(__half2*)(ch + base) = zz; *(__half2*)(ch + base + 2) = zz;
        return;
    }
    int idx = 31 - __clz(m);
    float4 x = *(const float4*)(ec + ((long)idx * NTOK + row) * 128 + lane * 4);
    float s  = x.x + x.y + x.z + x.w;
    float ss = fmaf(x.x, x.x, fmaf(x.y, x.y, fmaf(x.z, x.z, x.w * x.w)));
#pragma unroll
    for (int o = 16; o > 0; o >>= 1) {
        s  += __shfl_xor_sync(0xffffffffu, s,  o);
        ss += __shfl_xor_sync(0xffffffffu, ss, o);
    }
    float mn  = s * (1.f / 128.f);
    float inv = rsqrtf(ss * (1.f / 128.f) - mn * mn + 1e-5f);
    float4 gg = *(const float4*)(eg + (long)idx * 128 + lane * 4);
    float4 bb = *(const float4*)(eb + (long)idx * 128 + lane * 4);
    __half2 h0, h1;
    h0.x = __float2half(fmaf((x.x - mn) * inv, gg.x, bb.x));
    h0.y = __float2half(fmaf((x.y - mn) * inv, gg.y, bb.y));
    h1.x = __float2half(fmaf((x.z - mn) * inv, gg.z, bb.z));
    h1.y = __float2half(fmaf((x.w - mn) * inv, gg.w, bb.w));
    *(__half2*)(ch + base)     = h0;
    *(__half2*)(ch + base + 2) = h1;
}

// ---------------------------------------------------------------------------
// M[d,a] = sum_h w_out[d,h] * w_eproj[h,a]
// ---------------------------------------------------------------------------
__global__ void __launch_bounds__(256) mmat_k(
    const float* __restrict__ w_out, const float* __restrict__ w_eproj,
    float* __restrict__ Mo)
{
    __shared__ float ws[8][64];
    const int d0 = blockIdx.x * 8;
    const int a  = threadIdx.x & 127;
    const int ds = threadIdx.x >> 7;
    float acc[4] = {0.f, 0.f, 0.f, 0.f};
    for (int h0 = 0; h0 < H_; h0 += 64) {
        for (int i = threadIdx.x; i < 512; i += 256) {
            int r = i >> 6, c = i & 63;
            ws[r][c] = w_out[(long)(d0 + r) * H_ + h0 + c];
        }
        __syncthreads();
        for (int hh = 0; hh < 64; hh++) {
            float e = w_eproj[(long)(h0 + hh) * A_ + a];
#pragma unroll
            for (int j = 0; j < 4; j++)
                acc[j] = fmaf(ws[ds * 4 + j][hh], e, acc[j]);
        }
        __syncthreads();
    }
#pragma unroll
    for (int j = 0; j < 4; j++)
        Mo[(long)(d0 + ds * 4 + j) * A_ + a] = acc[j];
}

// ---------------------------------------------------------------------------
static void do_split(const float* X, __half* Hh, __half* Hl, long n, float sc)
{
    long n4 = n / 4;
    split_k<<<(unsigned)((n4 + 255) / 256), 256>>>(X, Hh, Hl, n4, sc);
}
static void do_splith(const float* X, __half* Hh, long n, float sc)
{
    long n4 = n / 4;
    splith_k<<<(unsigned)((n4 + 255) / 256), 256>>>(X, Hh, n4, sc);
}

extern "C" void kernel_launch(void* const* d_in, const int* in_sizes, int n_in,
                              void* d_out, int out_size)
{
    const float* x       = (const float*)d_in[0];
    const float* ew      = (const float*)d_in[1];
    const float* w_up    = (const float*)d_in[2];
    const float* w_gate  = (const float*)d_in[3];
    const float* w_down  = (const float*)d_in[4];
    const float* w_pre   = (const float*)d_in[5];
    const float* w_post  = (const float*)d_in[6];
    const float* an_g    = (const float*)d_in[7];
    const float* an_b    = (const float*)d_in[8];
    const float* w_aproj = (const float*)d_in[9];
    const float* w_exp   = (const float*)d_in[10];
    const float* eln_g   = (const float*)d_in[11];
    const float* eln_b   = (const float*)d_in[12];
    const float* w_eproj = (const float*)d_in[13];
    const float* w_out   = (const float*)d_in[14];
    float* out = (float*)d_out;

    float *U, *Hd, *pre, *ain, *pt, *aout, *Mm, *ec;
    cudaGetSymbolAddress((void**)&U,    g_U);
    cudaGetSymbolAddress((void**)&Hd,   g_Hd);
    cudaGetSymbolAddress((void**)&pre,  g_pre);
    cudaGetSymbolAddress((void**)&ain,  g_ain);
    cudaGetSymbolAddress((void**)&pt,   g_pt);
    cudaGetSymbolAddress((void**)&aout, g_aout);
    cudaGetSymbolAddress((void**)&Mm,   g_M);
    cudaGetSymbolAddress((void**)&ec,   g_ec);

    __half *xh,*xl,*Hdh,*preh,*ainh,*ainl,*aouth,*aoutl,*adph,*chh,*scrh,*aTh,*Mhp,*wexph;
    __half *wuph,*wupl,*wgh,*wgl,*wdh,*wdl,*wpreh,*wprel,*wpoh,*waph;
    cudaGetSymbolAddress((void**)&xh,    g_xh);   cudaGetSymbolAddress((void**)&xl,    g_xl);
    cudaGetSymbolAddress((void**)&Hdh,   g_Hdh);  cudaGetSymbolAddress((void**)&preh,  g_preh);
    cudaGetSymbolAddress((void**)&ainh,  g_ainh); cudaGetSymbolAddress((void**)&ainl,  g_ainl);
    cudaGetSymbolAddress((void**)&aouth, g_aouth);cudaGetSymbolAddress((void**)&aoutl, g_aoutl);
    cudaGetSymbolAddress((void**)&adph,  g_adph); cudaGetSymbolAddress((void**)&chh,   g_ch);
    cudaGetSymbolAddress((void**)&scrh,  g_scrh); cudaGetSymbolAddress((void**)&aTh,   g_aTh);
    cudaGetSymbolAddress((void**)&Mhp,   g_Mh);   cudaGetSymbolAddress((void**)&wexph, g_wexph);
    cudaGetSymbolAddress((void**)&wuph,  g_wuph); cudaGetSymbolAddress((void**)&wupl,  g_wupl);
    cudaGetSymbolAddress((void**)&wgh,   g_wgh);  cudaGetSymbolAddress((void**)&wgl,   g_wgl);
    cudaGetSymbolAddress((void**)&wdh,   g_wdh);  cudaGetSymbolAddress((void**)&wdl,   g_wdl);
    cudaGetSymbolAddress((void**)&wpreh, g_wpreh);cudaGetSymbolAddress((void**)&wprel, g_wprel);
    cudaGetSymbolAddress((void**)&wpoh,  g_wpoh); cudaGetSymbolAddress((void**)&waph,  g_waph);

    cudaFuncSetAttribute(tgemm_k<0,2,true ,false>, cudaFuncAttributeMaxDynamicSharedMemorySize, TG_SMEM);
    cudaFuncSetAttribute(tgemm_k<1,2,true ,true >, cudaFuncAttributeMaxDynamicSharedMemorySize, TG_SMEM);
    cudaFuncSetAttribute(tgemm_k<0,3,true ,true >, cudaFuncAttributeMaxDynamicSharedMemorySize, TG_SMEM);
    cudaFuncSetAttribute(tgemm_k<0,1,true ,false>, cudaFuncAttributeMaxDynamicSharedMemorySize, TG_SMEM);
    cudaFuncSetAttribute(tgemm_k<3,2,false,true >, cudaFuncAttributeMaxDynamicSharedMemorySize, TG_SMEM);
    cudaFuncSetAttribute(tgemm_k<0,1,false,true >, cudaFuncAttributeMaxDynamicSharedMemorySize, TG_SMEM);
    cudaFuncSetAttribute(tgemm_k<2,1,false,true >, cudaFuncAttributeMaxDynamicSharedMemorySize, TG_SMEM);
    cudaFuncSetAttribute(tgemm_k<2,1,true ,false>, cudaFuncAttributeMaxDynamicSharedMemorySize, TG_SMEM);

    const float DS = 1.0f / 512.0f;

    // 0. fused expert projection (fp32) + fp16 hi scaled 16384
    mmat_k<<<D_ / 8, 256>>>(w_out, w_eproj, Mm);
    do_splith(Mm, Mhp, (long)D_ * A_, 16384.f);

    // s. splits
    do_split (x,       xh,    xl,    (long)NTOK * D_, 1.f);
    do_split (w_up,    wuph,  wupl,  (long)H_ * D_,   1.f);
    do_split (w_gate,  wgh,   wgl,   (long)H_ * D_,   1.f);
    do_split (w_down,  wdh,   wdl,   (long)D_ * H_,   1.f);
    do_split (w_pre,   wpreh, wprel, (long)A_ * D_,   512.f);
    do_splith(w_post,  wpoh,  (long)A_ * H_,          512.f);
    do_splith(w_aproj, waph,  (long)H_ * A_,          512.f);
    do_splith(w_exp,   wexph, (long)E_ * A_ * A_,     512.f);

    // 1. U = x @ w_up^T                          (2-pass)
    tgemm_k<0,2,true,false><<<dim3(H_/128, NTOK/128, 1), 256, TG_SMEM>>>(
        xh, nullptr, wuph, wupl, U, nullptr, nullptr, NTOK, H_, D_, 0, 0, 0, 1.f, 1.f);

    // 2. Hid = silu(x @ w_gate^T) * U  (+Hdh)    (2-pass)
    tgemm_k<1,2,true,true><<<dim3(H_/128, NTOK/128, 1), 256, TG_SMEM>>>(
        xh, nullptr, wgh, wgl, Hd, U, Hdh, NTOK, H_, D_, 0, 0, 0, 1.f, 1.f);

    // 3. pre = x @ w_pre^T  (+preh = fp16(512*pre))   (3-pass)
    tgemm_k<0,3,true,true><<<dim3(1, NTOK/128, 1), 256, TG_SMEM>>>(
        xh, xl, wpreh, wprel, pre, nullptr, preh, NTOK, A_, D_, 0, 0, 0, DS, 512.f);

    // 4. ain = LN(pre)  (+h/l)
    ln_k<<<NTOK/8, 256>>>(pre, ain, ainh, ainl, an_g, an_b, NTOK);

    // 5. pt = Hid @ w_post^T                     (1-pass)
    tgemm_k<0,1,true,false><<<dim3(1, NTOK/128, 1), 256, TG_SMEM>>>(
        Hdh, nullptr, wpoh, nullptr, pt, nullptr, nullptr, NTOK, A_, H_, 0, 0, 0, DS, 1.f);

    // 6. aout = LN(pt)  (+h/l)
    ln_k<<<NTOK/8, 256>>>(pt, aout, aouth, aoutl, an_g, an_b, NTOK);

    // 7. scrh[b] = silu(clip(ain[b] @ aout[b]^T))    (2-pass)
    tgemm_k<3,2,false,true><<<dim3(S_/128, S_/128, B_), 256, TG_SMEM>>>(
        ainh, nullptr, aouth, aoutl, nullptr, nullptr, scrh,
        S_, S_, A_, (long)S_ * A_, (long)S_ * A_, (long)S_ * S_, 1.f, 1.f);

    // 7b. aTh = transpose(ain) hi
    tsplit_k<<<dim3(S_/32, A_/32, B_), dim3(32, 8)>>>(ain, aTh);

    // 8. adph[b] = scr[b] @ aT[b]^T              (1-pass)
    tgemm_k<0,1,false,true><<<dim3(1, S_/128, B_), 256, TG_SMEM>>>(
        scrh, nullptr, aTh, nullptr, nullptr, nullptr, adph,
        S_, A_, S_, (long)S_ * S_, (long)A_ * S_, (long)S_ * A_, 1.f, 1.f);

    // 9. Hdh = Hid + 0.1 * adp @ w_aproj^T       (1-pass)
    tgemm_k<2,1,false,true><<<dim3(H_/128, NTOK/128, 1), 256, TG_SMEM>>>(
        adph, nullptr, waph, nullptr, nullptr, Hd, Hdh, NTOK, H_, A_, 0, 0, 0, DS, 1.f);

    // 10. out = Hid @ w_down^T                   (2-pass)
    tgemm_k<0,2,true,false><<<dim3(D_/128, NTOK/128, 1), 256, TG_SMEM>>>(
        Hdh, nullptr, wdh, wdl, out, nullptr, nullptr, NTOK, D_, H_, 0, 0, 0, 1.f, 1.f);

    // e1. ec_i = pre @ w_exp[i]^T  (batched over 8 experts, 1-pass)
    //     preh scaled 512, wexph scaled 512 -> ds = 1/(512*512)
    tgemm_k<0,1,true,false><<<dim3(1, NTOK/128, E_), 256, TG_SMEM>>>(
        preh, nullptr, wexph, nullptr, ec, nullptr, nullptr,
        NTOK, A_, A_, 0, (long)A_ * A_, (long)NTOK * A_, 1.f / (512.f * 512.f), 1.f);

    // e2. ch = LN(ec[last-positive], eln)  (0 if none)
    lnsel_k<<<NTOK/8, 256>>>(ec, ew, eln_g, eln_b, chh, NTOK);

    // e3. out += 0.1 * ch @ Mh^T   (Mh scaled 16384 -> ds = 1/16384, 1-pass)
    tgemm_k<2,1,true,false><<<dim3(D_/128, NTOK/128, 1), 256, TG_SMEM>>>(
        chh, nullptr, Mhp, nullptr, out, out, nullptr,
        NTOK, D_, A_, 0, 0, 0, 1.f / 16384.f, 1.f);
}

// round 8
// speedup vs baseline: 4.1349x; 1.3753x over previous
#include <cuda_runtime.h>
#include <cuda_fp16.h>
#include <cstdint>

// ---------------------------------------------------------------------------
// LLaDAModel fused forward — mma.sync fp16-split GEMMs, pass counts tuned to
// each branch's error budget.  B=8,S=2048,D=1024,H=2048,A=128,E=8. N=16384.
//
//   0.  weT = transpose(w_eproj)*512 ; Mh = (32*w_out)@weT^T  (1-pass, sc 16384)
//   s.  fp16 splits (astd weights prescaled 512)
//   1.  U    = x @ w_up^T                          [N,H]  1-pass
//   2.  Hid  = silu(x @ w_gate^T)*U  (+Hdh)        [N,H]  1-pass
//   3.  pre  = x @ w_pre^T  (+preh*512)            [N,A]  3-pass
//   4.  ain  = LN(pre)  (+h)                       [N,A]
//   5.  pt   = Hid @ w_post^T                      [N,A]  1-pass
//   6.  aout = LN(pt)   (+h)                       [N,A]
//   7.  scrh = silu(clip(ain @ aout^T)) per b      [S,S]  1-pass
//   7b. aTh  = transpose(ain) hi          per b    [A,S]
//   8.  adph = scr @ aT^T                 per b    [N,A]  1-pass
//   9.  Hdh  = Hid + 0.1*adp @ w_aproj^T           [N,H]  1-pass
//  10.  out  = Hid @ w_down^T                      [N,D]  1-pass
//  e1.  ec_i = pre @ w_exp[i]^T  (all 8, batched)  [N,A]  1-pass
//  e2.  ch   = LN(ec[last-positive], eln)  per tok [N,A]
//  e3.  out += 0.1 * ch @ Mh^T                     [N,D]  1-pass
// ---------------------------------------------------------------------------

constexpr int B_ = 8, S_ = 2048, D_ = 1024, H_ = 2048, A_ = 128, E_ = 8;
constexpr int NTOK = B_ * S_;   // 16384

// fp32 scratch
__device__ float g_U   [(size_t)NTOK * H_];
__device__ float g_Hd  [(size_t)NTOK * H_];
__device__ float g_pre [(size_t)NTOK * A_];
__device__ float g_ain [(size_t)NTOK * A_];
__device__ float g_pt  [(size_t)NTOK * A_];
__device__ float g_aout[(size_t)NTOK * A_];
__device__ float g_ec  [(size_t)E_ * NTOK * A_];

// fp16 scratch
__device__ __half g_xh [(size_t)NTOK * D_], g_xl [(size_t)NTOK * D_];
__device__ __half g_Hdh[(size_t)NTOK * H_];
__device__ __half g_preh[(size_t)NTOK * A_];
__device__ __half g_ainh[(size_t)NTOK * A_], g_ainl[(size_t)NTOK * A_];
__device__ __half g_aouth[(size_t)NTOK * A_], g_aoutl[(size_t)NTOK * A_];
__device__ __half g_adph[(size_t)NTOK * A_];
__device__ __half g_ch  [(size_t)NTOK * A_];
__device__ __half g_scrh[(size_t)B_ * S_ * S_];
__device__ __half g_aTh[(size_t)B_ * A_ * S_];
__device__ __half g_Mh [(size_t)D_ * A_];
__device__ __half g_weT[(size_t)A_ * H_];
__device__ __half g_wouth[(size_t)D_ * H_];
__device__ __half g_wexph[(size_t)E_ * A_ * A_];
__device__ __half g_wuph[(size_t)H_ * D_];
__device__ __half g_wgh [(size_t)H_ * D_];
__device__ __half g_wdh [(size_t)D_ * H_];
__device__ __half g_wpreh[(size_t)A_ * D_], g_wprel[(size_t)A_ * D_];
__device__ __half g_wpoh[(size_t)A_ * H_];
__device__ __half g_waph[(size_t)H_ * A_];

__device__ __forceinline__ float siluf(float x) {
    return x * (1.0f / (1.0f + __expf(-x)));
}

#define LDSM4(r0,r1,r2,r3,addr) \
    asm volatile("ldmatrix.sync.aligned.m8n8.x4.shared.b16 {%0,%1,%2,%3},[%4];\n" \
        : "=r"(r0),"=r"(r1),"=r"(r2),"=r"(r3) : "r"(addr))

#define MMA16816(c,a,b) \
    asm volatile("mma.sync.aligned.m16n8k16.row.col.f32.f16.f16.f32 " \
        "{%0,%1,%2,%3},{%4,%5,%6,%7},{%8,%9},{%0,%1,%2,%3};\n" \
        : "+f"((c)[0]),"+f"((c)[1]),"+f"((c)[2]),"+f"((c)[3]) \
        : "r"((a)[0]),"r"((a)[1]),"r"((a)[2]),"r"((a)[3]),"r"((b)[0]),"r"((b)[1]))

#define CPA16(dst,src) \
    asm volatile("cp.async.cg.shared.global [%0],[%1],16;\n" :: "r"(dst),"l"(src))

constexpr int TG_STAGE = 40960;          // bytes per pipeline stage
constexpr int TG_SMEM  = 2 * TG_STAGE;   // 80 KB dynamic smem

// ---------------------------------------------------------------------------
// Tensor GEMM: C[M,N](f32) = split(A)[M,K] @ split(B)[N,K]^T
// PASSES=1: acc = Ah*Bh           PASSES=2: + Ah*Bl      PASSES=3: + Al*Bh
// CTA tile 128x128x32, 8 warps (4x2), warp tile 32x64, m16n8k16 fp16 mma.
// ds scales acc before epilogue transform; hs scales the fp16 write.
// EPI: 0 C=acc  1 C=silu(acc)*aux  2 C=aux+0.1*acc  3 C=silu(clip(acc,±5))
// WFP32 -> write fp32 C;  WH -> write fp16(hs*value) to Ch.  Batched via z.
// ---------------------------------------------------------------------------
template<int EPI, int PASSES, bool WFP32, bool WH>
__global__ void __launch_bounds__(256, 1) tgemm_k(
    const __half* __restrict__ Ah, const __half* __restrict__ Al,
    const __half* __restrict__ Bh, const __half* __restrict__ Bl,
    float* __restrict__ C, const float* __restrict__ aux,
    __half* __restrict__ Ch,
    int M, int N, int K, long sA, long sB, long sC, float ds, float hs)
{
    extern __shared__ char smem[];
    const unsigned sbase = (unsigned)__cvta_generic_to_shared(smem);
    const int tid = threadIdx.x, lane = tid & 31, warp = tid >> 5;
    const int wm = warp >> 1, wn = warp & 1;

    const long z = blockIdx.z;
    Ah += z * sA; Bh += z * sB;
    if (PASSES >= 2) Bl += z * sB;
    if (PASSES == 3) Al += z * sA;
    const float* auxp = (EPI == 1 || EPI == 2) ? aux + z * sC : nullptr;
    float* Cp = WFP32 ? C + z * sC : nullptr;
    __half* Chp = WH ? Ch + z * sC : nullptr;

    const int m0 = blockIdx.y * 128, n0 = blockIdx.x * 128;
    const int KT = K / 32;

    float acc[2][8][4];
#pragma unroll
    for (int i = 0; i < 2; i++)
#pragma unroll
        for (int j = 0; j < 8; j++)
#pragma unroll
            for (int e = 0; e < 4; e++) acc[i][j][e] = 0.f;

    const unsigned aAddr = (unsigned)((wm * 32 + (lane & 15)) * 80 + (lane >> 4) * 16);
    const unsigned bAddr = (unsigned)(20480 +
        (wn * 64 + ((lane >> 4) << 3) + (lane & 7)) * 80 + ((lane >> 3) & 1) * 16);

    auto issue = [&](int kt, int s) {
        const long k0 = (long)kt * 32;
        const unsigned st = sbase + s * TG_STAGE;
#pragma unroll
        for (int i = tid; i < 512; i += 256) {
            const int r = i >> 2, c = i & 3;
            const unsigned da = st + r * 80 + c * 16;
            const long  ga = (long)(m0 + r) * K + k0 + c * 8;
            CPA16(da, Ah + ga);
            if (PASSES == 3) CPA16(da + 10240, Al + ga);
            const unsigned db = st + 20480 + r * 80 + c * 16;
            const long  gb = (long)(n0 + r) * K + k0 + c * 8;
            CPA16(db, Bh + gb);
            if (PASSES >= 2) CPA16(db + 10240, Bl + gb);
        }
        asm volatile("cp.async.commit_group;\n");
    };

    issue(0, 0);
    for (int kt = 0; kt < KT; ++kt) {
        asm volatile("cp.async.wait_group 0;\n");
        __syncthreads();
        if (kt + 1 < KT) issue(kt + 1, (kt + 1) & 1);

        const unsigned st = sbase + (kt & 1) * TG_STAGE;
#pragma unroll
        for (int kk = 0; kk < 2; kk++) {
            const unsigned ko = kk * 32;
            unsigned ah[2][4], al[2][4], bh[8][2], bl[8][2];
#pragma unroll
            for (int im = 0; im < 2; im++) {
                LDSM4(ah[im][0], ah[im][1], ah[im][2], ah[im][3],
                      st + aAddr + im * 1280 + ko);
                if (PASSES == 3)
                    LDSM4(al[im][0], al[im][1], al[im][2], al[im][3],
                          st + 10240 + aAddr + im * 1280 + ko);
            }
#pragma unroll
            for (int jp = 0; jp < 4; jp++) {
                LDSM4(bh[2*jp][0], bh[2*jp][1], bh[2*jp+1][0], bh[2*jp+1][1],
                      st + bAddr + jp * 1280 + ko);
                if (PASSES >= 2)
                    LDSM4(bl[2*jp][0], bl[2*jp][1], bl[2*jp+1][0], bl[2*jp+1][1],
                          st + 10240 + bAddr + jp * 1280 + ko);
            }
#pragma unroll
            for (int im = 0; im < 2; im++)
#pragma unroll
                for (int jn = 0; jn < 8; jn++) MMA16816(acc[im][jn], ah[im], bh[jn]);
            if (PASSES >= 2) {
#pragma unroll
                for (int im = 0; im < 2; im++)
#pragma unroll
                    for (int jn = 0; jn < 8; jn++) MMA16816(acc[im][jn], ah[im], bl[jn]);
            }
            if (PASSES == 3) {
#pragma unroll
                for (int im = 0; im < 2; im++)
#pragma unroll
                    for (int jn = 0; jn < 8; jn++) MMA16816(acc[im][jn], al[im], bh[jn]);
            }
        }
        __syncthreads();
    }

    // epilogue
    const int gr = lane >> 2, q = lane & 3;
#pragma unroll
    for (int im = 0; im < 2; im++) {
#pragma unroll
        for (int jn = 0; jn < 8; jn++) {
            const long r0  = m0 + wm * 32 + im * 16 + gr;
            const long col = n0 + wn * 64 + jn * 8 + q * 2;
            const long i0 = r0 * N + col, i1 = i0 + 8L * N;
            float v0 = acc[im][jn][0] * ds, v1 = acc[im][jn][1] * ds;
            float v2 = acc[im][jn][2] * ds, v3 = acc[im][jn][3] * ds;
            if (EPI == 1) {
                float2 a0 = *(const float2*)(auxp + i0);
                float2 a1 = *(const float2*)(auxp + i1);
                v0 = siluf(v0) * a0.x; v1 = siluf(v1) * a0.y;
                v2 = siluf(v2) * a1.x; v3 = siluf(v3) * a1.y;
            } else if (EPI == 2) {
                float2 a0 = *(const float2*)(auxp + i0);
                float2 a1 = *(const float2*)(auxp + i1);
                v0 = fmaf(0.1f, v0, a0.x); v1 = fmaf(0.1f, v1, a0.y);
                v2 = fmaf(0.1f, v2, a1.x); v3 = fmaf(0.1f, v3, a1.y);
            } else if (EPI == 3) {
                v0 = siluf(fminf(fmaxf(v0, -5.f), 5.f));
                v1 = siluf(fminf(fmaxf(v1, -5.f), 5.f));
                v2 = siluf(fminf(fmaxf(v2, -5.f), 5.f));
                v3 = siluf(fminf(fmaxf(v3, -5.f), 5.f));
            }
            if (WFP32) {
                *(float2*)(Cp + i0) = make_float2(v0, v1);
                *(float2*)(Cp + i1) = make_float2(v2, v3);
            }
            if (WH) {
                __half2 hh;
                hh.x = __float2half(v0 * hs); hh.y = __float2half(v1 * hs);
                *(__half2*)(Chp + i0) = hh;
                hh.x = __float2half(v2 * hs); hh.y = __float2half(v3 * hs);
                *(__half2*)(Chp + i1) = hh;
            }
        }
    }
}

// ---------------------------------------------------------------------------
// fp32 -> fp16 hi/lo split with pre-scale
// ---------------------------------------------------------------------------
__global__ void split_k(const float* __restrict__ X,
                        __half* __restrict__ Hh, __half* __restrict__ Hl,
                        long n4, float scale)
{
    long i = blockIdx.x * (long)blockDim.x + threadIdx.x;
    if (i >= n4) return;
    float4 v = ((const float4*)X)[i];
    v.x *= scale; v.y *= scale; v.z *= scale; v.w *= scale;
    __half2 h0, h1, l0, l1;
    h0.x = __float2half(v.x); l0.x = __float2half(v.x - __half2float(h0.x));
    h0.y = __float2half(v.y); l0.y = __float2half(v.y - __half2float(h0.y));
    h1.x = __float2half(v.z); l1.x = __float2half(v.z - __half2float(h1.x));
    h1.y = __float2half(v.w); l1.y = __float2half(v.w - __half2float(h1.y));
    ((__half2*)Hh)[2*i]   = h0; ((__half2*)Hh)[2*i+1] = h1;
    ((__half2*)Hl)[2*i]   = l0; ((__half2*)Hl)[2*i+1] = l1;
}

// fp32 -> fp16 hi only, pre-scaled
__global__ void splith_k(const float* __restrict__ X,
                         __half* __restrict__ Hh, long n4, float scale)
{
    long i = blockIdx.x * (long)blockDim.x + threadIdx.x;
    if (i >= n4) return;
    float4 v = ((const float4*)X)[i];
    __half2 h0, h1;
    h0.x = __float2half(v.x * scale); h0.y = __float2half(v.y * scale);
    h1.x = __float2half(v.z * scale); h1.y = __float2half(v.w * scale);
    ((__half2*)Hh)[2*i] = h0; ((__half2*)Hh)[2*i+1] = h1;
}

// ---------------------------------------------------------------------------
// Generic transpose [R,C]->[C,R] fp32 -> fp16(scale).  grid(R/32, C/32, nz)
// z batches advance X by R*C and T by C*R.
// ---------------------------------------------------------------------------
__global__ void tsplitg_k(const float* __restrict__ X, __half* __restrict__ T,
                          int R, int C, float scale)
{
    __shared__ float t[32][33];
    const long zb = blockIdx.z;
    X += zb * (long)R * C;  T += zb * (long)R * C;
    const int r0 = blockIdx.x * 32, c0 = blockIdx.y * 32;
    const int tx = threadIdx.x, ty = threadIdx.y;
#pragma unroll
    for (int i = 0; i < 4; i++) {
        int rr = ty * 4 + i;
        t[rr][tx] = X[(long)(r0 + rr) * C + c0 + tx];
    }
    __syncthreads();
#pragma unroll
    for (int i = 0; i < 4; i++) {
        int cc = ty * 4 + i;
        T[(long)(c0 + cc) * R + r0 + tx] = __float2half(t[tx][cc] * scale);
    }
}

// ---------------------------------------------------------------------------
// LayerNorm rows of 128 (one warp/row); writes fp32 + fp16 hi/lo
// ---------------------------------------------------------------------------
__global__ void ln_k(const float* __restrict__ X, float* __restrict__ Y,
                     __half* __restrict__ Yh, __half* __restrict__ Yl,
                     const float* __restrict__ g, const float* __restrict__ b,
                     int rows)
{
    int row  = (blockIdx.x * blockDim.x + threadIdx.x) >> 5;
    int lane = threadIdx.x & 31;
    if (row >= rows) return;
    float4 x = *(const float4*)(X + (long)row * 128 + lane * 4);
    float s  = x.x + x.y + x.z + x.w;
    float ss = fmaf(x.x, x.x, fmaf(x.y, x.y, fmaf(x.z, x.z, x.w * x.w)));
#pragma unroll
    for (int o = 16; o > 0; o >>= 1) {
        s  += __shfl_xor_sync(0xffffffffu, s,  o);
        ss += __shfl_xor_sync(0xffffffffu, ss, o);
    }
    float m   = s * (1.f / 128.f);
    float inv = rsqrtf(ss * (1.f / 128.f) - m * m + 1e-5f);
    float4 gg = *(const float4*)(g + lane * 4);
    float4 bb = *(const float4*)(b + lane * 4);
    float4 y;
    y.x = fmaf((x.x - m) * inv, gg.x, bb.x);
    y.y = fmaf((x.y - m) * inv, gg.y, bb.y);
    y.z = fmaf((x.z - m) * inv, gg.z, bb.z);
    y.w = fmaf((x.w - m) * inv, gg.w, bb.w);
    const long base = (long)row * 128 + lane * 4;
    *(float4*)(Y + base) = y;
    __half2 h0, h1, l0, l1;
    h0.x = __float2half(y.x); l0.x = __float2half(y.x - __half2float(h0.x));
    h0.y = __float2half(y.y); l0.y = __float2half(y.y - __half2float(h0.y));
    h1.x = __float2half(y.z); l1.x = __float2half(y.z - __half2float(h1.x));
    h1.y = __float2half(y.w); l1.y = __float2half(y.w - __half2float(h1.y));
    *(__half2*)(Yh + base)     = h0;  *(__half2*)(Yh + base + 2) = h1;
    *(__half2*)(Yl + base)     = l0;  *(__half2*)(Yl + base + 2) = l1;
}

// ---------------------------------------------------------------------------
// Expert select + LN: per token (one warp), idx = LAST expert with ew>0;
// ch = fp16(LN(ec[idx], eln[idx])) or 0 if none.
// ---------------------------------------------------------------------------
__global__ void lnsel_k(const float* __restrict__ ec, const float* __restrict__ ew,
                        const float* __restrict__ eg, const float* __restrict__ eb,
                        __half* __restrict__ ch, int rows)
{
    int row  = (blockIdx.x * blockDim.x + threadIdx.x) >> 5;
    int lane = threadIdx.x & 31;
    if (row >= rows) return;
    float w = (lane < E_) ? ew[(long)row * E_ + lane] : 0.f;
    unsigned m = __ballot_sync(0xffffffffu, w > 0.f) & 0xFFu;
    const long base = (long)row * 128 + lane * 4;
    if (m == 0) {
        __half2 zz; zz.x = __float2half(0.f); zz.y = zz.x;
        *(__half2*)(ch + base) = zz; *(__half2*)(ch + base + 2) = zz;
        return;
    }
    int idx = 31 - __clz(m);
    float4 x = *(const float4*)(ec + ((long)idx * NTOK + row) * 128 + lane * 4);
    float s  = x.x + x.y + x.z + x.w;
    float ss = fmaf(x.x, x.x, fmaf(x.y, x.y, fmaf(x.z, x.z, x.w * x.w)));
#pragma unroll
    for (int o = 16; o > 0; o >>= 1) {
        s  += __shfl_xor_sync(0xffffffffu, s,  o);
        ss += __shfl_xor_sync(0xffffffffu, ss, o);
    }
    float mn  = s * (1.f / 128.f);
    float inv = rsqrtf(ss * (1.f / 128.f) - mn * mn + 1e-5f);
    float4 gg = *(const float4*)(eg + (long)idx * 128 + lane * 4);
    float4 bb = *(const float4*)(eb + (long)idx * 128 + lane * 4);
    __half2 h0, h1;
    h0.x = __float2half(fmaf((x.x - mn) * inv, gg.x, bb.x));
    h0.y = __float2half(fmaf((x.y - mn) * inv, gg.y, bb.y));
    h1.x = __float2half(fmaf((x.z - mn) * inv, gg.z, bb.z));
    h1.y = __float2half(fmaf((x.w - mn) * inv, gg.w, bb.w));
    *(__half2*)(ch + base)     = h0;
    *(__half2*)(ch + base + 2) = h1;
}

// ---------------------------------------------------------------------------
static void do_split(const float* X, __half* Hh, __half* Hl, long n, float sc)
{
    long n4 = n / 4;
    split_k<<<(unsigned)((n4 + 255) / 256), 256>>>(X, Hh, Hl, n4, sc);
}
static void do_splith(const float* X, __half* Hh, long n, float sc)
{
    long n4 = n / 4;
    splith_k<<<(unsigned)((n4 + 255) / 256), 256>>>(X, Hh, n4, sc);
}

extern "C" void kernel_launch(void* const* d_in, const int* in_sizes, int n_in,
                              void* d_out, int out_size)
{
    const float* x       = (const float*)d_in[0];
    const float* ew      = (const float*)d_in[1];
    const float* w_up    = (const float*)d_in[2];
    const float* w_gate  = (const float*)d_in[3];
    const float* w_down  = (const float*)d_in[4];
    const float* w_pre   = (const float*)d_in[5];
    const float* w_post  = (const float*)d_in[6];
    const float* an_g    = (const float*)d_in[7];
    const float* an_b    = (const float*)d_in[8];
    const float* w_aproj = (const float*)d_in[9];
    const float* w_exp   = (const float*)d_in[10];
    const float* eln_g   = (const float*)d_in[11];
    const float* eln_b   = (const float*)d_in[12];
    const float* w_eproj = (const float*)d_in[13];
    const float* w_out   = (const float*)d_in[14];
    float* out = (float*)d_out;

    float *U, *Hd, *pre, *ain, *pt, *aout, *ec;
    cudaGetSymbolAddress((void**)&U,    g_U);
    cudaGetSymbolAddress((void**)&Hd,   g_Hd);
    cudaGetSymbolAddress((void**)&pre,  g_pre);
    cudaGetSymbolAddress((void**)&ain,  g_ain);
    cudaGetSymbolAddress((void**)&pt,   g_pt);
    cudaGetSymbolAddress((void**)&aout, g_aout);
    cudaGetSymbolAddress((void**)&ec,   g_ec);

    __half *xh,*xl,*Hdh,*preh,*ainh,*ainl,*aouth,*aoutl,*adph,*chh,*scrh,*aTh;
    __half *Mhp,*weT,*wouth,*wexph;
    __half *wuph,*wgh,*wdh,*wpreh,*wprel,*wpoh,*waph;
    cudaGetSymbolAddress((void**)&xh,    g_xh);   cudaGetSymbolAddress((void**)&xl,    g_xl);
    cudaGetSymbolAddress((void**)&Hdh,   g_Hdh);  cudaGetSymbolAddress((void**)&preh,  g_preh);
    cudaGetSymbolAddress((void**)&ainh,  g_ainh); cudaGetSymbolAddress((void**)&ainl,  g_ainl);
    cudaGetSymbolAddress((void**)&aouth, g_aouth);cudaGetSymbolAddress((void**)&aoutl, g_aoutl);
    cudaGetSymbolAddress((void**)&adph,  g_adph); cudaGetSymbolAddress((void**)&chh,   g_ch);
    cudaGetSymbolAddress((void**)&scrh,  g_scrh); cudaGetSymbolAddress((void**)&aTh,   g_aTh);
    cudaGetSymbolAddress((void**)&Mhp,   g_Mh);   cudaGetSymbolAddress((void**)&weT,   g_weT);
    cudaGetSymbolAddress((void**)&wouth, g_wouth);cudaGetSymbolAddress((void**)&wexph, g_wexph);
    cudaGetSymbolAddress((void**)&wuph,  g_wuph); cudaGetSymbolAddress((void**)&wgh,   g_wgh);
    cudaGetSymbolAddress((void**)&wdh,   g_wdh);
    cudaGetSymbolAddress((void**)&wpreh, g_wpreh);cudaGetSymbolAddress((void**)&wprel, g_wprel);
    cudaGetSymbolAddress((void**)&wpoh,  g_wpoh); cudaGetSymbolAddress((void**)&waph,  g_waph);

    cudaFuncSetAttribute(tgemm_k<0,1,true ,false>, cudaFuncAttributeMaxDynamicSharedMemorySize, TG_SMEM);
    cudaFuncSetAttribute(tgemm_k<1,1,true ,true >, cudaFuncAttributeMaxDynamicSharedMemorySize, TG_SMEM);
    cudaFuncSetAttribute(tgemm_k<0,3,true ,true >, cudaFuncAttributeMaxDynamicSharedMemorySize, TG_SMEM);
    cudaFuncSetAttribute(tgemm_k<3,1,false,true >, cudaFuncAttributeMaxDynamicSharedMemorySize, TG_SMEM);
    cudaFuncSetAttribute(tgemm_k<0,1,false,true >, cudaFuncAttributeMaxDynamicSharedMemorySize, TG_SMEM);
    cudaFuncSetAttribute(tgemm_k<2,1,false,true >, cudaFuncAttributeMaxDynamicSharedMemorySize, TG_SMEM);
    cudaFuncSetAttribute(tgemm_k<2,1,true ,false>, cudaFuncAttributeMaxDynamicSharedMemorySize, TG_SMEM);

    const float DS = 1.0f / 512.0f;

    // s. splits (astd weights prescaled 512; w_out prescaled 32)
    do_split (x,       xh,    xl,    (long)NTOK * D_, 1.f);
    do_splith(w_up,    wuph,  (long)H_ * D_,          1.f);
    do_splith(w_gate,  wgh,   (long)H_ * D_,          1.f);
    do_splith(w_down,  wdh,   (long)D_ * H_,          1.f);
    do_split (w_pre,   wpreh, wprel, (long)A_ * D_,   512.f);
    do_splith(w_post,  wpoh,  (long)A_ * H_,          512.f);
    do_splith(w_aproj, waph,  (long)H_ * A_,          512.f);
    do_splith(w_exp,   wexph, (long)E_ * A_ * A_,     512.f);
    do_splith(w_out,   wouth, (long)D_ * H_,          32.f);

    // 0a. weT = transpose(w_eproj)[A,H] * 512
    tsplitg_k<<<dim3(H_/32, A_/32, 1), dim3(32, 8)>>>(w_eproj, weT, H_, A_, 512.f);

    // 0b. Mh = (32*w_out) @ weT^T   -> fp16, carries scale 16384  (1-pass)
    tgemm_k<0,1,false,true><<<dim3(1, D_/128, 1), 256, TG_SMEM>>>(
        wouth, nullptr, weT, nullptr, nullptr, nullptr, Mhp,
        D_, A_, H_, 0, 0, 0, 1.f, 1.f);

    // 1. U = x @ w_up^T                          (1-pass)
    tgemm_k<0,1,true,false><<<dim3(H_/128, NTOK/128, 1), 256, TG_SMEM>>>(
        xh, nullptr, wuph, nullptr, U, nullptr, nullptr, NTOK, H_, D_, 0, 0, 0, 1.f, 1.f);

    // 2. Hid = silu(x @ w_gate^T) * U  (+Hdh)    (1-pass)
    tgemm_k<1,1,true,true><<<dim3(H_/128, NTOK/128, 1), 256, TG_SMEM>>>(
        xh, nullptr, wgh, nullptr, Hd, U, Hdh, NTOK, H_, D_, 0, 0, 0, 1.f, 1.f);

    // 3. pre = x @ w_pre^T  (+preh = fp16(512*pre))   (3-pass)
    tgemm_k<0,3,true,true><<<dim3(1, NTOK/128, 1), 256, TG_SMEM>>>(
        xh, xl, wpreh, wprel, pre, nullptr, preh, NTOK, A_, D_, 0, 0, 0, DS, 512.f);

    // 4. ain = LN(pre)  (+h/l)
    ln_k<<<NTOK/8, 256>>>(pre, ain, ainh, ainl, an_g, an_b, NTOK);

    // 5. pt = Hid @ w_post^T                     (1-pass)
    tgemm_k<0,1,true,false><<<dim3(1, NTOK/128, 1), 256, TG_SMEM>>>(
        Hdh, nullptr, wpoh, nullptr, pt, nullptr, nullptr, NTOK, A_, H_, 0, 0, 0, DS, 1.f);

    // 6. aout = LN(pt)  (+h/l)
    ln_k<<<NTOK/8, 256>>>(pt, aout, aouth, aoutl, an_g, an_b, NTOK);

    // 7. scrh[b] = silu(clip(ain[b] @ aout[b]^T))    (1-pass)
    tgemm_k<3,1,false,true><<<dim3(S_/128, S_/128, B_), 256, TG_SMEM>>>(
        ainh, nullptr, aouth, nullptr, nullptr, nullptr, scrh,
        S_, S_, A_, (long)S_ * A_, (long)S_ * A_, (long)S_ * S_, 1.f, 1.f);

    // 7b. aTh = transpose(ain) hi  (per batch)
    tsplitg_k<<<dim3(S_/32, A_/32, B_), dim3(32, 8)>>>(ain, aTh, S_, A_, 1.f);

    // 8. adph[b] = scr[b] @ aT[b]^T              (1-pass)
    tgemm_k<0,1,false,true><<<dim3(1, S_/128, B_), 256, TG_SMEM>>>(
        scrh, nullptr, aTh, nullptr, nullptr, nullptr, adph,
        S_, A_, S_, (long)S_ * S_, (long)A_ * S_, (long)S_ * A_, 1.f, 1.f);

    // 9. Hdh = Hid + 0.1 * adp @ w_aproj^T       (1-pass)
    tgemm_k<2,1,false,true><<<dim3(H_/128, NTOK/128, 1), 256, TG_SMEM>>>(
        adph, nullptr, waph, nullptr, nullptr, Hd, Hdh, NTOK, H_, A_, 0, 0, 0, DS, 1.f);

    // 10. out = Hid @ w_down^T                   (1-pass)
    tgemm_k<0,1,true,false><<<dim3(D_/128, NTOK/128, 1), 256, TG_SMEM>>>(
        Hdh, nullptr, wdh, nullptr, out, nullptr, nullptr, NTOK, D_, H_, 0, 0, 0, 1.f, 1.f);

    // e1. ec_i = pre @ w_exp[i]^T  (batched over 8 experts, 1-pass)
    tgemm_k<0,1,true,false><<<dim3(1, NTOK/128, E_), 256, TG_SMEM>>>(
        preh, nullptr, wexph, nullptr, ec, nullptr, nullptr,
        NTOK, A_, A_, 0, (long)A_ * A_, (long)NTOK * A_, 1.f / (512.f * 512.f), 1.f);

    // e2. ch = LN(ec[last-positive], eln)  (0 if none)
    lnsel_k<<<NTOK/8, 256>>>(ec, ew, eln_g, eln_b, chh, NTOK);

    // e3. out += 0.1 * ch @ Mh^T   (Mh carries 16384 -> ds = 1/16384, 1-pass)
    tgemm_k<2,1,true,false><<<dim3(D_/128, NTOK/128, 1), 256, TG_SMEM>>>(
        chh, nullptr, Mhp, nullptr, out, out, nullptr,
        NTOK, D_, A_, 0, 0, 0, 1.f / 16384.f, 1.f);
}

// round 9
// speedup vs baseline: 5.8963x; 1.4260x over previous
#include <cuda_runtime.h>
#include <cuda_fp16.h>
#include <cstdint>

// ---------------------------------------------------------------------------
// LLaDAModel fused forward — mma.sync fp16-split GEMMs.
// B=8,S=2048,D=1024,H=2048,A=128,E=8. N=16384.
//
//   s.   split x (h/l);  fused weight splits (astd weights prescaled 512)
//   0a.  weT = transpose(w_eproj)*512
//   0b.  Mh  = (32*w_out) @ weT^T   (1-pass; carries scale 16384)
//   1.   U    = x @ w_up^T                         [N,H]  1-pass
//   2.   Hid  = silu(x @ w_gate^T)*U  (+Hdh)       [N,H]  1-pass
//   3.   pre  = x @ w_pre^T  (+preh*512)           [N,A]  3-pass
//   4.   ain  = LN(pre)  (+h)                      [N,A]
//   5.   pt   = Hid @ w_post^T                     [N,A]  1-pass
//   6.   aout = LN(pt)   (+h)                      [N,A]
//   7.   scrh = silu(clip(ain @ aout^T)) per b     [S,S]  1-pass
//   7b.  aTh  = transpose(ain) hi         per b    [A,S]
//   8.   adph = scr @ aT^T                per b    [N,A]  1-pass
//   9.   Hdh  = Hid + 0.1*adp @ w_aproj^T          [N,H]  1-pass
//  10.   out  = Hid @ w_down^T                     [N,D]  1-pass
//  e1.   ech_i = fp16(8192 * pre @ w_exp[i]^T)     [N,A]  1-pass (batched)
//  e2.   ch   = LN(ech[last-positive], eln)        [N,A]
//  e3.   out += 0.1 * ch @ Mh^T                    [N,D]  1-pass
// ---------------------------------------------------------------------------

constexpr int B_ = 8, S_ = 2048, D_ = 1024, H_ = 2048, A_ = 128, E_ = 8;
constexpr int NTOK = B_ * S_;   // 16384

// fp32 scratch
__device__ float g_U   [(size_t)NTOK * H_];
__device__ float g_Hd  [(size_t)NTOK * H_];
__device__ float g_pre [(size_t)NTOK * A_];
__device__ float g_ain [(size_t)NTOK * A_];
__device__ float g_pt  [(size_t)NTOK * A_];
__device__ float g_aout[(size_t)NTOK * A_];

// fp16 scratch
__device__ __half g_xh [(size_t)NTOK * D_], g_xl [(size_t)NTOK * D_];
__device__ __half g_Hdh[(size_t)NTOK * H_];
__device__ __half g_preh[(size_t)NTOK * A_];
__device__ __half g_ainh[(size_t)NTOK * A_];
__device__ __half g_aouth[(size_t)NTOK * A_];
__device__ __half g_adph[(size_t)NTOK * A_];
__device__ __half g_ch  [(size_t)NTOK * A_];
__device__ __half g_ech [(size_t)E_ * NTOK * A_];
__device__ __half g_scrh[(size_t)B_ * S_ * S_];
__device__ __half g_aTh[(size_t)B_ * A_ * S_];
__device__ __half g_Mh [(size_t)D_ * A_];
__device__ __half g_weT[(size_t)A_ * H_];
__device__ __half g_wouth[(size_t)D_ * H_];
__device__ __half g_wexph[(size_t)E_ * A_ * A_];
__device__ __half g_wuph[(size_t)H_ * D_];
__device__ __half g_wgh [(size_t)H_ * D_];
__device__ __half g_wdh [(size_t)D_ * H_];
__device__ __half g_wpreh[(size_t)A_ * D_], g_wprel[(size_t)A_ * D_];
__device__ __half g_wpoh[(size_t)A_ * H_];
__device__ __half g_waph[(size_t)H_ * A_];

__device__ __forceinline__ float siluf(float x) {
    return x * (1.0f / (1.0f + __expf(-x)));
}

#define LDSM4(r0,r1,r2,r3,addr) \
    asm volatile("ldmatrix.sync.aligned.m8n8.x4.shared.b16 {%0,%1,%2,%3},[%4];\n" \
        : "=r"(r0),"=r"(r1),"=r"(r2),"=r"(r3) : "r"(addr))

#define MMA16816(c,a,b) \
    asm volatile("mma.sync.aligned.m16n8k16.row.col.f32.f16.f16.f32 " \
        "{%0,%1,%2,%3},{%4,%5,%6,%7},{%8,%9},{%0,%1,%2,%3};\n" \
        : "+f"((c)[0]),"+f"((c)[1]),"+f"((c)[2]),"+f"((c)[3]) \
        : "r"((a)[0]),"r"((a)[1]),"r"((a)[2]),"r"((a)[3]),"r"((b)[0]),"r"((b)[1]))

#define CPA16(dst,src) \
    asm volatile("cp.async.cg.shared.global [%0],[%1],16;\n" :: "r"(dst),"l"(src))

// Per-operand tile: 128 rows x 32 halfs, 80B pitch = 10240 bytes.
// 1-pass stage: A@0,B@10240  (20480 B) x 4 stages = 80 KB, wait_group 2
// 3-pass stage: A@0,Al@10240,B@20480,Bl@30720 (40960 B) x 2 stages = 80 KB
constexpr int TG_SMEM = 81920;

// ---------------------------------------------------------------------------
// Tensor GEMM: C[M,N](f32) = split(A)[M,K] @ split(B)[N,K]^T
// PASSES=1: acc = Ah*Bh        PASSES=3: + Ah*Bl + Al*Bh
// CTA tile 128x128x32, 8 warps (4x2), warp tile 32x64, m16n8k16 fp16 mma.
// ds scales acc before epilogue; hs scales the fp16 write.
// EPI: 0 C=acc  1 C=silu(acc)*aux  2 C=aux+0.1*acc  3 C=silu(clip(acc,±5))
// ---------------------------------------------------------------------------
template<int EPI, int PASSES, bool WFP32, bool WH>
__global__ void __launch_bounds__(256, 2) tgemm_k(
    const __half* __restrict__ Ah, const __half* __restrict__ Al,
    const __half* __restrict__ Bh, const __half* __restrict__ Bl,
    float* __restrict__ C, const float* __restrict__ aux,
    __half* __restrict__ Ch,
    int M, int N, int K, long sA, long sB, long sC, float ds, float hs)
{
    constexpr int NST  = (PASSES == 1) ? 4 : 2;
    constexpr int SSZ  = (PASSES == 1) ? 20480 : 40960;
    constexpr unsigned BOFF  = (PASSES == 1) ? 10240u : 20480u;
    constexpr unsigned ALOFF = 10240u;

    extern __shared__ char smem[];
    const unsigned sbase = (unsigned)__cvta_generic_to_shared(smem);
    const int tid = threadIdx.x, lane = tid & 31, warp = tid >> 5;
    const int wm = warp >> 1, wn = warp & 1;

    const long z = blockIdx.z;
    Ah += z * sA; Bh += z * sB;
    if (PASSES == 3) { Al += z * sA; Bl += z * sB; }
    const float* auxp = (EPI == 1 || EPI == 2) ? aux + z * sC : nullptr;
    float* Cp = WFP32 ? C + z * sC : nullptr;
    __half* Chp = WH ? Ch + z * sC : nullptr;

    const int m0 = blockIdx.y * 128, n0 = blockIdx.x * 128;
    const int KT = K / 32;

    float acc[2][8][4];
#pragma unroll
    for (int i = 0; i < 2; i++)
#pragma unroll
        for (int j = 0; j < 8; j++)
#pragma unroll
            for (int e = 0; e < 4; e++) acc[i][j][e] = 0.f;

    const unsigned aAddr = (unsigned)((wm * 32 + (lane & 15)) * 80 + (lane >> 4) * 16);
    const unsigned bAddr = (unsigned)(BOFF +
        (wn * 64 + ((lane >> 4) << 3) + (lane & 7)) * 80 + ((lane >> 3) & 1) * 16);

    auto issue = [&](int kt, int s) {
        const long k0 = (long)kt * 32;
        const unsigned st = sbase + s * SSZ;
#pragma unroll
        for (int i = tid; i < 512; i += 256) {
            const int r = i >> 2, c = i & 3;
            const unsigned da = st + r * 80 + c * 16;
            const long  ga = (long)(m0 + r) * K + k0 + c * 8;
            CPA16(da, Ah + ga);
            if (PASSES == 3) CPA16(da + ALOFF, Al + ga);
            const unsigned db = st + BOFF + r * 80 + c * 16;
            const long  gb = (long)(n0 + r) * K + k0 + c * 8;
            CPA16(db, Bh + gb);
            if (PASSES == 3) CPA16(db + ALOFF, Bl + gb);
        }
        asm volatile("cp.async.commit_group;\n");
    };

    const int pre = (NST - 1 < KT) ? NST - 1 : KT;
    for (int p = 0; p < pre; p++) issue(p, p % NST);

    for (int kt = 0; kt < KT; ++kt) {
        if (NST == 2) {
            asm volatile("cp.async.wait_group 0;\n" ::: "memory");
        } else {
            const int rem = KT - 1 - kt;
            if (rem >= 2)      asm volatile("cp.async.wait_group 2;\n" ::: "memory");
            else if (rem == 1) asm volatile("cp.async.wait_group 1;\n" ::: "memory");
            else               asm volatile("cp.async.wait_group 0;\n" ::: "memory");
        }
        __syncthreads();
        if (kt + NST - 1 < KT) issue(kt + NST - 1, (kt + NST - 1) % NST);

        const unsigned st = sbase + (kt % NST) * SSZ;
#pragma unroll
        for (int kk = 0; kk < 2; kk++) {
            const unsigned ko = kk * 32;
            unsigned ah[2][4], al[2][4], bh[8][2], bl[8][2];
#pragma unroll
            for (int im = 0; im < 2; im++) {
                LDSM4(ah[im][0], ah[im][1], ah[im][2], ah[im][3],
                      st + aAddr + im * 1280 + ko);
                if (PASSES == 3)
                    LDSM4(al[im][0], al[im][1], al[im][2], al[im][3],
                          st + ALOFF + aAddr + im * 1280 + ko);
            }
#pragma unroll
            for (int jp = 0; jp < 4; jp++) {
                LDSM4(bh[2*jp][0], bh[2*jp][1], bh[2*jp+1][0], bh[2*jp+1][1],
                      st + bAddr + jp * 1280 + ko);
                if (PASSES == 3)
                    LDSM4(bl[2*jp][0], bl[2*jp][1], bl[2*jp+1][0], bl[2*jp+1][1],
                          st + ALOFF + bAddr + jp * 1280 + ko);
            }
#pragma unroll
            for (int im = 0; im < 2; im++)
#pragma unroll
                for (int jn = 0; jn < 8; jn++) MMA16816(acc[im][jn], ah[im], bh[jn]);
            if (PASSES == 3) {
#pragma unroll
                for (int im = 0; im < 2; im++)
#pragma unroll
                    for (int jn = 0; jn < 8; jn++) MMA16816(acc[im][jn], ah[im], bl[jn]);
#pragma unroll
                for (int im = 0; im < 2; im++)
#pragma unroll
                    for (int jn = 0; jn < 8; jn++) MMA16816(acc[im][jn], al[im], bh[jn]);
            }
        }
        __syncthreads();
    }

    // epilogue
    const int gr = lane >> 2, q = lane & 3;
#pragma unroll
    for (int im = 0; im < 2; im++) {
#pragma unroll
        for (int jn = 0; jn < 8; jn++) {
            const long r0  = m0 + wm * 32 + im * 16 + gr;
            const long col = n0 + wn * 64 + jn * 8 + q * 2;
            const long i0 = r0 * N + col, i1 = i0 + 8L * N;
            float v0 = acc[im][jn][0] * ds, v1 = acc[im][jn][1] * ds;
            float v2 = acc[im][jn][2] * ds, v3 = acc[im][jn][3] * ds;
            if (EPI == 1) {
                float2 a0 = *(const float2*)(auxp + i0);
                float2 a1 = *(const float2*)(auxp + i1);
                v0 = siluf(v0) * a0.x; v1 = siluf(v1) * a0.y;
                v2 = siluf(v2) * a1.x; v3 = siluf(v3) * a1.y;
            } else if (EPI == 2) {
                float2 a0 = *(const float2*)(auxp + i0);
                float2 a1 = *(const float2*)(auxp + i1);
                v0 = fmaf(0.1f, v0, a0.x); v1 = fmaf(0.1f, v1, a0.y);
                v2 = fmaf(0.1f, v2, a1.x); v3 = fmaf(0.1f, v3, a1.y);
            } else if (EPI == 3) {
                v0 = siluf(fminf(fmaxf(v0, -5.f), 5.f));
                v1 = siluf(fminf(fmaxf(v1, -5.f), 5.f));
                v2 = siluf(fminf(fmaxf(v2, -5.f), 5.f));
                v3 = siluf(fminf(fmaxf(v3, -5.f), 5.f));
            }
            if (WFP32) {
                *(float2*)(Cp + i0) = make_float2(v0, v1);
                *(float2*)(Cp + i1) = make_float2(v2, v3);
            }
            if (WH) {
                __half2 hh;
                hh.x = __float2half(v0 * hs); hh.y = __float2half(v1 * hs);
                *(__half2*)(Chp + i0) = hh;
                hh.x = __float2half(v2 * hs); hh.y = __float2half(v3 * hs);
                *(__half2*)(Chp + i1) = hh;
            }
        }
    }
}

// ---------------------------------------------------------------------------
// fp32 -> fp16 hi/lo split with pre-scale (x only)
// ---------------------------------------------------------------------------
__global__ void split_k(const float* __restrict__ X,
                        __half* __restrict__ Hh, __half* __restrict__ Hl,
                        long n4, float scale)
{
    long i = blockIdx.x * (long)blockDim.x + threadIdx.x;
    if (i >= n4) return;
    float4 v = ((const float4*)X)[i];
    v.x *= scale; v.y *= scale; v.z *= scale; v.w *= scale;
    __half2 h0, h1, l0, l1;
    h0.x = __float2half(v.x); l0.x = __float2half(v.x - __half2float(h0.x));
    h0.y = __float2half(v.y); l0.y = __float2half(v.y - __half2float(h0.y));
    h1.x = __float2half(v.z); l1.x = __float2half(v.z - __half2float(h1.x));
    h1.y = __float2half(v.w); l1.y = __float2half(v.w - __half2float(h1.y));
    ((__half2*)Hh)[2*i]   = h0; ((__half2*)Hh)[2*i+1] = h1;
    ((__half2*)Hl)[2*i]   = l0; ((__half2*)Hl)[2*i+1] = l1;
}

// ---------------------------------------------------------------------------
// Fused multi-array fp32 -> fp16 split (hi always; lo if dl != null)
// ---------------------------------------------------------------------------
struct SJobs {
    const float* src[8];
    __half* dh[8];
    __half* dl[8];
    int   nblk[8];
    long  n4[8];
    float sc[8];
};

__global__ void msplit_k(SJobs J)
{
    int b = blockIdx.x, j = 0;
    while (j < 7 && b >= J.nblk[j]) { b -= J.nblk[j]; j++; }
    long i = (long)b * 256 + threadIdx.x;
    if (i >= J.n4[j]) return;
    float sc = J.sc[j];
    float4 v = ((const float4*)J.src[j])[i];
    v.x *= sc; v.y *= sc; v.z *= sc; v.w *= sc;
    __half2 h0, h1;
    h0.x = __float2half(v.x); h0.y = __float2half(v.y);
    h1.x = __float2half(v.z); h1.y = __float2half(v.w);
    ((__half2*)J.dh[j])[2*i]   = h0;
    ((__half2*)J.dh[j])[2*i+1] = h1;
    if (J.dl[j]) {
        __half2 l0, l1;
        l0.x = __float2half(v.x - __half2float(h0.x));
        l0.y = __float2half(v.y - __half2float(h0.y));
        l1.x = __float2half(v.z - __half2float(h1.x));
        l1.y = __float2half(v.w - __half2float(h1.y));
        ((__half2*)J.dl[j])[2*i]   = l0;
        ((__half2*)J.dl[j])[2*i+1] = l1;
    }
}

// ---------------------------------------------------------------------------
// Generic transpose [R,C]->[C,R] fp32 -> fp16(scale).  grid(R/32, C/32, nz)
// ---------------------------------------------------------------------------
__global__ void tsplitg_k(const float* __restrict__ X, __half* __restrict__ T,
                          int R, int C, float scale)
{
    __shared__ float t[32][33];
    const long zb = blockIdx.z;
    X += zb * (long)R * C;  T += zb * (long)R * C;
    const int r0 = blockIdx.x * 32, c0 = blockIdx.y * 32;
    const int tx = threadIdx.x, ty = threadIdx.y;
#pragma unroll
    for (int i = 0; i < 4; i++) {
        int rr = ty * 4 + i;
        t[rr][tx] = X[(long)(r0 + rr) * C + c0 + tx];
    }
    __syncthreads();
#pragma unroll
    for (int i = 0; i < 4; i++) {
        int cc = ty * 4 + i;
        T[(long)(c0 + cc) * R + r0 + tx] = __float2half(t[tx][cc] * scale);
    }
}

// ---------------------------------------------------------------------------
// LayerNorm rows of 128 (one warp/row); writes fp32 + fp16 hi
// ---------------------------------------------------------------------------
__global__ void ln_k(const float* __restrict__ X, float* __restrict__ Y,
                     __half* __restrict__ Yh,
                     const float* __restrict__ g, const float* __restrict__ b,
                     int rows)
{
    int row  = (blockIdx.x * blockDim.x + threadIdx.x) >> 5;
    int lane = threadIdx.x & 31;
    if (row >= rows) return;
    float4 x = *(const float4*)(X + (long)row * 128 + lane * 4);
    float s  = x.x + x.y + x.z + x.w;
    float ss = fmaf(x.x, x.x, fmaf(x.y, x.y, fmaf(x.z, x.z, x.w * x.w)));
#pragma unroll
    for (int o = 16; o > 0; o >>= 1) {
        s  += __shfl_xor_sync(0xffffffffu, s,  o);
        ss += __shfl_xor_sync(0xffffffffu, ss, o);
    }
    float m   = s * (1.f / 128.f);
    float inv = rsqrtf(ss * (1.f / 128.f) - m * m + 1e-5f);
    float4 gg = *(const float4*)(g + lane * 4);
    float4 bb = *(const float4*)(b + lane * 4);
    float4 y;
    y.x = fmaf((x.x - m) * inv, gg.x, bb.x);
    y.y = fmaf((x.y - m) * inv, gg.y, bb.y);
    y.z = fmaf((x.z - m) * inv, gg.z, bb.z);
    y.w = fmaf((x.w - m) * inv, gg.w, bb.w);
    const long base = (long)row * 128 + lane * 4;
    *(float4*)(Y + base) = y;
    __half2 h0, h1;
    h0.x = __float2half(y.x); h0.y = __float2half(y.y);
    h1.x = __float2half(y.z); h1.y = __float2half(y.w);
    *(__half2*)(Yh + base)     = h0;
    *(__half2*)(Yh + base + 2) = h1;
}

// ---------------------------------------------------------------------------
// Expert select + LN from fp16 ec (scaled 8192): per token (one warp),
// idx = LAST expert with ew>0; ch = fp16(LN(ec[idx]/8192, eln[idx])) or 0.
// ---------------------------------------------------------------------------
__global__ void lnsel_k(const __half* __restrict__ ec, const float* __restrict__ ew,
                        const float* __restrict__ eg, const float* __restrict__ eb,
                        __half* __restrict__ ch, int rows)
{
    int row  = (blockIdx.x * blockDim.x + threadIdx.x) >> 5;
    int lane = threadIdx.x & 31;
    if (row >= rows) return;
    float w = (lane < E_) ? ew[(long)row * E_ + lane] : 0.f;
    unsigned m = __ballot_sync(0xffffffffu, w > 0.f) & 0xFFu;
    const long base = (long)row * 128 + lane * 4;
    if (m == 0) {
        __half2 zz; zz.x = __float2half(0.f); zz.y = zz.x;
        *(__half2*)(ch + base) = zz; *(__half2*)(ch + base + 2) = zz;
        return;
    }
    int idx = 31 - __clz(m);
    const long eb0 = ((long)idx * NTOK + row) * 128 + lane * 4;
    __half2 e0 = *(const __half2*)(ec + eb0);
    __half2 e1 = *(const __half2*)(ec + eb0 + 2);
    const float DSC = 1.f / 8192.f;
    float4 x;
    x.x = __half2float(e0.x) * DSC; x.y = __half2float(e0.y) * DSC;
    x.z = __half2float(e1.x) * DSC; x.w = __half2float(e1.y) * DSC;
    float s  = x.x + x.y + x.z + x.w;
    float ss = fmaf(x.x, x.x, fmaf(x.y, x.y, fmaf(x.z, x.z, x.w * x.w)));
#pragma unroll
    for (int o = 16; o > 0; o >>= 1) {
        s  += __shfl_xor_sync(0xffffffffu, s,  o);
        ss += __shfl_xor_sync(0xffffffffu, ss, o);
    }
    float mn  = s * (1.f / 128.f);
    float inv = rsqrtf(ss * (1.f / 128.f) - mn * mn + 1e-5f);
    float4 gg = *(const float4*)(eg + (long)idx * 128 + lane * 4);
    float4 bb = *(const float4*)(eb + (long)idx * 128 + lane * 4);
    __half2 h0, h1;
    h0.x = __float2half(fmaf((x.x - mn) * inv, gg.x, bb.x));
    h0.y = __float2half(fmaf((x.y - mn) * inv, gg.y, bb.y));
    h1.x = __float2half(fmaf((x.z - mn) * inv, gg.z, bb.z));
    h1.y = __float2half(fmaf((x.w - mn) * inv, gg.w, bb.w));
    *(__half2*)(ch + base)     = h0;
    *(__half2*)(ch + base + 2) = h1;
}

// ---------------------------------------------------------------------------
extern "C" void kernel_launch(void* const* d_in, const int* in_sizes, int n_in,
                              void* d_out, int out_size)
{
    const float* x       = (const float*)d_in[0];
    const float* ew      = (const float*)d_in[1];
    const float* w_up    = (const float*)d_in[2];
    const float* w_gate  = (const float*)d_in[3];
    const float* w_down  = (const float*)d_in[4];
    const float* w_pre   = (const float*)d_in[5];
    const float* w_post  = (const float*)d_in[6];
    const float* an_g    = (const float*)d_in[7];
    const float* an_b    = (const float*)d_in[8];
    const float* w_aproj = (const float*)d_in[9];
    const float* w_exp   = (const float*)d_in[10];
    const float* eln_g   = (const float*)d_in[11];
    const float* eln_b   = (const float*)d_in[12];
    const float* w_eproj = (const float*)d_in[13];
    const float* w_out   = (const float*)d_in[14];
    float* out = (float*)d_out;

    float *U, *Hd, *pre, *ain, *pt, *aout;
    cudaGetSymbolAddress((void**)&U,    g_U);
    cudaGetSymbolAddress((void**)&Hd,   g_Hd);
    cudaGetSymbolAddress((void**)&pre,  g_pre);
    cudaGetSymbolAddress((void**)&ain,  g_ain);
    cudaGetSymbolAddress((void**)&pt,   g_pt);
    cudaGetSymbolAddress((void**)&aout, g_aout);

    __half *xh,*xl,*Hdh,*preh,*ainh,*aouth,*adph,*chh,*ech,*scrh,*aTh;
    __half *Mhp,*weT,*wouth,*wexph;
    __half *wuph,*wgh,*wdh,*wpreh,*wprel,*wpoh,*waph;
    cudaGetSymbolAddress((void**)&xh,    g_xh);   cudaGetSymbolAddress((void**)&xl,    g_xl);
    cudaGetSymbolAddress((void**)&Hdh,   g_Hdh);  cudaGetSymbolAddress((void**)&preh,  g_preh);
    cudaGetSymbolAddress((void**)&ainh,  g_ainh); cudaGetSymbolAddress((void**)&aouth, g_aouth);
    cudaGetSymbolAddress((void**)&adph,  g_adph); cudaGetSymbolAddress((void**)&chh,   g_ch);
    cudaGetSymbolAddress((void**)&ech,   g_ech);
    cudaGetSymbolAddress((void**)&scrh,  g_scrh); cudaGetSymbolAddress((void**)&aTh,   g_aTh);
    cudaGetSymbolAddress((void**)&Mhp,   g_Mh);   cudaGetSymbolAddress((void**)&weT,   g_weT);
    cudaGetSymbolAddress((void**)&wouth, g_wouth);cudaGetSymbolAddress((void**)&wexph, g_wexph);
    cudaGetSymbolAddress((void**)&wuph,  g_wuph); cudaGetSymbolAddress((void**)&wgh,   g_wgh);
    cudaGetSymbolAddress((void**)&wdh,   g_wdh);
    cudaGetSymbolAddress((void**)&wpreh, g_wpreh);cudaGetSymbolAddress((void**)&wprel, g_wprel);
    cudaGetSymbolAddress((void**)&wpoh,  g_wpoh); cudaGetSymbolAddress((void**)&waph,  g_waph);

    cudaFuncSetAttribute(tgemm_k<0,1,true ,false>, cudaFuncAttributeMaxDynamicSharedMemorySize, TG_SMEM);
    cudaFuncSetAttribute(tgemm_k<1,1,true ,true >, cudaFuncAttributeMaxDynamicSharedMemorySize, TG_SMEM);
    cudaFuncSetAttribute(tgemm_k<0,3,true ,true >, cudaFuncAttributeMaxDynamicSharedMemorySize, TG_SMEM);
    cudaFuncSetAttribute(tgemm_k<3,1,false,true >, cudaFuncAttributeMaxDynamicSharedMemorySize, TG_SMEM);
    cudaFuncSetAttribute(tgemm_k<0,1,false,true >, cudaFuncAttributeMaxDynamicSharedMemorySize, TG_SMEM);
    cudaFuncSetAttribute(tgemm_k<2,1,false,true >, cudaFuncAttributeMaxDynamicSharedMemorySize, TG_SMEM);
    cudaFuncSetAttribute(tgemm_k<2,1,true ,false>, cudaFuncAttributeMaxDynamicSharedMemorySize, TG_SMEM);

    const float DS = 1.0f / 512.0f;

    // 1) split x (h/l)
    {
        long n4 = (long)NTOK * D_ / 4;
        split_k<<<(unsigned)((n4 + 255) / 256), 256>>>(x, xh, xl, n4, 1.f);
    }

    // 2) fused weight splits
    {
        SJobs J;
        auto set = [&](int j, const float* s, __half* dh, __half* dl, long n, float sc) {
            J.src[j] = s; J.dh[j] = dh; J.dl[j] = dl;
            J.n4[j] = n / 4; J.nblk[j] = (int)((J.n4[j] + 255) / 256); J.sc[j] = sc;
        };
        set(0, w_up,    wuph,  nullptr, (long)H_ * D_,      1.f);
        set(1, w_gate,  wgh,   nullptr, (long)H_ * D_,      1.f);
        set(2, w_down,  wdh,   nullptr, (long)D_ * H_,      1.f);
        set(3, w_pre,   wpreh, wprel,   (long)A_ * D_,      512.f);
        set(4, w_post,  wpoh,  nullptr, (long)A_ * H_,      512.f);
        set(5, w_aproj, waph,  nullptr, (long)H_ * A_,      512.f);
        set(6, w_exp,   wexph, nullptr, (long)E_ * A_ * A_, 512.f);
        set(7, w_out,   wouth, nullptr, (long)D_ * H_,      32.f);
        int total = 0;
        for (int j = 0; j < 8; j++) total += J.nblk[j];
        msplit_k<<<total, 256>>>(J);
    }

    // 3) weT = transpose(w_eproj)[A,H] * 512
    tsplitg_k<<<dim3(H_/32, A_/32, 1), dim3(32, 8)>>>(w_eproj, weT, H_, A_, 512.f);

    // 4) Mh = (32*w_out) @ weT^T  -> fp16, carries scale 16384
    tgemm_k<0,1,false,true><<<dim3(1, D_/128, 1), 256, TG_SMEM>>>(
        wouth, nullptr, weT, nullptr, nullptr, nullptr, Mhp,
        D_, A_, H_, 0, 0, 0, 1.f, 1.f);

    // 5) U = x @ w_up^T
    tgemm_k<0,1,true,false><<<dim3(H_/128, NTOK/128, 1), 256, TG_SMEM>>>(
        xh, nullptr, wuph, nullptr, U, nullptr, nullptr, NTOK, H_, D_, 0, 0, 0, 1.f, 1.f);

    // 6) Hid = silu(x @ w_gate^T) * U  (+Hdh)    <-- ncu -s 5 captures this
    tgemm_k<1,1,true,true><<<dim3(H_/128, NTOK/128, 1), 256, TG_SMEM>>>(
        xh, nullptr, wgh, nullptr, Hd, U, Hdh, NTOK, H_, D_, 0, 0, 0, 1.f, 1.f);

    // 7) pre = x @ w_pre^T  (+preh = fp16(512*pre))   (3-pass)
    tgemm_k<0,3,true,true><<<dim3(1, NTOK/128, 1), 256, TG_SMEM>>>(
        xh, xl, wpreh, wprel, pre, nullptr, preh, NTOK, A_, D_, 0, 0, 0, DS, 512.f);

    // 8) ain = LN(pre)  (+h)
    ln_k<<<NTOK/8, 256>>>(pre, ain, ainh, an_g, an_b, NTOK);

    // 9) pt = Hid @ w_post^T
    tgemm_k<0,1,true,false><<<dim3(1, NTOK/128, 1), 256, TG_SMEM>>>(
        Hdh, nullptr, wpoh, nullptr, pt, nullptr, nullptr, NTOK, A_, H_, 0, 0, 0, DS, 1.f);

    // 10) aout = LN(pt)  (+h)
    ln_k<<<NTOK/8, 256>>>(pt, aout, aouth, an_g, an_b, NTOK);

    // 11) scrh[b] = silu(clip(ain[b] @ aout[b]^T))
    tgemm_k<3,1,false,true><<<dim3(S_/128, S_/128, B_), 256, TG_SMEM>>>(
        ainh, nullptr, aouth, nullptr, nullptr, nullptr, scrh,
        S_, S_, A_, (long)S_ * A_, (long)S_ * A_, (long)S_ * S_, 1.f, 1.f);

    // 12) aTh = transpose(ain) hi  (per batch)
    tsplitg_k<<<dim3(S_/32, A_/32, B_), dim3(32, 8)>>>(ain, aTh, S_, A_, 1.f);

    // 13) adph[b] = scr[b] @ aT[b]^T
    tgemm_k<0,1,false,true><<<dim3(1, S_/128, B_), 256, TG_SMEM>>>(
        scrh, nullptr, aTh, nullptr, nullptr, nullptr, adph,
        S_, A_, S_, (long)S_ * S_, (long)A_ * S_, (long)S_ * A_, 1.f, 1.f);

    // 14) Hdh = Hid + 0.1 * adp @ w_aproj^T
    tgemm_k<2,1,false,true><<<dim3(H_/128, NTOK/128, 1), 256, TG_SMEM>>>(
        adph, nullptr, waph, nullptr, nullptr, Hd, Hdh, NTOK, H_, A_, 0, 0, 0, DS, 1.f);

    // 15) out = Hid @ w_down^T
    tgemm_k<0,1,true,false><<<dim3(D_/128, NTOK/128, 1), 256, TG_SMEM>>>(
        Hdh, nullptr, wdh, nullptr, out, nullptr, nullptr, NTOK, D_, H_, 0, 0, 0, 1.f, 1.f);

    // e1) ech_i = fp16(8192 * pre @ w_exp[i]^T)  (batched over 8 experts)
    //     acc carries 512*512; ds = 8192/(512*512) = 1/32
    tgemm_k<0,1,false,true><<<dim3(1, NTOK/128, E_), 256, TG_SMEM>>>(
        preh, nullptr, wexph, nullptr, nullptr, nullptr, ech,
        NTOK, A_, A_, 0, (long)A_ * A_, (long)NTOK * A_, 1.f / 32.f, 1.f);

    // e2) ch = LN(ech[last-positive]/8192, eln)  (0 if none)
    lnsel_k<<<NTOK/8, 256>>>(ech, ew, eln_g, eln_b, chh, NTOK);

    // e3) out += 0.1 * ch @ Mh^T   (Mh carries 16384 -> ds = 1/16384)
    tgemm_k<2,1,true,false><<<dim3(D_/128, NTOK/128, 1), 256, TG_SMEM>>>(
        chh, nullptr, Mhp, nullptr, out, out, nullptr,
        NTOK, D_, A_, 0, 0, 0, 1.f / 16384.f, 1.f);
}

// round 10
// speedup vs baseline: 6.0829x; 1.0317x over previous
#include <cuda_runtime.h>
#include <cuda_fp16.h>
#include <cstdint>

// ---------------------------------------------------------------------------
// LLaDAModel fused forward — mma.sync fp16-split GEMMs + split-K for
// under-occupied N=128 GEMMs.  B=8,S=2048,D=1024,H=2048,A=128,E=8. N=16384.
//
//   s.   split x (h/l);  fused weight splits (astd weights prescaled 512)
//   0a.  weT = transpose(w_eproj)*512
//   0b.  Mh  = (32*w_out) @ weT^T       split-K 8 + redsum  (carries 16384)
//   1.   U    = x @ w_up^T                         [N,H]  1-pass
//   2.   Hid  = silu(x @ w_gate^T)*U  (+Hdh)       [N,H]  1-pass
//   3.   pre  = x @ w_pre^T  (+preh*512)           [N,A]  3-pass, split-K 4
//   4.   ain  = LN(pre)  (+h)                      [N,A]
//   5.   pt   = Hid @ w_post^T                     [N,A]  1-pass, split-K 4
//   6.   aout = LN(pt)   (+h)                      [N,A]
//   7.   scrh = silu(clip(ain @ aout^T)) per b     [S,S]  1-pass
//   7b.  aTh  = transpose(ain) hi         per b    [A,S]
//   8.   adph = scr @ aT^T                per b    [N,A]  1-pass, split-K 4
//   9.   Hdh  = Hid + 0.1*adp @ w_aproj^T          [N,H]  1-pass
//  10.   out  = Hid @ w_down^T                     [N,D]  1-pass
//  e1.   ech_i = fp16(8192 * pre @ w_exp[i]^T)     [N,A]  1-pass (batched)
//  e2.   ch   = LN(ech[last-positive], eln)        [N,A]
//  e3.   out += 0.1 * ch @ Mh^T                    [N,D]  1-pass
// ---------------------------------------------------------------------------

constexpr int B_ = 8, S_ = 2048, D_ = 1024, H_ = 2048, A_ = 128, E_ = 8;
constexpr int NTOK = B_ * S_;   // 16384

// fp32 scratch
__device__ float g_U   [(size_t)NTOK * H_];
__device__ float g_Hd  [(size_t)NTOK * H_];
__device__ float g_pre [(size_t)NTOK * A_];
__device__ float g_ain [(size_t)NTOK * A_];
__device__ float g_pt  [(size_t)NTOK * A_];
__device__ float g_aout[(size_t)NTOK * A_];
__device__ float g_part[(size_t)NTOK * A_ * 4];   // split-K partials (max case)

// fp16 scratch
__device__ __half g_xh [(size_t)NTOK * D_], g_xl [(size_t)NTOK * D_];
__device__ __half g_Hdh[(size_t)NTOK * H_];
__device__ __half g_preh[(size_t)NTOK * A_];
__device__ __half g_ainh[(size_t)NTOK * A_];
__device__ __half g_aouth[(size_t)NTOK * A_];
__device__ __half g_adph[(size_t)NTOK * A_];
__device__ __half g_ch  [(size_t)NTOK * A_];
__device__ __half g_ech [(size_t)E_ * NTOK * A_];
__device__ __half g_scrh[(size_t)B_ * S_ * S_];
__device__ __half g_aTh[(size_t)B_ * A_ * S_];
__device__ __half g_Mh [(size_t)D_ * A_];
__device__ __half g_weT[(size_t)A_ * H_];
__device__ __half g_wouth[(size_t)D_ * H_];
__device__ __half g_wexph[(size_t)E_ * A_ * A_];
__device__ __half g_wuph[(size_t)H_ * D_];
__device__ __half g_wgh [(size_t)H_ * D_];
__device__ __half g_wdh [(size_t)D_ * H_];
__device__ __half g_wpreh[(size_t)A_ * D_], g_wprel[(size_t)A_ * D_];
__device__ __half g_wpoh[(size_t)A_ * H_];
__device__ __half g_waph[(size_t)H_ * A_];

__device__ __forceinline__ float siluf(float x) {
    return x * (1.0f / (1.0f + __expf(-x)));
}

#define LDSM4(r0,r1,r2,r3,addr) \
    asm volatile("ldmatrix.sync.aligned.m8n8.x4.shared.b16 {%0,%1,%2,%3},[%4];\n" \
        : "=r"(r0),"=r"(r1),"=r"(r2),"=r"(r3) : "r"(addr))

#define MMA16816(c,a,b) \
    asm volatile("mma.sync.aligned.m16n8k16.row.col.f32.f16.f16.f32 " \
        "{%0,%1,%2,%3},{%4,%5,%6,%7},{%8,%9},{%0,%1,%2,%3};\n" \
        : "+f"((c)[0]),"+f"((c)[1]),"+f"((c)[2]),"+f"((c)[3]) \
        : "r"((a)[0]),"r"((a)[1]),"r"((a)[2]),"r"((a)[3]),"r"((b)[0]),"r"((b)[1]))

#define CPA16(dst,src) \
    asm volatile("cp.async.cg.shared.global [%0],[%1],16;\n" :: "r"(dst),"l"(src))

constexpr int TG_SMEM = 81920;

// ---------------------------------------------------------------------------
// Tensor GEMM: C[M,N](f32) = split(A)[M,K] @ split(B)[N,K]^T
// PASSES=1: acc = Ah*Bh        PASSES=3: + Ah*Bl + Al*Bh
// CTA tile 128x128x32, 8 warps (4x2), warp tile 32x64, m16n8k16 fp16 mma.
// SPLIT: grid.x = K-split index (requires N=128); raw fp32 partials go to
//        C + (z*gridDim.x + blockIdx.x)*M*N; epilogue/scaling deferred.
// EPI: 0 C=acc  1 C=silu(acc)*aux  2 C=aux+0.1*acc  3 C=silu(clip(acc,±5))
// ---------------------------------------------------------------------------
template<int EPI, int PASSES, bool WFP32, bool WH, bool SPLIT>
__global__ void __launch_bounds__(256, 2) tgemm_k(
    const __half* __restrict__ Ah, const __half* __restrict__ Al,
    const __half* __restrict__ Bh, const __half* __restrict__ Bl,
    float* __restrict__ C, const float* __restrict__ aux,
    __half* __restrict__ Ch,
    int M, int N, int K, long sA, long sB, long sC, float ds, float hs)
{
    constexpr int NST  = (PASSES == 1) ? 4 : 2;
    constexpr int SSZ  = (PASSES == 1) ? 20480 : 40960;
    constexpr unsigned BOFF  = (PASSES == 1) ? 10240u : 20480u;
    constexpr unsigned ALOFF = 10240u;

    extern __shared__ char smem[];
    const unsigned sbase = (unsigned)__cvta_generic_to_shared(smem);
    const int tid = threadIdx.x, lane = tid & 31, warp = tid >> 5;
    const int wm = warp >> 1, wn = warp & 1;

    const long z = blockIdx.z;
    Ah += z * sA; Bh += z * sB;
    if (PASSES == 3) { Al += z * sA; Bl += z * sB; }
    const float* auxp = (EPI == 1 || EPI == 2) ? aux + z * sC : nullptr;
    float* Cp;
    __half* Chp = nullptr;
    if (SPLIT) {
        Cp = C + ((z * gridDim.x + blockIdx.x) * (long)M) * N;
    } else {
        Cp = WFP32 ? C + z * sC : nullptr;
        Chp = WH ? Ch + z * sC : nullptr;
    }

    const int m0 = blockIdx.y * 128;
    const int n0 = SPLIT ? 0 : blockIdx.x * 128;

    const int KT = K / 32;
    int t0k = 0, TCNT = KT;
    if (SPLIT) { TCNT = KT / gridDim.x; t0k = blockIdx.x * TCNT; }

    float acc[2][8][4];
#pragma unroll
    for (int i = 0; i < 2; i++)
#pragma unroll
        for (int j = 0; j < 8; j++)
#pragma unroll
            for (int e = 0; e < 4; e++) acc[i][j][e] = 0.f;

    const unsigned aAddr = (unsigned)((wm * 32 + (lane & 15)) * 80 + (lane >> 4) * 16);
    const unsigned bAddr = (unsigned)(BOFF +
        (wn * 64 + ((lane >> 4) << 3) + (lane & 7)) * 80 + ((lane >> 3) & 1) * 16);

    auto issue = [&](int t, int s) {
        const long k0 = (long)(t0k + t) * 32;
        const unsigned st = sbase + s * SSZ;
#pragma unroll
        for (int i = tid; i < 512; i += 256) {
            const int r = i >> 2, c = i & 3;
            const unsigned da = st + r * 80 + c * 16;
            const long  ga = (long)(m0 + r) * K + k0 + c * 8;
            CPA16(da, Ah + ga);
            if (PASSES == 3) CPA16(da + ALOFF, Al + ga);
            const unsigned db = st + BOFF + r * 80 + c * 16;
            const long  gb = (long)(n0 + r) * K + k0 + c * 8;
            CPA16(db, Bh + gb);
            if (PASSES == 3) CPA16(db + ALOFF, Bl + gb);
        }
        asm volatile("cp.async.commit_group;\n");
    };

    const int pre = (NST - 1 < TCNT) ? NST - 1 : TCNT;
    for (int p = 0; p < pre; p++) issue(p, p % NST);

    for (int t = 0; t < TCNT; ++t) {
        if (NST == 2) {
            asm volatile("cp.async.wait_group 0;\n" ::: "memory");
        } else {
            const int rem = TCNT - 1 - t;
            if (rem >= 2)      asm volatile("cp.async.wait_group 2;\n" ::: "memory");
            else if (rem == 1) asm volatile("cp.async.wait_group 1;\n" ::: "memory");
            else               asm volatile("cp.async.wait_group 0;\n" ::: "memory");
        }
        __syncthreads();
        if (t + NST - 1 < TCNT) issue(t + NST - 1, (t + NST - 1) % NST);

        const unsigned st = sbase + (t % NST) * SSZ;
#pragma unroll
        for (int kk = 0; kk < 2; kk++) {
            const unsigned ko = kk * 32;
            unsigned ah[2][4], al[2][4], bh[8][2], bl[8][2];
#pragma unroll
            for (int im = 0; im < 2; im++) {
                LDSM4(ah[im][0], ah[im][1], ah[im][2], ah[im][3],
                      st + aAddr + im * 1280 + ko);
                if (PASSES == 3)
                    LDSM4(al[im][0], al[im][1], al[im][2], al[im][3],
                          st + ALOFF + aAddr + im * 1280 + ko);
            }
#pragma unroll
            for (int jp = 0; jp < 4; jp++) {
                LDSM4(bh[2*jp][0], bh[2*jp][1], bh[2*jp+1][0], bh[2*jp+1][1],
                      st + bAddr + jp * 1280 + ko);
                if (PASSES == 3)
                    LDSM4(bl[2*jp][0], bl[2*jp][1], bl[2*jp+1][0], bl[2*jp+1][1],
                          st + ALOFF + bAddr + jp * 1280 + ko);
            }
#pragma unroll
            for (int im = 0; im < 2; im++)
#pragma unroll
                for (int jn = 0; jn < 8; jn++) MMA16816(acc[im][jn], ah[im], bh[jn]);
            if (PASSES == 3) {
#pragma unroll
                for (int im = 0; im < 2; im++)
#pragma unroll
                    for (int jn = 0; jn < 8; jn++) MMA16816(acc[im][jn], ah[im], bl[jn]);
#pragma unroll
                for (int im = 0; im < 2; im++)
#pragma unroll
                    for (int jn = 0; jn < 8; jn++) MMA16816(acc[im][jn], al[im], bh[jn]);
            }
        }
        __syncthreads();
    }

    // epilogue
    const int gr = lane >> 2, q = lane & 3;
#pragma unroll
    for (int im = 0; im < 2; im++) {
#pragma unroll
        for (int jn = 0; jn < 8; jn++) {
            const long r0  = m0 + wm * 32 + im * 16 + gr;
            const long col = n0 + wn * 64 + jn * 8 + q * 2;
            const long i0 = r0 * N + col, i1 = i0 + 8L * N;
            if (SPLIT) {   // raw partials, no scaling
                *(float2*)(Cp + i0) = make_float2(acc[im][jn][0], acc[im][jn][1]);
                *(float2*)(Cp + i1) = make_float2(acc[im][jn][2], acc[im][jn][3]);
                continue;
            }
            float v0 = acc[im][jn][0] * ds, v1 = acc[im][jn][1] * ds;
            float v2 = acc[im][jn][2] * ds, v3 = acc[im][jn][3] * ds;
            if (EPI == 1) {
                float2 a0 = *(const float2*)(auxp + i0);
                float2 a1 = *(const float2*)(auxp + i1);
                v0 = siluf(v0) * a0.x; v1 = siluf(v1) * a0.y;
                v2 = siluf(v2) * a1.x; v3 = siluf(v3) * a1.y;
            } else if (EPI == 2) {
                float2 a0 = *(const float2*)(auxp + i0);
                float2 a1 = *(const float2*)(auxp + i1);
                v0 = fmaf(0.1f, v0, a0.x); v1 = fmaf(0.1f, v1, a0.y);
                v2 = fmaf(0.1f, v2, a1.x); v3 = fmaf(0.1f, v3, a1.y);
            } else if (EPI == 3) {
                v0 = siluf(fminf(fmaxf(v0, -5.f), 5.f));
                v1 = siluf(fminf(fmaxf(v1, -5.f), 5.f));
                v2 = siluf(fminf(fmaxf(v2, -5.f), 5.f));
                v3 = siluf(fminf(fmaxf(v3, -5.f), 5.f));
            }
            if (WFP32) {
                *(float2*)(Cp + i0) = make_float2(v0, v1);
                *(float2*)(Cp + i1) = make_float2(v2, v3);
            }
            if (WH) {
                __half2 hh;
                hh.x = __float2half(v0 * hs); hh.y = __float2half(v1 * hs);
                *(__half2*)(Chp + i0) = hh;
                hh.x = __float2half(v2 * hs); hh.y = __float2half(v3 * hs);
                *(__half2*)(Chp + i1) = hh;
            }
        }
    }
}

// ---------------------------------------------------------------------------
// Split-K reduce + epilogue: sums SK partials (deterministic order), writes
// fp32 (dsY * sum) if Y != null and fp16 (dsH * sum) if Yh != null.
// Partial layout: part[(z*SK + s)*MN + r],  r in [0, MN).
// ---------------------------------------------------------------------------
__global__ void redsum_k(const float* __restrict__ part,
                         float* __restrict__ Y, __half* __restrict__ Yh,
                         int SK, long MN, long n4, float dsY, float dsH)
{
    long i = blockIdx.x * (long)blockDim.x + threadIdx.x;
    if (i >= n4) return;
    long e0 = i * 4;
    long zz = e0 / MN, r = e0 - zz * MN;
    const float* p = part + (zz * SK) * MN + r;
    float4 s = *(const float4*)p;
    for (int k = 1; k < SK; k++) {
        float4 v = *(const float4*)(p + (long)k * MN);
        s.x += v.x; s.y += v.y; s.z += v.z; s.w += v.w;
    }
    if (Y) {
        float4 o;
        o.x = s.x * dsY; o.y = s.y * dsY; o.z = s.z * dsY; o.w = s.w * dsY;
        *(float4*)(Y + e0) = o;
    }
    if (Yh) {
        __half2 h0, h1;
        h0.x = __float2half(s.x * dsH); h0.y = __float2half(s.y * dsH);
        h1.x = __float2half(s.z * dsH); h1.y = __float2half(s.w * dsH);
        *(__half2*)(Yh + e0)     = h0;
        *(__half2*)(Yh + e0 + 2) = h1;
    }
}

// ---------------------------------------------------------------------------
// fp32 -> fp16 hi/lo split with pre-scale (x only)
// ---------------------------------------------------------------------------
__global__ void split_k(const float* __restrict__ X,
                        __half* __restrict__ Hh, __half* __restrict__ Hl,
                        long n4, float scale)
{
    long i = blockIdx.x * (long)blockDim.x + threadIdx.x;
    if (i >= n4) return;
    float4 v = ((const float4*)X)[i];
    v.x *= scale; v.y *= scale; v.z *= scale; v.w *= scale;
    __half2 h0, h1, l0, l1;
    h0.x = __float2half(v.x); l0.x = __float2half(v.x - __half2float(h0.x));
    h0.y = __float2half(v.y); l0.y = __float2half(v.y - __half2float(h0.y));
    h1.x = __float2half(v.z); l1.x = __float2half(v.z - __half2float(h1.x));
    h1.y = __float2half(v.w); l1.y = __float2half(v.w - __half2float(h1.y));
    ((__half2*)Hh)[2*i]   = h0; ((__half2*)Hh)[2*i+1] = h1;
    ((__half2*)Hl)[2*i]   = l0; ((__half2*)Hl)[2*i+1] = l1;
}

// ---------------------------------------------------------------------------
// Fused multi-array fp32 -> fp16 split (hi always; lo if dl != null)
// ---------------------------------------------------------------------------
struct SJobs {
    const float* src[8];
    __half* dh[8];
    __half* dl[8];
    int   nblk[8];
    long  n4[8];
    float sc[8];
};

__global__ void msplit_k(SJobs J)
{
    int b = blockIdx.x, j = 0;
    while (j < 7 && b >= J.nblk[j]) { b -= J.nblk[j]; j++; }
    long i = (long)b * 256 + threadIdx.x;
    if (i >= J.n4[j]) return;
    float sc = J.sc[j];
    float4 v = ((const float4*)J.src[j])[i];
    v.x *= sc; v.y *= sc; v.z *= sc; v.w *= sc;
    __half2 h0, h1;
    h0.x = __float2half(v.x); h0.y = __float2half(v.y);
    h1.x = __float2half(v.z); h1.y = __float2half(v.w);
    ((__half2*)J.dh[j])[2*i]   = h0;
    ((__half2*)J.dh[j])[2*i+1] = h1;
    if (J.dl[j]) {
        __half2 l0, l1;
        l0.x = __float2half(v.x - __half2float(h0.x));
        l0.y = __float2half(v.y - __half2float(h0.y));
        l1.x = __float2half(v.z - __half2float(h1.x));
        l1.y = __float2half(v.w - __half2float(h1.y));
        ((__half2*)J.dl[j])[2*i]   = l0;
        ((__half2*)J.dl[j])[2*i+1] = l1;
    }
}

// ---------------------------------------------------------------------------
// Generic transpose [R,C]->[C,R] fp32 -> fp16(scale).  grid(R/32, C/32, nz)
// ---------------------------------------------------------------------------
__global__ void tsplitg_k(const float* __restrict__ X, __half* __restrict__ T,
                          int R, int C, float scale)
{
    __shared__ float t[32][33];
    const long zb = blockIdx.z;
    X += zb * (long)R * C;  T += zb * (long)R * C;
    const int r0 = blockIdx.x * 32, c0 = blockIdx.y * 32;
    const int tx = threadIdx.x, ty = threadIdx.y;
#pragma unroll
    for (int i = 0; i < 4; i++) {
        int rr = ty * 4 + i;
        t[rr][tx] = X[(long)(r0 + rr) * C + c0 + tx];
    }
    __syncthreads();
#pragma unroll
    for (int i = 0; i < 4; i++) {
        int cc = ty * 4 + i;
        T[(long)(c0 + cc) * R + r0 + tx] = __float2half(t[tx][cc] * scale);
    }
}

// ---------------------------------------------------------------------------
// LayerNorm rows of 128 (one warp/row); writes fp32 + fp16 hi
// ---------------------------------------------------------------------------
__global__ void ln_k(const float* __restrict__ X, float* __restrict__ Y,
                     __half* __restrict__ Yh,
                     const float* __restrict__ g, const float* __restrict__ b,
                     int rows)
{
    int row  = (blockIdx.x * blockDim.x + threadIdx.x) >> 5;
    int lane = threadIdx.x & 31;
    if (row >= rows) return;
    float4 x = *(const float4*)(X + (long)row * 128 + lane * 4);
    float s  = x.x + x.y + x.z + x.w;
    float ss = fmaf(x.x, x.x, fmaf(x.y, x.y, fmaf(x.z, x.z, x.w * x.w)));
#pragma unroll
    for (int o = 16; o > 0; o >>= 1) {
        s  += __shfl_xor_sync(0xffffffffu, s,  o);
        ss += __shfl_xor_sync(0xffffffffu, ss, o);
    }
    float m   = s * (1.f / 128.f);
    float inv = rsqrtf(ss * (1.f / 128.f) - m * m + 1e-5f);
    float4 gg = *(const float4*)(g + lane * 4);
    float4 bb = *(const float4*)(b + lane * 4);
    float4 y;
    y.x = fmaf((x.x - m) * inv, gg.x, bb.x);
    y.y = fmaf((x.y - m) * inv, gg.y, bb.y);
    y.z = fmaf((x.z - m) * inv, gg.z, bb.z);
    y.w = fmaf((x.w - m) * inv, gg.w, bb.w);
    const long base = (long)row * 128 + lane * 4;
    *(float4*)(Y + base) = y;
    __half2 h0, h1;
    h0.x = __float2half(y.x); h0.y = __float2half(y.y);
    h1.x = __float2half(y.z); h1.y = __float2half(y.w);
    *(__half2*)(Yh + base)     = h0;
    *(__half2*)(Yh + base + 2) = h1;
}

// ---------------------------------------------------------------------------
// Expert select + LN from fp16 ec (scaled 8192): per token (one warp),
// idx = LAST expert with ew>0; ch = fp16(LN(ec[idx]/8192, eln[idx])) or 0.
// ---------------------------------------------------------------------------
__global__ void lnsel_k(const __half* __restrict__ ec, const float* __restrict__ ew,
                        const float* __restrict__ eg, const float* __restrict__ eb,
                        __half* __restrict__ ch, int rows)
{
    int row  = (blockIdx.x * blockDim.x + threadIdx.x) >> 5;
    int lane = threadIdx.x & 31;
    if (row >= rows) return;
    float w = (lane < E_) ? ew[(long)row * E_ + lane] : 0.f;
    unsigned m = __ballot_sync(0xffffffffu, w > 0.f) & 0xFFu;
    const long base = (long)row * 128 + lane * 4;
    if (m == 0) {
        __half2 zz; zz.x = __float2half(0.f); zz.y = zz.x;
        *(__half2*)(ch + base) = zz; *(__half2*)(ch + base + 2) = zz;
        return;
    }
    int idx = 31 - __clz(m);
    const long eb0 = ((long)idx * NTOK + row) * 128 + lane * 4;
    __half2 e0 = *(const __half2*)(ec + eb0);
    __half2 e1 = *(const __half2*)(ec + eb0 + 2);
    const float DSC = 1.f / 8192.f;
    float4 x;
    x.x = __half2float(e0.x) * DSC; x.y = __half2float(e0.y) * DSC;
    x.z = __half2float(e1.x) * DSC; x.w = __half2float(e1.y) * DSC;
    float s  = x.x + x.y + x.z + x.w;
    float ss = fmaf(x.x, x.x, fmaf(x.y, x.y, fmaf(x.z, x.z, x.w * x.w)));
#pragma unroll
    for (int o = 16; o > 0; o >>= 1) {
        s  += __shfl_xor_sync(0xffffffffu, s,  o);
        ss += __shfl_xor_sync(0xffffffffu, ss, o);
    }
    float mn  = s * (1.f / 128.f);
    float inv = rsqrtf(ss * (1.f / 128.f) - mn * mn + 1e-5f);
    float4 gg = *(const float4*)(eg + (long)idx * 128 + lane * 4);
    float4 bb = *(const float4*)(eb + (long)idx * 128 + lane * 4);
    __half2 h0, h1;
    h0.x = __float2half(fmaf((x.x - mn) * inv, gg.x, bb.x));
    h0.y = __float2half(fmaf((x.y - mn) * inv, gg.y, bb.y));
    h1.x = __float2half(fmaf((x.z - mn) * inv, gg.z, bb.z));
    h1.y = __float2half(fmaf((x.w - mn) * inv, gg.w, bb.w));
    *(__half2*)(ch + base)     = h0;
    *(__half2*)(ch + base + 2) = h1;
}

// ---------------------------------------------------------------------------
extern "C" void kernel_launch(void* const* d_in, const int* in_sizes, int n_in,
                              void* d_out, int out_size)
{
    const float* x       = (const float*)d_in[0];
    const float* ew      = (const float*)d_in[1];
    const float* w_up    = (const float*)d_in[2];
    const float* w_gate  = (const float*)d_in[3];
    const float* w_down  = (const float*)d_in[4];
    const float* w_pre   = (const float*)d_in[5];
    const float* w_post  = (const float*)d_in[6];
    const float* an_g    = (const float*)d_in[7];
    const float* an_b    = (const float*)d_in[8];
    const float* w_aproj = (const float*)d_in[9];
    const float* w_exp   = (const float*)d_in[10];
    const float* eln_g   = (const float*)d_in[11];
    const float* eln_b   = (const float*)d_in[12];
    const float* w_eproj = (const float*)d_in[13];
    const float* w_out   = (const float*)d_in[14];
    float* out = (float*)d_out;

    float *U, *Hd, *pre, *ain, *pt, *aout, *part;
    cudaGetSymbolAddress((void**)&U,    g_U);
    cudaGetSymbolAddress((void**)&Hd,   g_Hd);
    cudaGetSymbolAddress((void**)&pre,  g_pre);
    cudaGetSymbolAddress((void**)&ain,  g_ain);
    cudaGetSymbolAddress((void**)&pt,   g_pt);
    cudaGetSymbolAddress((void**)&aout, g_aout);
    cudaGetSymbolAddress((void**)&part, g_part);

    __half *xh,*xl,*Hdh,*preh,*ainh,*aouth,*adph,*chh,*ech,*scrh,*aTh;
    __half *Mhp,*weT,*wouth,*wexph;
    __half *wuph,*wgh,*wdh,*wpreh,*wprel,*wpoh,*waph;
    cudaGetSymbolAddress((void**)&xh,    g_xh);   cudaGetSymbolAddress((void**)&xl,    g_xl);
    cudaGetSymbolAddress((void**)&Hdh,   g_Hdh);  cudaGetSymbolAddress((void**)&preh,  g_preh);
    cudaGetSymbolAddress((void**)&ainh,  g_ainh); cudaGetSymbolAddress((void**)&aouth, g_aouth);
    cudaGetSymbolAddress((void**)&adph,  g_adph); cudaGetSymbolAddress((void**)&chh,   g_ch);
    cudaGetSymbolAddress((void**)&ech,   g_ech);
    cudaGetSymbolAddress((void**)&scrh,  g_scrh); cudaGetSymbolAddress((void**)&aTh,   g_aTh);
    cudaGetSymbolAddress((void**)&Mhp,   g_Mh);   cudaGetSymbolAddress((void**)&weT,   g_weT);
    cudaGetSymbolAddress((void**)&wouth, g_wouth);cudaGetSymbolAddress((void**)&wexph, g_wexph);
    cudaGetSymbolAddress((void**)&wuph,  g_wuph); cudaGetSymbolAddress((void**)&wgh,   g_wgh);
    cudaGetSymbolAddress((void**)&wdh,   g_wdh);
    cudaGetSymbolAddress((void**)&wpreh, g_wpreh);cudaGetSymbolAddress((void**)&wprel, g_wprel);
    cudaGetSymbolAddress((void**)&wpoh,  g_wpoh); cudaGetSymbolAddress((void**)&waph,  g_waph);

    cudaFuncSetAttribute(tgemm_k<0,1,true ,false,false>, cudaFuncAttributeMaxDynamicSharedMemorySize, TG_SMEM);
    cudaFuncSetAttribute(tgemm_k<1,1,true ,true ,false>, cudaFuncAttributeMaxDynamicSharedMemorySize, TG_SMEM);
    cudaFuncSetAttribute(tgemm_k<3,1,false,true ,false>, cudaFuncAttributeMaxDynamicSharedMemorySize, TG_SMEM);
    cudaFuncSetAttribute(tgemm_k<0,1,false,true ,false>, cudaFuncAttributeMaxDynamicSharedMemorySize, TG_SMEM);
    cudaFuncSetAttribute(tgemm_k<2,1,false,true ,false>, cudaFuncAttributeMaxDynamicSharedMemorySize, TG_SMEM);
    cudaFuncSetAttribute(tgemm_k<2,1,true ,false,false>, cudaFuncAttributeMaxDynamicSharedMemorySize, TG_SMEM);
    cudaFuncSetAttribute(tgemm_k<0,1,true ,false,true >, cudaFuncAttributeMaxDynamicSharedMemorySize, TG_SMEM);
    cudaFuncSetAttribute(tgemm_k<0,3,true ,false,true >, cudaFuncAttributeMaxDynamicSharedMemorySize, TG_SMEM);

    // 1) split x (h/l)
    {
        long n4 = (long)NTOK * D_ / 4;
        split_k<<<(unsigned)((n4 + 255) / 256), 256>>>(x, xh, xl, n4, 1.f);
    }

    // 2) fused weight splits
    {
        SJobs J;
        auto set = [&](int j, const float* s, __half* dh, __half* dl, long n, float sc) {
            J.src[j] = s; J.dh[j] = dh; J.dl[j] = dl;
            J.n4[j] = n / 4; J.nblk[j] = (int)((J.n4[j] + 255) / 256); J.sc[j] = sc;
        };
        set(0, w_up,    wuph,  nullptr, (long)H_ * D_,      1.f);
        set(1, w_gate,  wgh,   nullptr, (long)H_ * D_,      1.f);
        set(2, w_down,  wdh,   nullptr, (long)D_ * H_,      1.f);
        set(3, w_pre,   wpreh, wprel,   (long)A_ * D_,      512.f);
        set(4, w_post,  wpoh,  nullptr, (long)A_ * H_,      512.f);
        set(5, w_aproj, waph,  nullptr, (long)H_ * A_,      512.f);
        set(6, w_exp,   wexph, nullptr, (long)E_ * A_ * A_, 512.f);
        set(7, w_out,   wouth, nullptr, (long)D_ * H_,      32.f);
        int total = 0;
        for (int j = 0; j < 8; j++) total += J.nblk[j];
        msplit_k<<<total, 256>>>(J);
    }

    // 3) weT = transpose(w_eproj)[A,H] * 512
    tsplitg_k<<<dim3(H_/32, A_/32, 1), dim3(32, 8)>>>(w_eproj, weT, H_, A_, 512.f);

    // 4) Mh = (32*w_out) @ weT^T   split-K 8 -> redsum (fp16, carries 16384)
    tgemm_k<0,1,true,false,true><<<dim3(8, D_/128, 1), 256, TG_SMEM>>>(
        wouth, nullptr, weT, nullptr, part, nullptr, nullptr,
        D_, A_, H_, 0, 0, 0, 1.f, 1.f);
    redsum_k<<<(unsigned)(((long)D_ * A_ / 4 + 255) / 256), 256>>>(
        part, nullptr, Mhp, 8, (long)D_ * A_, (long)D_ * A_ / 4, 1.f, 1.f);

    // 5) U = x @ w_up^T
    tgemm_k<0,1,true,false,false><<<dim3(H_/128, NTOK/128, 1), 256, TG_SMEM>>>(
        xh, nullptr, wuph, nullptr, U, nullptr, nullptr, NTOK, H_, D_, 0, 0, 0, 1.f, 1.f);

    // 6) Hid = silu(x @ w_gate^T) * U  (+Hdh)
    tgemm_k<1,1,true,true,false><<<dim3(H_/128, NTOK/128, 1), 256, TG_SMEM>>>(
        xh, nullptr, wgh, nullptr, Hd, U, Hdh, NTOK, H_, D_, 0, 0, 0, 1.f, 1.f);

    // 7) pre partials (3-pass, split-K 4) -> redsum: pre fp32 (1/512), preh fp16 (1)
    tgemm_k<0,3,true,false,true><<<dim3(4, NTOK/128, 1), 256, TG_SMEM>>>(
        xh, xl, wpreh, wprel, part, nullptr, nullptr, NTOK, A_, D_, 0, 0, 0, 1.f, 1.f);
    redsum_k<<<(unsigned)(((long)NTOK * A_ / 4 + 255) / 256), 256>>>(
        part, pre, preh, 4, (long)NTOK * A_, (long)NTOK * A_ / 4, 1.f / 512.f, 1.f);

    // 8) ain = LN(pre)  (+h)
    ln_k<<<NTOK/8, 256>>>(pre, ain, ainh, an_g, an_b, NTOK);

    // 9) pt partials (split-K 4) -> redsum fp32 (1/512)
    tgemm_k<0,1,true,false,true><<<dim3(4, NTOK/128, 1), 256, TG_SMEM>>>(
        Hdh, nullptr, wpoh, nullptr, part, nullptr, nullptr, NTOK, A_, H_, 0, 0, 0, 1.f, 1.f);
    redsum_k<<<(unsigned)(((long)NTOK * A_ / 4 + 255) / 256), 256>>>(
        part, pt, nullptr, 4, (long)NTOK * A_, (long)NTOK * A_ / 4, 1.f / 512.f, 1.f);

    // 10) aout = LN(pt)  (+h)
    ln_k<<<NTOK/8, 256>>>(pt, aout, aouth, an_g, an_b, NTOK);

    // 11) scrh[b] = silu(clip(ain[b] @ aout[b]^T))
    tgemm_k<3,1,false,true,false><<<dim3(S_/128, S_/128, B_), 256, TG_SMEM>>>(
        ainh, nullptr, aouth, nullptr, nullptr, nullptr, scrh,
        S_, S_, A_, (long)S_ * A_, (long)S_ * A_, (long)S_ * S_, 1.f, 1.f);

    // 12) aTh = transpose(ain) hi  (per batch)
    tsplitg_k<<<dim3(S_/32, A_/32, B_), dim3(32, 8)>>>(ain, aTh, S_, A_, 1.f);

    // 13) adp partials (split-K 4, batched z=8) -> redsum fp16 (1)
    tgemm_k<0,1,true,false,true><<<dim3(4, S_/128, B_), 256, TG_SMEM>>>(
        scrh, nullptr, aTh, nullptr, part, nullptr, nullptr,
        S_, A_, S_, (long)S_ * S_, (long)A_ * S_, 0, 1.f, 1.f);
    redsum_k<<<(unsigned)(((long)NTOK * A_ / 4 + 255) / 256), 256>>>(
        part, nullptr, adph, 4, (long)S_ * A_, (long)NTOK * A_ / 4, 1.f, 1.f);

    // 14) Hdh = Hid + 0.1 * adp @ w_aproj^T
    tgemm_k<2,1,false,true,false><<<dim3(H_/128, NTOK/128, 1), 256, TG_SMEM>>>(
        adph, nullptr, waph, nullptr, nullptr, Hd, Hdh, NTOK, H_, A_, 0, 0, 0,
        1.f / 512.f, 1.f);

    // 15) out = Hid @ w_down^T
    tgemm_k<0,1,true,false,false><<<dim3(D_/128, NTOK/128, 1), 256, TG_SMEM>>>(
        Hdh, nullptr, wdh, nullptr, out, nullptr, nullptr, NTOK, D_, H_, 0, 0, 0, 1.f, 1.f);

    // e1) ech_i = fp16(8192 * pre @ w_exp[i]^T)  (batched over 8 experts)
    tgemm_k<0,1,false,true,false><<<dim3(1, NTOK/128, E_), 256, TG_SMEM>>>(
        preh, nullptr, wexph, nullptr, nullptr, nullptr, ech,
        NTOK, A_, A_, 0, (long)A_ * A_, (long)NTOK * A_, 1.f / 32.f, 1.f);

    // e2) ch = LN(ech[last-positive]/8192, eln)  (0 if none)
    lnsel_k<<<NTOK/8, 256>>>(ech, ew, eln_g, eln_b, chh, NTOK);

    // e3) out += 0.1 * ch @ Mh^T   (Mh carries 16384 -> ds = 1/16384)
    tgemm_k<2,1,true,false,false><<<dim3(D_/128, NTOK/128, 1), 256, TG_SMEM>>>(
        chh, nullptr, Mhp, nullptr, out, out, nullptr,
        NTOK, D_, A_, 0, 0, 0, 1.f / 16384.f, 1.f);
}

// round 11
// speedup vs baseline: 6.2101x; 1.0209x over previous
#include <cuda_runtime.h>
#include <cuda_fp16.h>
#include <cstdint>

// ---------------------------------------------------------------------------
// LLaDAModel fused forward — mma.sync fp16-split GEMMs + split-K; fp16
// intermediates everywhere (no fp32 U/Hd round-trips).
// B=8,S=2048,D=1024,H=2048,A=128,E=8. N=16384.
//
//   s.   split x (h/l);  fused weight splits (astd weights prescaled 512)
//   0a.  weT = transpose(w_eproj)*512
//   0b.  Mh  = (32*w_out) @ weT^T       split-K 8 + redsum  (carries 16384)
//   1.   Uh   = fp16(x @ w_up^T)                   [N,H]  1-pass
//   2.   Hdh  = fp16(silu(x @ w_gate^T)*Uh)        [N,H]  1-pass, fp16 aux
//   3.   pre  = x @ w_pre^T  (+preh*512)           [N,A]  3-pass, split-K 4
//   4.   ain  = LN(pre)  (+h)                      [N,A]
//   5.   pt   = Hdh @ w_post^T                     [N,A]  1-pass, split-K 4
//   6.   aout = LN(pt)   (+h)                      [N,A]
//   7.   scrh = silu(clip(ain @ aout^T)) per b     [S,S]  1-pass
//   7b.  aTh  = transpose(ain) hi         per b    [A,S]
//   8.   adph = scr @ aT^T                per b    [N,A]  1-pass, split-K 4
//   9.   Hdh  = Hdh + 0.1*adp @ w_aproj^T          [N,H]  1-pass, fp16 aux
//  10.   out  = Hdh @ w_down^T                     [N,D]  1-pass
//  e1.   ech_i = fp16(8192 * pre @ w_exp[i]^T)     [N,A]  1-pass (batched)
//  e2.   ch   = LN(ech[last-positive], eln)        [N,A]
//  e3.   out += 0.1 * ch @ Mh^T                    [N,D]  1-pass
// ---------------------------------------------------------------------------

constexpr int B_ = 8, S_ = 2048, D_ = 1024, H_ = 2048, A_ = 128, E_ = 8;
constexpr int NTOK = B_ * S_;   // 16384

// fp32 scratch
__device__ float g_pre [(size_t)NTOK * A_];
__device__ float g_ain [(size_t)NTOK * A_];
__device__ float g_pt  [(size_t)NTOK * A_];
__device__ float g_aout[(size_t)NTOK * A_];
__device__ float g_part[(size_t)NTOK * A_ * 4];   // split-K partials (max case)

// fp16 scratch
__device__ __half g_xh [(size_t)NTOK * D_], g_xl [(size_t)NTOK * D_];
__device__ __half g_Uh [(size_t)NTOK * H_];
__device__ __half g_Hdh[(size_t)NTOK * H_];
__device__ __half g_preh[(size_t)NTOK * A_];
__device__ __half g_ainh[(size_t)NTOK * A_];
__device__ __half g_aouth[(size_t)NTOK * A_];
__device__ __half g_adph[(size_t)NTOK * A_];
__device__ __half g_ch  [(size_t)NTOK * A_];
__device__ __half g_ech [(size_t)E_ * NTOK * A_];
__device__ __half g_scrh[(size_t)B_ * S_ * S_];
__device__ __half g_aTh[(size_t)B_ * A_ * S_];
__device__ __half g_Mh [(size_t)D_ * A_];
__device__ __half g_weT[(size_t)A_ * H_];
__device__ __half g_wouth[(size_t)D_ * H_];
__device__ __half g_wexph[(size_t)E_ * A_ * A_];
__device__ __half g_wuph[(size_t)H_ * D_];
__device__ __half g_wgh [(size_t)H_ * D_];
__device__ __half g_wdh [(size_t)D_ * H_];
__device__ __half g_wpreh[(size_t)A_ * D_], g_wprel[(size_t)A_ * D_];
__device__ __half g_wpoh[(size_t)A_ * H_];
__device__ __half g_waph[(size_t)H_ * A_];

__device__ __forceinline__ float siluf(float x) {
    return x * (1.0f / (1.0f + __expf(-x)));
}

#define LDSM4(r0,r1,r2,r3,addr) \
    asm volatile("ldmatrix.sync.aligned.m8n8.x4.shared.b16 {%0,%1,%2,%3},[%4];\n" \
        : "=r"(r0),"=r"(r1),"=r"(r2),"=r"(r3) : "r"(addr))

#define MMA16816(c,a,b) \
    asm volatile("mma.sync.aligned.m16n8k16.row.col.f32.f16.f16.f32 " \
        "{%0,%1,%2,%3},{%4,%5,%6,%7},{%8,%9},{%0,%1,%2,%3};\n" \
        : "+f"((c)[0]),"+f"((c)[1]),"+f"((c)[2]),"+f"((c)[3]) \
        : "r"((a)[0]),"r"((a)[1]),"r"((a)[2]),"r"((a)[3]),"r"((b)[0]),"r"((b)[1]))

#define CPA16(dst,src) \
    asm volatile("cp.async.cg.shared.global [%0],[%1],16;\n" :: "r"(dst),"l"(src))

constexpr int TG_SMEM = 81920;

// ---------------------------------------------------------------------------
// Tensor GEMM: C[M,N](f32) = split(A)[M,K] @ split(B)[N,K]^T
// PASSES=1: acc = Ah*Bh        PASSES=3: + Ah*Bl + Al*Bh
// CTA tile 128x128x32, 8 warps (4x2), warp tile 32x64, m16n8k16 fp16 mma.
// SPLIT: grid.x = K-split index (requires N=128); raw fp32 partials to
//        C + (z*gridDim.x + blockIdx.x)*M*N.
// AUXH: aux buffer is fp16 (else fp32).
// EPI: 0 C=acc  1 C=silu(acc)*aux  2 C=aux+0.1*acc  3 C=silu(clip(acc,±5))
// ---------------------------------------------------------------------------
template<int EPI, int PASSES, bool WFP32, bool WH, bool SPLIT, bool AUXH>
__global__ void __launch_bounds__(256, 2) tgemm_k(
    const __half* __restrict__ Ah, const __half* __restrict__ Al,
    const __half* __restrict__ Bh, const __half* __restrict__ Bl,
    float* __restrict__ C, const void* __restrict__ aux,
    __half* __restrict__ Ch,
    int M, int N, int K, long sA, long sB, long sC, float ds, float hs)
{
    constexpr int NST  = (PASSES == 1) ? 4 : 2;
    constexpr int SSZ  = (PASSES == 1) ? 20480 : 40960;
    constexpr unsigned BOFF  = (PASSES == 1) ? 10240u : 20480u;
    constexpr unsigned ALOFF = 10240u;

    extern __shared__ char smem[];
    const unsigned sbase = (unsigned)__cvta_generic_to_shared(smem);
    const int tid = threadIdx.x, lane = tid & 31, warp = tid >> 5;
    const int wm = warp >> 1, wn = warp & 1;

    const long z = blockIdx.z;
    Ah += z * sA; Bh += z * sB;
    if (PASSES == 3) { Al += z * sA; Bl += z * sB; }
    const float*  auxF = (!AUXH && (EPI == 1 || EPI == 2)) ? (const float*)aux + z * sC : nullptr;
    const __half* auxH = ( AUXH && (EPI == 1 || EPI == 2)) ? (const __half*)aux + z * sC : nullptr;
    float* Cp;
    __half* Chp = nullptr;
    if (SPLIT) {
        Cp = C + ((z * gridDim.x + blockIdx.x) * (long)M) * N;
    } else {
        Cp = WFP32 ? C + z * sC : nullptr;
        Chp = WH ? Ch + z * sC : nullptr;
    }

    const int m0 = blockIdx.y * 128;
    const int n0 = SPLIT ? 0 : blockIdx.x * 128;

    const int KT = K / 32;
    int t0k = 0, TCNT = KT;
    if (SPLIT) { TCNT = KT / gridDim.x; t0k = blockIdx.x * TCNT; }

    float acc[2][8][4];
#pragma unroll
    for (int i = 0; i < 2; i++)
#pragma unroll
        for (int j = 0; j < 8; j++)
#pragma unroll
            for (int e = 0; e < 4; e++) acc[i][j][e] = 0.f;

    const unsigned aAddr = (unsigned)((wm * 32 + (lane & 15)) * 80 + (lane >> 4) * 16);
    const unsigned bAddr = (unsigned)(BOFF +
        (wn * 64 + ((lane >> 4) << 3) + (lane & 7)) * 80 + ((lane >> 3) & 1) * 16);

    auto issue = [&](int t, int s) {
        const long k0 = (long)(t0k + t) * 32;
        const unsigned st = sbase + s * SSZ;
#pragma unroll
        for (int i = tid; i < 512; i += 256) {
            const int r = i >> 2, c = i & 3;
            const unsigned da = st + r * 80 + c * 16;
            const long  ga = (long)(m0 + r) * K + k0 + c * 8;
            CPA16(da, Ah + ga);
            if (PASSES == 3) CPA16(da + ALOFF, Al + ga);
            const unsigned db = st + BOFF + r * 80 + c * 16;
            const long  gb = (long)(n0 + r) * K + k0 + c * 8;
            CPA16(db, Bh + gb);
            if (PASSES == 3) CPA16(db + ALOFF, Bl + gb);
        }
        asm volatile("cp.async.commit_group;\n");
    };

    const int pre = (NST - 1 < TCNT) ? NST - 1 : TCNT;
    for (int p = 0; p < pre; p++) issue(p, p % NST);

    for (int t = 0; t < TCNT; ++t) {
        if (NST == 2) {
            asm volatile("cp.async.wait_group 0;\n" ::: "memory");
        } else {
            const int rem = TCNT - 1 - t;
            if (rem >= 2)      asm volatile("cp.async.wait_group 2;\n" ::: "memory");
            else if (rem == 1) asm volatile("cp.async.wait_group 1;\n" ::: "memory");
            else               asm volatile("cp.async.wait_group 0;\n" ::: "memory");
        }
        __syncthreads();
        if (t + NST - 1 < TCNT) issue(t + NST - 1, (t + NST - 1) % NST);

        const unsigned st = sbase + (t % NST) * SSZ;
#pragma unroll
        for (int kk = 0; kk < 2; kk++) {
            const unsigned ko = kk * 32;
            unsigned ah[2][4], al[2][4], bh[8][2], bl[8][2];
#pragma unroll
            for (int im = 0; im < 2; im++) {
                LDSM4(ah[im][0], ah[im][1], ah[im][2], ah[im][3],
                      st + aAddr + im * 1280 + ko);
                if (PASSES == 3)
                    LDSM4(al[im][0], al[im][1], al[im][2], al[im][3],
                          st + ALOFF + aAddr + im * 1280 + ko);
            }
#pragma unroll
            for (int jp = 0; jp < 4; jp++) {
                LDSM4(bh[2*jp][0], bh[2*jp][1], bh[2*jp+1][0], bh[2*jp+1][1],
                      st + bAddr + jp * 1280 + ko);
                if (PASSES == 3)
                    LDSM4(bl[2*jp][0], bl[2*jp][1], bl[2*jp+1][0], bl[2*jp+1][1],
                          st + ALOFF + bAddr + jp * 1280 + ko);
            }
#pragma unroll
            for (int im = 0; im < 2; im++)
#pragma unroll
                for (int jn = 0; jn < 8; jn++) MMA16816(acc[im][jn], ah[im], bh[jn]);
            if (PASSES == 3) {
#pragma unroll
                for (int im = 0; im < 2; im++)
#pragma unroll
                    for (int jn = 0; jn < 8; jn++) MMA16816(acc[im][jn], ah[im], bl[jn]);
#pragma unroll
                for (int im = 0; im < 2; im++)
#pragma unroll
                    for (int jn = 0; jn < 8; jn++) MMA16816(acc[im][jn], al[im], bh[jn]);
            }
        }
        __syncthreads();
    }

    // epilogue
    const int gr = lane >> 2, q = lane & 3;
#pragma unroll
    for (int im = 0; im < 2; im++) {
#pragma unroll
        for (int jn = 0; jn < 8; jn++) {
            const long r0  = m0 + wm * 32 + im * 16 + gr;
            const long col = n0 + wn * 64 + jn * 8 + q * 2;
            const long i0 = r0 * N + col, i1 = i0 + 8L * N;
            if (SPLIT) {   // raw partials, no scaling
                *(float2*)(Cp + i0) = make_float2(acc[im][jn][0], acc[im][jn][1]);
                *(float2*)(Cp + i1) = make_float2(acc[im][jn][2], acc[im][jn][3]);
                continue;
            }
            float v0 = acc[im][jn][0] * ds, v1 = acc[im][jn][1] * ds;
            float v2 = acc[im][jn][2] * ds, v3 = acc[im][jn][3] * ds;
            if (EPI == 1 || EPI == 2) {
                float a0x, a0y, a1x, a1y;
                if (AUXH) {
                    __half2 u0 = *(const __half2*)(auxH + i0);
                    __half2 u1 = *(const __half2*)(auxH + i1);
                    a0x = __half2float(u0.x); a0y = __half2float(u0.y);
                    a1x = __half2float(u1.x); a1y = __half2float(u1.y);
                } else {
                    float2 a0 = *(const float2*)(auxF + i0);
                    float2 a1 = *(const float2*)(auxF + i1);
                    a0x = a0.x; a0y = a0.y; a1x = a1.x; a1y = a1.y;
                }
                if (EPI == 1) {
                    v0 = siluf(v0) * a0x; v1 = siluf(v1) * a0y;
                    v2 = siluf(v2) * a1x; v3 = siluf(v3) * a1y;
                } else {
                    v0 = fmaf(0.1f, v0, a0x); v1 = fmaf(0.1f, v1, a0y);
                    v2 = fmaf(0.1f, v2, a1x); v3 = fmaf(0.1f, v3, a1y);
                }
            } else if (EPI == 3) {
                v0 = siluf(fminf(fmaxf(v0, -5.f), 5.f));
                v1 = siluf(fminf(fmaxf(v1, -5.f), 5.f));
                v2 = siluf(fminf(fmaxf(v2, -5.f), 5.f));
                v3 = siluf(fminf(fmaxf(v3, -5.f), 5.f));
            }
            if (WFP32) {
                *(float2*)(Cp + i0) = make_float2(v0, v1);
                *(float2*)(Cp + i1) = make_float2(v2, v3);
            }
            if (WH) {
                __half2 hh;
                hh.x = __float2half(v0 * hs); hh.y = __float2half(v1 * hs);
                *(__half2*)(Chp + i0) = hh;
                hh.x = __float2half(v2 * hs); hh.y = __float2half(v3 * hs);
                *(__half2*)(Chp + i1) = hh;
            }
        }
    }
}

// ---------------------------------------------------------------------------
// Split-K reduce + epilogue: sums SK partials (deterministic order), writes
// fp32 (dsY * sum) if Y != null and fp16 (dsH * sum) if Yh != null.
// ---------------------------------------------------------------------------
__global__ void redsum_k(const float* __restrict__ part,
                         float* __restrict__ Y, __half* __restrict__ Yh,
                         int SK, long MN, long n4, float dsY, float dsH)
{
    long i = blockIdx.x * (long)blockDim.x + threadIdx.x;
    if (i >= n4) return;
    long e0 = i * 4;
    long zz = e0 / MN, r = e0 - zz * MN;
    const float* p = part + (zz * SK) * MN + r;
    float4 s = *(const float4*)p;
    for (int k = 1; k < SK; k++) {
        float4 v = *(const float4*)(p + (long)k * MN);
        s.x += v.x; s.y += v.y; s.z += v.z; s.w += v.w;
    }
    if (Y) {
        float4 o;
        o.x = s.x * dsY; o.y = s.y * dsY; o.z = s.z * dsY; o.w = s.w * dsY;
        *(float4*)(Y + e0) = o;
    }
    if (Yh) {
        __half2 h0, h1;
        h0.x = __float2half(s.x * dsH); h0.y = __float2half(s.y * dsH);
        h1.x = __float2half(s.z * dsH); h1.y = __float2half(s.w * dsH);
        *(__half2*)(Yh + e0)     = h0;
        *(__half2*)(Yh + e0 + 2) = h1;
    }
}

// ---------------------------------------------------------------------------
// fp32 -> fp16 hi/lo split with pre-scale (x only)
// ---------------------------------------------------------------------------
__global__ void split_k(const float* __restrict__ X,
                        __half* __restrict__ Hh, __half* __restrict__ Hl,
                        long n4, float scale)
{
    long i = blockIdx.x * (long)blockDim.x + threadIdx.x;
    if (i >= n4) return;
    float4 v = ((const float4*)X)[i];
    v.x *= scale; v.y *= scale; v.z *= scale; v.w *= scale;
    __half2 h0, h1, l0, l1;
    h0.x = __float2half(v.x); l0.x = __float2half(v.x - __half2float(h0.x));
    h0.y = __float2half(v.y); l0.y = __float2half(v.y - __half2float(h0.y));
    h1.x = __float2half(v.z); l1.x = __float2half(v.z - __half2float(h1.x));
    h1.y = __float2half(v.w); l1.y = __float2half(v.w - __half2float(h1.y));
    ((__half2*)Hh)[2*i]   = h0; ((__half2*)Hh)[2*i+1] = h1;
    ((__half2*)Hl)[2*i]   = l0; ((__half2*)Hl)[2*i+1] = l1;
}

// ---------------------------------------------------------------------------
// Fused multi-array fp32 -> fp16 split (hi always; lo if dl != null)
// ---------------------------------------------------------------------------
struct SJobs {
    const float* src[8];
    __half* dh[8];
    __half* dl[8];
    int   nblk[8];
    long  n4[8];
    float sc[8];
};

__global__ void msplit_k(SJobs J)
{
    int b = blockIdx.x, j = 0;
    while (j < 7 && b >= J.nblk[j]) { b -= J.nblk[j]; j++; }
    long i = (long)b * 256 + threadIdx.x;
    if (i >= J.n4[j]) return;
    float sc = J.sc[j];
    float4 v = ((const float4*)J.src[j])[i];
    v.x *= sc; v.y *= sc; v.z *= sc; v.w *= sc;
    __half2 h0, h1;
    h0.x = __float2half(v.x); h0.y = __float2half(v.y);
    h1.x = __float2half(v.z); h1.y = __float2half(v.w);
    ((__half2*)J.dh[j])[2*i]   = h0;
    ((__half2*)J.dh[j])[2*i+1] = h1;
    if (J.dl[j]) {
        __half2 l0, l1;
        l0.x = __float2half(v.x - __half2float(h0.x));
        l0.y = __float2half(v.y - __half2float(h0.y));
        l1.x = __float2half(v.z - __half2float(h1.x));
        l1.y = __float2half(v.w - __half2float(h1.y));
        ((__half2*)J.dl[j])[2*i]   = l0;
        ((__half2*)J.dl[j])[2*i+1] = l1;
    }
}

// ---------------------------------------------------------------------------
// Generic transpose [R,C]->[C,R] fp32 -> fp16(scale).  grid(R/32, C/32, nz)
// ---------------------------------------------------------------------------
__global__ void tsplitg_k(const float* __restrict__ X, __half* __restrict__ T,
                          int R, int C, float scale)
{
    __shared__ float t[32][33];
    const long zb = blockIdx.z;
    X += zb * (long)R * C;  T += zb * (long)R * C;
    const int r0 = blockIdx.x * 32, c0 = blockIdx.y * 32;
    const int tx = threadIdx.x, ty = threadIdx.y;
#pragma unroll
    for (int i = 0; i < 4; i++) {
        int rr = ty * 4 + i;
        t[rr][tx] = X[(long)(r0 + rr) * C + c0 + tx];
    }
    __syncthreads();
#pragma unroll
    for (int i = 0; i < 4; i++) {
        int cc = ty * 4 + i;
        T[(long)(c0 + cc) * R + r0 + tx] = __float2half(t[tx][cc] * scale);
    }
}

// ---------------------------------------------------------------------------
// LayerNorm rows of 128 (one warp/row); writes fp32 + fp16 hi
// ---------------------------------------------------------------------------
__global__ void ln_k(const float* __restrict__ X, float* __restrict__ Y,
                     __half* __restrict__ Yh,
                     const float* __restrict__ g, const float* __restrict__ b,
                     int rows)
{
    int row  = (blockIdx.x * blockDim.x + threadIdx.x) >> 5;
    int lane = threadIdx.x & 31;
    if (row >= rows) return;
    float4 x = *(const float4*)(X + (long)row * 128 + lane * 4);
    float s  = x.x + x.y + x.z + x.w;
    float ss = fmaf(x.x, x.x, fmaf(x.y, x.y, fmaf(x.z, x.z, x.w * x.w)));
#pragma unroll
    for (int o = 16; o > 0; o >>= 1) {
        s  += __shfl_xor_sync(0xffffffffu, s,  o);
        ss += __shfl_xor_sync(0xffffffffu, ss, o);
    }
    float m   = s * (1.f / 128.f);
    float inv = rsqrtf(ss * (1.f / 128.f) - m * m + 1e-5f);
    float4 gg = *(const float4*)(g + lane * 4);
    float4 bb = *(const float4*)(b + lane * 4);
    float4 y;
    y.x = fmaf((x.x - m) * inv, gg.x, bb.x);
    y.y = fmaf((x.y - m) * inv, gg.y, bb.y);
    y.z = fmaf((x.z - m) * inv, gg.z, bb.z);
    y.w = fmaf((x.w - m) * inv, gg.w, bb.w);
    const long base = (long)row * 128 + lane * 4;
    *(float4*)(Y + base) = y;
    __half2 h0, h1;
    h0.x = __float2half(y.x); h0.y = __float2half(y.y);
    h1.x = __float2half(y.z); h1.y = __float2half(y.w);
    *(__half2*)(Yh + base)     = h0;
    *(__half2*)(Yh + base + 2) = h1;
}

// ---------------------------------------------------------------------------
// Expert select + LN from fp16 ec (scaled 8192): per token (one warp),
// idx = LAST expert with ew>0; ch = fp16(LN(ec[idx]/8192, eln[idx])) or 0.
// ---------------------------------------------------------------------------
__global__ void lnsel_k(const __half* __restrict__ ec, const float* __restrict__ ew,
                        const float* __restrict__ eg, const float* __restrict__ eb,
                        __half* __restrict__ ch, int rows)
{
    int row  = (blockIdx.x * blockDim.x + threadIdx.x) >> 5;
    int lane = threadIdx.x & 31;
    if (row >= rows) return;
    float w = (lane < E_) ? ew[(long)row * E_ + lane] : 0.f;
    unsigned m = __ballot_sync(0xffffffffu, w > 0.f) & 0xFFu;
    const long base = (long)row * 128 + lane * 4;
    if (m == 0) {
        __half2 zz; zz.x = __float2half(0.f); zz.y = zz.x;
        *(__half2*)(ch + base) = zz; *(__half2*)(ch + base + 2) = zz;
        return;
    }
    int idx = 31 - __clz(m);
    const long eb0 = ((long)idx * NTOK + row) * 128 + lane * 4;
    __half2 e0 = *(const __half2*)(ec + eb0);
    __half2 e1 = *(const __half2*)(ec + eb0 + 2);
    const float DSC = 1.f / 8192.f;
    float4 x;
    x.x = __half2float(e0.x) * DSC; x.y = __half2float(e0.y) * DSC;
    x.z = __half2float(e1.x) * DSC; x.w = __half2float(e1.y) * DSC;
    float s  = x.x + x.y + x.z + x.w;
    float ss = fmaf(x.x, x.x, fmaf(x.y, x.y, fmaf(x.z, x.z, x.w * x.w)));
#pragma unroll
    for (int o = 16; o > 0; o >>= 1) {
        s  += __shfl_xor_sync(0xffffffffu, s,  o);
        ss += __shfl_xor_sync(0xffffffffu, ss, o);
    }
    float mn  = s * (1.f / 128.f);
    float inv = rsqrtf(ss * (1.f / 128.f) - mn * mn + 1e-5f);
    float4 gg = *(const float4*)(eg + (long)idx * 128 + lane * 4);
    float4 bb = *(const float4*)(eb + (long)idx * 128 + lane * 4);
    __half2 h0, h1;
    h0.x = __float2half(fmaf((x.x - mn) * inv, gg.x, bb.x));
    h0.y = __float2half(fmaf((x.y - mn) * inv, gg.y, bb.y));
    h1.x = __float2half(fmaf((x.z - mn) * inv, gg.z, bb.z));
    h1.y = __float2half(fmaf((x.w - mn) * inv, gg.w, bb.w));
    *(__half2*)(ch + base)     = h0;
    *(__half2*)(ch + base + 2) = h1;
}

// ---------------------------------------------------------------------------
extern "C" void kernel_launch(void* const* d_in, const int* in_sizes, int n_in,
                              void* d_out, int out_size)
{
    const float* x       = (const float*)d_in[0];
    const float* ew      = (const float*)d_in[1];
    const float* w_up    = (const float*)d_in[2];
    const float* w_gate  = (const float*)d_in[3];
    const float* w_down  = (const float*)d_in[4];
    const float* w_pre   = (const float*)d_in[5];
    const float* w_post  = (const float*)d_in[6];
    const float* an_g    = (const float*)d_in[7];
    const float* an_b    = (const float*)d_in[8];
    const float* w_aproj = (const float*)d_in[9];
    const float* w_exp   = (const float*)d_in[10];
    const float* eln_g   = (const float*)d_in[11];
    const float* eln_b   = (const float*)d_in[12];
    const float* w_eproj = (const float*)d_in[13];
    const float* w_out   = (const float*)d_in[14];
    float* out = (float*)d_out;

    float *pre, *ain, *pt, *aout, *part;
    cudaGetSymbolAddress((void**)&pre,  g_pre);
    cudaGetSymbolAddress((void**)&ain,  g_ain);
    cudaGetSymbolAddress((void**)&pt,   g_pt);
    cudaGetSymbolAddress((void**)&aout, g_aout);
    cudaGetSymbolAddress((void**)&part, g_part);

    __half *xh,*xl,*Uh,*Hdh,*preh,*ainh,*aouth,*adph,*chh,*ech,*scrh,*aTh;
    __half *Mhp,*weT,*wouth,*wexph;
    __half *wuph,*wgh,*wdh,*wpreh,*wprel,*wpoh,*waph;
    cudaGetSymbolAddress((void**)&xh,    g_xh);   cudaGetSymbolAddress((void**)&xl,    g_xl);
    cudaGetSymbolAddress((void**)&Uh,    g_Uh);   cudaGetSymbolAddress((void**)&Hdh,   g_Hdh);
    cudaGetSymbolAddress((void**)&preh,  g_preh);
    cudaGetSymbolAddress((void**)&ainh,  g_ainh); cudaGetSymbolAddress((void**)&aouth, g_aouth);
    cudaGetSymbolAddress((void**)&adph,  g_adph); cudaGetSymbolAddress((void**)&chh,   g_ch);
    cudaGetSymbolAddress((void**)&ech,   g_ech);
    cudaGetSymbolAddress((void**)&scrh,  g_scrh); cudaGetSymbolAddress((void**)&aTh,   g_aTh);
    cudaGetSymbolAddress((void**)&Mhp,   g_Mh);   cudaGetSymbolAddress((void**)&weT,   g_weT);
    cudaGetSymbolAddress((void**)&wouth, g_wouth);cudaGetSymbolAddress((void**)&wexph, g_wexph);
    cudaGetSymbolAddress((void**)&wuph,  g_wuph); cudaGetSymbolAddress((void**)&wgh,   g_wgh);
    cudaGetSymbolAddress((void**)&wdh,   g_wdh);
    cudaGetSymbolAddress((void**)&wpreh, g_wpreh);cudaGetSymbolAddress((void**)&wprel, g_wprel);
    cudaGetSymbolAddress((void**)&wpoh,  g_wpoh); cudaGetSymbolAddress((void**)&waph,  g_waph);

    cudaFuncSetAttribute(tgemm_k<0,1,false,true ,false,false>, cudaFuncAttributeMaxDynamicSharedMemorySize, TG_SMEM);
    cudaFuncSetAttribute(tgemm_k<1,1,false,true ,false,true >, cudaFuncAttributeMaxDynamicSharedMemorySize, TG_SMEM);
    cudaFuncSetAttribute(tgemm_k<0,3,true ,false,true ,false>, cudaFuncAttributeMaxDynamicSharedMemorySize, TG_SMEM);
    cudaFuncSetAttribute(tgemm_k<0,1,true ,false,true ,false>, cudaFuncAttributeMaxDynamicSharedMemorySize, TG_SMEM);
    cudaFuncSetAttribute(tgemm_k<3,1,false,true ,false,false>, cudaFuncAttributeMaxDynamicSharedMemorySize, TG_SMEM);
    cudaFuncSetAttribute(tgemm_k<2,1,false,true ,false,true >, cudaFuncAttributeMaxDynamicSharedMemorySize, TG_SMEM);
    cudaFuncSetAttribute(tgemm_k<0,1,true ,false,false,false>, cudaFuncAttributeMaxDynamicSharedMemorySize, TG_SMEM);
    cudaFuncSetAttribute(tgemm_k<2,1,true ,false,false,false>, cudaFuncAttributeMaxDynamicSharedMemorySize, TG_SMEM);

    // 1) split x (h/l)
    {
        long n4 = (long)NTOK * D_ / 4;
        split_k<<<(unsigned)((n4 + 255) / 256), 256>>>(x, xh, xl, n4, 1.f);
    }

    // 2) fused weight splits
    {
        SJobs J;
        auto set = [&](int j, const float* s, __half* dh, __half* dl, long n, float sc) {
            J.src[j] = s; J.dh[j] = dh; J.dl[j] = dl;
            J.n4[j] = n / 4; J.nblk[j] = (int)((J.n4[j] + 255) / 256); J.sc[j] = sc;
        };
        set(0, w_up,    wuph,  nullptr, (long)H_ * D_,      1.f);
        set(1, w_gate,  wgh,   nullptr, (long)H_ * D_,      1.f);
        set(2, w_down,  wdh,   nullptr, (long)D_ * H_,      1.f);
        set(3, w_pre,   wpreh, wprel,   (long)A_ * D_,      512.f);
        set(4, w_post,  wpoh,  nullptr, (long)A_ * H_,      512.f);
        set(5, w_aproj, waph,  nullptr, (long)H_ * A_,      512.f);
        set(6, w_exp,   wexph, nullptr, (long)E_ * A_ * A_, 512.f);
        set(7, w_out,   wouth, nullptr, (long)D_ * H_,      32.f);
        int total = 0;
        for (int j = 0; j < 8; j++) total += J.nblk[j];
        msplit_k<<<total, 256>>>(J);
    }

    // 3) weT = transpose(w_eproj)[A,H] * 512
    tsplitg_k<<<dim3(H_/32, A_/32, 1), dim3(32, 8)>>>(w_eproj, weT, H_, A_, 512.f);

    // 4) Mh = (32*w_out) @ weT^T   split-K 8 -> redsum (fp16, carries 16384)
    tgemm_k<0,1,true,false,true,false><<<dim3(8, D_/128, 1), 256, TG_SMEM>>>(
        wouth, nullptr, weT, nullptr, part, nullptr, nullptr,
        D_, A_, H_, 0, 0, 0, 1.f, 1.f);
    redsum_k<<<(unsigned)(((long)D_ * A_ / 4 + 255) / 256), 256>>>(
        part, nullptr, Mhp, 8, (long)D_ * A_, (long)D_ * A_ / 4, 1.f, 1.f);

    // 5) Uh = fp16(x @ w_up^T)
    tgemm_k<0,1,false,true,false,false><<<dim3(H_/128, NTOK/128, 1), 256, TG_SMEM>>>(
        xh, nullptr, wuph, nullptr, nullptr, nullptr, Uh, NTOK, H_, D_, 0, 0, 0, 1.f, 1.f);

    // 6) Hdh = fp16(silu(x @ w_gate^T) * Uh)   (fp16 aux)
    tgemm_k<1,1,false,true,false,true><<<dim3(H_/128, NTOK/128, 1), 256, TG_SMEM>>>(
        xh, nullptr, wgh, nullptr, nullptr, Uh, Hdh, NTOK, H_, D_, 0, 0, 0, 1.f, 1.f);

    // 7) pre partials (3-pass, split-K 4) -> redsum: pre fp32 (1/512), preh fp16 (1)
    tgemm_k<0,3,true,false,true,false><<<dim3(4, NTOK/128, 1), 256, TG_SMEM>>>(
        xh, xl, wpreh, wprel, part, nullptr, nullptr, NTOK, A_, D_, 0, 0, 0, 1.f, 1.f);
    redsum_k<<<(unsigned)(((long)NTOK * A_ / 4 + 255) / 256), 256>>>(
        part, pre, preh, 4, (long)NTOK * A_, (long)NTOK * A_ / 4, 1.f / 512.f, 1.f);

    // 8) ain = LN(pre)  (+h)
    ln_k<<<NTOK/8, 256>>>(pre, ain, ainh, an_g, an_b, NTOK);

    // 9) pt partials (split-K 4) -> redsum fp32 (1/512)
    tgemm_k<0,1,true,false,true,false><<<dim3(4, NTOK/128, 1), 256, TG_SMEM>>>(
        Hdh, nullptr, wpoh, nullptr, part, nullptr, nullptr, NTOK, A_, H_, 0, 0, 0, 1.f, 1.f);
    redsum_k<<<(unsigned)(((long)NTOK * A_ / 4 + 255) / 256), 256>>>(
        part, pt, nullptr, 4, (long)NTOK * A_, (long)NTOK * A_ / 4, 1.f / 512.f, 1.f);

    // 10) aout = LN(pt)  (+h)
    ln_k<<<NTOK/8, 256>>>(pt, aout, aouth, an_g, an_b, NTOK);

    // 11) scrh[b] = silu(clip(ain[b] @ aout[b]^T))
    tgemm_k<3,1,false,true,false,false><<<dim3(S_/128, S_/128, B_), 256, TG_SMEM>>>(
        ainh, nullptr, aouth, nullptr, nullptr, nullptr, scrh,
        S_, S_, A_, (long)S_ * A_, (long)S_ * A_, (long)S_ * S_, 1.f, 1.f);

    // 12) aTh = transpose(ain) hi  (per batch)
    tsplitg_k<<<dim3(S_/32, A_/32, B_), dim3(32, 8)>>>(ain, aTh, S_, A_, 1.f);

    // 13) adp partials (split-K 4, batched z=8) -> redsum fp16 (1)
    tgemm_k<0,1,true,false,true,false><<<dim3(4, S_/128, B_), 256, TG_SMEM>>>(
        scrh, nullptr, aTh, nullptr, part, nullptr, nullptr,
        S_, A_, S_, (long)S_ * S_, (long)A_ * S_, 0, 1.f, 1.f);
    redsum_k<<<(unsigned)(((long)NTOK * A_ / 4 + 255) / 256), 256>>>(
        part, nullptr, adph, 4, (long)S_ * A_, (long)NTOK * A_ / 4, 1.f, 1.f);

    // 14) Hdh = Hdh + 0.1 * adp @ w_aproj^T   (fp16 aux, in-place)
    tgemm_k<2,1,false,true,false,true><<<dim3(H_/128, NTOK/128, 1), 256, TG_SMEM>>>(
        adph, nullptr, waph, nullptr, nullptr, Hdh, Hdh, NTOK, H_, A_, 0, 0, 0,
        1.f / 512.f, 1.f);

    // 15) out = Hdh @ w_down^T
    tgemm_k<0,1,true,false,false,false><<<dim3(D_/128, NTOK/128, 1), 256, TG_SMEM>>>(
        Hdh, nullptr, wdh, nullptr, out, nullptr, nullptr, NTOK, D_, H_, 0, 0, 0, 1.f, 1.f);

    // e1) ech_i = fp16(8192 * pre @ w_exp[i]^T)  (batched over 8 experts)
    tgemm_k<0,1,false,true,false,false><<<dim3(1, NTOK/128, E_), 256, TG_SMEM>>>(
        preh, nullptr, wexph, nullptr, nullptr, nullptr, ech,
        NTOK, A_, A_, 0, (long)A_ * A_, (long)NTOK * A_, 1.f / 32.f, 1.f);

    // e2) ch = LN(ech[last-positive]/8192, eln)  (0 if none)
    lnsel_k<<<NTOK/8, 256>>>(ech, ew, eln_g, eln_b, chh, NTOK);

    // e3) out += 0.1 * ch @ Mh^T   (Mh carries 16384 -> ds = 1/16384)
    tgemm_k<2,1,true,false,false,false><<<dim3(D_/128, NTOK/128, 1), 256, TG_SMEM>>>(
        chh, nullptr, Mhp, nullptr, out, out, nullptr,
        NTOK, D_, A_, 0, 0, 0, 1.f / 16384.f, 1.f);
}

// round 13
// speedup vs baseline: 6.2509x; 1.0066x over previous
#include <cuda_runtime.h>
#include <cuda_fp16.h>
#include <cstdint>

// ---------------------------------------------------------------------------
// LLaDAModel fused forward — mma.sync fp16-split GEMMs, split-K, fused
// reduce+LN, and K-concat final GEMM (expert path folded into w_down GEMM).
// B=8,S=2048,D=1024,H=2048,A=128,E=8. N=16384.
//
//   s.   split x (h/l);  fused weight splits (w_down routed into wdc[:,0:2048])
//   0a.  weT = transpose(w_eproj)*512
//   0b.  Mh  = (32*w_out)@weT^T  split-K 8 -> redsum -> wdc[:,2048:2176]*(12.8/16384)
//   1.   Uh   = fp16(x @ w_up^T)                   [N,H]
//   2.   Hdc[:,:2048] = fp16(silu(x@w_gate^T)*Uh)  [N,H]   (stride 2176)
//   3.   pre partials (3-pass, split-K 4) -> redln -> ainh + preh(raw*512)
//   5.   pt  partials (split-K 4, A=Hdc)  -> redln -> aouth
//   7.   scrh = silu(clip(ain @ aout^T)) per b     [S,S]
//   7b.  aTh  = transpose(ainh)           per b    [A,S]
//   8.   adp partials (split-K 4, batched) -> redsum -> adph
//   9.   Hdc[:,:2048] += 0.1 * adp @ w_aproj^T     (in-place, fp16 aux)
//  e1.   ech_i = fp16(8192 * pre @ w_exp[i]^T)     (batched)
//  e2.   lnsel -> Hdc[:,2048:2176] = LN(ech[last-pos])/128
//  10.   out  = Hdc @ wdc^T      K=2176  (= Hid@w_down^T + 0.1*ch@M^T)
// ---------------------------------------------------------------------------

constexpr int B_ = 8, S_ = 2048, D_ = 1024, H_ = 2048, A_ = 128, E_ = 8;
constexpr int NTOK = B_ * S_;   // 16384
constexpr int KC = H_ + A_;     // 2176 concat-K

// fp32 scratch
__device__ float g_part[(size_t)NTOK * A_ * 4];   // split-K partials (max case)

// fp16 scratch
__device__ __half g_xh [(size_t)NTOK * D_], g_xl [(size_t)NTOK * D_];
__device__ __half g_Uh [(size_t)NTOK * H_];
__device__ __half g_Hdc[(size_t)NTOK * KC];       // [N, 2176]: Hid | ch/128
__device__ __half g_wdc[(size_t)D_ * KC];         // [D, 2176]: w_down | 12.8*M
__device__ __half g_preh[(size_t)NTOK * A_];
__device__ __half g_ainh[(size_t)NTOK * A_];
__device__ __half g_aouth[(size_t)NTOK * A_];
__device__ __half g_adph[(size_t)NTOK * A_];
__device__ __half g_ech [(size_t)E_ * NTOK * A_];
__device__ __half g_scrh[(size_t)B_ * S_ * S_];
__device__ __half g_aTh[(size_t)B_ * A_ * S_];
__device__ __half g_weT[(size_t)A_ * H_];
__device__ __half g_wouth[(size_t)D_ * H_];
__device__ __half g_wexph[(size_t)E_ * A_ * A_];
__device__ __half g_wuph[(size_t)H_ * D_];
__device__ __half g_wgh [(size_t)H_ * D_];
__device__ __half g_wpreh[(size_t)A_ * D_], g_wprel[(size_t)A_ * D_];
__device__ __half g_wpoh[(size_t)A_ * H_];
__device__ __half g_waph[(size_t)H_ * A_];

__device__ __forceinline__ float siluf(float x) {
    return x * (1.0f / (1.0f + __expf(-x)));
}

#define LDSM4(r0,r1,r2,r3,addr) \
    asm volatile("ldmatrix.sync.aligned.m8n8.x4.shared.b16 {%0,%1,%2,%3},[%4];\n" \
        : "=r"(r0),"=r"(r1),"=r"(r2),"=r"(r3) : "r"(addr))

#define MMA16816(c,a,b) \
    asm volatile("mma.sync.aligned.m16n8k16.row.col.f32.f16.f16.f32 " \
        "{%0,%1,%2,%3},{%4,%5,%6,%7},{%8,%9},{%0,%1,%2,%3};\n" \
        : "+f"((c)[0]),"+f"((c)[1]),"+f"((c)[2]),"+f"((c)[3]) \
        : "r"((a)[0]),"r"((a)[1]),"r"((a)[2]),"r"((a)[3]),"r"((b)[0]),"r"((b)[1]))

#define CPA16(dst,src) \
    asm volatile("cp.async.cg.shared.global [%0],[%1],16;\n" :: "r"(dst),"l"(src))

constexpr int TG_SMEM = 81920;

// ---------------------------------------------------------------------------
// Tensor GEMM: C[M,N](f32) = split(A)[M,K] @ split(B)[N,K]^T
// PASSES=1: acc = Ah*Bh        PASSES=3: + Ah*Bl + Al*Bh
// CTA tile 128x128x32, 8 warps (4x2), warp tile 32x64, m16n8k16 fp16 mma.
// lda/ldb: operand row strides.  ldc: C/Ch row stride.  ldx: aux row stride.
// SPLIT: grid.x = K-split index (N must be 128); raw fp32 partials to
//        C + (z*gridDim.x + blockIdx.x)*M*N (compact).
// AUXH: aux is fp16.  EPI: 0 C=acc  1 silu(acc)*aux  2 aux+0.1*acc  3 silu(clip)
// ---------------------------------------------------------------------------
template<int EPI, int PASSES, bool WFP32, bool WH, bool SPLIT, bool AUXH>
__global__ void __launch_bounds__(256, 2) tgemm_k(
    const __half* __restrict__ Ah, const __half* __restrict__ Al,
    const __half* __restrict__ Bh, const __half* __restrict__ Bl,
    float* __restrict__ C, const void* __restrict__ aux,
    __half* __restrict__ Ch,
    int M, int N, int K, long lda, long ldb, long ldc, long ldx,
    long sA, long sB, long sC, float ds, float hs)
{
    constexpr int NST  = (PASSES == 1) ? 4 : 2;
    constexpr int SSZ  = (PASSES == 1) ? 20480 : 40960;
    constexpr unsigned BOFF  = (PASSES == 1) ? 10240u : 20480u;
    constexpr unsigned ALOFF = 10240u;

    extern __shared__ char smem[];
    const unsigned sbase = (unsigned)__cvta_generic_to_shared(smem);
    const int tid = threadIdx.x, lane = tid & 31, warp = tid >> 5;
    const int wm = warp >> 1, wn = warp & 1;

    const long z = blockIdx.z;
    Ah += z * sA; Bh += z * sB;
    if (PASSES == 3) { Al += z * sA; Bl += z * sB; }
    const float*  auxF = (!AUXH && (EPI == 1 || EPI == 2)) ? (const float*)aux + z * sC : nullptr;
    const __half* auxH = ( AUXH && (EPI == 1 || EPI == 2)) ? (const __half*)aux + z * sC : nullptr;
    float* Cp;
    __half* Chp = nullptr;
    if (SPLIT) {
        Cp = C + ((z * gridDim.x + blockIdx.x) * (long)M) * N;
    } else {
        Cp = WFP32 ? C + z * sC : nullptr;
        Chp = WH ? Ch + z * sC : nullptr;
    }

    const int m0 = blockIdx.y * 128;
    const int n0 = SPLIT ? 0 : blockIdx.x * 128;

    const int KT = K / 32;
    int t0k = 0, TCNT = KT;
    if (SPLIT) { TCNT = KT / gridDim.x; t0k = blockIdx.x * TCNT; }

    float acc[2][8][4];
#pragma unroll
    for (int i = 0; i < 2; i++)
#pragma unroll
        for (int j = 0; j < 8; j++)
#pragma unroll
            for (int e = 0; e < 4; e++) acc[i][j][e] = 0.f;

    const unsigned aAddr = (unsigned)((wm * 32 + (lane & 15)) * 80 + (lane >> 4) * 16);
    const unsigned bAddr = (unsigned)(BOFF +
        (wn * 64 + ((lane >> 4) << 3) + (lane & 7)) * 80 + ((lane >> 3) & 1) * 16);

    auto issue = [&](int t, int s) {
        const long k0 = (long)(t0k + t) * 32;
        const unsigned st = sbase + s * SSZ;
#pragma unroll
        for (int i = tid; i < 512; i += 256) {
            const int r = i >> 2, c = i & 3;
            const unsigned da = st + r * 80 + c * 16;
            const long  ga = (long)(m0 + r) * lda + k0 + c * 8;
            CPA16(da, Ah + ga);
            if (PASSES == 3) CPA16(da + ALOFF, Al + ga);
            const unsigned db = st + BOFF + r * 80 + c * 16;
            const long  gb = (long)(n0 + r) * ldb + k0 + c * 8;
            CPA16(db, Bh + gb);
            if (PASSES == 3) CPA16(db + ALOFF, Bl + gb);
        }
        asm volatile("cp.async.commit_group;\n");
    };

    const int pre = (NST - 1 < TCNT) ? NST - 1 : TCNT;
    for (int p = 0; p < pre; p++) issue(p, p % NST);

    for (int t = 0; t < TCNT; ++t) {
        if (NST == 2) {
            asm volatile("cp.async.wait_group 0;\n" ::: "memory");
        } else {
            const int rem = TCNT - 1 - t;
            if (rem >= 2)      asm volatile("cp.async.wait_group 2;\n" ::: "memory");
            else if (rem == 1) asm volatile("cp.async.wait_group 1;\n" ::: "memory");
            else               asm volatile("cp.async.wait_group 0;\n" ::: "memory");
        }
        __syncthreads();
        if (t + NST - 1 < TCNT) issue(t + NST - 1, (t + NST - 1) % NST);

        const unsigned st = sbase + (t % NST) * SSZ;
#pragma unroll
        for (int kk = 0; kk < 2; kk++) {
            const unsigned ko = kk * 32;
            unsigned ah[2][4], al[2][4], bh[8][2], bl[8][2];
#pragma unroll
            for (int im = 0; im < 2; im++) {
                LDSM4(ah[im][0], ah[im][1], ah[im][2], ah[im][3],
                      st + aAddr + im * 1280 + ko);
                if (PASSES == 3)
                    LDSM4(al[im][0], al[im][1], al[im][2], al[im][3],
                          st + ALOFF + aAddr + im * 1280 + ko);
            }
#pragma unroll
            for (int jp = 0; jp < 4; jp++) {
                LDSM4(bh[2*jp][0], bh[2*jp][1], bh[2*jp+1][0], bh[2*jp+1][1],
                      st + bAddr + jp * 1280 + ko);
                if (PASSES == 3)
                    LDSM4(bl[2*jp][0], bl[2*jp][1], bl[2*jp+1][0], bl[2*jp+1][1],
                          st + ALOFF + bAddr + jp * 1280 + ko);
            }
#pragma unroll
            for (int im = 0; im < 2; im++)
#pragma unroll
                for (int jn = 0; jn < 8; jn++) MMA16816(acc[im][jn], ah[im], bh[jn]);
            if (PASSES == 3) {
#pragma unroll
                for (int im = 0; im < 2; im++)
#pragma unroll
                    for (int jn = 0; jn < 8; jn++) MMA16816(acc[im][jn], ah[im], bl[jn]);
#pragma unroll
                for (int im = 0; im < 2; im++)
#pragma unroll
                    for (int jn = 0; jn < 8; jn++) MMA16816(acc[im][jn], al[im], bh[jn]);
            }
        }
        __syncthreads();
    }

    // epilogue
    const int gr = lane >> 2, q = lane & 3;
#pragma unroll
    for (int im = 0; im < 2; im++) {
#pragma unroll
        for (int jn = 0; jn < 8; jn++) {
            const long r0  = m0 + wm * 32 + im * 16 + gr;
            const long col = n0 + wn * 64 + jn * 8 + q * 2;
            if (SPLIT) {   // raw partials, compact layout
                const long i0 = r0 * N + col, i1 = i0 + 8L * N;
                *(float2*)(Cp + i0) = make_float2(acc[im][jn][0], acc[im][jn][1]);
                *(float2*)(Cp + i1) = make_float2(acc[im][jn][2], acc[im][jn][3]);
                continue;
            }
            const long i0 = r0 * ldc + col, i1 = i0 + 8L * ldc;
            float v0 = acc[im][jn][0] * ds, v1 = acc[im][jn][1] * ds;
            float v2 = acc[im][jn][2] * ds, v3 = acc[im][jn][3] * ds;
            if (EPI == 1 || EPI == 2) {
                const long j0 = r0 * ldx + col, j1 = j0 + 8L * ldx;
                float a0x, a0y, a1x, a1y;
                if (AUXH) {
                    __half2 u0 = *(const __half2*)(auxH + j0);
                    __half2 u1 = *(const __half2*)(auxH + j1);
                    a0x = __half2float(u0.x); a0y = __half2float(u0.y);
                    a1x = __half2float(u1.x); a1y = __half2float(u1.y);
                } else {
                    float2 a0 = *(const float2*)(auxF + j0);
                    float2 a1 = *(const float2*)(auxF + j1);
                    a0x = a0.x; a0y = a0.y; a1x = a1.x; a1y = a1.y;
                }
                if (EPI == 1) {
                    v0 = siluf(v0) * a0x; v1 = siluf(v1) * a0y;
                    v2 = siluf(v2) * a1x; v3 = siluf(v3) * a1y;
                } else {
                    v0 = fmaf(0.1f, v0, a0x); v1 = fmaf(0.1f, v1, a0y);
                    v2 = fmaf(0.1f, v2, a1x); v3 = fmaf(0.1f, v3, a1y);
                }
            } else if (EPI == 3) {
                v0 = siluf(fminf(fmaxf(v0, -5.f), 5.f));
                v1 = siluf(fminf(fmaxf(v1, -5.f), 5.f));
                v2 = siluf(fminf(fmaxf(v2, -5.f), 5.f));
                v3 = siluf(fminf(fmaxf(v3, -5.f), 5.f));
            }
            if (WFP32) {
                *(float2*)(Cp + i0) = make_float2(v0, v1);
                *(float2*)(Cp + i1) = make_float2(v2, v3);
            }
            if (WH) {
                __half2 hh;
                hh.x = __float2half(v0 * hs); hh.y = __float2half(v1 * hs);
                *(__half2*)(Chp + i0) = hh;
                hh.x = __float2half(v2 * hs); hh.y = __float2half(v3 * hs);
                *(__half2*)(Chp + i1) = hh;
            }
        }
    }
}

// ---------------------------------------------------------------------------
// Split-K reduce: sums SK partials (fixed order) PER BATCH, fp16 out with
// optional row remap.  Partial layout: part[(z*SK + s)*MN + r], r in [0,MN).
// Global element index e0 runs over concatenated batches (z = e0 / MN).
// Output: dst = (e0/rowLen)*outW + outOff + e0%rowLen.
// ---------------------------------------------------------------------------
__global__ void redsum_k(const float* __restrict__ part,
                         __half* __restrict__ Yh,
                         int SK, long MN, long n4, float dsH,
                         int rowLen, int outW, int outOff)
{
    long i = blockIdx.x * (long)blockDim.x + threadIdx.x;
    if (i >= n4) return;
    long e0 = i * 4;
    long zz = e0 / MN, r = e0 - zz * MN;          // batch + offset within batch
    const float* p = part + (zz * SK) * MN + r;
    float4 s = *(const float4*)p;
    for (int k = 1; k < SK; k++) {
        float4 v = *(const float4*)(p + (long)k * MN);
        s.x += v.x; s.y += v.y; s.z += v.z; s.w += v.w;
    }
    long row = e0 / rowLen, col = e0 - row * rowLen;
    long d = row * outW + outOff + col;
    __half2 h0, h1;
    h0.x = __float2half(s.x * dsH); h0.y = __float2half(s.y * dsH);
    h1.x = __float2half(s.z * dsH); h1.y = __float2half(s.w * dsH);
    *(__half2*)(Yh + d)     = h0;
    *(__half2*)(Yh + d + 2) = h1;
}

// ---------------------------------------------------------------------------
// Fused split-K reduce + LayerNorm (rows of 128, one warp/row, single batch).
// sum*dsc = true values.  LN fp16 -> Yh; optional raw sum fp16 -> Ph.
// ---------------------------------------------------------------------------
__global__ void redln_k(const float* __restrict__ part, int SK, long MN,
                        const float* __restrict__ g, const float* __restrict__ b,
                        __half* __restrict__ Yh, __half* __restrict__ Ph,
                        float dsc, int rows)
{
    int row  = (blockIdx.x * blockDim.x + threadIdx.x) >> 5;
    int lane = threadIdx.x & 31;
    if (row >= rows) return;
    const long base = (long)row * 128 + lane * 4;
    float4 x = *(const float4*)(part + base);
    for (int k = 1; k < SK; k++) {
        float4 v = *(const float4*)(part + (long)k * MN + base);
        x.x += v.x; x.y += v.y; x.z += v.z; x.w += v.w;
    }
    if (Ph) {
        __half2 h0, h1;
        h0.x = __float2half(x.x); h0.y = __float2half(x.y);
        h1.x = __float2half(x.z); h1.y = __float2half(x.w);
        *(__half2*)(Ph + base)     = h0;
        *(__half2*)(Ph + base + 2) = h1;
    }
    x.x *= dsc; x.y *= dsc; x.z *= dsc; x.w *= dsc;
    float s  = x.x + x.y + x.z + x.w;
    float ss = fmaf(x.x, x.x, fmaf(x.y, x.y, fmaf(x.z, x.z, x.w * x.w)));
#pragma unroll
    for (int o = 16; o > 0; o >>= 1) {
        s  += __shfl_xor_sync(0xffffffffu, s,  o);
        ss += __shfl_xor_sync(0xffffffffu, ss, o);
    }
    float m   = s * (1.f / 128.f);
    float inv = rsqrtf(ss * (1.f / 128.f) - m * m + 1e-5f);
    float4 gg = *(const float4*)(g + lane * 4);
    float4 bb = *(const float4*)(b + lane * 4);
    __half2 h0, h1;
    h0.x = __float2half(fmaf((x.x - m) * inv, gg.x, bb.x));
    h0.y = __float2half(fmaf((x.y - m) * inv, gg.y, bb.y));
    h1.x = __float2half(fmaf((x.z - m) * inv, gg.z, bb.z));
    h1.y = __float2half(fmaf((x.w - m) * inv, gg.w, bb.w));
    *(__half2*)(Yh + base)     = h0;
    *(__half2*)(Yh + base + 2) = h1;
}

// ---------------------------------------------------------------------------
// fp32 -> fp16 hi/lo split (x only)
// ---------------------------------------------------------------------------
__global__ void split_k(const float* __restrict__ X,
                        __half* __restrict__ Hh, __half* __restrict__ Hl,
                        long n4)
{
    long i = blockIdx.x * (long)blockDim.x + threadIdx.x;
    if (i >= n4) return;
    float4 v = ((const float4*)X)[i];
    __half2 h0, h1, l0, l1;
    h0.x = __float2half(v.x); l0.x = __float2half(v.x - __half2float(h0.x));
    h0.y = __float2half(v.y); l0.y = __float2half(v.y - __half2float(h0.y));
    h1.x = __float2half(v.z); l1.x = __float2half(v.z - __half2float(h1.x));
    h1.y = __float2half(v.w); l1.y = __float2half(v.w - __half2float(h1.y));
    ((__half2*)Hh)[2*i]   = h0; ((__half2*)Hh)[2*i+1] = h1;
    ((__half2*)Hl)[2*i]   = l0; ((__half2*)Hl)[2*i+1] = l1;
}

// ---------------------------------------------------------------------------
// Fused multi-array fp32 -> fp16 split (hi always; lo if dl != null).
// Optional row remap per job: dst = (e/rowLen)*dstW + e%rowLen  (dstW=0: identity)
// ---------------------------------------------------------------------------
struct SJobs {
    const float* src[8];
    __half* dh[8];
    __half* dl[8];
    int   nblk[8];
    long  n4[8];
    float sc[8];
    int   rowLen[8];
    int   dstW[8];
};

__global__ void msplit_k(SJobs J)
{
    int b = blockIdx.x, j = 0;
    while (j < 7 && b >= J.nblk[j]) { b -= J.nblk[j]; j++; }
    long i = (long)b * 256 + threadIdx.x;
    if (i >= J.n4[j]) return;
    float sc = J.sc[j];
    float4 v = ((const float4*)J.src[j])[i];
    v.x *= sc; v.y *= sc; v.z *= sc; v.w *= sc;
    long e0 = i * 4, d = e0;
    if (J.dstW[j]) {
        long row = e0 / J.rowLen[j], col = e0 - row * J.rowLen[j];
        d = row * J.dstW[j] + col;
    }
    __half2 h0, h1;
    h0.x = __float2half(v.x); h0.y = __float2half(v.y);
    h1.x = __float2half(v.z); h1.y = __float2half(v.w);
    *(__half2*)(J.dh[j] + d)     = h0;
    *(__half2*)(J.dh[j] + d + 2) = h1;
    if (J.dl[j]) {
        __half2 l0, l1;
        l0.x = __float2half(v.x - __half2float(h0.x));
        l0.y = __float2half(v.y - __half2float(h0.y));
        l1.x = __float2half(v.z - __half2float(h1.x));
        l1.y = __float2half(v.w - __half2float(h1.y));
        *(__half2*)(J.dl[j] + d)     = l0;
        *(__half2*)(J.dl[j] + d + 2) = l1;
    }
}

// ---------------------------------------------------------------------------
// Transpose [R,C]->[C,R], input fp32 or fp16, out fp16(scale). grid(R/32,C/32,nz)
// ---------------------------------------------------------------------------
template<typename TI>
__global__ void tsplitg_k(const TI* __restrict__ X, __half* __restrict__ T,
                          int R, int C, float scale)
{
    __shared__ float t[32][33];
    const long zb = blockIdx.z;
    X += zb * (long)R * C;  T += zb * (long)R * C;
    const int r0 = blockIdx.x * 32, c0 = blockIdx.y * 32;
    const int tx = threadIdx.x, ty = threadIdx.y;
#pragma unroll
    for (int i = 0; i < 4; i++) {
        int rr = ty * 4 + i;
        t[rr][tx] = (float)X[(long)(r0 + rr) * C + c0 + tx];
    }
    __syncthreads();
#pragma unroll
    for (int i = 0; i < 4; i++) {
        int cc = ty * 4 + i;
        T[(long)(c0 + cc) * R + r0 + tx] = __float2half(t[tx][cc] * scale);
    }
}

// ---------------------------------------------------------------------------
// Expert select + LN from fp16 ec (scaled 8192): idx = LAST expert with ew>0;
// writes LN*outDiv into out[row*outW + outOff + col] (0 if no expert).
// ---------------------------------------------------------------------------
__global__ void lnsel_k(const __half* __restrict__ ec, const float* __restrict__ ew,
                        const float* __restrict__ eg, const float* __restrict__ eb,
                        __half* __restrict__ chO, int rows, long outW, long outOff,
                        float outDiv)
{
    int row  = (blockIdx.x * blockDim.x + threadIdx.x) >> 5;
    int lane = threadIdx.x & 31;
    if (row >= rows) return;
    float w = (lane < E_) ? ew[(long)row * E_ + lane] : 0.f;
    unsigned m = __ballot_sync(0xffffffffu, w > 0.f) & 0xFFu;
    const long base = (long)row * outW + outOff + lane * 4;
    if (m == 0) {
        __half2 zz; zz.x = __float2half(0.f); zz.y = zz.x;
        *(__half2*)(chO + base) = zz; *(__half2*)(chO + base + 2) = zz;
        return;
    }
    int idx = 31 - __clz(m);
    const long eb0 = ((long)idx * NTOK + row) * 128 + lane * 4;
    __half2 e0 = *(const __half2*)(ec + eb0);
    __half2 e1 = *(const __half2*)(ec + eb0 + 2);
    const float DSC = 1.f / 8192.f;
    float4 x;
    x.x = __half2float(e0.x) * DSC; x.y = __half2float(e0.y) * DSC;
    x.z = __half2float(e1.x) * DSC; x.w = __half2float(e1.y) * DSC;
    float s  = x.x + x.y + x.z + x.w;
    float ss = fmaf(x.x, x.x, fmaf(x.y, x.y, fmaf(x.z, x.z, x.w * x.w)));
#pragma unroll
    for (int o = 16; o > 0; o >>= 1) {
        s  += __shfl_xor_sync(0xffffffffu, s,  o);
        ss += __shfl_xor_sync(0xffffffffu, ss, o);
    }
    float mn  = s * (1.f / 128.f);
    float inv = rsqrtf(ss * (1.f / 128.f) - mn * mn + 1e-5f);
    float4 gg = *(const float4*)(eg + (long)idx * 128 + lane * 4);
    float4 bb = *(const float4*)(eb + (long)idx * 128 + lane * 4);
    __half2 h0, h1;
    h0.x = __float2half(fmaf((x.x - mn) * inv, gg.x, bb.x) * outDiv);
    h0.y = __float2half(fmaf((x.y - mn) * inv, gg.y, bb.y) * outDiv);
    h1.x = __float2half(fmaf((x.z - mn) * inv, gg.z, bb.z) * outDiv);
    h1.y = __float2half(fmaf((x.w - mn) * inv, gg.w, bb.w) * outDiv);
    *(__half2*)(chO + base)     = h0;
    *(__half2*)(chO + base + 2) = h1;
}

// ---------------------------------------------------------------------------
extern "C" void kernel_launch(void* const* d_in, const int* in_sizes, int n_in,
                              void* d_out, int out_size)
{
    const float* x       = (const float*)d_in[0];
    const float* ew      = (const float*)d_in[1];
    const float* w_up    = (const float*)d_in[2];
    const float* w_gate  = (const float*)d_in[3];
    const float* w_down  = (const float*)d_in[4];
    const float* w_pre   = (const float*)d_in[5];
    const float* w_post  = (const float*)d_in[6];
    const float* an_g    = (const float*)d_in[7];
    const float* an_b    = (const float*)d_in[8];
    const float* w_aproj = (const float*)d_in[9];
    const float* w_exp   = (const float*)d_in[10];
    const float* eln_g   = (const float*)d_in[11];
    const float* eln_b   = (const float*)d_in[12];
    const float* w_eproj = (const float*)d_in[13];
    const float* w_out   = (const float*)d_in[14];
    float* out = (float*)d_out;

    float* part;
    cudaGetSymbolAddress((void**)&part, g_part);

    __half *xh,*xl,*Uh,*Hdc,*wdc,*preh,*ainh,*aouth,*adph,*ech,*scrh,*aTh;
    __half *weT,*wouth,*wexph,*wuph,*wgh,*wpreh,*wprel,*wpoh,*waph;
    cudaGetSymbolAddress((void**)&xh,    g_xh);   cudaGetSymbolAddress((void**)&xl,    g_xl);
    cudaGetSymbolAddress((void**)&Uh,    g_Uh);   cudaGetSymbolAddress((void**)&Hdc,   g_Hdc);
    cudaGetSymbolAddress((void**)&wdc,   g_wdc);  cudaGetSymbolAddress((void**)&preh,  g_preh);
    cudaGetSymbolAddress((void**)&ainh,  g_ainh); cudaGetSymbolAddress((void**)&aouth, g_aouth);
    cudaGetSymbolAddress((void**)&adph,  g_adph); cudaGetSymbolAddress((void**)&ech,   g_ech);
    cudaGetSymbolAddress((void**)&scrh,  g_scrh); cudaGetSymbolAddress((void**)&aTh,   g_aTh);
    cudaGetSymbolAddress((void**)&weT,   g_weT);  cudaGetSymbolAddress((void**)&wouth, g_wouth);
    cudaGetSymbolAddress((void**)&wexph, g_wexph);
    cudaGetSymbolAddress((void**)&wuph,  g_wuph); cudaGetSymbolAddress((void**)&wgh,   g_wgh);
    cudaGetSymbolAddress((void**)&wpreh, g_wpreh);cudaGetSymbolAddress((void**)&wprel, g_wprel);
    cudaGetSymbolAddress((void**)&wpoh,  g_wpoh); cudaGetSymbolAddress((void**)&waph,  g_waph);

    cudaFuncSetAttribute(tgemm_k<0,1,false,true ,false,false>, cudaFuncAttributeMaxDynamicSharedMemorySize, TG_SMEM);
    cudaFuncSetAttribute(tgemm_k<1,1,false,true ,false,true >, cudaFuncAttributeMaxDynamicSharedMemorySize, TG_SMEM);
    cudaFuncSetAttribute(tgemm_k<0,3,true ,false,true ,false>, cudaFuncAttributeMaxDynamicSharedMemorySize, TG_SMEM);
    cudaFuncSetAttribute(tgemm_k<0,1,true ,false,true ,false>, cudaFuncAttributeMaxDynamicSharedMemorySize, TG_SMEM);
    cudaFuncSetAttribute(tgemm_k<3,1,false,true ,false,false>, cudaFuncAttributeMaxDynamicSharedMemorySize, TG_SMEM);
    cudaFuncSetAttribute(tgemm_k<2,1,false,true ,false,true >, cudaFuncAttributeMaxDynamicSharedMemorySize, TG_SMEM);
    cudaFuncSetAttribute(tgemm_k<0,1,true ,false,false,false>, cudaFuncAttributeMaxDynamicSharedMemorySize, TG_SMEM);

    // 1) split x (h/l)
    {
        long n4 = (long)NTOK * D_ / 4;
        split_k<<<(unsigned)((n4 + 255) / 256), 256>>>(x, xh, xl, n4);
    }

    // 2) fused weight splits (w_down goes into wdc[:,0:2048])
    {
        SJobs J;
        auto set = [&](int j, const float* s, __half* dh, __half* dl, long n,
                       float sc, int rowLen, int dstW) {
            J.src[j] = s; J.dh[j] = dh; J.dl[j] = dl;
            J.n4[j] = n / 4; J.nblk[j] = (int)((J.n4[j] + 255) / 256); J.sc[j] = sc;
            J.rowLen[j] = rowLen; J.dstW[j] = dstW;
        };
        set(0, w_up,    wuph,  nullptr, (long)H_ * D_,      1.f,   0, 0);
        set(1, w_gate,  wgh,   nullptr, (long)H_ * D_,      1.f,   0, 0);
        set(2, w_down,  wdc,   nullptr, (long)D_ * H_,      1.f,   H_, KC);
        set(3, w_pre,   wpreh, wprel,   (long)A_ * D_,      512.f, 0, 0);
        set(4, w_post,  wpoh,  nullptr, (long)A_ * H_,      512.f, 0, 0);
        set(5, w_aproj, waph,  nullptr, (long)H_ * A_,      512.f, 0, 0);
        set(6, w_exp,   wexph, nullptr, (long)E_ * A_ * A_, 512.f, 0, 0);
        set(7, w_out,   wouth, nullptr, (long)D_ * H_,      32.f,  0, 0);
        int total = 0;
        for (int j = 0; j < 8; j++) total += J.nblk[j];
        msplit_k<<<total, 256>>>(J);
    }

    // 3) weT = transpose(w_eproj)[A,H] * 512
    tsplitg_k<float><<<dim3(H_/32, A_/32, 1), dim3(32, 8)>>>(w_eproj, weT, H_, A_, 512.f);

    // 4) Mh partials (split-K 8) -> redsum into wdc[:,2048:] as 12.8*M
    //    raw sum carries 16384*M -> dsH = 12.8/16384
    tgemm_k<0,1,true,false,true,false><<<dim3(8, D_/128, 1), 256, TG_SMEM>>>(
        wouth, nullptr, weT, nullptr, part, nullptr, nullptr,
        D_, A_, H_, H_, H_, 0, 0, 0, 0, 0, 1.f, 1.f);
    redsum_k<<<(unsigned)(((long)D_ * A_ / 4 + 255) / 256), 256>>>(
        part, wdc, 8, (long)D_ * A_, (long)D_ * A_ / 4, 12.8f / 16384.f, A_, KC, H_);

    // 5) Uh = fp16(x @ w_up^T)
    tgemm_k<0,1,false,true,false,false><<<dim3(H_/128, NTOK/128, 1), 256, TG_SMEM>>>(
        xh, nullptr, wuph, nullptr, nullptr, nullptr, Uh,
        NTOK, H_, D_, D_, D_, H_, 0, 0, 0, 0, 1.f, 1.f);

    // 6) Hdc[:,:2048] = fp16(silu(x @ w_gate^T) * Uh)
    tgemm_k<1,1,false,true,false,true><<<dim3(H_/128, NTOK/128, 1), 256, TG_SMEM>>>(
        xh, nullptr, wgh, nullptr, nullptr, Uh, Hdc,
        NTOK, H_, D_, D_, D_, KC, H_, 0, 0, 0, 1.f, 1.f);

    // 7) pre partials (3-pass, split-K 4) -> redln: ainh + preh(raw=512*pre)
    tgemm_k<0,3,true,false,true,false><<<dim3(4, NTOK/128, 1), 256, TG_SMEM>>>(
        xh, xl, wpreh, wprel, part, nullptr, nullptr,
        NTOK, A_, D_, D_, D_, 0, 0, 0, 0, 0, 1.f, 1.f);
    redln_k<<<NTOK/8, 256>>>(part, 4, (long)NTOK * A_, an_g, an_b,
                             ainh, preh, 1.f / 512.f, NTOK);

    // 9) pt partials (split-K 4, A = Hdc) -> redln: aouth
    tgemm_k<0,1,true,false,true,false><<<dim3(4, NTOK/128, 1), 256, TG_SMEM>>>(
        Hdc, nullptr, wpoh, nullptr, part, nullptr, nullptr,
        NTOK, A_, H_, KC, H_, 0, 0, 0, 0, 0, 1.f, 1.f);
    redln_k<<<NTOK/8, 256>>>(part, 4, (long)NTOK * A_, an_g, an_b,
                             aouth, nullptr, 1.f / 512.f, NTOK);

    // 11) scrh[b] = silu(clip(ain[b] @ aout[b]^T))
    tgemm_k<3,1,false,true,false,false><<<dim3(S_/128, S_/128, B_), 256, TG_SMEM>>>(
        ainh, nullptr, aouth, nullptr, nullptr, nullptr, scrh,
        S_, S_, A_, A_, A_, S_, 0, (long)S_ * A_, (long)S_ * A_, (long)S_ * S_, 1.f, 1.f);

    // 12) aTh = transpose(ainh)  (per batch)
    tsplitg_k<__half><<<dim3(S_/32, A_/32, B_), dim3(32, 8)>>>(ainh, aTh, S_, A_, 1.f);

    // 13) adp partials (split-K 4, batched z=8) -> redsum -> adph
    tgemm_k<0,1,true,false,true,false><<<dim3(4, S_/128, B_), 256, TG_SMEM>>>(
        scrh, nullptr, aTh, nullptr, part, nullptr, nullptr,
        S_, A_, S_, S_, S_, 0, 0, (long)S_ * S_, (long)A_ * S_, 0, 1.f, 1.f);
    redsum_k<<<(unsigned)(((long)NTOK * A_ / 4 + 255) / 256), 256>>>(
        part, adph, 4, (long)S_ * A_, (long)NTOK * A_ / 4, 1.f, A_, A_, 0);

    // 14) Hdc[:,:2048] += 0.1 * adp @ w_aproj^T   (in-place, fp16 aux)
    tgemm_k<2,1,false,true,false,true><<<dim3(H_/128, NTOK/128, 1), 256, TG_SMEM>>>(
        adph, nullptr, waph, nullptr, nullptr, Hdc, Hdc,
        NTOK, H_, A_, A_, A_, KC, KC, 0, 0, 0, 1.f / 512.f, 1.f);

    // e1) ech_i = fp16(8192 * pre @ w_exp[i]^T)  (batched over 8 experts)
    tgemm_k<0,1,false,true,false,false><<<dim3(1, NTOK/128, E_), 256, TG_SMEM>>>(
        preh, nullptr, wexph, nullptr, nullptr, nullptr, ech,
        NTOK, A_, A_, A_, A_, A_, 0, 0, (long)A_ * A_, (long)NTOK * A_, 1.f / 32.f, 1.f);

    // e2) Hdc[:,2048:] = LN(ech[last-positive]/8192, eln) / 128   (0 if none)
    lnsel_k<<<NTOK/8, 256>>>(ech, ew, eln_g, eln_b, Hdc, NTOK, KC, H_, 1.f / 128.f);

    // 10) out = Hdc @ wdc^T  over K=2176  (= Hid@w_down^T + 0.1*ch@M^T)
    tgemm_k<0,1,true,false,false,false><<<dim3(D_/128, NTOK/128, 1), 256, TG_SMEM>>>(
        Hdc, nullptr, wdc, nullptr, out, nullptr, nullptr,
        NTOK, D_, KC, KC, KC, D_, 0, 0, 0, 0, 1.f, 1.f);
}

// round 14
// speedup vs baseline: 6.6792x; 1.0685x over previous
#include <cuda_runtime.h>
#include <cuda_fp16.h>
#include <cstdint>

// ---------------------------------------------------------------------------
// LLaDAModel fused forward — mma.sync fp16-split GEMMs, split-K, fused
// reduce+LN, interleaved up/gate GEMM, and triple K-concat final GEMM
// (aproj + expert paths folded into the w_down GEMM).
// B=8,S=2048,D=1024,H=2048,A=128,E=8. N=16384.
//
//   s.   split x (h/l);  fused weight splits:
//          wug  [2H,D]: rows 2r=w_up_r, 2r+1=w_gate_r
//          wdc[:,0:2048]=w_down ; wpre h/l*512 ; wpo*512 ; wexp*512 ; wout*32
//   0a.  weT  = transpose(w_eproj)*512 ; wapT = transpose(w_aproj)*512
//   0b.  Mh  partials -> redsum -> wdc[:,2176:2304] = 12.8*M
//   0c.  W2  partials (A=wdc[:, :2048]) -> redsum -> wdc[:,2048:2176]=12.8*W2
//   1.   Hdc[:,:2048] = fp16(silu(gate)*up)  — ONE GEMM vs wug (EPI=4)
//   3.   pre partials (3-pass, split-K 4) -> redln -> ainh + preh(raw*512)
//   5.   pt  partials (split-K 4, A=Hdc)  -> redln -> aouth
//   7.   scrh = silu(clip(ain @ aout^T)) per b
//   7b.  aTh  = transpose(ainh) per b
//   8.   adp partials (split-K 4, batched) -> redsum -> Hdc[:,2048:2176]=adp/128
//  e1.   ech_i = fp16(8192 * pre @ w_exp[i]^T)  (batched)
//  e2.   lnsel -> Hdc[:,2176:2304] = LN(ech[last-pos])/128
//  10.   out = Hdc @ wdc^T over K=2304
//           = Hid@w_down^T + 0.1*adp@W2^T + 0.1*ch@M^T
// ---------------------------------------------------------------------------

constexpr int B_ = 8, S_ = 2048, D_ = 1024, H_ = 2048, A_ = 128, E_ = 8;
constexpr int NTOK = B_ * S_;        // 16384
constexpr int KC = H_ + 2 * A_;      // 2304 concat-K

// fp32 scratch
__device__ float g_part[(size_t)NTOK * A_ * 4];   // split-K partials (max case)

// fp16 scratch
__device__ __half g_xh [(size_t)NTOK * D_], g_xl [(size_t)NTOK * D_];
__device__ __half g_Hdc[(size_t)NTOK * KC];       // [N,2304]: Hid | adp/128 | ch/128
__device__ __half g_wdc[(size_t)D_ * KC];         // [D,2304]: w_down | 12.8*W2 | 12.8*M
__device__ __half g_wug[(size_t)2 * H_ * D_];     // interleaved up/gate
__device__ __half g_preh[(size_t)NTOK * A_];
__device__ __half g_ainh[(size_t)NTOK * A_];
__device__ __half g_aouth[(size_t)NTOK * A_];
__device__ __half g_ech [(size_t)E_ * NTOK * A_];
__device__ __half g_scrh[(size_t)B_ * S_ * S_];
__device__ __half g_aTh[(size_t)B_ * A_ * S_];
__device__ __half g_weT[(size_t)A_ * H_];
__device__ __half g_wapT[(size_t)A_ * H_];
__device__ __half g_wouth[(size_t)D_ * H_];
__device__ __half g_wexph[(size_t)E_ * A_ * A_];
__device__ __half g_wpreh[(size_t)A_ * D_], g_wprel[(size_t)A_ * D_];
__device__ __half g_wpoh[(size_t)A_ * H_];

__device__ __forceinline__ float siluf(float x) {
    return x * (1.0f / (1.0f + __expf(-x)));
}

#define LDSM4(r0,r1,r2,r3,addr) \
    asm volatile("ldmatrix.sync.aligned.m8n8.x4.shared.b16 {%0,%1,%2,%3},[%4];\n" \
        : "=r"(r0),"=r"(r1),"=r"(r2),"=r"(r3) : "r"(addr))

#define MMA16816(c,a,b) \
    asm volatile("mma.sync.aligned.m16n8k16.row.col.f32.f16.f16.f32 " \
        "{%0,%1,%2,%3},{%4,%5,%6,%7},{%8,%9},{%0,%1,%2,%3};\n" \
        : "+f"((c)[0]),"+f"((c)[1]),"+f"((c)[2]),"+f"((c)[3]) \
        : "r"((a)[0]),"r"((a)[1]),"r"((a)[2]),"r"((a)[3]),"r"((b)[0]),"r"((b)[1]))

#define CPA16(dst,src) \
    asm volatile("cp.async.cg.shared.global [%0],[%1],16;\n" :: "r"(dst),"l"(src))

constexpr int TG_SMEM = 81920;

// ---------------------------------------------------------------------------
// Tensor GEMM: C[M,N](f32) = split(A)[M,K] @ split(B)[N,K]^T
// PASSES=1: acc = Ah*Bh        PASSES=3: + Ah*Bl + Al*Bh
// CTA tile 128x128x32, 8 warps (4x2), warp tile 32x64, m16n8k16 fp16 mma.
// lda/ldb/ldc: row strides.  SPLIT: grid.x = K-split (N must be 128), raw
// fp32 partials to C + (z*gridDim.x+blockIdx.x)*M*N.
// EPI: 0 C=acc   3 C=silu(clip(acc,±5))
//      4 (pair): Ch[r, col/2] = fp16(silu(odd)*even)  — interleaved up/gate
// ---------------------------------------------------------------------------
template<int EPI, int PASSES, bool WFP32, bool WH, bool SPLIT>
__global__ void __launch_bounds__(256, 2) tgemm_k(
    const __half* __restrict__ Ah, const __half* __restrict__ Al,
    const __half* __restrict__ Bh, const __half* __restrict__ Bl,
    float* __restrict__ C, __half* __restrict__ Ch,
    int M, int N, int K, long lda, long ldb, long ldc,
    long sA, long sB, long sC, float ds, float hs)
{
    constexpr int NST  = (PASSES == 1) ? 4 : 2;
    constexpr int SSZ  = (PASSES == 1) ? 20480 : 40960;
    constexpr unsigned BOFF  = (PASSES == 1) ? 10240u : 20480u;
    constexpr unsigned ALOFF = 10240u;

    extern __shared__ char smem[];
    const unsigned sbase = (unsigned)__cvta_generic_to_shared(smem);
    const int tid = threadIdx.x, lane = tid & 31, warp = tid >> 5;
    const int wm = warp >> 1, wn = warp & 1;

    const long z = blockIdx.z;
    Ah += z * sA; Bh += z * sB;
    if (PASSES == 3) { Al += z * sA; Bl += z * sB; }
    float* Cp;
    __half* Chp = nullptr;
    if (SPLIT) {
        Cp = C + ((z * gridDim.x + blockIdx.x) * (long)M) * N;
    } else {
        Cp = WFP32 ? C + z * sC : nullptr;
        Chp = WH ? Ch + z * sC : nullptr;
    }

    const int m0 = blockIdx.y * 128;
    const int n0 = SPLIT ? 0 : blockIdx.x * 128;

    const int KT = K / 32;
    int t0k = 0, TCNT = KT;
    if (SPLIT) { TCNT = KT / gridDim.x; t0k = blockIdx.x * TCNT; }

    float acc[2][8][4];
#pragma unroll
    for (int i = 0; i < 2; i++)
#pragma unroll
        for (int j = 0; j < 8; j++)
#pragma unroll
            for (int e = 0; e < 4; e++) acc[i][j][e] = 0.f;

    const unsigned aAddr = (unsigned)((wm * 32 + (lane & 15)) * 80 + (lane >> 4) * 16);
    const unsigned bAddr = (unsigned)(BOFF +
        (wn * 64 + ((lane >> 4) << 3) + (lane & 7)) * 80 + ((lane >> 3) & 1) * 16);

    auto issue = [&](int t, int s) {
        const long k0 = (long)(t0k + t) * 32;
        const unsigned st = sbase + s * SSZ;
#pragma unroll
        for (int i = tid; i < 512; i += 256) {
            const int r = i >> 2, c = i & 3;
            const unsigned da = st + r * 80 + c * 16;
            const long  ga = (long)(m0 + r) * lda + k0 + c * 8;
            CPA16(da, Ah + ga);
            if (PASSES == 3) CPA16(da + ALOFF, Al + ga);
            const unsigned db = st + BOFF + r * 80 + c * 16;
            const long  gb = (long)(n0 + r) * ldb + k0 + c * 8;
            CPA16(db, Bh + gb);
            if (PASSES == 3) CPA16(db + ALOFF, Bl + gb);
        }
        asm volatile("cp.async.commit_group;\n");
    };

    const int pre = (NST - 1 < TCNT) ? NST - 1 : TCNT;
    for (int p = 0; p < pre; p++) issue(p, p % NST);

    for (int t = 0; t < TCNT; ++t) {
        if (NST == 2) {
            asm volatile("cp.async.wait_group 0;\n" ::: "memory");
        } else {
            const int rem = TCNT - 1 - t;
            if (rem >= 2)      asm volatile("cp.async.wait_group 2;\n" ::: "memory");
            else if (rem == 1) asm volatile("cp.async.wait_group 1;\n" ::: "memory");
            else               asm volatile("cp.async.wait_group 0;\n" ::: "memory");
        }
        __syncthreads();
        if (t + NST - 1 < TCNT) issue(t + NST - 1, (t + NST - 1) % NST);

        const unsigned st = sbase + (t % NST) * SSZ;
#pragma unroll
        for (int kk = 0; kk < 2; kk++) {
            const unsigned ko = kk * 32;
            unsigned ah[2][4], al[2][4], bh[8][2], bl[8][2];
#pragma unroll
            for (int im = 0; im < 2; im++) {
                LDSM4(ah[im][0], ah[im][1], ah[im][2], ah[im][3],
                      st + aAddr + im * 1280 + ko);
                if (PASSES == 3)
                    LDSM4(al[im][0], al[im][1], al[im][2], al[im][3],
                          st + ALOFF + aAddr + im * 1280 + ko);
            }
#pragma unroll
            for (int jp = 0; jp < 4; jp++) {
                LDSM4(bh[2*jp][0], bh[2*jp][1], bh[2*jp+1][0], bh[2*jp+1][1],
                      st + bAddr + jp * 1280 + ko);
                if (PASSES == 3)
                    LDSM4(bl[2*jp][0], bl[2*jp][1], bl[2*jp+1][0], bl[2*jp+1][1],
                          st + ALOFF + bAddr + jp * 1280 + ko);
            }
#pragma unroll
            for (int im = 0; im < 2; im++)
#pragma unroll
                for (int jn = 0; jn < 8; jn++) MMA16816(acc[im][jn], ah[im], bh[jn]);
            if (PASSES == 3) {
#pragma unroll
                for (int im = 0; im < 2; im++)
#pragma unroll
                    for (int jn = 0; jn < 8; jn++) MMA16816(acc[im][jn], ah[im], bl[jn]);
#pragma unroll
                for (int im = 0; im < 2; im++)
#pragma unroll
                    for (int jn = 0; jn < 8; jn++) MMA16816(acc[im][jn], al[im], bh[jn]);
            }
        }
        __syncthreads();
    }

    // epilogue
    const int gr = lane >> 2, q = lane & 3;
#pragma unroll
    for (int im = 0; im < 2; im++) {
#pragma unroll
        for (int jn = 0; jn < 8; jn++) {
            const long r0  = m0 + wm * 32 + im * 16 + gr;
            const long col = n0 + wn * 64 + jn * 8 + q * 2;
            if (SPLIT) {   // raw partials, compact layout
                const long i0 = r0 * N + col, i1 = i0 + 8L * N;
                *(float2*)(Cp + i0) = make_float2(acc[im][jn][0], acc[im][jn][1]);
                *(float2*)(Cp + i1) = make_float2(acc[im][jn][2], acc[im][jn][3]);
                continue;
            }
            float v0 = acc[im][jn][0] * ds, v1 = acc[im][jn][1] * ds;
            float v2 = acc[im][jn][2] * ds, v3 = acc[im][jn][3] * ds;
            if (EPI == 4) {
                // interleaved up/gate: (even,odd) = (up, gate)
                const long oc = col >> 1;
                Chp[r0 * ldc + oc]       = __float2half(siluf(v1) * v0);
                Chp[(r0 + 8) * ldc + oc] = __float2half(siluf(v3) * v2);
                continue;
            }
            const long i0 = r0 * ldc + col, i1 = i0 + 8L * ldc;
            if (EPI == 3) {
                v0 = siluf(fminf(fmaxf(v0, -5.f), 5.f));
                v1 = siluf(fminf(fmaxf(v1, -5.f), 5.f));
                v2 = siluf(fminf(fmaxf(v2, -5.f), 5.f));
                v3 = siluf(fminf(fmaxf(v3, -5.f), 5.f));
            }
            if (WFP32) {
                *(float2*)(Cp + i0) = make_float2(v0, v1);
                *(float2*)(Cp + i1) = make_float2(v2, v3);
            }
            if (WH) {
                __half2 hh;
                hh.x = __float2half(v0 * hs); hh.y = __float2half(v1 * hs);
                *(__half2*)(Chp + i0) = hh;
                hh.x = __float2half(v2 * hs); hh.y = __float2half(v3 * hs);
                *(__half2*)(Chp + i1) = hh;
            }
        }
    }
}

// ---------------------------------------------------------------------------
// Split-K reduce: per-batch sum of SK partials (fixed order), fp16 out with
// row remap.  Partials: part[(z*SK + s)*MN + r].  e0 global over batches.
// dst = (e0/rowLen)*outW + outOff + e0%rowLen.
// ---------------------------------------------------------------------------
__global__ void redsum_k(const float* __restrict__ part,
                         __half* __restrict__ Yh,
                         int SK, long MN, long n4, float dsH,
                         int rowLen, int outW, int outOff)
{
    long i = blockIdx.x * (long)blockDim.x + threadIdx.x;
    if (i >= n4) return;
    long e0 = i * 4;
    long zz = e0 / MN, r = e0 - zz * MN;
    const float* p = part + (zz * SK) * MN + r;
    float4 s = *(const float4*)p;
    for (int k = 1; k < SK; k++) {
        float4 v = *(const float4*)(p + (long)k * MN);
        s.x += v.x; s.y += v.y; s.z += v.z; s.w += v.w;
    }
    long row = e0 / rowLen, col = e0 - row * rowLen;
    long d = row * outW + outOff + col;
    __half2 h0, h1;
    h0.x = __float2half(s.x * dsH); h0.y = __float2half(s.y * dsH);
    h1.x = __float2half(s.z * dsH); h1.y = __float2half(s.w * dsH);
    *(__half2*)(Yh + d)     = h0;
    *(__half2*)(Yh + d + 2) = h1;
}

// ---------------------------------------------------------------------------
// Fused split-K reduce + LayerNorm (rows of 128, one warp/row, single batch).
// sum*dsc = true values.  LN fp16 -> Yh; optional raw sum fp16 -> Ph.
// ---------------------------------------------------------------------------
__global__ void redln_k(const float* __restrict__ part, int SK, long MN,
                        const float* __restrict__ g, const float* __restrict__ b,
                        __half* __restrict__ Yh, __half* __restrict__ Ph,
                        float dsc, int rows)
{
    int row  = (blockIdx.x * blockDim.x + threadIdx.x) >> 5;
    int lane = threadIdx.x & 31;
    if (row >= rows) return;
    const long base = (long)row * 128 + lane * 4;
    float4 x = *(const float4*)(part + base);
    for (int k = 1; k < SK; k++) {
        float4 v = *(const float4*)(part + (long)k * MN + base);
        x.x += v.x; x.y += v.y; x.z += v.z; x.w += v.w;
    }
    if (Ph) {
        __half2 h0, h1;
        h0.x = __float2half(x.x); h0.y = __float2half(x.y);
        h1.x = __float2half(x.z); h1.y = __float2half(x.w);
        *(__half2*)(Ph + base)     = h0;
        *(__half2*)(Ph + base + 2) = h1;
    }
    x.x *= dsc; x.y *= dsc; x.z *= dsc; x.w *= dsc;
    float s  = x.x + x.y + x.z + x.w;
    float ss = fmaf(x.x, x.x, fmaf(x.y, x.y, fmaf(x.z, x.z, x.w * x.w)));
#pragma unroll
    for (int o = 16; o > 0; o >>= 1) {
        s  += __shfl_xor_sync(0xffffffffu, s,  o);
        ss += __shfl_xor_sync(0xffffffffu, ss, o);
    }
    float m   = s * (1.f / 128.f);
    float inv = rsqrtf(ss * (1.f / 128.f) - m * m + 1e-5f);
    float4 gg = *(const float4*)(g + lane * 4);
    float4 bb = *(const float4*)(b + lane * 4);
    __half2 h0, h1;
    h0.x = __float2half(fmaf((x.x - m) * inv, gg.x, bb.x));
    h0.y = __float2half(fmaf((x.y - m) * inv, gg.y, bb.y));
    h1.x = __float2half(fmaf((x.z - m) * inv, gg.z, bb.z));
    h1.y = __float2half(fmaf((x.w - m) * inv, gg.w, bb.w));
    *(__half2*)(Yh + base)     = h0;
    *(__half2*)(Yh + base + 2) = h1;
}

// ---------------------------------------------------------------------------
// fp32 -> fp16 hi/lo split (x only)
// ---------------------------------------------------------------------------
__global__ void split_k(const float* __restrict__ X,
                        __half* __restrict__ Hh, __half* __restrict__ Hl,
                        long n4)
{
    long i = blockIdx.x * (long)blockDim.x + threadIdx.x;
    if (i >= n4) return;
    float4 v = ((const float4*)X)[i];
    __half2 h0, h1, l0, l1;
    h0.x = __float2half(v.x); l0.x = __float2half(v.x - __half2float(h0.x));
    h0.y = __float2half(v.y); l0.y = __float2half(v.y - __half2float(h0.y));
    h1.x = __float2half(v.z); l1.x = __float2half(v.z - __half2float(h1.x));
    h1.y = __float2half(v.w); l1.y = __float2half(v.w - __half2float(h1.y));
    ((__half2*)Hh)[2*i]   = h0; ((__half2*)Hh)[2*i+1] = h1;
    ((__half2*)Hl)[2*i]   = l0; ((__half2*)Hl)[2*i+1] = l1;
}

// ---------------------------------------------------------------------------
// Fused multi-array fp32 -> fp16 split (hi always; lo if dl != null).
// Row remap per job: dst = (e/rowLen)*dstW + dstOff + e%rowLen (dstW=0: identity)
// ---------------------------------------------------------------------------
struct SJobs {
    const float* src[8];
    __half* dh[8];
    __half* dl[8];
    int   nblk[8];
    long  n4[8];
    float sc[8];
    int   rowLen[8];
    int   dstW[8];
    int   dstOff[8];
};

__global__ void msplit_k(SJobs J)
{
    int b = blockIdx.x, j = 0;
    while (j < 7 && b >= J.nblk[j]) { b -= J.nblk[j]; j++; }
    long i = (long)b * 256 + threadIdx.x;
    if (i >= J.n4[j]) return;
    float sc = J.sc[j];
    float4 v = ((const float4*)J.src[j])[i];
    v.x *= sc; v.y *= sc; v.z *= sc; v.w *= sc;
    long e0 = i * 4, d = e0;
    if (J.dstW[j]) {
        long row = e0 / J.rowLen[j], col = e0 - row * J.rowLen[j];
        d = row * J.dstW[j] + J.dstOff[j] + col;
    }
    __half2 h0, h1;
    h0.x = __float2half(v.x); h0.y = __float2half(v.y);
    h1.x = __float2half(v.z); h1.y = __float2half(v.w);
    *(__half2*)(J.dh[j] + d)     = h0;
    *(__half2*)(J.dh[j] + d + 2) = h1;
    if (J.dl[j]) {
        __half2 l0, l1;
        l0.x = __float2half(v.x - __half2float(h0.x));
        l0.y = __float2half(v.y - __half2float(h0.y));
        l1.x = __float2half(v.z - __half2float(h1.x));
        l1.y = __float2half(v.w - __half2float(h1.y));
        *(__half2*)(J.dl[j] + d)     = l0;
        *(__half2*)(J.dl[j] + d + 2) = l1;
    }
}

// ---------------------------------------------------------------------------
// Transpose [R,C]->[C,R], input fp32 or fp16, out fp16(scale). grid(R/32,C/32,nz)
// ---------------------------------------------------------------------------
template<typename TI>
__global__ void tsplitg_k(const TI* __restrict__ X, __half* __restrict__ T,
                          int R, int C, float scale)
{
    __shared__ float t[32][33];
    const long zb = blockIdx.z;
    X += zb * (long)R * C;  T += zb * (long)R * C;
    const int r0 = blockIdx.x * 32, c0 = blockIdx.y * 32;
    const int tx = threadIdx.x, ty = threadIdx.y;
#pragma unroll
    for (int i = 0; i < 4; i++) {
        int rr = ty * 4 + i;
        t[rr][tx] = (float)X[(long)(r0 + rr) * C + c0 + tx];
    }
    __syncthreads();
#pragma unroll
    for (int i = 0; i < 4; i++) {
        int cc = ty * 4 + i;
        T[(long)(c0 + cc) * R + r0 + tx] = __float2half(t[tx][cc] * scale);
    }
}

// ---------------------------------------------------------------------------
// Expert select + LN from fp16 ec (scaled 8192): idx = LAST expert with ew>0;
// writes LN*outDiv into out[row*outW + outOff + col] (0 if no expert).
// ---------------------------------------------------------------------------
__global__ void lnsel_k(const __half* __restrict__ ec, const float* __restrict__ ew,
                        const float* __restrict__ eg, const float* __restrict__ eb,
                        __half* __restrict__ chO, int rows, long outW, long outOff,
                        float outDiv)
{
    int row  = (blockIdx.x * blockDim.x + threadIdx.x) >> 5;
    int lane = threadIdx.x & 31;
    if (row >= rows) return;
    float w = (lane < E_) ? ew[(long)row * E_ + lane] : 0.f;
    unsigned m = __ballot_sync(0xffffffffu, w > 0.f) & 0xFFu;
    const long base = (long)row * outW + outOff + lane * 4;
    if (m == 0) {
        __half2 zz; zz.x = __float2half(0.f); zz.y = zz.x;
        *(__half2*)(chO + base) = zz; *(__half2*)(chO + base + 2) = zz;
        return;
    }
    int idx = 31 - __clz(m);
    const long eb0 = ((long)idx * NTOK + row) * 128 + lane * 4;
    __half2 e0 = *(const __half2*)(ec + eb0);
    __half2 e1 = *(const __half2*)(ec + eb0 + 2);
    const float DSC = 1.f / 8192.f;
    float4 x;
    x.x = __half2float(e0.x) * DSC; x.y = __half2float(e0.y) * DSC;
    x.z = __half2float(e1.x) * DSC; x.w = __half2float(e1.y) * DSC;
    float s  = x.x + x.y + x.z + x.w;
    float ss = fmaf(x.x, x.x, fmaf(x.y, x.y, fmaf(x.z, x.z, x.w * x.w)));
#pragma unroll
    for (int o = 16; o > 0; o >>= 1) {
        s  += __shfl_xor_sync(0xffffffffu, s,  o);
        ss += __shfl_xor_sync(0xffffffffu, ss, o);
    }
    float mn  = s * (1.f / 128.f);
    float inv = rsqrtf(ss * (1.f / 128.f) - mn * mn + 1e-5f);
    float4 gg = *(const float4*)(eg + (long)idx * 128 + lane * 4);
    float4 bb = *(const float4*)(eb + (long)idx * 128 + lane * 4);
    __half2 h0, h1;
    h0.x = __float2half(fmaf((x.x - mn) * inv, gg.x, bb.x) * outDiv);
    h0.y = __float2half(fmaf((x.y - mn) * inv, gg.y, bb.y) * outDiv);
    h1.x = __float2half(fmaf((x.z - mn) * inv, gg.z, bb.z) * outDiv);
    h1.y = __float2half(fmaf((x.w - mn) * inv, gg.w, bb.w) * outDiv);
    *(__half2*)(chO + base)     = h0;
    *(__half2*)(chO + base + 2) = h1;
}

// ---------------------------------------------------------------------------
extern "C" void kernel_launch(void* const* d_in, const int* in_sizes, int n_in,
                              void* d_out, int out_size)
{
    const float* x       = (const float*)d_in[0];
    const float* ew      = (const float*)d_in[1];
    const float* w_up    = (const float*)d_in[2];
    const float* w_gate  = (const float*)d_in[3];
    const float* w_down  = (const float*)d_in[4];
    const float* w_pre   = (const float*)d_in[5];
    const float* w_post  = (const float*)d_in[6];
    const float* an_g    = (const float*)d_in[7];
    const float* an_b    = (const float*)d_in[8];
    const float* w_aproj = (const float*)d_in[9];
    const float* w_exp   = (const float*)d_in[10];
    const float* eln_g   = (const float*)d_in[11];
    const float* eln_b   = (const float*)d_in[12];
    const float* w_eproj = (const float*)d_in[13];
    const float* w_out   = (const float*)d_in[14];
    float* out = (float*)d_out;

    float* part;
    cudaGetSymbolAddress((void**)&part, g_part);

    __half *xh,*xl,*Hdc,*wdc,*wug,*preh,*ainh,*aouth,*ech,*scrh,*aTh;
    __half *weT,*wapT,*wouth,*wexph,*wpreh,*wprel,*wpoh;
    cudaGetSymbolAddress((void**)&xh,    g_xh);   cudaGetSymbolAddress((void**)&xl,    g_xl);
    cudaGetSymbolAddress((void**)&Hdc,   g_Hdc);  cudaGetSymbolAddress((void**)&wdc,   g_wdc);
    cudaGetSymbolAddress((void**)&wug,   g_wug);  cudaGetSymbolAddress((void**)&preh,  g_preh);
    cudaGetSymbolAddress((void**)&ainh,  g_ainh); cudaGetSymbolAddress((void**)&aouth, g_aouth);
    cudaGetSymbolAddress((void**)&ech,   g_ech);
    cudaGetSymbolAddress((void**)&scrh,  g_scrh); cudaGetSymbolAddress((void**)&aTh,   g_aTh);
    cudaGetSymbolAddress((void**)&weT,   g_weT);  cudaGetSymbolAddress((void**)&wapT,  g_wapT);
    cudaGetSymbolAddress((void**)&wouth, g_wouth);cudaGetSymbolAddress((void**)&wexph, g_wexph);
    cudaGetSymbolAddress((void**)&wpreh, g_wpreh);cudaGetSymbolAddress((void**)&wprel, g_wprel);
    cudaGetSymbolAddress((void**)&wpoh,  g_wpoh);

    cudaFuncSetAttribute(tgemm_k<4,1,false,true ,false>, cudaFuncAttributeMaxDynamicSharedMemorySize, TG_SMEM);
    cudaFuncSetAttribute(tgemm_k<0,3,true ,false,true >, cudaFuncAttributeMaxDynamicSharedMemorySize, TG_SMEM);
    cudaFuncSetAttribute(tgemm_k<0,1,true ,false,true >, cudaFuncAttributeMaxDynamicSharedMemorySize, TG_SMEM);
    cudaFuncSetAttribute(tgemm_k<3,1,false,true ,false>, cudaFuncAttributeMaxDynamicSharedMemorySize, TG_SMEM);
    cudaFuncSetAttribute(tgemm_k<0,1,false,true ,false>, cudaFuncAttributeMaxDynamicSharedMemorySize, TG_SMEM);
    cudaFuncSetAttribute(tgemm_k<0,1,true ,false,false>, cudaFuncAttributeMaxDynamicSharedMemorySize, TG_SMEM);

    // 1) split x (h/l)
    {
        long n4 = (long)NTOK * D_ / 4;
        split_k<<<(unsigned)((n4 + 255) / 256), 256>>>(x, xh, xl, n4);
    }

    // 2) fused weight splits
    {
        SJobs J;
        auto set = [&](int j, const float* s, __half* dh, __half* dl, long n,
                       float sc, int rowLen, int dstW, int dstOff) {
            J.src[j] = s; J.dh[j] = dh; J.dl[j] = dl;
            J.n4[j] = n / 4; J.nblk[j] = (int)((J.n4[j] + 255) / 256); J.sc[j] = sc;
            J.rowLen[j] = rowLen; J.dstW[j] = dstW; J.dstOff[j] = dstOff;
        };
        set(0, w_up,    wug,   nullptr, (long)H_ * D_,      1.f,   D_, 2*D_, 0);
        set(1, w_gate,  wug,   nullptr, (long)H_ * D_,      1.f,   D_, 2*D_, D_);
        set(2, w_down,  wdc,   nullptr, (long)D_ * H_,      1.f,   H_, KC,   0);
        set(3, w_pre,   wpreh, wprel,   (long)A_ * D_,      512.f, 0, 0, 0);
        set(4, w_post,  wpoh,  nullptr, (long)A_ * H_,      512.f, 0, 0, 0);
        set(5, w_exp,   wexph, nullptr, (long)E_ * A_ * A_, 512.f, 0, 0, 0);
        set(6, w_out,   wouth, nullptr, (long)D_ * H_,      32.f,  0, 0, 0);
        set(7, w_out,   wouth, nullptr, 0,                  1.f,   0, 0, 0);  // dummy
        J.nblk[7] = 0;
        int total = 0;
        for (int j = 0; j < 7; j++) total += J.nblk[j];
        msplit_k<<<total, 256>>>(J);
    }

    // 3) weT = transpose(w_eproj)*512 ; wapT = transpose(w_aproj)*512
    tsplitg_k<float><<<dim3(H_/32, A_/32, 1), dim3(32, 8)>>>(w_eproj, weT, H_, A_, 512.f);
    tsplitg_k<float><<<dim3(H_/32, A_/32, 1), dim3(32, 8)>>>(w_aproj, wapT, H_, A_, 512.f);

    // 4) Mh partials (split-K 8) -> redsum -> wdc[:,2176:2304] = 12.8*M
    //    raw sum = 16384*M -> dsH = 12.8/16384
    tgemm_k<0,1,true,false,true><<<dim3(8, D_/128, 1), 256, TG_SMEM>>>(
        wouth, nullptr, weT, nullptr, part, nullptr,
        D_, A_, H_, H_, H_, 0, 0, 0, 0, 1.f, 1.f);
    redsum_k<<<(unsigned)(((long)D_ * A_ / 4 + 255) / 256), 256>>>(
        part, wdc, 8, (long)D_ * A_, (long)D_ * A_ / 4, 12.8f / 16384.f, A_, KC, H_ + A_);

    // 5) W2 partials (A = wdc[:, :2048] fp16 w_down, split-K 8)
    //    -> redsum -> wdc[:,2048:2176] = 12.8*W2   (raw sum = 512*W2)
    tgemm_k<0,1,true,false,true><<<dim3(8, D_/128, 1), 256, TG_SMEM>>>(
        wdc, nullptr, wapT, nullptr, part, nullptr,
        D_, A_, H_, KC, H_, 0, 0, 0, 0, 1.f, 1.f);
    redsum_k<<<(unsigned)(((long)D_ * A_ / 4 + 255) / 256), 256>>>(
        part, wdc, 8, (long)D_ * A_, (long)D_ * A_ / 4, 12.8f / 512.f, A_, KC, H_);

    // 6) Hdc[:,:2048] = fp16(silu(gate)*up) — ONE interleaved GEMM (EPI=4)
    tgemm_k<4,1,false,true,false><<<dim3(2*H_/128, NTOK/128, 1), 256, TG_SMEM>>>(
        xh, nullptr, wug, nullptr, nullptr, Hdc,
        NTOK, 2*H_, D_, D_, D_, KC, 0, 0, 0, 1.f, 1.f);

    // 7) pre partials (3-pass, split-K 4) -> redln: ainh + preh(raw=512*pre)
    tgemm_k<0,3,true,false,true><<<dim3(4, NTOK/128, 1), 256, TG_SMEM>>>(
        xh, xl, wpreh, wprel, part, nullptr,
        NTOK, A_, D_, D_, D_, 0, 0, 0, 0, 1.f, 1.f);
    redln_k<<<NTOK/8, 256>>>(part, 4, (long)NTOK * A_, an_g, an_b,
                             ainh, preh, 1.f / 512.f, NTOK);

    // 8) pt partials (split-K 4, A = Hdc cols 0:2048) -> redln: aouth
    tgemm_k<0,1,true,false,true><<<dim3(4, NTOK/128, 1), 256, TG_SMEM>>>(
        Hdc, nullptr, wpoh, nullptr, part, nullptr,
        NTOK, A_, H_, KC, H_, 0, 0, 0, 0, 1.f, 1.f);
    redln_k<<<NTOK/8, 256>>>(part, 4, (long)NTOK * A_, an_g, an_b,
                             aouth, nullptr, 1.f / 512.f, NTOK);

    // 9) scrh[b] = silu(clip(ain[b] @ aout[b]^T))
    tgemm_k<3,1,false,true,false><<<dim3(S_/128, S_/128, B_), 256, TG_SMEM>>>(
        ainh, nullptr, aouth, nullptr, nullptr, scrh,
        S_, S_, A_, A_, A_, S_, (long)S_ * A_, (long)S_ * A_, (long)S_ * S_, 1.f, 1.f);

    // 10) aTh = transpose(ainh)  (per batch)
    tsplitg_k<__half><<<dim3(S_/32, A_/32, B_), dim3(32, 8)>>>(ainh, aTh, S_, A_, 1.f);

    // 11) adp partials (split-K 4, batched z=8) -> redsum -> Hdc[:,2048:2176]=adp/128
    tgemm_k<0,1,true,false,true><<<dim3(4, S_/128, B_), 256, TG_SMEM>>>(
        scrh, nullptr, aTh, nullptr, part, nullptr,
        S_, A_, S_, S_, S_, 0, (long)S_ * S_, (long)A_ * S_, 0, 1.f, 1.f);
    redsum_k<<<(unsigned)(((long)NTOK * A_ / 4 + 255) / 256), 256>>>(
        part, Hdc, 4, (long)S_ * A_, (long)NTOK * A_ / 4, 1.f / 128.f, A_, KC, H_);

    // e1) ech_i = fp16(8192 * pre @ w_exp[i]^T)  (batched over 8 experts)
    tgemm_k<0,1,false,true,false><<<dim3(1, NTOK/128, E_), 256, TG_SMEM>>>(
        preh, nullptr, wexph, nullptr, nullptr, ech,
        NTOK, A_, A_, A_, A_, A_, 0, (long)A_ * A_, (long)NTOK * A_, 1.f / 32.f, 1.f);

    // e2) Hdc[:,2176:2304] = LN(ech[last-positive]/8192, eln) / 128  (0 if none)
    lnsel_k<<<NTOK/8, 256>>>(ech, ew, eln_g, eln_b, Hdc, NTOK, KC, H_ + A_, 1.f / 128.f);

    // 12) out = Hdc @ wdc^T over K=2304
    //        = Hid@w_down^T + 0.1*adp@W2^T + 0.1*ch@M^T
    tgemm_k<0,1,true,false,false><<<dim3(D_/128, NTOK/128, 1), 256, TG_SMEM>>>(
        Hdc, nullptr, wdc, nullptr, out, nullptr,
        NTOK, D_, KC, KC, KC, D_, 0, 0, 0, 1.f, 1.f);
}

// round 15
// speedup vs baseline: 6.8292x; 1.0225x over previous
#include <cuda_runtime.h>
#include <cuda_fp16.h>
#include <cstdint>

// ---------------------------------------------------------------------------
// LLaDAModel fused forward — mma.sync fp16-split GEMMs, split-K, fused
// reduce+LN, interleaved up/gate GEMM, and triple K-concat final GEMM
// (aproj + expert paths folded into the w_down GEMM).
// B=8,S=2048,D=1024,H=2048,A=128,E=8. N=16384.
//
//   s.   split x (h/l);  fused weight splits:
//          wug  [2H,D]: rows 2r=w_up_r, 2r+1=w_gate_r
//          wdc[:,0:2048]=w_down ; wpre h/l*512 ; wpo*512 ; wexp*512 ; wout*32
//   0a.  weT  = transpose(w_eproj)*512 ; wapT = transpose(w_aproj)*512
//   0b.  Mh  partials -> redsum -> wdc[:,2176:2304] = 12.8*M
//   0c.  W2  partials (A=wdc[:, :2048]) -> redsum -> wdc[:,2048:2176]=12.8*W2
//   1.   Hdc[:,:2048] = fp16(silu(gate)*up)  — ONE GEMM vs wug (EPI=4)
//   3.   pre partials (2-pass, split-K 2) -> redln -> ainh + preh(raw*512)
//   5.   pt  partials (split-K 2, A=Hdc)  -> redln -> aouth
//   7.   scrh = silu(clip(ain @ aout^T)) per b
//   7b.  aTh  = transpose(ainh) per b
//   8.   adp partials (split-K 2, batched) -> redsum -> Hdc[:,2048:2176]=adp/128
//  e1.   ech_i = fp16(8192 * pre @ w_exp[i]^T)  (batched)
//  e2.   lnsel -> Hdc[:,2176:2304] = LN(ech[last-pos])/128
//  10.   out = Hdc @ wdc^T over K=2304
//           = Hid@w_down^T + 0.1*adp@W2^T + 0.1*ch@M^T
// ---------------------------------------------------------------------------

constexpr int B_ = 8, S_ = 2048, D_ = 1024, H_ = 2048, A_ = 128, E_ = 8;
constexpr int NTOK = B_ * S_;        // 16384
constexpr int KC = H_ + 2 * A_;      // 2304 concat-K

// fp32 scratch
__device__ float g_part[(size_t)NTOK * A_ * 4];   // split-K partials

// fp16 scratch
__device__ __half g_xh [(size_t)NTOK * D_], g_xl [(size_t)NTOK * D_];
__device__ __half g_Hdc[(size_t)NTOK * KC];       // [N,2304]: Hid | adp/128 | ch/128
__device__ __half g_wdc[(size_t)D_ * KC];         // [D,2304]: w_down | 12.8*W2 | 12.8*M
__device__ __half g_wug[(size_t)2 * H_ * D_];     // interleaved up/gate
__device__ __half g_preh[(size_t)NTOK * A_];
__device__ __half g_ainh[(size_t)NTOK * A_];
__device__ __half g_aouth[(size_t)NTOK * A_];
__device__ __half g_ech [(size_t)E_ * NTOK * A_];
__device__ __half g_scrh[(size_t)B_ * S_ * S_];
__device__ __half g_aTh[(size_t)B_ * A_ * S_];
__device__ __half g_weT[(size_t)A_ * H_];
__device__ __half g_wapT[(size_t)A_ * H_];
__device__ __half g_wouth[(size_t)D_ * H_];
__device__ __half g_wexph[(size_t)E_ * A_ * A_];
__device__ __half g_wpreh[(size_t)A_ * D_], g_wprel[(size_t)A_ * D_];
__device__ __half g_wpoh[(size_t)A_ * H_];

__device__ __forceinline__ float siluf(float x) {
    return x * (1.0f / (1.0f + __expf(-x)));
}

#define LDSM4(r0,r1,r2,r3,addr) \
    asm volatile("ldmatrix.sync.aligned.m8n8.x4.shared.b16 {%0,%1,%2,%3},[%4];\n" \
        : "=r"(r0),"=r"(r1),"=r"(r2),"=r"(r3) : "r"(addr))

#define MMA16816(c,a,b) \
    asm volatile("mma.sync.aligned.m16n8k16.row.col.f32.f16.f16.f32 " \
        "{%0,%1,%2,%3},{%4,%5,%6,%7},{%8,%9},{%0,%1,%2,%3};\n" \
        : "+f"((c)[0]),"+f"((c)[1]),"+f"((c)[2]),"+f"((c)[3]) \
        : "r"((a)[0]),"r"((a)[1]),"r"((a)[2]),"r"((a)[3]),"r"((b)[0]),"r"((b)[1]))

#define CPA16(dst,src) \
    asm volatile("cp.async.cg.shared.global [%0],[%1],16;\n" :: "r"(dst),"l"(src))

constexpr int TG_SMEM = 81920;

// ---------------------------------------------------------------------------
// Tensor GEMM: C[M,N](f32) = split(A)[M,K] @ split(B)[N,K]^T
// PASSES=1: acc = Ah*Bh   PASSES=2: + Ah*Bl   PASSES=3: + Ah*Bl + Al*Bh
// CTA tile 128x128x32, 8 warps (4x2), warp tile 32x64, m16n8k16 fp16 mma.
// lda/ldb/ldc: row strides.  SPLIT: grid.x = K-split (N must be 128), raw
// fp32 partials to C + (z*gridDim.x+blockIdx.x)*M*N.
// EPI: 0 C=acc   3 C=silu(clip(acc,±5))
//      4 (pair): Ch[r, col/2] = fp16(silu(odd)*even)  — interleaved up/gate
// ---------------------------------------------------------------------------
template<int EPI, int PASSES, bool WFP32, bool WH, bool SPLIT>
__global__ void __launch_bounds__(256, 2) tgemm_k(
    const __half* __restrict__ Ah, const __half* __restrict__ Al,
    const __half* __restrict__ Bh, const __half* __restrict__ Bl,
    float* __restrict__ C, __half* __restrict__ Ch,
    int M, int N, int K, long lda, long ldb, long ldc,
    long sA, long sB, long sC, float ds, float hs)
{
    constexpr int NST  = (PASSES == 1) ? 4 : 2;
    constexpr int SSZ  = (PASSES == 1) ? 20480 : (PASSES == 2 ? 30720 : 40960);
    constexpr unsigned ALOFF = 10240u;                         // P3 A-lo
    constexpr unsigned BOFF  = (PASSES == 3) ? 20480u : 10240u;
    constexpr unsigned BLOFF = BOFF + 10240u;                  // P2/P3 B-lo

    extern __shared__ char smem[];
    const unsigned sbase = (unsigned)__cvta_generic_to_shared(smem);
    const int tid = threadIdx.x, lane = tid & 31, warp = tid >> 5;
    const int wm = warp >> 1, wn = warp & 1;

    const long z = blockIdx.z;
    Ah += z * sA; Bh += z * sB;
    if (PASSES >= 2) Bl += z * sB;
    if (PASSES == 3) Al += z * sA;
    float* Cp;
    __half* Chp = nullptr;
    if (SPLIT) {
        Cp = C + ((z * gridDim.x + blockIdx.x) * (long)M) * N;
    } else {
        Cp = WFP32 ? C + z * sC : nullptr;
        Chp = WH ? Ch + z * sC : nullptr;
    }

    const int m0 = blockIdx.y * 128;
    const int n0 = SPLIT ? 0 : blockIdx.x * 128;

    const int KT = K / 32;
    int t0k = 0, TCNT = KT;
    if (SPLIT) { TCNT = KT / gridDim.x; t0k = blockIdx.x * TCNT; }

    float acc[2][8][4];
#pragma unroll
    for (int i = 0; i < 2; i++)
#pragma unroll
        for (int j = 0; j < 8; j++)
#pragma unroll
            for (int e = 0; e < 4; e++) acc[i][j][e] = 0.f;

    const unsigned aAddr = (unsigned)((wm * 32 + (lane & 15)) * 80 + (lane >> 4) * 16);
    const unsigned bAddr = (unsigned)(BOFF +
        (wn * 64 + ((lane >> 4) << 3) + (lane & 7)) * 80 + ((lane >> 3) & 1) * 16);
    const unsigned blAddr = (unsigned)(BLOFF +
        (wn * 64 + ((lane >> 4) << 3) + (lane & 7)) * 80 + ((lane >> 3) & 1) * 16);

    auto issue = [&](int t, int s) {
        const long k0 = (long)(t0k + t) * 32;
        const unsigned st = sbase + s * SSZ;
#pragma unroll
        for (int i = tid; i < 512; i += 256) {
            const int r = i >> 2, c = i & 3;
            const unsigned off16 = (unsigned)(r * 80 + c * 16);
            const long  ga = (long)(m0 + r) * lda + k0 + c * 8;
            CPA16(st + off16, Ah + ga);
            if (PASSES == 3) CPA16(st + ALOFF + off16, Al + ga);
            const long  gb = (long)(n0 + r) * ldb + k0 + c * 8;
            CPA16(st + BOFF + off16, Bh + gb);
            if (PASSES >= 2) CPA16(st + BLOFF + off16, Bl + gb);
        }
        asm volatile("cp.async.commit_group;\n");
    };

    const int pre = (NST - 1 < TCNT) ? NST - 1 : TCNT;
    for (int p = 0; p < pre; p++) issue(p, p % NST);

    for (int t = 0; t < TCNT; ++t) {
        if (NST == 2) {
            asm volatile("cp.async.wait_group 0;\n" ::: "memory");
        } else {
            const int rem = TCNT - 1 - t;
            if (rem >= 2)      asm volatile("cp.async.wait_group 2;\n" ::: "memory");
            else if (rem == 1) asm volatile("cp.async.wait_group 1;\n" ::: "memory");
            else               asm volatile("cp.async.wait_group 0;\n" ::: "memory");
        }
        __syncthreads();
        if (t + NST - 1 < TCNT) issue(t + NST - 1, (t + NST - 1) % NST);

        const unsigned st = sbase + (t % NST) * SSZ;
#pragma unroll
        for (int kk = 0; kk < 2; kk++) {
            const unsigned ko = kk * 32;
            unsigned ah[2][4], al[2][4], bh[8][2], bl[8][2];
#pragma unroll
            for (int im = 0; im < 2; im++) {
                LDSM4(ah[im][0], ah[im][1], ah[im][2], ah[im][3],
                      st + aAddr + im * 1280 + ko);
                if (PASSES == 3)
                    LDSM4(al[im][0], al[im][1], al[im][2], al[im][3],
                          st + ALOFF + aAddr + im * 1280 + ko);
            }
#pragma unroll
            for (int jp = 0; jp < 4; jp++) {
                LDSM4(bh[2*jp][0], bh[2*jp][1], bh[2*jp+1][0], bh[2*jp+1][1],
                      st + bAddr + jp * 1280 + ko);
                if (PASSES >= 2)
                    LDSM4(bl[2*jp][0], bl[2*jp][1], bl[2*jp+1][0], bl[2*jp+1][1],
                          st + blAddr + jp * 1280 + ko);
            }
#pragma unroll
            for (int im = 0; im < 2; im++)
#pragma unroll
                for (int jn = 0; jn < 8; jn++) MMA16816(acc[im][jn], ah[im], bh[jn]);
            if (PASSES >= 2) {
#pragma unroll
                for (int im = 0; im < 2; im++)
#pragma unroll
                    for (int jn = 0; jn < 8; jn++) MMA16816(acc[im][jn], ah[im], bl[jn]);
            }
            if (PASSES == 3) {
#pragma unroll
                for (int im = 0; im < 2; im++)
#pragma unroll
                    for (int jn = 0; jn < 8; jn++) MMA16816(acc[im][jn], al[im], bh[jn]);
            }
        }
        __syncthreads();
    }

    // epilogue
    const int gr = lane >> 2, q = lane & 3;
#pragma unroll
    for (int im = 0; im < 2; im++) {
#pragma unroll
        for (int jn = 0; jn < 8; jn++) {
            const long r0  = m0 + wm * 32 + im * 16 + gr;
            const long col = n0 + wn * 64 + jn * 8 + q * 2;
            if (SPLIT) {   // raw partials, compact layout
                const long i0 = r0 * N + col, i1 = i0 + 8L * N;
                *(float2*)(Cp + i0) = make_float2(acc[im][jn][0], acc[im][jn][1]);
                *(float2*)(Cp + i1) = make_float2(acc[im][jn][2], acc[im][jn][3]);
                continue;
            }
            float v0 = acc[im][jn][0] * ds, v1 = acc[im][jn][1] * ds;
            float v2 = acc[im][jn][2] * ds, v3 = acc[im][jn][3] * ds;
            if (EPI == 4) {
                // interleaved up/gate: (even,odd) = (up, gate)
                const long oc = col >> 1;
                Chp[r0 * ldc + oc]       = __float2half(siluf(v1) * v0);
                Chp[(r0 + 8) * ldc + oc] = __float2half(siluf(v3) * v2);
                continue;
            }
            const long i0 = r0 * ldc + col, i1 = i0 + 8L * ldc;
            if (EPI == 3) {
                v0 = siluf(fminf(fmaxf(v0, -5.f), 5.f));
                v1 = siluf(fminf(fmaxf(v1, -5.f), 5.f));
                v2 = siluf(fminf(fmaxf(v2, -5.f), 5.f));
                v3 = siluf(fminf(fmaxf(v3, -5.f), 5.f));
            }
            if (WFP32) {
                *(float2*)(Cp + i0) = make_float2(v0, v1);
                *(float2*)(Cp + i1) = make_float2(v2, v3);
            }
            if (WH) {
                __half2 hh;
                hh.x = __float2half(v0 * hs); hh.y = __float2half(v1 * hs);
                *(__half2*)(Chp + i0) = hh;
                hh.x = __float2half(v2 * hs); hh.y = __float2half(v3 * hs);
                *(__half2*)(Chp + i1) = hh;
            }
        }
    }
}

// ---------------------------------------------------------------------------
// Split-K reduce: per-batch sum of SK partials (fixed order), fp16 out with
// row remap.  Partials: part[(z*SK + s)*MN + r].  e0 global over batches.
// dst = (e0/rowLen)*outW + outOff + e0%rowLen.
// ---------------------------------------------------------------------------
__global__ void redsum_k(const float* __restrict__ part,
                         __half* __restrict__ Yh,
                         int SK, long MN, long n4, float dsH,
                         int rowLen, int outW, int outOff)
{
    long i = blockIdx.x * (long)blockDim.x + threadIdx.x;
    if (i >= n4) return;
    long e0 = i * 4;
    long zz = e0 / MN, r = e0 - zz * MN;
    const float* p = part + (zz * SK) * MN + r;
    float4 s = *(const float4*)p;
    for (int k = 1; k < SK; k++) {
        float4 v = *(const float4*)(p + (long)k * MN);
        s.x += v.x; s.y += v.y; s.z += v.z; s.w += v.w;
    }
    long row = e0 / rowLen, col = e0 - row * rowLen;
    long d = row * outW + outOff + col;
    __half2 h0, h1;
    h0.x = __float2half(s.x * dsH); h0.y = __float2half(s.y * dsH);
    h1.x = __float2half(s.z * dsH); h1.y = __float2half(s.w * dsH);
    *(__half2*)(Yh + d)     = h0;
    *(__half2*)(Yh + d + 2) = h1;
}

// ---------------------------------------------------------------------------
// Fused split-K reduce + LayerNorm (rows of 128, one warp/row, single batch).
// sum*dsc = true values.  LN fp16 -> Yh; optional raw sum fp16 -> Ph.
// ---------------------------------------------------------------------------
__global__ void redln_k(const float* __restrict__ part, int SK, long MN,
                        const float* __restrict__ g, const float* __restrict__ b,
                        __half* __restrict__ Yh, __half* __restrict__ Ph,
                        float dsc, int rows)
{
    int row  = (blockIdx.x * blockDim.x + threadIdx.x) >> 5;
    int lane = threadIdx.x & 31;
    if (row >= rows) return;
    const long base = (long)row * 128 + lane * 4;
    float4 x = *(const float4*)(part + base);
    for (int k = 1; k < SK; k++) {
        float4 v = *(const float4*)(part + (long)k * MN + base);
        x.x += v.x; x.y += v.y; x.z += v.z; x.w += v.w;
    }
    if (Ph) {
        __half2 h0, h1;
        h0.x = __float2half(x.x); h0.y = __float2half(x.y);
        h1.x = __float2half(x.z); h1.y = __float2half(x.w);
        *(__half2*)(Ph + base)     = h0;
        *(__half2*)(Ph + base + 2) = h1;
    }
    x.x *= dsc; x.y *= dsc; x.z *= dsc; x.w *= dsc;
    float s  = x.x + x.y + x.z + x.w;
    float ss = fmaf(x.x, x.x, fmaf(x.y, x.y, fmaf(x.z, x.z, x.w * x.w)));
#pragma unroll
    for (int o = 16; o > 0; o >>= 1) {
        s  += __shfl_xor_sync(0xffffffffu, s,  o);
        ss += __shfl_xor_sync(0xffffffffu, ss, o);
    }
    float m   = s * (1.f / 128.f);
    float inv = rsqrtf(ss * (1.f / 128.f) - m * m + 1e-5f);
    float4 gg = *(const float4*)(g + lane * 4);
    float4 bb = *(const float4*)(b + lane * 4);
    __half2 h0, h1;
    h0.x = __float2half(fmaf((x.x - m) * inv, gg.x, bb.x));
    h0.y = __float2half(fmaf((x.y - m) * inv, gg.y, bb.y));
    h1.x = __float2half(fmaf((x.z - m) * inv, gg.z, bb.z));
    h1.y = __float2half(fmaf((x.w - m) * inv, gg.w, bb.w));
    *(__half2*)(Yh + base)     = h0;
    *(__half2*)(Yh + base + 2) = h1;
}

// ---------------------------------------------------------------------------
// fp32 -> fp16 hi/lo split (x only)
// ---------------------------------------------------------------------------
__global__ void split_k(const float* __restrict__ X,
                        __half* __restrict__ Hh, __half* __restrict__ Hl,
                        long n4)
{
    long i = blockIdx.x * (long)blockDim.x + threadIdx.x;
    if (i >= n4) return;
    float4 v = ((const float4*)X)[i];
    __half2 h0, h1, l0, l1;
    h0.x = __float2half(v.x); l0.x = __float2half(v.x - __half2float(h0.x));
    h0.y = __float2half(v.y); l0.y = __float2half(v.y - __half2float(h0.y));
    h1.x = __float2half(v.z); l1.x = __float2half(v.z - __half2float(h1.x));
    h1.y = __float2half(v.w); l1.y = __float2half(v.w - __half2float(h1.y));
    ((__half2*)Hh)[2*i]   = h0; ((__half2*)Hh)[2*i+1] = h1;
    ((__half2*)Hl)[2*i]   = l0; ((__half2*)Hl)[2*i+1] = l1;
}

// ---------------------------------------------------------------------------
// Fused multi-array fp32 -> fp16 split (hi always; lo if dl != null).
// Row remap per job: dst = (e/rowLen)*dstW + dstOff + e%rowLen (dstW=0: identity)
// ---------------------------------------------------------------------------
struct SJobs {
    const float* src[8];
    __half* dh[8];
    __half* dl[8];
    int   nblk[8];
    long  n4[8];
    float sc[8];
    int   rowLen[8];
    int   dstW[8];
    int   dstOff[8];
};

__global__ void msplit_k(SJobs J)
{
    int b = blockIdx.x, j = 0;
    while (j < 7 && b >= J.nblk[j]) { b -= J.nblk[j]; j++; }
    long i = (long)b * 256 + threadIdx.x;
    if (i >= J.n4[j]) return;
    float sc = J.sc[j];
    float4 v = ((const float4*)J.src[j])[i];
    v.x *= sc; v.y *= sc; v.z *= sc; v.w *= sc;
    long e0 = i * 4, d = e0;
    if (J.dstW[j]) {
        long row = e0 / J.rowLen[j], col = e0 - row * J.rowLen[j];
        d = row * J.dstW[j] + J.dstOff[j] + col;
    }
    __half2 h0, h1;
    h0.x = __float2half(v.x); h0.y = __float2half(v.y);
    h1.x = __float2half(v.z); h1.y = __float2half(v.w);
    *(__half2*)(J.dh[j] + d)     = h0;
    *(__half2*)(J.dh[j] + d + 2) = h1;
    if (J.dl[j]) {
        __half2 l0, l1;
        l0.x = __float2half(v.x - __half2float(h0.x));
        l0.y = __float2half(v.y - __half2float(h0.y));
        l1.x = __float2half(v.z - __half2float(h1.x));
        l1.y = __float2half(v.w - __half2float(h1.y));
        *(__half2*)(J.dl[j] + d)     = l0;
        *(__half2*)(J.dl[j] + d + 2) = l1;
    }
}

// ---------------------------------------------------------------------------
// Transpose [R,C]->[C,R], input fp32 or fp16, out fp16(scale). grid(R/32,C/32,nz)
// ---------------------------------------------------------------------------
template<typename TI>
__global__ void tsplitg_k(const TI* __restrict__ X, __half* __restrict__ T,
                          int R, int C, float scale)
{
    __shared__ float t[32][33];
    const long zb = blockIdx.z;
    X += zb * (long)R * C;  T += zb * (long)R * C;
    const int r0 = blockIdx.x * 32, c0 = blockIdx.y * 32;
    const int tx = threadIdx.x, ty = threadIdx.y;
#pragma unroll
    for (int i = 0; i < 4; i++) {
        int rr = ty * 4 + i;
        t[rr][tx] = (float)X[(long)(r0 + rr) * C + c0 + tx];
    }
    __syncthreads();
#pragma unroll
    for (int i = 0; i < 4; i++) {
        int cc = ty * 4 + i;
        T[(long)(c0 + cc) * R + r0 + tx] = __float2half(t[tx][cc] * scale);
    }
}

// ---------------------------------------------------------------------------
// Expert select + LN from fp16 ec (scaled 8192): idx = LAST expert with ew>0;
// writes LN*outDiv into out[row*outW + outOff + col] (0 if no expert).
// ---------------------------------------------------------------------------
__global__ void lnsel_k(const __half* __restrict__ ec, const float* __restrict__ ew,
                        const float* __restrict__ eg, const float* __restrict__ eb,
                        __half* __restrict__ chO, int rows, long outW, long outOff,
                        float outDiv)
{
    int row  = (blockIdx.x * blockDim.x + threadIdx.x) >> 5;
    int lane = threadIdx.x & 31;
    if (row >= rows) return;
    float w = (lane < E_) ? ew[(long)row * E_ + lane] : 0.f;
    unsigned m = __ballot_sync(0xffffffffu, w > 0.f) & 0xFFu;
    const long base = (long)row * outW + outOff + lane * 4;
    if (m == 0) {
        __half2 zz; zz.x = __float2half(0.f); zz.y = zz.x;
        *(__half2*)(chO + base) = zz; *(__half2*)(chO + base + 2) = zz;
        return;
    }
    int idx = 31 - __clz(m);
    const long eb0 = ((long)idx * NTOK + row) * 128 + lane * 4;
    __half2 e0 = *(const __half2*)(ec + eb0);
    __half2 e1 = *(const __half2*)(ec + eb0 + 2);
    const float DSC = 1.f / 8192.f;
    float4 x;
    x.x = __half2float(e0.x) * DSC; x.y = __half2float(e0.y) * DSC;
    x.z = __half2float(e1.x) * DSC; x.w = __half2float(e1.y) * DSC;
    float s  = x.x + x.y + x.z + x.w;
    float ss = fmaf(x.x, x.x, fmaf(x.y, x.y, fmaf(x.z, x.z, x.w * x.w)));
#pragma unroll
    for (int o = 16; o > 0; o >>= 1) {
        s  += __shfl_xor_sync(0xffffffffu, s,  o);
        ss += __shfl_xor_sync(0xffffffffu, ss, o);
    }
    float mn  = s * (1.f / 128.f);
    float inv = rsqrtf(ss * (1.f / 128.f) - mn * mn + 1e-5f);
    float4 gg = *(const float4*)(eg + (long)idx * 128 + lane * 4);
    float4 bb = *(const float4*)(eb + (long)idx * 128 + lane * 4);
    __half2 h0, h1;
    h0.x = __float2half(fmaf((x.x - mn) * inv, gg.x, bb.x) * outDiv);
    h0.y = __float2half(fmaf((x.y - mn) * inv, gg.y, bb.y) * outDiv);
    h1.x = __float2half(fmaf((x.z - mn) * inv, gg.z, bb.z) * outDiv);
    h1.y = __float2half(fmaf((x.w - mn) * inv, gg.w, bb.w) * outDiv);
    *(__half2*)(chO + base)     = h0;
    *(__half2*)(chO + base + 2) = h1;
}

// ---------------------------------------------------------------------------
extern "C" void kernel_launch(void* const* d_in, const int* in_sizes, int n_in,
                              void* d_out, int out_size)
{
    const float* x       = (const float*)d_in[0];
    const float* ew      = (const float*)d_in[1];
    const float* w_up    = (const float*)d_in[2];
    const float* w_gate  = (const float*)d_in[3];
    const float* w_down  = (const float*)d_in[4];
    const float* w_pre   = (const float*)d_in[5];
    const float* w_post  = (const float*)d_in[6];
    const float* an_g    = (const float*)d_in[7];
    const float* an_b    = (const float*)d_in[8];
    const float* w_aproj = (const float*)d_in[9];
    const float* w_exp   = (const float*)d_in[10];
    const float* eln_g   = (const float*)d_in[11];
    const float* eln_b   = (const float*)d_in[12];
    const float* w_eproj = (const float*)d_in[13];
    const float* w_out   = (const float*)d_in[14];
    float* out = (float*)d_out;

    float* part;
    cudaGetSymbolAddress((void**)&part, g_part);

    __half *xh,*xl,*Hdc,*wdc,*wug,*preh,*ainh,*aouth,*ech,*scrh,*aTh;
    __half *weT,*wapT,*wouth,*wexph,*wpreh,*wprel,*wpoh;
    cudaGetSymbolAddress((void**)&xh,    g_xh);   cudaGetSymbolAddress((void**)&xl,    g_xl);
    cudaGetSymbolAddress((void**)&Hdc,   g_Hdc);  cudaGetSymbolAddress((void**)&wdc,   g_wdc);
    cudaGetSymbolAddress((void**)&wug,   g_wug);  cudaGetSymbolAddress((void**)&preh,  g_preh);
    cudaGetSymbolAddress((void**)&ainh,  g_ainh); cudaGetSymbolAddress((void**)&aouth, g_aouth);
    cudaGetSymbolAddress((void**)&ech,   g_ech);
    cudaGetSymbolAddress((void**)&scrh,  g_scrh); cudaGetSymbolAddress((void**)&aTh,   g_aTh);
    cudaGetSymbolAddress((void**)&weT,   g_weT);  cudaGetSymbolAddress((void**)&wapT,  g_wapT);
    cudaGetSymbolAddress((void**)&wouth, g_wouth);cudaGetSymbolAddress((void**)&wexph, g_wexph);
    cudaGetSymbolAddress((void**)&wpreh, g_wpreh);cudaGetSymbolAddress((void**)&wprel, g_wprel);
    cudaGetSymbolAddress((void**)&wpoh,  g_wpoh);

    cudaFuncSetAttribute(tgemm_k<4,1,false,true ,false>, cudaFuncAttributeMaxDynamicSharedMemorySize, TG_SMEM);
    cudaFuncSetAttribute(tgemm_k<0,2,true ,false,true >, cudaFuncAttributeMaxDynamicSharedMemorySize, TG_SMEM);
    cudaFuncSetAttribute(tgemm_k<0,1,true ,false,true >, cudaFuncAttributeMaxDynamicSharedMemorySize, TG_SMEM);
    cudaFuncSetAttribute(tgemm_k<3,1,false,true ,false>, cudaFuncAttributeMaxDynamicSharedMemorySize, TG_SMEM);
    cudaFuncSetAttribute(tgemm_k<0,1,false,true ,false>, cudaFuncAttributeMaxDynamicSharedMemorySize, TG_SMEM);
    cudaFuncSetAttribute(tgemm_k<0,1,true ,false,false>, cudaFuncAttributeMaxDynamicSharedMemorySize, TG_SMEM);

    // 1) split x (h/l)
    {
        long n4 = (long)NTOK * D_ / 4;
        split_k<<<(unsigned)((n4 + 255) / 256), 256>>>(x, xh, xl, n4);
    }

    // 2) fused weight splits
    {
        SJobs J;
        auto set = [&](int j, const float* s, __half* dh, __half* dl, long n,
                       float sc, int rowLen, int dstW, int dstOff) {
            J.src[j] = s; J.dh[j] = dh; J.dl[j] = dl;
            J.n4[j] = n / 4; J.nblk[j] = (int)((J.n4[j] + 255) / 256); J.sc[j] = sc;
            J.rowLen[j] = rowLen; J.dstW[j] = dstW; J.dstOff[j] = dstOff;
        };
        set(0, w_up,    wug,   nullptr, (long)H_ * D_,      1.f,   D_, 2*D_, 0);
        set(1, w_gate,  wug,   nullptr, (long)H_ * D_,      1.f,   D_, 2*D_, D_);
        set(2, w_down,  wdc,   nullptr, (long)D_ * H_,      1.f,   H_, KC,   0);
        set(3, w_pre,   wpreh, wprel,   (long)A_ * D_,      512.f, 0, 0, 0);
        set(4, w_post,  wpoh,  nullptr, (long)A_ * H_,      512.f, 0, 0, 0);
        set(5, w_exp,   wexph, nullptr, (long)E_ * A_ * A_, 512.f, 0, 0, 0);
        set(6, w_out,   wouth, nullptr, (long)D_ * H_,      32.f,  0, 0, 0);
        set(7, w_out,   wouth, nullptr, 0,                  1.f,   0, 0, 0);  // dummy
        J.nblk[7] = 0;
        int total = 0;
        for (int j = 0; j < 7; j++) total += J.nblk[j];
        msplit_k<<<total, 256>>>(J);
    }

    // 3) weT = transpose(w_eproj)*512 ; wapT = transpose(w_aproj)*512
    tsplitg_k<float><<<dim3(H_/32, A_/32, 1), dim3(32, 8)>>>(w_eproj, weT, H_, A_, 512.f);
    tsplitg_k<float><<<dim3(H_/32, A_/32, 1), dim3(32, 8)>>>(w_aproj, wapT, H_, A_, 512.f);

    // 4) Mh partials (split-K 8) -> redsum -> wdc[:,2176:2304] = 12.8*M
    //    raw sum = 16384*M -> dsH = 12.8/16384
    tgemm_k<0,1,true,false,true><<<dim3(8, D_/128, 1), 256, TG_SMEM>>>(
        wouth, nullptr, weT, nullptr, part, nullptr,
        D_, A_, H_, H_, H_, 0, 0, 0, 0, 1.f, 1.f);
    redsum_k<<<(unsigned)(((long)D_ * A_ / 4 + 255) / 256), 256>>>(
        part, wdc, 8, (long)D_ * A_, (long)D_ * A_ / 4, 12.8f / 16384.f, A_, KC, H_ + A_);

    // 5) W2 partials (A = wdc[:, :2048] fp16 w_down, split-K 8)
    //    -> redsum -> wdc[:,2048:2176] = 12.8*W2   (raw sum = 512*W2)
    tgemm_k<0,1,true,false,true><<<dim3(8, D_/128, 1), 256, TG_SMEM>>>(
        wdc, nullptr, wapT, nullptr, part, nullptr,
        D_, A_, H_, KC, H_, 0, 0, 0, 0, 1.f, 1.f);
    redsum_k<<<(unsigned)(((long)D_ * A_ / 4 + 255) / 256), 256>>>(
        part, wdc, 8, (long)D_ * A_, (long)D_ * A_ / 4, 12.8f / 512.f, A_, KC, H_);

    // 6) Hdc[:,:2048] = fp16(silu(gate)*up) — ONE interleaved GEMM (EPI=4)
    tgemm_k<4,1,false,true,false><<<dim3(2*H_/128, NTOK/128, 1), 256, TG_SMEM>>>(
        xh, nullptr, wug, nullptr, nullptr, Hdc,
        NTOK, 2*H_, D_, D_, D_, KC, 0, 0, 0, 1.f, 1.f);

    // 7) pre partials (2-pass: xh*(wpre h+l), split-K 2) -> redln:
    //    ainh + preh(raw=512*pre)
    tgemm_k<0,2,true,false,true><<<dim3(2, NTOK/128, 1), 256, TG_SMEM>>>(
        xh, nullptr, wpreh, wprel, part, nullptr,
        NTOK, A_, D_, D_, D_, 0, 0, 0, 0, 1.f, 1.f);
    redln_k<<<NTOK/8, 256>>>(part, 2, (long)NTOK * A_, an_g, an_b,
                             ainh, preh, 1.f / 512.f, NTOK);

    // 8) pt partials (split-K 2, A = Hdc cols 0:2048) -> redln: aouth
    tgemm_k<0,1,true,false,true><<<dim3(2, NTOK/128, 1), 256, TG_SMEM>>>(
        Hdc, nullptr, wpoh, nullptr, part, nullptr,
        NTOK, A_, H_, KC, H_, 0, 0, 0, 0, 1.f, 1.f);
    redln_k<<<NTOK/8, 256>>>(part, 2, (long)NTOK * A_, an_g, an_b,
                             aouth, nullptr, 1.f / 512.f, NTOK);

    // 9) scrh[b] = silu(clip(ain[b] @ aout[b]^T))
    tgemm_k<3,1,false,true,false><<<dim3(S_/128, S_/128, B_), 256, TG_SMEM>>>(
        ainh, nullptr, aouth, nullptr, nullptr, scrh,
        S_, S_, A_, A_, A_, S_, (long)S_ * A_, (long)S_ * A_, (long)S_ * S_, 1.f, 1.f);

    // 10) aTh = transpose(ainh)  (per batch)
    tsplitg_k<__half><<<dim3(S_/32, A_/32, B_), dim3(32, 8)>>>(ainh, aTh, S_, A_, 1.f);

    // 11) adp partials (split-K 2, batched z=8) -> redsum -> Hdc[:,2048:2176]=adp/128
    tgemm_k<0,1,true,false,true><<<dim3(2, S_/128, B_), 256, TG_SMEM>>>(
        scrh, nullptr, aTh, nullptr, part, nullptr,
        S_, A_, S_, S_, S_, 0, (long)S_ * S_, (long)A_ * S_, 0, 1.f, 1.f);
    redsum_k<<<(unsigned)(((long)NTOK * A_ / 4 + 255) / 256), 256>>>(
        part, Hdc, 2, (long)S_ * A_, (long)NTOK * A_ / 4, 1.f / 128.f, A_, KC, H_);

    // e1) ech_i = fp16(8192 * pre @ w_exp[i]^T)  (batched over 8 experts)
    tgemm_k<0,1,false,true,false><<<dim3(1, NTOK/128, E_), 256, TG_SMEM>>>(
        preh, nullptr, wexph, nullptr, nullptr, ech,
        NTOK, A_, A_, A_, A_, A_, 0, (long)A_ * A_, (long)NTOK * A_, 1.f / 32.f, 1.f);

    // e2) Hdc[:,2176:2304] = LN(ech[last-positive]/8192, eln) / 128  (0 if none)
    lnsel_k<<<NTOK/8, 256>>>(ech, ew, eln_g, eln_b, Hdc, NTOK, KC, H_ + A_, 1.f / 128.f);

    // 12) out = Hdc @ wdc^T over K=2304
    //        = Hid@w_down^T + 0.1*adp@W2^T + 0.1*ch@M^T
    tgemm_k<0,1,true,false,false><<<dim3(D_/128, NTOK/128, 1), 256, TG_SMEM>>>(
        Hdc, nullptr, wdc, nullptr, out, nullptr,
        NTOK, D_, KC, KC, KC, D_, 0, 0, 0, 1.f, 1.f);
}

// round 16
// speedup vs baseline: 6.8466x; 1.0025x over previous
#include <cuda_runtime.h>
#include <cuda_fp16.h>
#include <cstdint>

// ---------------------------------------------------------------------------
// LLaDAModel fused forward — mma.sync fp16-split GEMMs, split-K, fused
// reduce+LN, interleaved up/gate GEMM, and triple K-concat final GEMM
// (aproj + expert paths folded into the w_down GEMM).
// B=8,S=2048,D=1024,H=2048,A=128,E=8. N=16384.
//
//   s.   split x (h/l, grid-stride);  fused weight splits:
//          wug  [2H,D]: rows 2r=w_up_r, 2r+1=w_gate_r
//          wdc[:,0:2048]=w_down ; wpre h/l*512 ; wpo*512 ; wexp*512 ; wout*32
//   0a.  {weT, wapT} = transpose({w_eproj, w_aproj})*512  (one z-batched launch)
//   0b.  Mh  partials -> redsum -> wdc[:,2176:2304] = 12.8*M
//   0c.  W2  partials (A=wdc[:, :2048]) -> redsum -> wdc[:,2048:2176]=12.8*W2
//   1.   Hdc[:,:2048] = fp16(silu(gate)*up)  — ONE GEMM vs wug (EPI=4)
//   3.   pre partials (2-pass, split-K 2) -> redln -> ainh + preh(raw*512)
//   5.   pt  partials (split-K 2, A=Hdc)  -> redln -> aouth
//   7.   scrh = silu(clip(ain @ aout^T)) per b
//   7b.  aTh  = transpose(ainh) per b
//   8.   adp partials (split-K 2, batched) -> redsum -> Hdc[:,2048:2176]=adp/128
//  e1.   ech_i = fp16(8192 * pre @ w_exp[i]^T)  (batched)
//  e2.   lnsel -> Hdc[:,2176:2304] = LN(ech[last-pos])/128
//  10.   out = Hdc @ wdc^T over K=2304
//           = Hid@w_down^T + 0.1*adp@W2^T + 0.1*ch@M^T
// ---------------------------------------------------------------------------

constexpr int B_ = 8, S_ = 2048, D_ = 1024, H_ = 2048, A_ = 128, E_ = 8;
constexpr int NTOK = B_ * S_;        // 16384
constexpr int KC = H_ + 2 * A_;      // 2304 concat-K

// fp32 scratch
__device__ float g_part[(size_t)NTOK * A_ * 4];   // split-K partials

// fp16 scratch
__device__ __half g_xh [(size_t)NTOK * D_], g_xl [(size_t)NTOK * D_];
__device__ __half g_Hdc[(size_t)NTOK * KC];       // [N,2304]: Hid | adp/128 | ch/128
__device__ __half g_wdc[(size_t)D_ * KC];         // [D,2304]: w_down | 12.8*W2 | 12.8*M
__device__ __half g_wug[(size_t)2 * H_ * D_];     // interleaved up/gate
__device__ __half g_preh[(size_t)NTOK * A_];
__device__ __half g_ainh[(size_t)NTOK * A_];
__device__ __half g_aouth[(size_t)NTOK * A_];
__device__ __half g_ech [(size_t)E_ * NTOK * A_];
__device__ __half g_scrh[(size_t)B_ * S_ * S_];
__device__ __half g_aTh[(size_t)B_ * A_ * S_];
__device__ __half g_weT[(size_t)A_ * H_];
__device__ __half g_wapT[(size_t)A_ * H_];
__device__ __half g_wouth[(size_t)D_ * H_];
__device__ __half g_wexph[(size_t)E_ * A_ * A_];
__device__ __half g_wpreh[(size_t)A_ * D_], g_wprel[(size_t)A_ * D_];
__device__ __half g_wpoh[(size_t)A_ * H_];

__device__ __forceinline__ float siluf(float x) {
    return x * (1.0f / (1.0f + __expf(-x)));
}

#define LDSM4(r0,r1,r2,r3,addr) \
    asm volatile("ldmatrix.sync.aligned.m8n8.x4.shared.b16 {%0,%1,%2,%3},[%4];\n" \
        : "=r"(r0),"=r"(r1),"=r"(r2),"=r"(r3) : "r"(addr))

#define MMA16816(c,a,b) \
    asm volatile("mma.sync.aligned.m16n8k16.row.col.f32.f16.f16.f32 " \
        "{%0,%1,%2,%3},{%4,%5,%6,%7},{%8,%9},{%0,%1,%2,%3};\n" \
        : "+f"((c)[0]),"+f"((c)[1]),"+f"((c)[2]),"+f"((c)[3]) \
        : "r"((a)[0]),"r"((a)[1]),"r"((a)[2]),"r"((a)[3]),"r"((b)[0]),"r"((b)[1]))

#define CPA16(dst,src) \
    asm volatile("cp.async.cg.shared.global [%0],[%1],16;\n" :: "r"(dst),"l"(src))

constexpr int TG_SMEM = 81920;

// ---------------------------------------------------------------------------
// Tensor GEMM: C[M,N](f32) = split(A)[M,K] @ split(B)[N,K]^T
// PASSES=1: acc = Ah*Bh   PASSES=2: + Ah*Bl   PASSES=3: + Ah*Bl + Al*Bh
// CTA tile 128x128x32, 8 warps (4x2), warp tile 32x64, m16n8k16 fp16 mma.
// lda/ldb/ldc: row strides.  SPLIT: grid.x = K-split (N must be 128), raw
// fp32 partials to C + (z*gridDim.x+blockIdx.x)*M*N.
// EPI: 0 C=acc   3 C=silu(clip(acc,±5))
//      4 (pair): Ch[r, col/2] = fp16(silu(odd)*even)  — interleaved up/gate
// ---------------------------------------------------------------------------
template<int EPI, int PASSES, bool WFP32, bool WH, bool SPLIT>
__global__ void __launch_bounds__(256, 2) tgemm_k(
    const __half* __restrict__ Ah, const __half* __restrict__ Al,
    const __half* __restrict__ Bh, const __half* __restrict__ Bl,
    float* __restrict__ C, __half* __restrict__ Ch,
    int M, int N, int K, long lda, long ldb, long ldc,
    long sA, long sB, long sC, float ds, float hs)
{
    constexpr int NST  = (PASSES == 1) ? 4 : 2;
    constexpr int SSZ  = (PASSES == 1) ? 20480 : (PASSES == 2 ? 30720 : 40960);
    constexpr unsigned ALOFF = 10240u;                         // P3 A-lo
    constexpr unsigned BOFF  = (PASSES == 3) ? 20480u : 10240u;
    constexpr unsigned BLOFF = BOFF + 10240u;                  // P2/P3 B-lo

    extern __shared__ char smem[];
    const unsigned sbase = (unsigned)__cvta_generic_to_shared(smem);
    const int tid = threadIdx.x, lane = tid & 31, warp = tid >> 5;
    const int wm = warp >> 1, wn = warp & 1;

    const long z = blockIdx.z;
    Ah += z * sA; Bh += z * sB;
    if (PASSES >= 2) Bl += z * sB;
    if (PASSES == 3) Al += z * sA;
    float* Cp;
    __half* Chp = nullptr;
    if (SPLIT) {
        Cp = C + ((z * gridDim.x + blockIdx.x) * (long)M) * N;
    } else {
        Cp = WFP32 ? C + z * sC : nullptr;
        Chp = WH ? Ch + z * sC : nullptr;
    }

    const int m0 = blockIdx.y * 128;
    const int n0 = SPLIT ? 0 : blockIdx.x * 128;

    const int KT = K / 32;
    int t0k = 0, TCNT = KT;
    if (SPLIT) { TCNT = KT / gridDim.x; t0k = blockIdx.x * TCNT; }

    float acc[2][8][4];
#pragma unroll
    for (int i = 0; i < 2; i++)
#pragma unroll
        for (int j = 0; j < 8; j++)
#pragma unroll
            for (int e = 0; e < 4; e++) acc[i][j][e] = 0.f;

    const unsigned aAddr = (unsigned)((wm * 32 + (lane & 15)) * 80 + (lane >> 4) * 16);
    const unsigned bAddr = (unsigned)(BOFF +
        (wn * 64 + ((lane >> 4) << 3) + (lane & 7)) * 80 + ((lane >> 3) & 1) * 16);
    const unsigned blAddr = (unsigned)(BLOFF +
        (wn * 64 + ((lane >> 4) << 3) + (lane & 7)) * 80 + ((lane >> 3) & 1) * 16);

    auto issue = [&](int t, int s) {
        const long k0 = (long)(t0k + t) * 32;
        const unsigned st = sbase + s * SSZ;
#pragma unroll
        for (int i = tid; i < 512; i += 256) {
            const int r = i >> 2, c = i & 3;
            const unsigned off16 = (unsigned)(r * 80 + c * 16);
            const long  ga = (long)(m0 + r) * lda + k0 + c * 8;
            CPA16(st + off16, Ah + ga);
            if (PASSES == 3) CPA16(st + ALOFF + off16, Al + ga);
            const long  gb = (long)(n0 + r) * ldb + k0 + c * 8;
            CPA16(st + BOFF + off16, Bh + gb);
            if (PASSES >= 2) CPA16(st + BLOFF + off16, Bl + gb);
        }
        asm volatile("cp.async.commit_group;\n");
    };

    const int pre = (NST - 1 < TCNT) ? NST - 1 : TCNT;
    for (int p = 0; p < pre; p++) issue(p, p % NST);

    for (int t = 0; t < TCNT; ++t) {
        if (NST == 2) {
            asm volatile("cp.async.wait_group 0;\n" ::: "memory");
        } else {
            const int rem = TCNT - 1 - t;
            if (rem >= 2)      asm volatile("cp.async.wait_group 2;\n" ::: "memory");
            else if (rem == 1) asm volatile("cp.async.wait_group 1;\n" ::: "memory");
            else               asm volatile("cp.async.wait_group 0;\n" ::: "memory");
        }
        __syncthreads();
        if (t + NST - 1 < TCNT) issue(t + NST - 1, (t + NST - 1) % NST);

        const unsigned st = sbase + (t % NST) * SSZ;
#pragma unroll
        for (int kk = 0; kk < 2; kk++) {
            const unsigned ko = kk * 32;
            unsigned ah[2][4], al[2][4], bh[8][2], bl[8][2];
#pragma unroll
            for (int im = 0; im < 2; im++) {
                LDSM4(ah[im][0], ah[im][1], ah[im][2], ah[im][3],
                      st + aAddr + im * 1280 + ko);
                if (PASSES == 3)
                    LDSM4(al[im][0], al[im][1], al[im][2], al[im][3],
                          st + ALOFF + aAddr + im * 1280 + ko);
            }
#pragma unroll
            for (int jp = 0; jp < 4; jp++) {
                LDSM4(bh[2*jp][0], bh[2*jp][1], bh[2*jp+1][0], bh[2*jp+1][1],
                      st + bAddr + jp * 1280 + ko);
                if (PASSES >= 2)
                    LDSM4(bl[2*jp][0], bl[2*jp][1], bl[2*jp+1][0], bl[2*jp+1][1],
                          st + blAddr + jp * 1280 + ko);
            }
#pragma unroll
            for (int im = 0; im < 2; im++)
#pragma unroll
                for (int jn = 0; jn < 8; jn++) MMA16816(acc[im][jn], ah[im], bh[jn]);
            if (PASSES >= 2) {
#pragma unroll
                for (int im = 0; im < 2; im++)
#pragma unroll
                    for (int jn = 0; jn < 8; jn++) MMA16816(acc[im][jn], ah[im], bl[jn]);
            }
            if (PASSES == 3) {
#pragma unroll
                for (int im = 0; im < 2; im++)
#pragma unroll
                    for (int jn = 0; jn < 8; jn++) MMA16816(acc[im][jn], al[im], bh[jn]);
            }
        }
        __syncthreads();
    }

    // epilogue
    const int gr = lane >> 2, q = lane & 3;
#pragma unroll
    for (int im = 0; im < 2; im++) {
#pragma unroll
        for (int jn = 0; jn < 8; jn++) {
            const long r0  = m0 + wm * 32 + im * 16 + gr;
            const long col = n0 + wn * 64 + jn * 8 + q * 2;
            if (SPLIT) {   // raw partials, compact layout
                const long i0 = r0 * N + col, i1 = i0 + 8L * N;
                *(float2*)(Cp + i0) = make_float2(acc[im][jn][0], acc[im][jn][1]);
                *(float2*)(Cp + i1) = make_float2(acc[im][jn][2], acc[im][jn][3]);
                continue;
            }
            float v0 = acc[im][jn][0] * ds, v1 = acc[im][jn][1] * ds;
            float v2 = acc[im][jn][2] * ds, v3 = acc[im][jn][3] * ds;
            if (EPI == 4) {
                // interleaved up/gate: (even,odd) = (up, gate)
                const long oc = col >> 1;
                Chp[r0 * ldc + oc]       = __float2half(siluf(v1) * v0);
                Chp[(r0 + 8) * ldc + oc] = __float2half(siluf(v3) * v2);
                continue;
            }
            const long i0 = r0 * ldc + col, i1 = i0 + 8L * ldc;
            if (EPI == 3) {
                v0 = siluf(fminf(fmaxf(v0, -5.f), 5.f));
                v1 = siluf(fminf(fmaxf(v1, -5.f), 5.f));
                v2 = siluf(fminf(fmaxf(v2, -5.f), 5.f));
                v3 = siluf(fminf(fmaxf(v3, -5.f), 5.f));
            }
            if (WFP32) {
                *(float2*)(Cp + i0) = make_float2(v0, v1);
                *(float2*)(Cp + i1) = make_float2(v2, v3);
            }
            if (WH) {
                __half2 hh;
                hh.x = __float2half(v0 * hs); hh.y = __float2half(v1 * hs);
                *(__half2*)(Chp + i0) = hh;
                hh.x = __float2half(v2 * hs); hh.y = __float2half(v3 * hs);
                *(__half2*)(Chp + i1) = hh;
            }
        }
    }
}

// ---------------------------------------------------------------------------
// Split-K reduce: per-batch sum of SK partials (fixed order), fp16 out with
// row remap.  Partials: part[(z*SK + s)*MN + r].  e0 global over batches.
// dst = (e0/rowLen)*outW + outOff + e0%rowLen.
// ---------------------------------------------------------------------------
__global__ void redsum_k(const float* __restrict__ part,
                         __half* __restrict__ Yh,
                         int SK, long MN, long n4, float dsH,
                         int rowLen, int outW, int outOff)
{
    long i = blockIdx.x * (long)blockDim.x + threadIdx.x;
    if (i >= n4) return;
    long e0 = i * 4;
    long zz = e0 / MN, r = e0 - zz * MN;
    const float* p = part + (zz * SK) * MN + r;
    float4 s = *(const float4*)p;
    for (int k = 1; k < SK; k++) {
        float4 v = *(const float4*)(p + (long)k * MN);
        s.x += v.x; s.y += v.y; s.z += v.z; s.w += v.w;
    }
    long row = e0 / rowLen, col = e0 - row * rowLen;
    long d = row * outW + outOff + col;
    __half2 h0, h1;
    h0.x = __float2half(s.x * dsH); h0.y = __float2half(s.y * dsH);
    h1.x = __float2half(s.z * dsH); h1.y = __float2half(s.w * dsH);
    *(__half2*)(Yh + d)     = h0;
    *(__half2*)(Yh + d + 2) = h1;
}

// ---------------------------------------------------------------------------
// Fused split-K reduce + LayerNorm (rows of 128, one warp/row, single batch).
// sum*dsc = true values.  LN fp16 -> Yh; optional raw sum fp16 -> Ph.
// ---------------------------------------------------------------------------
__global__ void redln_k(const float* __restrict__ part, int SK, long MN,
                        const float* __restrict__ g, const float* __restrict__ b,
                        __half* __restrict__ Yh, __half* __restrict__ Ph,
                        float dsc, int rows)
{
    int row  = (blockIdx.x * blockDim.x + threadIdx.x) >> 5;
    int lane = threadIdx.x & 31;
    if (row >= rows) return;
    const long base = (long)row * 128 + lane * 4;
    float4 x = *(const float4*)(part + base);
    for (int k = 1; k < SK; k++) {
        float4 v = *(const float4*)(part + (long)k * MN + base);
        x.x += v.x; x.y += v.y; x.z += v.z; x.w += v.w;
    }
    if (Ph) {
        __half2 h0, h1;
        h0.x = __float2half(x.x); h0.y = __float2half(x.y);
        h1.x = __float2half(x.z); h1.y = __float2half(x.w);
        *(__half2*)(Ph + base)     = h0;
        *(__half2*)(Ph + base + 2) = h1;
    }
    x.x *= dsc; x.y *= dsc; x.z *= dsc; x.w *= dsc;
    float s  = x.x + x.y + x.z + x.w;
    float ss = fmaf(x.x, x.x, fmaf(x.y, x.y, fmaf(x.z, x.z, x.w * x.w)));
#pragma unroll
    for (int o = 16; o > 0; o >>= 1) {
        s  += __shfl_xor_sync(0xffffffffu, s,  o);
        ss += __shfl_xor_sync(0xffffffffu, ss, o);
    }
    float m   = s * (1.f / 128.f);
    float inv = rsqrtf(ss * (1.f / 128.f) - m * m + 1e-5f);
    float4 gg = *(const float4*)(g + lane * 4);
    float4 bb = *(const float4*)(b + lane * 4);
    __half2 h0, h1;
    h0.x = __float2half(fmaf((x.x - m) * inv, gg.x, bb.x));
    h0.y = __float2half(fmaf((x.y - m) * inv, gg.y, bb.y));
    h1.x = __float2half(fmaf((x.z - m) * inv, gg.z, bb.z));
    h1.y = __float2half(fmaf((x.w - m) * inv, gg.w, bb.w));
    *(__half2*)(Yh + base)     = h0;
    *(__half2*)(Yh + base + 2) = h1;
}

// ---------------------------------------------------------------------------
// fp32 -> fp16 hi/lo split (x only), grid-stride for ILP
// ---------------------------------------------------------------------------
__global__ void split_k(const float* __restrict__ X,
                        __half* __restrict__ Hh, __half* __restrict__ Hl,
                        long n4)
{
    const long stride = (long)gridDim.x * blockDim.x;
    for (long i = blockIdx.x * (long)blockDim.x + threadIdx.x; i < n4; i += stride) {
        float4 v = ((const float4*)X)[i];
        __half2 h0, h1, l0, l1;
        h0.x = __float2half(v.x); l0.x = __float2half(v.x - __half2float(h0.x));
        h0.y = __float2half(v.y); l0.y = __float2half(v.y - __half2float(h0.y));
        h1.x = __float2half(v.z); l1.x = __float2half(v.z - __half2float(h1.x));
        h1.y = __float2half(v.w); l1.y = __float2half(v.w - __half2float(h1.y));
        ((__half2*)Hh)[2*i]   = h0; ((__half2*)Hh)[2*i+1] = h1;
        ((__half2*)Hl)[2*i]   = l0; ((__half2*)Hl)[2*i+1] = l1;
    }
}

// ---------------------------------------------------------------------------
// Fused multi-array fp32 -> fp16 split (hi always; lo if dl != null).
// Row remap per job: dst = (e/rowLen)*dstW + dstOff + e%rowLen (dstW=0: identity)
// ---------------------------------------------------------------------------
struct SJobs {
    const float* src[8];
    __half* dh[8];
    __half* dl[8];
    int   nblk[8];
    long  n4[8];
    float sc[8];
    int   rowLen[8];
    int   dstW[8];
    int   dstOff[8];
};

__global__ void msplit_k(SJobs J)
{
    int b = blockIdx.x, j = 0;
    while (j < 7 && b >= J.nblk[j]) { b -= J.nblk[j]; j++; }
    long i = (long)b * 256 + threadIdx.x;
    if (i >= J.n4[j]) return;
    float sc = J.sc[j];
    float4 v = ((const float4*)J.src[j])[i];
    v.x *= sc; v.y *= sc; v.z *= sc; v.w *= sc;
    long e0 = i * 4, d = e0;
    if (J.dstW[j]) {
        long row = e0 / J.rowLen[j], col = e0 - row * J.rowLen[j];
        d = row * J.dstW[j] + J.dstOff[j] + col;
    }
    __half2 h0, h1;
    h0.x = __float2half(v.x); h0.y = __float2half(v.y);
    h1.x = __float2half(v.z); h1.y = __float2half(v.w);
    *(__half2*)(J.dh[j] + d)     = h0;
    *(__half2*)(J.dh[j] + d + 2) = h1;
    if (J.dl[j]) {
        __half2 l0, l1;
        l0.x = __float2half(v.x - __half2float(h0.x));
        l0.y = __float2half(v.y - __half2float(h0.y));
        l1.x = __float2half(v.z - __half2float(h1.x));
        l1.y = __float2half(v.w - __half2float(h1.y));
        *(__half2*)(J.dl[j] + d)     = l0;
        *(__half2*)(J.dl[j] + d + 2) = l1;
    }
}

// ---------------------------------------------------------------------------
// Transpose [R,C]->[C,R], input fp32 or fp16, out fp16(scale). grid(R/32,C/32,nz)
// ---------------------------------------------------------------------------
template<typename TI>
__global__ void tsplitg_k(const TI* __restrict__ X, __half* __restrict__ T,
                          int R, int C, float scale)
{
    __shared__ float t[32][33];
    const long zb = blockIdx.z;
    X += zb * (long)R * C;  T += zb * (long)R * C;
    const int r0 = blockIdx.x * 32, c0 = blockIdx.y * 32;
    const int tx = threadIdx.x, ty = threadIdx.y;
#pragma unroll
    for (int i = 0; i < 4; i++) {
        int rr = ty * 4 + i;
        t[rr][tx] = (float)X[(long)(r0 + rr) * C + c0 + tx];
    }
    __syncthreads();
#pragma unroll
    for (int i = 0; i < 4; i++) {
        int cc = ty * 4 + i;
        T[(long)(c0 + cc) * R + r0 + tx] = __float2half(t[tx][cc] * scale);
    }
}

// Dual-source variant: z selects (src,dst) pair; same R,C,scale for both.
__global__ void tsplit2_k(const float* __restrict__ X0, __half* __restrict__ T0,
                          const float* __restrict__ X1, __half* __restrict__ T1,
                          int R, int C, float scale)
{
    __shared__ float t[32][33];
    const float* X = blockIdx.z ? X1 : X0;
    __half* T = blockIdx.z ? T1 : T0;
    const int r0 = blockIdx.x * 32, c0 = blockIdx.y * 32;
    const int tx = threadIdx.x, ty = threadIdx.y;
#pragma unroll
    for (int i = 0; i < 4; i++) {
        int rr = ty * 4 + i;
        t[rr][tx] = X[(long)(r0 + rr) * C + c0 + tx];
    }
    __syncthreads();
#pragma unroll
    for (int i = 0; i < 4; i++) {
        int cc = ty * 4 + i;
        T[(long)(c0 + cc) * R + r0 + tx] = __float2half(t[tx][cc] * scale);
    }
}

// ---------------------------------------------------------------------------
// Expert select + LN from fp16 ec (scaled 8192): idx = LAST expert with ew>0;
// writes LN*outDiv into out[row*outW + outOff + col] (0 if no expert).
// ---------------------------------------------------------------------------
__global__ void lnsel_k(const __half* __restrict__ ec, const float* __restrict__ ew,
                        const float* __restrict__ eg, const float* __restrict__ eb,
                        __half* __restrict__ chO, int rows, long outW, long outOff,
                        float outDiv)
{
    int row  = (blockIdx.x * blockDim.x + threadIdx.x) >> 5;
    int lane = threadIdx.x & 31;
    if (row >= rows) return;
    float w = (lane < E_) ? ew[(long)row * E_ + lane] : 0.f;
    unsigned m = __ballot_sync(0xffffffffu, w > 0.f) & 0xFFu;
    const long base = (long)row * outW + outOff + lane * 4;
    if (m == 0) {
        __half2 zz; zz.x = __float2half(0.f); zz.y = zz.x;
        *(__half2*)(chO + base) = zz; *(__half2*)(chO + base + 2) = zz;
        return;
    }
    int idx = 31 - __clz(m);
    const long eb0 = ((long)idx * NTOK + row) * 128 + lane * 4;
    __half2 e0 = *(const __half2*)(ec + eb0);
    __half2 e1 = *(const __half2*)(ec + eb0 + 2);
    const float DSC = 1.f / 8192.f;
    float4 x;
    x.x = __half2float(e0.x) * DSC; x.y = __half2float(e0.y) * DSC;
    x.z = __half2float(e1.x) * DSC; x.w = __half2float(e1.y) * DSC;
    float s  = x.x + x.y + x.z + x.w;
    float ss = fmaf(x.x, x.x, fmaf(x.y, x.y, fmaf(x.z, x.z, x.w * x.w)));
#pragma unroll
    for (int o = 16; o > 0; o >>= 1) {
        s  += __shfl_xor_sync(0xffffffffu, s,  o);
        ss += __shfl_xor_sync(0xffffffffu, ss, o);
    }
    float mn  = s * (1.f / 128.f);
    float inv = rsqrtf(ss * (1.f / 128.f) - mn * mn + 1e-5f);
    float4 gg = *(const float4*)(eg + (long)idx * 128 + lane * 4);
    float4 bb = *(const float4*)(eb + (long)idx * 128 + lane * 4);
    __half2 h0, h1;
    h0.x = __float2half(fmaf((x.x - mn) * inv, gg.x, bb.x) * outDiv);
    h0.y = __float2half(fmaf((x.y - mn) * inv, gg.y, bb.y) * outDiv);
    h1.x = __float2half(fmaf((x.z - mn) * inv, gg.z, bb.z) * outDiv);
    h1.y = __float2half(fmaf((x.w - mn) * inv, gg.w, bb.w) * outDiv);
    *(__half2*)(chO + base)     = h0;
    *(__half2*)(chO + base + 2) = h1;
}

// ---------------------------------------------------------------------------
extern "C" void kernel_launch(void* const* d_in, const int* in_sizes, int n_in,
                              void* d_out, int out_size)
{
    const float* x       = (const float*)d_in[0];
    const float* ew      = (const float*)d_in[1];
    const float* w_up    = (const float*)d_in[2];
    const float* w_gate  = (const float*)d_in[3];
    const float* w_down  = (const float*)d_in[4];
    const float* w_pre   = (const float*)d_in[5];
    const float* w_post  = (const float*)d_in[6];
    const float* an_g    = (const float*)d_in[7];
    const float* an_b    = (const float*)d_in[8];
    const float* w_aproj = (const float*)d_in[9];
    const float* w_exp   = (const float*)d_in[10];
    const float* eln_g   = (const float*)d_in[11];
    const float* eln_b   = (const float*)d_in[12];
    const float* w_eproj = (const float*)d_in[13];
    const float* w_out   = (const float*)d_in[14];
    float* out = (float*)d_out;

    float* part;
    cudaGetSymbolAddress((void**)&part, g_part);

    __half *xh,*xl,*Hdc,*wdc,*wug,*preh,*ainh,*aouth,*ech,*scrh,*aTh;
    __half *weT,*wapT,*wouth,*wexph,*wpreh,*wprel,*wpoh;
    cudaGetSymbolAddress((void**)&xh,    g_xh);   cudaGetSymbolAddress((void**)&xl,    g_xl);
    cudaGetSymbolAddress((void**)&Hdc,   g_Hdc);  cudaGetSymbolAddress((void**)&wdc,   g_wdc);
    cudaGetSymbolAddress((void**)&wug,   g_wug);  cudaGetSymbolAddress((void**)&preh,  g_preh);
    cudaGetSymbolAddress((void**)&ainh,  g_ainh); cudaGetSymbolAddress((void**)&aouth, g_aouth);
    cudaGetSymbolAddress((void**)&ech,   g_ech);
    cudaGetSymbolAddress((void**)&scrh,  g_scrh); cudaGetSymbolAddress((void**)&aTh,   g_aTh);
    cudaGetSymbolAddress((void**)&weT,   g_weT);  cudaGetSymbolAddress((void**)&wapT,  g_wapT);
    cudaGetSymbolAddress((void**)&wouth, g_wouth);cudaGetSymbolAddress((void**)&wexph, g_wexph);
    cudaGetSymbolAddress((void**)&wpreh, g_wpreh);cudaGetSymbolAddress((void**)&wprel, g_wprel);
    cudaGetSymbolAddress((void**)&wpoh,  g_wpoh);

    cudaFuncSetAttribute(tgemm_k<4,1,false,true ,false>, cudaFuncAttributeMaxDynamicSharedMemorySize, TG_SMEM);
    cudaFuncSetAttribute(tgemm_k<0,2,true ,false,true >, cudaFuncAttributeMaxDynamicSharedMemorySize, TG_SMEM);
    cudaFuncSetAttribute(tgemm_k<0,1,true ,false,true >, cudaFuncAttributeMaxDynamicSharedMemorySize, TG_SMEM);
    cudaFuncSetAttribute(tgemm_k<3,1,false,true ,false>, cudaFuncAttributeMaxDynamicSharedMemorySize, TG_SMEM);
    cudaFuncSetAttribute(tgemm_k<0,1,false,true ,false>, cudaFuncAttributeMaxDynamicSharedMemorySize, TG_SMEM);
    cudaFuncSetAttribute(tgemm_k<0,1,true ,false,false>, cudaFuncAttributeMaxDynamicSharedMemorySize, TG_SMEM);

    // 1) split x (h/l) — grid-stride
    {
        long n4 = (long)NTOK * D_ / 4;
        split_k<<<1184, 256>>>(x, xh, xl, n4);
    }

    // 2) fused weight splits
    {
        SJobs J;
        auto set = [&](int j, const float* s, __half* dh, __half* dl, long n,
                       float sc, int rowLen, int dstW, int dstOff) {
            J.src[j] = s; J.dh[j] = dh; J.dl[j] = dl;
            J.n4[j] = n / 4; J.nblk[j] = (int)((J.n4[j] + 255) / 256); J.sc[j] = sc;
            J.rowLen[j] = rowLen; J.dstW[j] = dstW; J.dstOff[j] = dstOff;
        };
        set(0, w_up,    wug,   nullptr, (long)H_ * D_,      1.f,   D_, 2*D_, 0);
        set(1, w_gate,  wug,   nullptr, (long)H_ * D_,      1.f,   D_, 2*D_, D_);
        set(2, w_down,  wdc,   nullptr, (long)D_ * H_,      1.f,   H_, KC,   0);
        set(3, w_pre,   wpreh, wprel,   (long)A_ * D_,      512.f, 0, 0, 0);
        set(4, w_post,  wpoh,  nullptr, (long)A_ * H_,      512.f, 0, 0, 0);
        set(5, w_exp,   wexph, nullptr, (long)E_ * A_ * A_, 512.f, 0, 0, 0);
        set(6, w_out,   wouth, nullptr, (long)D_ * H_,      32.f,  0, 0, 0);
        set(7, w_out,   wouth, nullptr, 0,                  1.f,   0, 0, 0);  // dummy
        J.nblk[7] = 0;
        int total = 0;
        for (int j = 0; j < 7; j++) total += J.nblk[j];
        msplit_k<<<total, 256>>>(J);
    }

    // 3) {weT, wapT} = transpose({w_eproj, w_aproj}) * 512  (one launch)
    tsplit2_k<<<dim3(H_/32, A_/32, 2), dim3(32, 8)>>>(
        w_eproj, weT, w_aproj, wapT, H_, A_, 512.f);

    // 4) Mh partials (split-K 8) -> redsum -> wdc[:,2176:2304] = 12.8*M
    //    raw sum = 16384*M -> dsH = 12.8/16384
    tgemm_k<0,1,true,false,true><<<dim3(8, D_/128, 1), 256, TG_SMEM>>>(
        wouth, nullptr, weT, nullptr, part, nullptr,
        D_, A_, H_, H_, H_, 0, 0, 0, 0, 1.f, 1.f);
    redsum_k<<<(unsigned)(((long)D_ * A_ / 4 + 255) / 256), 256>>>(
        part, wdc, 8, (long)D_ * A_, (long)D_ * A_ / 4, 12.8f / 16384.f, A_, KC, H_ + A_);

    // 5) W2 partials (A = wdc[:, :2048] fp16 w_down, split-K 8)
    //    -> redsum -> wdc[:,2048:2176] = 12.8*W2   (raw sum = 512*W2)
    tgemm_k<0,1,true,false,true><<<dim3(8, D_/128, 1), 256, TG_SMEM>>>(
        wdc, nullptr, wapT, nullptr, part, nullptr,
        D_, A_, H_, KC, H_, 0, 0, 0, 0, 1.f, 1.f);
    redsum_k<<<(unsigned)(((long)D_ * A_ / 4 + 255) / 256), 256>>>(
        part, wdc, 8, (long)D_ * A_, (long)D_ * A_ / 4, 12.8f / 512.f, A_, KC, H_);

    // 6) Hdc[:,:2048] = fp16(silu(gate)*up) — ONE interleaved GEMM (EPI=4)
    tgemm_k<4,1,false,true,false><<<dim3(2*H_/128, NTOK/128, 1), 256, TG_SMEM>>>(
        xh, nullptr, wug, nullptr, nullptr, Hdc,
        NTOK, 2*H_, D_, D_, D_, KC, 0, 0, 0, 1.f, 1.f);

    // 7) pre partials (2-pass: xh*(wpre h+l), split-K 2) -> redln:
    //    ainh + preh(raw=512*pre)
    tgemm_k<0,2,true,false,true><<<dim3(2, NTOK/128, 1), 256, TG_SMEM>>>(
        xh, nullptr, wpreh, wprel, part, nullptr,
        NTOK, A_, D_, D_, D_, 0, 0, 0, 0, 1.f, 1.f);
    redln_k<<<NTOK/8, 256>>>(part, 2, (long)NTOK * A_, an_g, an_b,
                             ainh, preh, 1.f / 512.f, NTOK);

    // 8) pt partials (split-K 2, A = Hdc cols 0:2048) -> redln: aouth
    tgemm_k<0,1,true,false,true><<<dim3(2, NTOK/128, 1), 256, TG_SMEM>>>(
        Hdc, nullptr, wpoh, nullptr, part, nullptr,
        NTOK, A_, H_, KC, H_, 0, 0, 0, 0, 1.f, 1.f);
    redln_k<<<NTOK/8, 256>>>(part, 2, (long)NTOK * A_, an_g, an_b,
                             aouth, nullptr, 1.f / 512.f, NTOK);

    // 9) scrh[b] = silu(clip(ain[b] @ aout[b]^T))
    tgemm_k<3,1,false,true,false><<<dim3(S_/128, S_/128, B_), 256, TG_SMEM>>>(
        ainh, nullptr, aouth, nullptr, nullptr, scrh,
        S_, S_, A_, A_, A_, S_, (long)S_ * A_, (long)S_ * A_, (long)S_ * S_, 1.f, 1.f);

    // 10) aTh = transpose(ainh)  (per batch)
    tsplitg_k<__half><<<dim3(S_/32, A_/32, B_), dim3(32, 8)>>>(ainh, aTh, S_, A_, 1.f);

    // 11) adp partials (split-K 2, batched z=8) -> redsum -> Hdc[:,2048:2176]=adp/128
    tgemm_k<0,1,true,false,true><<<dim3(2, S_/128, B_), 256, TG_SMEM>>>(
        scrh, nullptr, aTh, nullptr, part, nullptr,
        S_, A_, S_, S_, S_, 0, (long)S_ * S_, (long)A_ * S_, 0, 1.f, 1.f);
    redsum_k<<<(unsigned)(((long)NTOK * A_ / 4 + 255) / 256), 256>>>(
        part, Hdc, 2, (long)S_ * A_, (long)NTOK * A_ / 4, 1.f / 128.f, A_, KC, H_);

    // e1) ech_i = fp16(8192 * pre @ w_exp[i]^T)  (batched over 8 experts)
    tgemm_k<0,1,false,true,false><<<dim3(1, NTOK/128, E_), 256, TG_SMEM>>>(
        preh, nullptr, wexph, nullptr, nullptr, ech,
        NTOK, A_, A_, A_, A_, A_, 0, (long)A_ * A_, (long)NTOK * A_, 1.f / 32.f, 1.f);

    // e2) Hdc[:,2176:2304] = LN(ech[last-positive]/8192, eln) / 128  (0 if none)
    lnsel_k<<<NTOK/8, 256>>>(ech, ew, eln_g, eln_b, Hdc, NTOK, KC, H_ + A_, 1.f / 128.f);

    // 12) out = Hdc @ wdc^T over K=2304
    //        = Hid@w_down^T + 0.1*adp@W2^T + 0.1*ch@M^T
    tgemm_k<0,1,true,false,false><<<dim3(D_/128, NTOK/128, 1), 256, TG_SMEM>>>(
        Hdc, nullptr, wdc, nullptr, out, nullptr,
        NTOK, D_, KC, KC, KC, D_, 0, 0, 0, 1.f, 1.f);
}

// round 17
// speedup vs baseline: 6.9629x; 1.0170x over previous
#include <cuda_runtime.h>
#include <cuda_fp16.h>
#include <cstdint>

// ---------------------------------------------------------------------------
// LLaDAModel fused forward — mma.sync fp16 GEMMs, split-K, fused reduce+LN,
// interleaved up/gate GEMM, and triple K-concat final GEMM (aproj + expert
// paths folded into the w_down GEMM).
// B=8,S=2048,D=1024,H=2048,A=128,E=8. N=16384.
//
//   s.   split x (hi, grid-stride);  fused weight splits:
//          wug  [2H,D]: rows 2r=w_up_r, 2r+1=w_gate_r
//          wdc[:,0:2048]=w_down ; wpre*512 ; wpo*512 ; wexp*512 ; wout*32
//   0a.  {weT, wapT} = transpose({w_eproj, w_aproj})*512  (one z-batched launch)
//   0b.  Mh  partials -> redsum -> wdc[:,2176:2304] = 12.8*M
//   0c.  W2  partials (A=wdc[:, :2048]) -> redsum -> wdc[:,2048:2176]=12.8*W2
//   1.   Hdc[:,:2048] = fp16(silu(gate)*up)  — ONE GEMM vs wug (EPI=4)
//   3.   pre partials (1-pass, split-K 2) -> redln -> ainh + preh(raw*512)
//   5.   pt  partials (split-K 2, A=Hdc)  -> redln -> aouth
//   7.   scrh = silu(clip(ain @ aout^T)) per b
//   7b.  aTh  = transpose(ainh) per b
//   8.   adp partials (split-K 2, batched) -> redsum -> Hdc[:,2048:2176]=adp/128
//  e1.   ech_i = fp16(8192 * pre @ w_exp[i]^T)  (batched)
//  e2.   lnsel -> Hdc[:,2176:2304] = LN(ech[last-pos])/128
//  10.   out = Hdc @ wdc^T over K=2304
//           = Hid@w_down^T + 0.1*adp@W2^T + 0.1*ch@M^T
// ---------------------------------------------------------------------------

constexpr int B_ = 8, S_ = 2048, D_ = 1024, H_ = 2048, A_ = 128, E_ = 8;
constexpr int NTOK = B_ * S_;        // 16384
constexpr int KC = H_ + 2 * A_;      // 2304 concat-K

// fp32 scratch
__device__ float g_part[(size_t)NTOK * A_ * 4];   // split-K partials

// fp16 scratch
__device__ __half g_xh [(size_t)NTOK * D_];
__device__ __half g_Hdc[(size_t)NTOK * KC];       // [N,2304]: Hid | adp/128 | ch/128
__device__ __half g_wdc[(size_t)D_ * KC];         // [D,2304]: w_down | 12.8*W2 | 12.8*M
__device__ __half g_wug[(size_t)2 * H_ * D_];     // interleaved up/gate
__device__ __half g_preh[(size_t)NTOK * A_];
__device__ __half g_ainh[(size_t)NTOK * A_];
__device__ __half g_aouth[(size_t)NTOK * A_];
__device__ __half g_ech [(size_t)E_ * NTOK * A_];
__device__ __half g_scrh[(size_t)B_ * S_ * S_];
__device__ __half g_aTh[(size_t)B_ * A_ * S_];
__device__ __half g_weT[(size_t)A_ * H_];
__device__ __half g_wapT[(size_t)A_ * H_];
__device__ __half g_wouth[(size_t)D_ * H_];
__device__ __half g_wexph[(size_t)E_ * A_ * A_];
__device__ __half g_wpreh[(size_t)A_ * D_];
__device__ __half g_wpoh[(size_t)A_ * H_];

__device__ __forceinline__ float siluf(float x) {
    return x * (1.0f / (1.0f + __expf(-x)));
}

#define LDSM4(r0,r1,r2,r3,addr) \
    asm volatile("ldmatrix.sync.aligned.m8n8.x4.shared.b16 {%0,%1,%2,%3},[%4];\n" \
        : "=r"(r0),"=r"(r1),"=r"(r2),"=r"(r3) : "r"(addr))

#define MMA16816(c,a,b) \
    asm volatile("mma.sync.aligned.m16n8k16.row.col.f32.f16.f16.f32 " \
        "{%0,%1,%2,%3},{%4,%5,%6,%7},{%8,%9},{%0,%1,%2,%3};\n" \
        : "+f"((c)[0]),"+f"((c)[1]),"+f"((c)[2]),"+f"((c)[3]) \
        : "r"((a)[0]),"r"((a)[1]),"r"((a)[2]),"r"((a)[3]),"r"((b)[0]),"r"((b)[1]))

#define CPA16(dst,src) \
    asm volatile("cp.async.cg.shared.global [%0],[%1],16;\n" :: "r"(dst),"l"(src))

constexpr int TG_SMEM = 81920;

// ---------------------------------------------------------------------------
// Tensor GEMM: C[M,N](f32) = A[M,K](fp16) @ B[N,K](fp16)^T   (1-pass only)
// CTA tile 128x128x32, 8 warps (4x2), warp tile 32x64, m16n8k16 fp16 mma.
// lda/ldb/ldc: row strides.  SPLIT: grid.x = K-split (N must be 128), raw
// fp32 partials to C + (z*gridDim.x+blockIdx.x)*M*N.
// EPI: 0 C=acc   3 C=silu(clip(acc,±5))
//      4 (pair): Ch[r, col/2] = fp16(silu(odd)*even)  — interleaved up/gate
// ---------------------------------------------------------------------------
template<int EPI, bool WFP32, bool WH, bool SPLIT>
__global__ void __launch_bounds__(256, 2) tgemm_k(
    const __half* __restrict__ Ah, const __half* __restrict__ Bh,
    float* __restrict__ C, __half* __restrict__ Ch,
    int M, int N, int K, long lda, long ldb, long ldc,
    long sA, long sB, long sC, float ds, float hs)
{
    constexpr int NST = 4;
    constexpr int SSZ = 20480;
    constexpr unsigned BOFF = 10240u;

    extern __shared__ char smem[];
    const unsigned sbase = (unsigned)__cvta_generic_to_shared(smem);
    const int tid = threadIdx.x, lane = tid & 31, warp = tid >> 5;
    const int wm = warp >> 1, wn = warp & 1;

    const long z = blockIdx.z;
    Ah += z * sA; Bh += z * sB;
    float* Cp;
    __half* Chp = nullptr;
    if (SPLIT) {
        Cp = C + ((z * gridDim.x + blockIdx.x) * (long)M) * N;
    } else {
        Cp = WFP32 ? C + z * sC : nullptr;
        Chp = WH ? Ch + z * sC : nullptr;
    }

    const int m0 = blockIdx.y * 128;
    const int n0 = SPLIT ? 0 : blockIdx.x * 128;

    const int KT = K / 32;
    int t0k = 0, TCNT = KT;
    if (SPLIT) { TCNT = KT / gridDim.x; t0k = blockIdx.x * TCNT; }

    float acc[2][8][4];
#pragma unroll
    for (int i = 0; i < 2; i++)
#pragma unroll
        for (int j = 0; j < 8; j++)
#pragma unroll
            for (int e = 0; e < 4; e++) acc[i][j][e] = 0.f;

    const unsigned aAddr = (unsigned)((wm * 32 + (lane & 15)) * 80 + (lane >> 4) * 16);
    const unsigned bAddr = (unsigned)(BOFF +
        (wn * 64 + ((lane >> 4) << 3) + (lane & 7)) * 80 + ((lane >> 3) & 1) * 16);

    auto issue = [&](int t, int s) {
        const long k0 = (long)(t0k + t) * 32;
        const unsigned st = sbase + s * SSZ;
#pragma unroll
        for (int i = tid; i < 512; i += 256) {
            const int r = i >> 2, c = i & 3;
            const unsigned off16 = (unsigned)(r * 80 + c * 16);
            CPA16(st + off16,        Ah + (long)(m0 + r) * lda + k0 + c * 8);
            CPA16(st + BOFF + off16, Bh + (long)(n0 + r) * ldb + k0 + c * 8);
        }
        asm volatile("cp.async.commit_group;\n");
    };

    const int pre = (NST - 1 < TCNT) ? NST - 1 : TCNT;
    for (int p = 0; p < pre; p++) issue(p, p % NST);

    for (int t = 0; t < TCNT; ++t) {
        const int rem = TCNT - 1 - t;
        if (rem >= 2)      asm volatile("cp.async.wait_group 2;\n" ::: "memory");
        else if (rem == 1) asm volatile("cp.async.wait_group 1;\n" ::: "memory");
        else               asm volatile("cp.async.wait_group 0;\n" ::: "memory");
        __syncthreads();
        if (t + NST - 1 < TCNT) issue(t + NST - 1, (t + NST - 1) % NST);

        const unsigned st = sbase + (t % NST) * SSZ;
#pragma unroll
        for (int kk = 0; kk < 2; kk++) {
            const unsigned ko = kk * 32;
            unsigned ah[2][4], bh[8][2];
#pragma unroll
            for (int im = 0; im < 2; im++)
                LDSM4(ah[im][0], ah[im][1], ah[im][2], ah[im][3],
                      st + aAddr + im * 1280 + ko);
#pragma unroll
            for (int jp = 0; jp < 4; jp++)
                LDSM4(bh[2*jp][0], bh[2*jp][1], bh[2*jp+1][0], bh[2*jp+1][1],
                      st + bAddr + jp * 1280 + ko);
#pragma unroll
            for (int im = 0; im < 2; im++)
#pragma unroll
                for (int jn = 0; jn < 8; jn++) MMA16816(acc[im][jn], ah[im], bh[jn]);
        }
        __syncthreads();
    }

    // epilogue
    const int gr = lane >> 2, q = lane & 3;
#pragma unroll
    for (int im = 0; im < 2; im++) {
#pragma unroll
        for (int jn = 0; jn < 8; jn++) {
            const long r0  = m0 + wm * 32 + im * 16 + gr;
            const long col = n0 + wn * 64 + jn * 8 + q * 2;
            if (SPLIT) {   // raw partials, compact layout
                const long i0 = r0 * N + col, i1 = i0 + 8L * N;
                *(float2*)(Cp + i0) = make_float2(acc[im][jn][0], acc[im][jn][1]);
                *(float2*)(Cp + i1) = make_float2(acc[im][jn][2], acc[im][jn][3]);
                continue;
            }
            float v0 = acc[im][jn][0] * ds, v1 = acc[im][jn][1] * ds;
            float v2 = acc[im][jn][2] * ds, v3 = acc[im][jn][3] * ds;
            if (EPI == 4) {
                // interleaved up/gate: (even,odd) = (up, gate)
                const long oc = col >> 1;
                Chp[r0 * ldc + oc]       = __float2half(siluf(v1) * v0);
                Chp[(r0 + 8) * ldc + oc] = __float2half(siluf(v3) * v2);
                continue;
            }
            const long i0 = r0 * ldc + col, i1 = i0 + 8L * ldc;
            if (EPI == 3) {
                v0 = siluf(fminf(fmaxf(v0, -5.f), 5.f));
                v1 = siluf(fminf(fmaxf(v1, -5.f), 5.f));
                v2 = siluf(fminf(fmaxf(v2, -5.f), 5.f));
                v3 = siluf(fminf(fmaxf(v3, -5.f), 5.f));
            }
            if (WFP32) {
                *(float2*)(Cp + i0) = make_float2(v0, v1);
                *(float2*)(Cp + i1) = make_float2(v2, v3);
            }
            if (WH) {
                __half2 hh;
                hh.x = __float2half(v0 * hs); hh.y = __float2half(v1 * hs);
                *(__half2*)(Chp + i0) = hh;
                hh.x = __float2half(v2 * hs); hh.y = __float2half(v3 * hs);
                *(__half2*)(Chp + i1) = hh;
            }
        }
    }
}

// ---------------------------------------------------------------------------
// Split-K reduce: per-batch sum of SK partials (fixed order), fp16 out with
// row remap.  Partials: part[(z*SK + s)*MN + r].  e0 global over batches.
// dst = (e0/rowLen)*outW + outOff + e0%rowLen.
// ---------------------------------------------------------------------------
__global__ void redsum_k(const float* __restrict__ part,
                         __half* __restrict__ Yh,
                         int SK, long MN, long n4, float dsH,
                         int rowLen, int outW, int outOff)
{
    long i = blockIdx.x * (long)blockDim.x + threadIdx.x;
    if (i >= n4) return;
    long e0 = i * 4;
    long zz = e0 / MN, r = e0 - zz * MN;
    const float* p = part + (zz * SK) * MN + r;
    float4 s = *(const float4*)p;
    for (int k = 1; k < SK; k++) {
        float4 v = *(const float4*)(p + (long)k * MN);
        s.x += v.x; s.y += v.y; s.z += v.z; s.w += v.w;
    }
    long row = e0 / rowLen, col = e0 - row * rowLen;
    long d = row * outW + outOff + col;
    __half2 h0, h1;
    h0.x = __float2half(s.x * dsH); h0.y = __float2half(s.y * dsH);
    h1.x = __float2half(s.z * dsH); h1.y = __float2half(s.w * dsH);
    *(__half2*)(Yh + d)     = h0;
    *(__half2*)(Yh + d + 2) = h1;
}

// ---------------------------------------------------------------------------
// Fused split-K reduce + LayerNorm (rows of 128, one warp/row, single batch).
// sum*dsc = true values.  LN fp16 -> Yh; optional raw sum fp16 -> Ph.
// ---------------------------------------------------------------------------
__global__ void redln_k(const float* __restrict__ part, int SK, long MN,
                        const float* __restrict__ g, const float* __restrict__ b,
                        __half* __restrict__ Yh, __half* __restrict__ Ph,
                        float dsc, int rows)
{
    int row  = (blockIdx.x * blockDim.x + threadIdx.x) >> 5;
    int lane = threadIdx.x & 31;
    if (row >= rows) return;
    const long base = (long)row * 128 + lane * 4;
    float4 x = *(const float4*)(part + base);
    for (int k = 1; k < SK; k++) {
        float4 v = *(const float4*)(part + (long)k * MN + base);
        x.x += v.x; x.y += v.y; x.z += v.z; x.w += v.w;
    }
    if (Ph) {
        __half2 h0, h1;
        h0.x = __float2half(x.x); h0.y = __float2half(x.y);
        h1.x = __float2half(x.z); h1.y = __float2half(x.w);
        *(__half2*)(Ph + base)     = h0;
        *(__half2*)(Ph + base + 2) = h1;
    }
    x.x *= dsc; x.y *= dsc; x.z *= dsc; x.w *= dsc;
    float s  = x.x + x.y + x.z + x.w;
    float ss = fmaf(x.x, x.x, fmaf(x.y, x.y, fmaf(x.z, x.z, x.w * x.w)));
#pragma unroll
    for (int o = 16; o > 0; o >>= 1) {
        s  += __shfl_xor_sync(0xffffffffu, s,  o);
        ss += __shfl_xor_sync(0xffffffffu, ss, o);
    }
    float m   = s * (1.f / 128.f);
    float inv = rsqrtf(ss * (1.f / 128.f) - m * m + 1e-5f);
    float4 gg = *(const float4*)(g + lane * 4);
    float4 bb = *(const float4*)(b + lane * 4);
    __half2 h0, h1;
    h0.x = __float2half(fmaf((x.x - m) * inv, gg.x, bb.x));
    h0.y = __float2half(fmaf((x.y - m) * inv, gg.y, bb.y));
    h1.x = __float2half(fmaf((x.z - m) * inv, gg.z, bb.z));
    h1.y = __float2half(fmaf((x.w - m) * inv, gg.w, bb.w));
    *(__half2*)(Yh + base)     = h0;
    *(__half2*)(Yh + base + 2) = h1;
}

// ---------------------------------------------------------------------------
// fp32 -> fp16 hi split (x only), grid-stride for ILP
// ---------------------------------------------------------------------------
__global__ void split_k(const float* __restrict__ X,
                        __half* __restrict__ Hh, long n4)
{
    const long stride = (long)gridDim.x * blockDim.x;
    for (long i = blockIdx.x * (long)blockDim.x + threadIdx.x; i < n4; i += stride) {
        float4 v = ((const float4*)X)[i];
        __half2 h0, h1;
        h0.x = __float2half(v.x); h0.y = __float2half(v.y);
        h1.x = __float2half(v.z); h1.y = __float2half(v.w);
        ((__half2*)Hh)[2*i]   = h0;
        ((__half2*)Hh)[2*i+1] = h1;
    }
}

// ---------------------------------------------------------------------------
// Fused multi-array fp32 -> fp16 split (hi only).
// Row remap per job: dst = (e/rowLen)*dstW + dstOff + e%rowLen (dstW=0: identity)
// ---------------------------------------------------------------------------
struct SJobs {
    const float* src[8];
    __half* dh[8];
    int   nblk[8];
    long  n4[8];
    float sc[8];
    int   rowLen[8];
    int   dstW[8];
    int   dstOff[8];
};

__global__ void msplit_k(SJobs J)
{
    int b = blockIdx.x, j = 0;
    while (j < 7 && b >= J.nblk[j]) { b -= J.nblk[j]; j++; }
    long i = (long)b * 256 + threadIdx.x;
    if (i >= J.n4[j]) return;
    float sc = J.sc[j];
    float4 v = ((const float4*)J.src[j])[i];
    v.x *= sc; v.y *= sc; v.z *= sc; v.w *= sc;
    long e0 = i * 4, d = e0;
    if (J.dstW[j]) {
        long row = e0 / J.rowLen[j], col = e0 - row * J.rowLen[j];
        d = row * J.dstW[j] + J.dstOff[j] + col;
    }
    __half2 h0, h1;
    h0.x = __float2half(v.x); h0.y = __float2half(v.y);
    h1.x = __float2half(v.z); h1.y = __float2half(v.w);
    *(__half2*)(J.dh[j] + d)     = h0;
    *(__half2*)(J.dh[j] + d + 2) = h1;
}

// ---------------------------------------------------------------------------
// Transpose [R,C]->[C,R], input fp32 or fp16, out fp16(scale). grid(R/32,C/32,nz)
// ---------------------------------------------------------------------------
template<typename TI>
__global__ void tsplitg_k(const TI* __restrict__ X, __half* __restrict__ T,
                          int R, int C, float scale)
{
    __shared__ float t[32][33];
    const long zb = blockIdx.z;
    X += zb * (long)R * C;  T += zb * (long)R * C;
    const int r0 = blockIdx.x * 32, c0 = blockIdx.y * 32;
    const int tx = threadIdx.x, ty = threadIdx.y;
#pragma unroll
    for (int i = 0; i < 4; i++) {
        int rr = ty * 4 + i;
        t[rr][tx] = (float)X[(long)(r0 + rr) * C + c0 + tx];
    }
    __syncthreads();
#pragma unroll
    for (int i = 0; i < 4; i++) {
        int cc = ty * 4 + i;
        T[(long)(c0 + cc) * R + r0 + tx] = __float2half(t[tx][cc] * scale);
    }
}

// Dual-source variant: z selects (src,dst) pair; same R,C,scale for both.
__global__ void tsplit2_k(const float* __restrict__ X0, __half* __restrict__ T0,
                          const float* __restrict__ X1, __half* __restrict__ T1,
                          int R, int C, float scale)
{
    __shared__ float t[32][33];
    const float* X = blockIdx.z ? X1 : X0;
    __half* T = blockIdx.z ? T1 : T0;
    const int r0 = blockIdx.x * 32, c0 = blockIdx.y * 32;
    const int tx = threadIdx.x, ty = threadIdx.y;
#pragma unroll
    for (int i = 0; i < 4; i++) {
        int rr = ty * 4 + i;
        t[rr][tx] = X[(long)(r0 + rr) * C + c0 + tx];
    }
    __syncthreads();
#pragma unroll
    for (int i = 0; i < 4; i++) {
        int cc = ty * 4 + i;
        T[(long)(c0 + cc) * R + r0 + tx] = __float2half(t[tx][cc] * scale);
    }
}

// ---------------------------------------------------------------------------
// Expert select + LN from fp16 ec (scaled 8192): idx = LAST expert with ew>0;
// writes LN*outDiv into out[row*outW + outOff + col] (0 if no expert).
// ---------------------------------------------------------------------------
__global__ void lnsel_k(const __half* __restrict__ ec, const float* __restrict__ ew,
                        const float* __restrict__ eg, const float* __restrict__ eb,
                        __half* __restrict__ chO, int rows, long outW, long outOff,
                        float outDiv)
{
    int row  = (blockIdx.x * blockDim.x + threadIdx.x) >> 5;
    int lane = threadIdx.x & 31;
    if (row >= rows) return;
    float w = (lane < E_) ? ew[(long)row * E_ + lane] : 0.f;
    unsigned m = __ballot_sync(0xffffffffu, w > 0.f) & 0xFFu;
    const long base = (long)row * outW + outOff + lane * 4;
    if (m == 0) {
        __half2 zz; zz.x = __float2half(0.f); zz.y = zz.x;
        *(__half2*)(chO + base) = zz; *(__half2*)(chO + base + 2) = zz;
        return;
    }
    int idx = 31 - __clz(m);
    const long eb0 = ((long)idx * NTOK + row) * 128 + lane * 4;
    __half2 e0 = *(const __half2*)(ec + eb0);
    __half2 e1 = *(const __half2*)(ec + eb0 + 2);
    const float DSC = 1.f / 8192.f;
    float4 x;
    x.x = __half2float(e0.x) * DSC; x.y = __half2float(e0.y) * DSC;
    x.z = __half2float(e1.x) * DSC; x.w = __half2float(e1.y) * DSC;
    float s  = x.x + x.y + x.z + x.w;
    float ss = fmaf(x.x, x.x, fmaf(x.y, x.y, fmaf(x.z, x.z, x.w * x.w)));
#pragma unroll
    for (int o = 16; o > 0; o >>= 1) {
        s  += __shfl_xor_sync(0xffffffffu, s,  o);
        ss += __shfl_xor_sync(0xffffffffu, ss, o);
    }
    float mn  = s * (1.f / 128.f);
    float inv = rsqrtf(ss * (1.f / 128.f) - mn * mn + 1e-5f);
    float4 gg = *(const float4*)(eg + (long)idx * 128 + lane * 4);
    float4 bb = *(const float4*)(eb + (long)idx * 128 + lane * 4);
    __half2 h0, h1;
    h0.x = __float2half(fmaf((x.x - mn) * inv, gg.x, bb.x) * outDiv);
    h0.y = __float2half(fmaf((x.y - mn) * inv, gg.y, bb.y) * outDiv);
    h1.x = __float2half(fmaf((x.z - mn) * inv, gg.z, bb.z) * outDiv);
    h1.y = __float2half(fmaf((x.w - mn) * inv, gg.w, bb.w) * outDiv);
    *(__half2*)(chO + base)     = h0;
    *(__half2*)(chO + base + 2) = h1;
}

// ---------------------------------------------------------------------------
extern "C" void kernel_launch(void* const* d_in, const int* in_sizes, int n_in,
                              void* d_out, int out_size)
{
    const float* x       = (const float*)d_in[0];
    const float* ew      = (const float*)d_in[1];
    const float* w_up    = (const float*)d_in[2];
    const float* w_gate  = (const float*)d_in[3];
    const float* w_down  = (const float*)d_in[4];
    const float* w_pre   = (const float*)d_in[5];
    const float* w_post  = (const float*)d_in[6];
    const float* an_g    = (const float*)d_in[7];
    const float* an_b    = (const float*)d_in[8];
    const float* w_aproj = (const float*)d_in[9];
    const float* w_exp   = (const float*)d_in[10];
    const float* eln_g   = (const float*)d_in[11];
    const float* eln_b   = (const float*)d_in[12];
    const float* w_eproj = (const float*)d_in[13];
    const float* w_out   = (const float*)d_in[14];
    float* out = (float*)d_out;

    float* part;
    cudaGetSymbolAddress((void**)&part, g_part);

    __half *xh,*Hdc,*wdc,*wug,*preh,*ainh,*aouth,*ech,*scrh,*aTh;
    __half *weT,*wapT,*wouth,*wexph,*wpreh,*wpoh;
    cudaGetSymbolAddress((void**)&xh,    g_xh);
    cudaGetSymbolAddress((void**)&Hdc,   g_Hdc);  cudaGetSymbolAddress((void**)&wdc,   g_wdc);
    cudaGetSymbolAddress((void**)&wug,   g_wug);  cudaGetSymbolAddress((void**)&preh,  g_preh);
    cudaGetSymbolAddress((void**)&ainh,  g_ainh); cudaGetSymbolAddress((void**)&aouth, g_aouth);
    cudaGetSymbolAddress((void**)&ech,   g_ech);
    cudaGetSymbolAddress((void**)&scrh,  g_scrh); cudaGetSymbolAddress((void**)&aTh,   g_aTh);
    cudaGetSymbolAddress((void**)&weT,   g_weT);  cudaGetSymbolAddress((void**)&wapT,  g_wapT);
    cudaGetSymbolAddress((void**)&wouth, g_wouth);cudaGetSymbolAddress((void**)&wexph, g_wexph);
    cudaGetSymbolAddress((void**)&wpreh, g_wpreh);cudaGetSymbolAddress((void**)&wpoh,  g_wpoh);

    cudaFuncSetAttribute(tgemm_k<4,false,true ,false>, cudaFuncAttributeMaxDynamicSharedMemorySize, TG_SMEM);
    cudaFuncSetAttribute(tgemm_k<0,true ,false,true >, cudaFuncAttributeMaxDynamicSharedMemorySize, TG_SMEM);
    cudaFuncSetAttribute(tgemm_k<3,false,true ,false>, cudaFuncAttributeMaxDynamicSharedMemorySize, TG_SMEM);
    cudaFuncSetAttribute(tgemm_k<0,false,true ,false>, cudaFuncAttributeMaxDynamicSharedMemorySize, TG_SMEM);
    cudaFuncSetAttribute(tgemm_k<0,true ,false,false>, cudaFuncAttributeMaxDynamicSharedMemorySize, TG_SMEM);

    // 1) split x (hi only; lo is unused by any consumer) — grid-stride
    {
        long n4 = (long)NTOK * D_ / 4;
        split_k<<<1184, 256>>>(x, xh, n4);
    }

    // 2) fused weight splits
    {
        SJobs J;
        auto set = [&](int j, const float* s, __half* dh, long n,
                       float sc, int rowLen, int dstW, int dstOff) {
            J.src[j] = s; J.dh[j] = dh;
            J.n4[j] = n / 4; J.nblk[j] = (int)((J.n4[j] + 255) / 256); J.sc[j] = sc;
            J.rowLen[j] = rowLen; J.dstW[j] = dstW; J.dstOff[j] = dstOff;
        };
        set(0, w_up,    wug,   (long)H_ * D_,      1.f,   D_, 2*D_, 0);
        set(1, w_gate,  wug,   (long)H_ * D_,      1.f,   D_, 2*D_, D_);
        set(2, w_down,  wdc,   (long)D_ * H_,      1.f,   H_, KC,   0);
        set(3, w_pre,   wpreh, (long)A_ * D_,      512.f, 0, 0, 0);
        set(4, w_post,  wpoh,  (long)A_ * H_,      512.f, 0, 0, 0);
        set(5, w_exp,   wexph, (long)E_ * A_ * A_, 512.f, 0, 0, 0);
        set(6, w_out,   wouth, (long)D_ * H_,      32.f,  0, 0, 0);
        set(7, w_out,   wouth, 0,                  1.f,   0, 0, 0);  // dummy
        J.nblk[7] = 0;
        int total = 0;
        for (int j = 0; j < 7; j++) total += J.nblk[j];
        msplit_k<<<total, 256>>>(J);
    }

    // 3) {weT, wapT} = transpose({w_eproj, w_aproj}) * 512  (one launch)
    tsplit2_k<<<dim3(H_/32, A_/32, 2), dim3(32, 8)>>>(
        w_eproj, weT, w_aproj, wapT, H_, A_, 512.f);

    // 4) Mh partials (split-K 8) -> redsum -> wdc[:,2176:2304] = 12.8*M
    //    raw sum = 16384*M -> dsH = 12.8/16384
    tgemm_k<0,true,false,true><<<dim3(8, D_/128, 1), 256, TG_SMEM>>>(
        wouth, weT, part, nullptr,
        D_, A_, H_, H_, H_, 0, 0, 0, 0, 1.f, 1.f);
    redsum_k<<<(unsigned)(((long)D_ * A_ / 4 + 255) / 256), 256>>>(
        part, wdc, 8, (long)D_ * A_, (long)D_ * A_ / 4, 12.8f / 16384.f, A_, KC, H_ + A_);

    // 5) W2 partials (A = wdc[:, :2048] fp16 w_down, split-K 8)
    //    -> redsum -> wdc[:,2048:2176] = 12.8*W2   (raw sum = 512*W2)
    tgemm_k<0,true,false,true><<<dim3(8, D_/128, 1), 256, TG_SMEM>>>(
        wdc, wapT, part, nullptr,
        D_, A_, H_, KC, H_, 0, 0, 0, 0, 1.f, 1.f);
    redsum_k<<<(unsigned)(((long)D_ * A_ / 4 + 255) / 256), 256>>>(
        part, wdc, 8, (long)D_ * A_, (long)D_ * A_ / 4, 12.8f / 512.f, A_, KC, H_);

    // 6) Hdc[:,:2048] = fp16(silu(gate)*up) — ONE interleaved GEMM (EPI=4)
    tgemm_k<4,false,true,false><<<dim3(2*H_/128, NTOK/128, 1), 256, TG_SMEM>>>(
        xh, wug, nullptr, Hdc,
        NTOK, 2*H_, D_, D_, D_, KC, 0, 0, 0, 1.f, 1.f);

    // 7) pre partials (1-pass, split-K 2) -> redln: ainh + preh(raw=512*pre)
    tgemm_k<0,true,false,true><<<dim3(2, NTOK/128, 1), 256, TG_SMEM>>>(
        xh, wpreh, part, nullptr,
        NTOK, A_, D_, D_, D_, 0, 0, 0, 0, 1.f, 1.f);
    redln_k<<<NTOK/8, 256>>>(part, 2, (long)NTOK * A_, an_g, an_b,
                             ainh, preh, 1.f / 512.f, NTOK);

    // 8) pt partials (split-K 2, A = Hdc cols 0:2048) -> redln: aouth
    tgemm_k<0,true,false,true><<<dim3(2, NTOK/128, 1), 256, TG_SMEM>>>(
        Hdc, wpoh, part, nullptr,
        NTOK, A_, H_, KC, H_, 0, 0, 0, 0, 1.f, 1.f);
    redln_k<<<NTOK/8, 256>>>(part, 2, (long)NTOK * A_, an_g, an_b,
                             aouth, nullptr, 1.f / 512.f, NTOK);

    // 9) scrh[b] = silu(clip(ain[b] @ aout[b]^T))
    tgemm_k<3,false,true,false><<<dim3(S_/128, S_/128, B_), 256, TG_SMEM>>>(
        ainh, aouth, nullptr, scrh,
        S_, S_, A_, A_, A_, S_, (long)S_ * A_, (long)S_ * A_, (long)S_ * S_, 1.f, 1.f);

    // 10) aTh = transpose(ainh)  (per batch)
    tsplitg_k<__half><<<dim3(S_/32, A_/32, B_), dim3(32, 8)>>>(ainh, aTh, S_, A_, 1.f);

    // 11) adp partials (split-K 2, batched z=8) -> redsum -> Hdc[:,2048:2176]=adp/128
    tgemm_k<0,true,false,true><<<dim3(2, S_/128, B_), 256, TG_SMEM>>>(
        scrh, aTh, part, nullptr,
        S_, A_, S_, S_, S_, 0, (long)S_ * S_, (long)A_ * S_, 0, 1.f, 1.f);
    redsum_k<<<(unsigned)(((long)NTOK * A_ / 4 + 255) / 256), 256>>>(
        part, Hdc, 2, (long)S_ * A_, (long)NTOK * A_ / 4, 1.f / 128.f, A_, KC, H_);

    // e1) ech_i = fp16(8192 * pre @ w_exp[i]^T)  (batched over 8 experts)
    tgemm_k<0,false,true,false><<<dim3(1, NTOK/128, E_), 256, TG_SMEM>>>(
        preh, wexph, nullptr, ech,
        NTOK, A_, A_, A_, A_, A_, 0, (long)A_ * A_, (long)NTOK * A_, 1.f / 32.f, 1.f);

    // e2) Hdc[:,2176:2304] = LN(ech[last-positive]/8192, eln) / 128  (0 if none)
    lnsel_k<<<NTOK/8, 256>>>(ech, ew, eln_g, eln_b, Hdc, NTOK, KC, H_ + A_, 1.f / 128.f);

    // 12) out = Hdc @ wdc^T over K=2304
    //        = Hid@w_down^T + 0.1*adp@W2^T + 0.1*ch@M^T
    tgemm_k<0,true,false,false><<<dim3(D_/128, NTOK/128, 1), 256, TG_SMEM>>>(
        Hdc, wdc, out, nullptr,
        NTOK, D_, KC, KC, KC, D_, 0, 0, 0, 1.f, 1.f);
}